// round 1
// baseline (speedup 1.0000x reference)
#include <cuda_runtime.h>
#include <math.h>

#define NTOK 4096
#define DIM 768
#define DEPTH 6
#define HEADS 12
#define DH 64
#define FF 3072
#define MF 256
#define VOCAB 102
#define DNORM 0.35355339059327373f   /* 64^-0.25 */
#define RATIO 0.0625f                /* 256^-0.5 */

// ---------------- scratch (device globals, no allocation) ----------------
__device__ float g_x[NTOK * DIM];
__device__ float g_h[NTOK * DIM];
__device__ float g_q[NTOK * DIM];
__device__ float g_k[NTOK * DIM];
__device__ float g_v[NTOK * DIM];
__device__ float g_attn[NTOK * DIM];
__device__ float g_ff[NTOK * FF];
__device__ float g_qf[HEADS * NTOK * MF];
__device__ float g_kf[HEADS * NTOK * MF];   // pass1: xd, pass2: kf (in place)
__device__ float g_diagk[HEADS * NTOK];
__device__ float g_maxk[HEADS];
__device__ float g_ksum[HEADS * MF];
__device__ float g_ctx[HEADS * MF * DH];

// ---------------- helpers ----------------
__device__ __forceinline__ void atomicMaxFloat(float* addr, float val) {
    int* ia = (int*)addr;
    int old = *ia;
    while (val > __int_as_float(old)) {
        int assumed = old;
        old = atomicCAS(ia, assumed, __float_as_int(val));
        if (old == assumed) break;
    }
}

__device__ __forceinline__ float gelu_tanh(float u) {
    return 0.5f * u * (1.0f + tanhf(0.7978845608028654f * (u + 0.044715f * u * u * u)));
}

// ---------------- embedding + bucketize ----------------
__global__ void embed_kernel(const float* __restrict__ methy,
                             const int* __restrict__ chromo,
                             const int* __restrict__ pos,
                             const float* __restrict__ mt,
                             const float* __restrict__ ct,
                             const float* __restrict__ pt) {
    int n = blockIdx.x;
    float x = methy[n];
    // boundaries[:-1] = [-2, -1, 0, 0.01, ..., 0.99]; searchsorted side='left'
    int idx = (x > -2.0f) + (x > -1.0f);
    #pragma unroll 4
    for (int i = 0; i < 100; i++) idx += ((float)i * 0.01f < x) ? 1 : 0;
    int c = chromo[n], p = pos[n];
    const float* mrow = mt + (size_t)idx * DIM;
    const float* prow = pt + (size_t)p * DIM;
    const float* crow = ct + (size_t)c * DIM;
    for (int d = threadIdx.x; d < DIM; d += blockDim.x)
        g_x[n * DIM + d] = mrow[d] + prow[d] + crow[d];
}

// ---------------- layernorm (1 block / row, 256 thr) ----------------
__global__ __launch_bounds__(256) void ln_kernel(const float* __restrict__ in,
                                                 const float* __restrict__ g,
                                                 const float* __restrict__ b,
                                                 float* __restrict__ out) {
    int n = blockIdx.x, t = threadIdx.x;
    __shared__ float red[256];
    float v[3];
    float s = 0.f;
    #pragma unroll
    for (int i = 0; i < 3; i++) { v[i] = in[n * DIM + t + i * 256]; s += v[i]; }
    red[t] = s; __syncthreads();
    for (int off = 128; off > 0; off >>= 1) { if (t < off) red[t] += red[t + off]; __syncthreads(); }
    float mu = red[0] * (1.0f / DIM);
    __syncthreads();
    float s2 = 0.f;
    #pragma unroll
    for (int i = 0; i < 3; i++) { float d = v[i] - mu; s2 += d * d; }
    red[t] = s2; __syncthreads();
    for (int off = 128; off > 0; off >>= 1) { if (t < off) red[t] += red[t + off]; __syncthreads(); }
    float rstd = rsqrtf(red[0] * (1.0f / DIM) + 1e-5f);
    #pragma unroll
    for (int i = 0; i < 3; i++) {
        int d = t + i * 256;
        out[n * DIM + d] = (v[i] - mu) * rstd * g[d] + b[d];
    }
}

// ---------------- SGEMM 128x128x8, fused bias/gelu/residual ----------------
#define BM 128
#define BN 128
#define BK 8
__global__ __launch_bounds__(256) void sgemm_kernel(const float* __restrict__ A,
                                                    const float* __restrict__ B,
                                                    const float* __restrict__ bias,
                                                    const float* __restrict__ resid,
                                                    float* __restrict__ C,
                                                    int Mm, int Nn, int Kk, int act) {
    __shared__ float As[BK][BM];
    __shared__ float Bs[BK][BN];
    int t = threadIdx.x;
    int rb = blockIdx.y * BM, cb = blockIdx.x * BN;
    int arow = t >> 1, acol = (t & 1) * 4;
    int brow = t >> 5, bcol = (t & 31) * 4;
    int ty = t >> 4, tx = t & 15;
    float acc[8][8];
    #pragma unroll
    for (int i = 0; i < 8; i++)
        #pragma unroll
        for (int j = 0; j < 8; j++) acc[i][j] = 0.f;

    for (int k0 = 0; k0 < Kk; k0 += BK) {
        float4 a = *(const float4*)(A + (size_t)(rb + arow) * Kk + k0 + acol);
        As[acol + 0][arow] = a.x; As[acol + 1][arow] = a.y;
        As[acol + 2][arow] = a.z; As[acol + 3][arow] = a.w;
        *(float4*)(&Bs[brow][bcol]) = *(const float4*)(B + (size_t)(k0 + brow) * Nn + cb + bcol);
        __syncthreads();
        #pragma unroll
        for (int k = 0; k < BK; k++) {
            float4 a0 = *(float4*)&As[k][ty * 8];
            float4 a1 = *(float4*)&As[k][ty * 8 + 4];
            float4 b0 = *(float4*)&Bs[k][tx * 8];
            float4 b1 = *(float4*)&Bs[k][tx * 8 + 4];
            float ra[8] = {a0.x, a0.y, a0.z, a0.w, a1.x, a1.y, a1.z, a1.w};
            float rbv[8] = {b0.x, b0.y, b0.z, b0.w, b1.x, b1.y, b1.z, b1.w};
            #pragma unroll
            for (int i = 0; i < 8; i++)
                #pragma unroll
                for (int j = 0; j < 8; j++) acc[i][j] += ra[i] * rbv[j];
        }
        __syncthreads();
    }
    #pragma unroll
    for (int i = 0; i < 8; i++) {
        int row = rb + ty * 8 + i;
        #pragma unroll
        for (int j = 0; j < 8; j++) {
            int col = cb + tx * 8 + j;
            float val = acc[i][j];
            if (bias) val += bias[col];
            if (act) val = gelu_tanh(val);
            if (resid) val += resid[(size_t)row * Nn + col];
            C[(size_t)row * Nn + col] = val;
        }
    }
}

// ---------------- per-layer init ----------------
__global__ void init_kernel() {
    int i = blockIdx.x * blockDim.x + threadIdx.x;
    if (i < HEADS) g_maxk[i] = -1e30f;
    if (i < HEADS * MF) g_ksum[i] = 0.f;
    for (int j = i; j < HEADS * MF * DH; j += gridDim.x * blockDim.x) g_ctx[j] = 0.f;
}

// ---------------- FAVOR+ query features (per-row max) ----------------
// grid (HEADS, NTOK/32), 256 thr, dyn smem: projT[64*256] + xs[32*64] + diag[32]
__global__ __launch_bounds__(256) void featq_kernel(const float* __restrict__ proj) {
    int h = blockIdx.x, n0 = blockIdx.y * 32, t = threadIdx.x;
    extern __shared__ float sm[];
    float* projT = sm;               // [d][m]
    float* xs = sm + MF * DH;        // [r][d]
    float* diag = xs + 32 * DH;
    for (int i = t; i < MF * DH; i += 256) { int m = i >> 6, d = i & 63; projT[d * MF + m] = proj[i]; }
    for (int i = t; i < 32 * DH; i += 256) {
        int r = i >> 6, d = i & 63;
        xs[i] = g_q[(n0 + r) * DIM + h * DH + d] * DNORM;
    }
    __syncthreads();
    if (t < 32) {
        float s = 0.f;
        for (int d = 0; d < DH; d++) { float v = xs[t * DH + d]; s += v * v; }
        diag[t] = 0.5f * s;
    }
    __syncthreads();
    float acc[32];
    #pragma unroll
    for (int r = 0; r < 32; r++) acc[r] = 0.f;
    for (int d = 0; d < DH; d++) {
        float p = projT[d * MF + t];
        #pragma unroll
        for (int r = 0; r < 32; r++) acc[r] += xs[r * DH + d] * p;
    }
    __shared__ float wmax[8];
    int lane = t & 31, wid = t >> 5;
    #pragma unroll
    for (int r = 0; r < 32; r++) {
        float v = acc[r];
        for (int off = 16; off; off >>= 1) v = fmaxf(v, __shfl_xor_sync(0xffffffffu, v, off));
        if (lane == 0) wmax[wid] = v;
        __syncthreads();
        float mx = wmax[0];
        #pragma unroll
        for (int w = 1; w < 8; w++) mx = fmaxf(mx, wmax[w]);
        g_qf[((size_t)h * NTOK + n0 + r) * MF + t] = RATIO * (expf(acc[r] - diag[r] - mx) + 1e-4f);
        __syncthreads();
    }
}

// ---------------- FAVOR+ key features pass 1: xd + diag + per-head max ----------------
__global__ __launch_bounds__(256) void featk1_kernel(const float* __restrict__ proj) {
    int h = blockIdx.x, n0 = blockIdx.y * 32, t = threadIdx.x;
    extern __shared__ float sm[];
    float* projT = sm;
    float* xs = sm + MF * DH;
    float* diag = xs + 32 * DH;
    for (int i = t; i < MF * DH; i += 256) { int m = i >> 6, d = i & 63; projT[d * MF + m] = proj[i]; }
    for (int i = t; i < 32 * DH; i += 256) {
        int r = i >> 6, d = i & 63;
        xs[i] = g_k[(n0 + r) * DIM + h * DH + d] * DNORM;
    }
    __syncthreads();
    if (t < 32) {
        float s = 0.f;
        for (int d = 0; d < DH; d++) { float v = xs[t * DH + d]; s += v * v; }
        diag[t] = 0.5f * s;
        g_diagk[h * NTOK + n0 + t] = diag[t];
    }
    __syncthreads();
    float acc[32];
    #pragma unroll
    for (int r = 0; r < 32; r++) acc[r] = 0.f;
    for (int d = 0; d < DH; d++) {
        float p = projT[d * MF + t];
        #pragma unroll
        for (int r = 0; r < 32; r++) acc[r] += xs[r * DH + d] * p;
    }
    float lmax = -1e30f;
    #pragma unroll
    for (int r = 0; r < 32; r++) {
        g_kf[((size_t)h * NTOK + n0 + r) * MF + t] = acc[r];
        lmax = fmaxf(lmax, acc[r]);
    }
    for (int off = 16; off; off >>= 1) lmax = fmaxf(lmax, __shfl_xor_sync(0xffffffffu, lmax, off));
    __shared__ float wmax[8];
    int lane = t & 31, wid = t >> 5;
    if (lane == 0) wmax[wid] = lmax;
    __syncthreads();
    if (t == 0) {
        float mx = wmax[0];
        #pragma unroll
        for (int w = 1; w < 8; w++) mx = fmaxf(mx, wmax[w]);
        atomicMaxFloat(&g_maxk[h], mx);
    }
}

// ---------------- key features pass 2: exp + mask (in place) ----------------
__global__ void featk2_kernel(const float* __restrict__ methy) {
    int i = blockIdx.x * blockDim.x + threadIdx.x;   // exactly HEADS*NTOK*MF threads
    int n = (i / MF) & (NTOK - 1);
    int h = i / (NTOK * MF);
    float xd = g_kf[i];
    float m = (methy[n] != 0.0f) ? 1.0f : 0.0f;
    g_kf[i] = RATIO * (expf(xd - g_diagk[h * NTOK + n] - g_maxk[h]) + 1e-4f) * m;
}

// ---------------- k_sum[h,m] = sum_n kf ----------------
__global__ __launch_bounds__(256) void ksum_kernel() {
    int h = blockIdx.x, t = threadIdx.x;
    int n0 = blockIdx.y * 256;
    float s = 0.f;
    for (int n = n0; n < n0 + 256; n++) s += g_kf[((size_t)h * NTOK + n) * MF + t];
    atomicAdd(&g_ksum[h * MF + t], s);
}

// ---------------- ctx[h,m,d] = sum_n kf[h,n,m] * v[h,n,d] ----------------
// grid (HEADS, 16), 256 thr (thread = m), split-N with atomicAdd
__global__ __launch_bounds__(256) void ctx_kernel() {
    int h = blockIdx.x, t = threadIdx.x;
    int n0 = blockIdx.y * 256;
    __shared__ float kfs[8 * 256];
    __shared__ float4 vs4[8 * 16];
    float acc[DH];
    #pragma unroll
    for (int d = 0; d < DH; d++) acc[d] = 0.f;
    for (int c = 0; c < 256; c += 8) {
        for (int i = t; i < 8 * 256; i += 256) {
            int r = i >> 8, m = i & 255;
            kfs[i] = g_kf[((size_t)h * NTOK + n0 + c + r) * MF + m];
        }
        if (t < 128) {
            int r = t >> 4, d4 = t & 15;
            vs4[r * 16 + d4] = *(const float4*)&g_v[(n0 + c + r) * DIM + h * DH + d4 * 4];
        }
        __syncthreads();
        #pragma unroll
        for (int r = 0; r < 8; r++) {
            float kv = kfs[r * 256 + t];
            #pragma unroll
            for (int d4 = 0; d4 < 16; d4++) {
                float4 vv = vs4[r * 16 + d4];
                acc[d4 * 4 + 0] += kv * vv.x;
                acc[d4 * 4 + 1] += kv * vv.y;
                acc[d4 * 4 + 2] += kv * vv.z;
                acc[d4 * 4 + 3] += kv * vv.w;
            }
        }
        __syncthreads();
    }
    #pragma unroll
    for (int d = 0; d < DH; d++) atomicAdd(&g_ctx[(size_t)h * MF * DH + t * DH + d], acc[d]);
}

// ---------------- o = (qf @ ctx) / (qf . k_sum) ----------------
// grid (HEADS, NTOK/64), 256 thr; dyn smem: ctx[256*64] + ksum[256] + qf[4*256]
__global__ __launch_bounds__(256) void attnout_kernel() {
    int h = blockIdx.x, t = threadIdx.x;
    int n0 = blockIdx.y * 64;
    extern __shared__ float sm[];
    float* ctxs = sm;                 // [m][d]
    float* ks = sm + MF * DH;         // [m]
    float* qfs = ks + MF;             // [4][256]
    for (int i = t; i < MF * DH; i += 256) ctxs[i] = g_ctx[(size_t)h * MF * DH + i];
    ks[t] = g_ksum[h * MF + t];
    __syncthreads();
    int r = t >> 6, d = t & 63;
    for (int rr = 0; rr < 64; rr += 4) {
        for (int i = t; i < 4 * MF; i += 256)
            qfs[i] = g_qf[((size_t)h * NTOK + n0 + rr + (i >> 8)) * MF + (i & 255)];
        __syncthreads();
        float acc = 0.f, den = 0.f;
        const float* qrow = &qfs[r * MF];
        #pragma unroll 8
        for (int m = 0; m < MF; m++) {
            float qv = qrow[m];
            acc += qv * ctxs[m * DH + d];
            den += qv * ks[m];
        }
        g_attn[(n0 + rr + r) * DIM + h * DH + d] = acc / den;
        __syncthreads();
    }
}

// ---------------- output head: out = LN(x) @ Wout + bout ----------------
__global__ __launch_bounds__(128) void wout_kernel(const float* __restrict__ Wout,
                                                   const float* __restrict__ bout,
                                                   float* __restrict__ out) {
    int n = blockIdx.x, t = threadIdx.x;
    __shared__ float xs[DIM];
    for (int i = t; i < DIM; i += 128) xs[i] = g_h[n * DIM + i];
    __syncthreads();
    if (t < VOCAB) {
        float acc = bout[t];
        for (int k = 0; k < DIM; k++) acc += xs[k] * Wout[k * VOCAB + t];
        out[n * VOCAB + t] = acc;
    }
}

// ---------------- host ----------------
extern "C" void kernel_launch(void* const* d_in, const int* in_sizes, int n_in,
                              void* d_out, int out_size) {
    const float* methy = (const float*)d_in[0];
    const int* chromo = (const int*)d_in[1];
    const int* pos    = (const int*)d_in[2];
    const float* mt = (const float*)d_in[3];
    const float* ct = (const float*)d_in[4];
    const float* pt = (const float*)d_in[5];
    const float* ln1g = (const float*)d_in[6];
    const float* ln1b = (const float*)d_in[7];
    const float* ln2g = (const float*)d_in[8];
    const float* ln2b = (const float*)d_in[9];
    const float* Wq = (const float*)d_in[10];
    const float* Wk = (const float*)d_in[11];
    const float* Wv = (const float*)d_in[12];
    const float* Wo = (const float*)d_in[13];
    const float* bo = (const float*)d_in[14];
    const float* W1 = (const float*)d_in[15];
    const float* b1 = (const float*)d_in[16];
    const float* W2 = (const float*)d_in[17];
    const float* b2 = (const float*)d_in[18];
    const float* proj = (const float*)d_in[19];
    const float* nfg = (const float*)d_in[20];
    const float* nfb = (const float*)d_in[21];
    const float* Wout = (const float*)d_in[22];
    const float* bout = (const float*)d_in[23];
    float* out = (float*)d_out;

    float *px, *ph, *pq, *pk, *pv, *pattn, *pff;
    cudaGetSymbolAddress((void**)&px, g_x);
    cudaGetSymbolAddress((void**)&ph, g_h);
    cudaGetSymbolAddress((void**)&pq, g_q);
    cudaGetSymbolAddress((void**)&pk, g_k);
    cudaGetSymbolAddress((void**)&pv, g_v);
    cudaGetSymbolAddress((void**)&pattn, g_attn);
    cudaGetSymbolAddress((void**)&pff, g_ff);

    const int FEAT_SMEM = (MF * DH + 32 * DH + 32) * sizeof(float);          // ~73.9 KB
    const int ATT_SMEM  = (MF * DH + MF + 4 * MF) * sizeof(float);           // ~70.7 KB
    cudaFuncSetAttribute(featq_kernel,  cudaFuncAttributeMaxDynamicSharedMemorySize, FEAT_SMEM);
    cudaFuncSetAttribute(featk1_kernel, cudaFuncAttributeMaxDynamicSharedMemorySize, FEAT_SMEM);
    cudaFuncSetAttribute(attnout_kernel, cudaFuncAttributeMaxDynamicSharedMemorySize, ATT_SMEM);

    embed_kernel<<<NTOK, 256>>>(methy, chromo, pos, mt, ct, pt);

    dim3 g768(DIM / BN, NTOK / BM);     // (6, 32)
    dim3 gff(FF / BN, NTOK / BM);       // (24, 32)

    for (int l = 0; l < DEPTH; l++) {
        const float* pj = proj + (size_t)l * MF * DH;
        // --- attention ---
        ln_kernel<<<NTOK, 256>>>(px, ln1g + l * DIM, ln1b + l * DIM, ph);
        sgemm_kernel<<<g768, 256>>>(ph, Wq + (size_t)l * DIM * DIM, nullptr, nullptr, pq, NTOK, DIM, DIM, 0);
        sgemm_kernel<<<g768, 256>>>(ph, Wk + (size_t)l * DIM * DIM, nullptr, nullptr, pk, NTOK, DIM, DIM, 0);
        sgemm_kernel<<<g768, 256>>>(ph, Wv + (size_t)l * DIM * DIM, nullptr, nullptr, pv, NTOK, DIM, DIM, 0);
        init_kernel<<<64, 256>>>();
        featq_kernel<<<dim3(HEADS, NTOK / 32), 256, FEAT_SMEM>>>(pj);
        featk1_kernel<<<dim3(HEADS, NTOK / 32), 256, FEAT_SMEM>>>(pj);
        featk2_kernel<<<HEADS * NTOK * MF / 256, 256>>>(methy);
        ksum_kernel<<<dim3(HEADS, NTOK / 256), 256>>>();
        ctx_kernel<<<dim3(HEADS, 16), 256>>>();
        attnout_kernel<<<dim3(HEADS, NTOK / 64), 256, ATT_SMEM>>>();
        sgemm_kernel<<<g768, 256>>>(pattn, Wo + (size_t)l * DIM * DIM, bo + l * DIM, px, px, NTOK, DIM, DIM, 0);
        // --- FFN ---
        ln_kernel<<<NTOK, 256>>>(px, ln2g + l * DIM, ln2b + l * DIM, ph);
        sgemm_kernel<<<gff, 256>>>(ph, W1 + (size_t)l * DIM * FF, b1 + l * FF, nullptr, pff, NTOK, FF, DIM, 1);
        sgemm_kernel<<<g768, 256>>>(pff, W2 + (size_t)l * FF * DIM, b2 + l * DIM, px, px, NTOK, DIM, FF, 0);
    }

    ln_kernel<<<NTOK, 256>>>(px, nfg, nfb, ph);
    wout_kernel<<<NTOK, 128>>>(Wout, bout, out);
}

// round 2
// speedup vs baseline: 1.5348x; 1.5348x over previous
#include <cuda_runtime.h>
#include <math.h>
#include <stdint.h>

#define NTOK 4096
#define DIM 768
#define DEPTH 6
#define HEADS 12
#define DH 64
#define FF 3072
#define MF 256
#define VOCAB 102
#define DNORM 0.35355339059327373f   /* 64^-0.25 */
#define RATIO 0.0625f                /* 256^-0.5 */

// ---------------- scratch (device globals, no allocation) ----------------
__device__ float g_x[NTOK * DIM];
__device__ float g_h[NTOK * DIM];
__device__ float g_q[NTOK * DIM];
__device__ float g_k[NTOK * DIM];
__device__ float g_v[NTOK * DIM];
__device__ float g_attn[NTOK * DIM];
__device__ float g_ff[NTOK * FF];
__device__ float g_qf[HEADS * NTOK * MF];
__device__ float g_kf[HEADS * NTOK * MF];
__device__ float g_diagk[HEADS * NTOK];
__device__ float g_maxk[HEADS];
__device__ float g_ksum[HEADS * MF];
__device__ float g_ctx[HEADS * MF * DH];

// ---------------- helpers ----------------
__device__ __forceinline__ void atomicMaxFloat(float* addr, float val) {
    int* ia = (int*)addr;
    int old = *ia;
    while (val > __int_as_float(old)) {
        int assumed = old;
        old = atomicCAS(ia, assumed, __float_as_int(val));
        if (old == assumed) break;
    }
}

__device__ __forceinline__ float gelu_tanh(float u) {
    return 0.5f * u * (1.0f + tanhf(0.7978845608028654f * (u + 0.044715f * u * u * u)));
}

__device__ __forceinline__ float to_tf32(float x) {
    float r;
    asm("cvt.rna.tf32.f32 %0, %1;" : "=f"(r) : "f"(x));
    return r;
}

__device__ __forceinline__ void mma8(float* c, const uint32_t* a, const uint32_t* b) {
    asm volatile(
        "mma.sync.aligned.m16n8k8.row.col.f32.tf32.tf32.f32 "
        "{%0,%1,%2,%3}, {%4,%5,%6,%7}, {%8,%9}, {%0,%1,%2,%3};"
        : "+f"(c[0]), "+f"(c[1]), "+f"(c[2]), "+f"(c[3])
        : "r"(a[0]), "r"(a[1]), "r"(a[2]), "r"(a[3]), "r"(b[0]), "r"(b[1]));
}

// ---------------- embedding + bucketize ----------------
__global__ void embed_kernel(const float* __restrict__ methy,
                             const int* __restrict__ chromo,
                             const int* __restrict__ pos,
                             const float* __restrict__ mt,
                             const float* __restrict__ ct,
                             const float* __restrict__ pt) {
    int n = blockIdx.x;
    float x = methy[n];
    int idx = (x > -2.0f) + (x > -1.0f);
    #pragma unroll 4
    for (int i = 0; i < 100; i++) idx += ((float)i * 0.01f < x) ? 1 : 0;
    int c = chromo[n], p = pos[n];
    const float* mrow = mt + (size_t)idx * DIM;
    const float* prow = pt + (size_t)p * DIM;
    const float* crow = ct + (size_t)c * DIM;
    for (int d = threadIdx.x; d < DIM; d += blockDim.x)
        g_x[n * DIM + d] = mrow[d] + prow[d] + crow[d];
}

// ---------------- layernorm (1 block / row, 256 thr) ----------------
__global__ __launch_bounds__(256) void ln_kernel(const float* __restrict__ in,
                                                 const float* __restrict__ g,
                                                 const float* __restrict__ b,
                                                 float* __restrict__ out) {
    int n = blockIdx.x, t = threadIdx.x;
    __shared__ float red[256];
    float v[3];
    float s = 0.f;
    #pragma unroll
    for (int i = 0; i < 3; i++) { v[i] = in[n * DIM + t + i * 256]; s += v[i]; }
    red[t] = s; __syncthreads();
    for (int off = 128; off > 0; off >>= 1) { if (t < off) red[t] += red[t + off]; __syncthreads(); }
    float mu = red[0] * (1.0f / DIM);
    __syncthreads();
    float s2 = 0.f;
    #pragma unroll
    for (int i = 0; i < 3; i++) { float d = v[i] - mu; s2 += d * d; }
    red[t] = s2; __syncthreads();
    for (int off = 128; off > 0; off >>= 1) { if (t < off) red[t] += red[t + off]; __syncthreads(); }
    float rstd = rsqrtf(red[0] * (1.0f / DIM) + 1e-5f);
    #pragma unroll
    for (int i = 0; i < 3; i++) {
        int d = t + i * 256;
        out[n * DIM + d] = (v[i] - mu) * rstd * g[d] + b[d];
    }
}

// ---------------- TF32 tensor-core GEMM 128x128x32, fused epilogue --------
// 256 threads, 8 warps: warp grid 2(m) x 4(n), warp tile 64x32.
// A [4096,K] row-major, B [K,N] row-major. Double-buffered via register staging.
#define BM 128
#define BN 128
#define BK 32
#define ASTR 36   /* BK+4 pad */
#define BSTR 136  /* BN+8 pad */
#define AELE (BM * ASTR)  /* 4608 */
#define BELE (BK * BSTR)  /* 4352 */

__global__ __launch_bounds__(256) void tgemm_kernel(const float* __restrict__ A,
                                                    const float* __restrict__ B,
                                                    const float* __restrict__ bias,
                                                    const float* __restrict__ resid,
                                                    float* __restrict__ C,
                                                    int Nn, int Kk, int act) {
    extern __shared__ float sm[];
    float* Asm[2] = { sm, sm + AELE };
    float* Bsm[2] = { sm + 2 * AELE, sm + 2 * AELE + BELE };

    int t = threadIdx.x;
    int rb = blockIdx.y * BM, cb = blockIdx.x * BN;
    int lane = t & 31, wid = t >> 5;
    int warp_m = (wid & 1) * 64, warp_n = (wid >> 1) * 32;
    int q = lane & 3, g = lane >> 2;

    // global load indices
    int ar = t >> 3;          // 0..31 (rows ar + 32*i)
    int ac = (t & 7) * 4;
    int br = t >> 5;          // 0..7 (rows br + 8*i)
    int bc = (t & 31) * 4;

    float4 ta[4], tb[4];

    const float* Abase = A + (size_t)(rb + ar) * Kk + ac;
    const float* Bbase = B + (size_t)br * Nn + cb + bc;

    // prologue: load + store tile 0
    #pragma unroll
    for (int i = 0; i < 4; i++) ta[i] = *(const float4*)(Abase + (size_t)(32 * i) * Kk);
    #pragma unroll
    for (int i = 0; i < 4; i++) tb[i] = *(const float4*)(Bbase + (size_t)(8 * i) * Nn);
    #pragma unroll
    for (int i = 0; i < 4; i++) {
        float4 v = ta[i];
        float4 w = make_float4(to_tf32(v.x), to_tf32(v.y), to_tf32(v.z), to_tf32(v.w));
        *(float4*)&Asm[0][(ar + 32 * i) * ASTR + ac] = w;
        float4 u = tb[i];
        float4 z = make_float4(to_tf32(u.x), to_tf32(u.y), to_tf32(u.z), to_tf32(u.w));
        *(float4*)&Bsm[0][(br + 8 * i) * BSTR + bc] = z;
    }
    __syncthreads();

    float acc[4][4][4];
    #pragma unroll
    for (int mt = 0; mt < 4; mt++)
        #pragma unroll
        for (int nt = 0; nt < 4; nt++)
            #pragma unroll
            for (int e = 0; e < 4; e++) acc[mt][nt][e] = 0.f;

    int niter = Kk / BK;
    int cur = 0;
    for (int it = 0; it < niter; it++) {
        if (it + 1 < niter) {
            size_t k0n = (size_t)(it + 1) * BK;
            #pragma unroll
            for (int i = 0; i < 4; i++) ta[i] = *(const float4*)(Abase + (size_t)(32 * i) * Kk + k0n);
            #pragma unroll
            for (int i = 0; i < 4; i++) tb[i] = *(const float4*)(Bbase + ((size_t)(8 * i) + k0n) * Nn);
        }
        const float* as = Asm[cur];
        const float* bs = Bsm[cur];
        #pragma unroll
        for (int kk = 0; kk < 4; kk++) {
            int k = kk * 8;
            uint32_t af[4][4], bf[4][2];
            #pragma unroll
            for (int mt = 0; mt < 4; mt++) {
                int m = warp_m + mt * 16 + g;
                af[mt][0] = __float_as_uint(as[m * ASTR + k + q]);
                af[mt][1] = __float_as_uint(as[(m + 8) * ASTR + k + q]);
                af[mt][2] = __float_as_uint(as[m * ASTR + k + q + 4]);
                af[mt][3] = __float_as_uint(as[(m + 8) * ASTR + k + q + 4]);
            }
            #pragma unroll
            for (int nt = 0; nt < 4; nt++) {
                int n = warp_n + nt * 8 + g;
                bf[nt][0] = __float_as_uint(bs[(k + q) * BSTR + n]);
                bf[nt][1] = __float_as_uint(bs[(k + 4 + q) * BSTR + n]);
            }
            #pragma unroll
            for (int mt = 0; mt < 4; mt++)
                #pragma unroll
                for (int nt = 0; nt < 4; nt++)
                    mma8(acc[mt][nt], af[mt], bf[nt]);
        }
        if (it + 1 < niter) {
            #pragma unroll
            for (int i = 0; i < 4; i++) {
                float4 v = ta[i];
                float4 w = make_float4(to_tf32(v.x), to_tf32(v.y), to_tf32(v.z), to_tf32(v.w));
                *(float4*)&Asm[cur ^ 1][(ar + 32 * i) * ASTR + ac] = w;
                float4 u = tb[i];
                float4 z = make_float4(to_tf32(u.x), to_tf32(u.y), to_tf32(u.z), to_tf32(u.w));
                *(float4*)&Bsm[cur ^ 1][(br + 8 * i) * BSTR + bc] = z;
            }
        }
        __syncthreads();
        cur ^= 1;
    }

    // epilogue
    #pragma unroll
    for (int mt = 0; mt < 4; mt++) {
        #pragma unroll
        for (int nt = 0; nt < 4; nt++) {
            #pragma unroll
            for (int e = 0; e < 4; e++) {
                int row = rb + warp_m + mt * 16 + g + (e >> 1) * 8;
                int col = cb + warp_n + nt * 8 + q * 2 + (e & 1);
                float val = acc[mt][nt][e];
                if (bias) val += bias[col];
                if (act) val = gelu_tanh(val);
                if (resid) val += resid[(size_t)row * Nn + col];
                C[(size_t)row * Nn + col] = val;
            }
        }
    }
}

// ---------------- per-layer init ----------------
__global__ void init_kernel() {
    int i = blockIdx.x * blockDim.x + threadIdx.x;
    if (i < HEADS) g_maxk[i] = -1e30f;
    if (i < HEADS * MF) g_ksum[i] = 0.f;
    for (int j = i; j < HEADS * MF * DH; j += gridDim.x * blockDim.x) g_ctx[j] = 0.f;
}

// ---------------- FAVOR+ query features (per-row max) ----------------
__global__ __launch_bounds__(256) void featq_kernel(const float* __restrict__ proj) {
    int h = blockIdx.x, n0 = blockIdx.y * 32, t = threadIdx.x;
    extern __shared__ float sm[];
    float* projT = sm;               // [d][m]
    float* xs = sm + MF * DH;        // [r][d]
    float* diag = xs + 32 * DH;
    for (int i = t; i < MF * DH; i += 256) { int m = i >> 6, d = i & 63; projT[d * MF + m] = proj[i]; }
    for (int i = t; i < 32 * DH; i += 256) {
        int r = i >> 6, d = i & 63;
        xs[i] = g_q[(n0 + r) * DIM + h * DH + d] * DNORM;
    }
    __syncthreads();
    if (t < 32) {
        float s = 0.f;
        for (int d = 0; d < DH; d++) { float v = xs[t * DH + d]; s += v * v; }
        diag[t] = 0.5f * s;
    }
    __syncthreads();
    float acc[32];
    #pragma unroll
    for (int r = 0; r < 32; r++) acc[r] = 0.f;
    for (int d = 0; d < DH; d++) {
        float p = projT[d * MF + t];
        #pragma unroll
        for (int r = 0; r < 32; r++) acc[r] += xs[r * DH + d] * p;
    }
    __shared__ float wmax[8];
    int lane = t & 31, wid = t >> 5;
    #pragma unroll
    for (int r = 0; r < 32; r++) {
        float v = acc[r];
        for (int off = 16; off; off >>= 1) v = fmaxf(v, __shfl_xor_sync(0xffffffffu, v, off));
        if (lane == 0) wmax[wid] = v;
        __syncthreads();
        float mx = wmax[0];
        #pragma unroll
        for (int w = 1; w < 8; w++) mx = fmaxf(mx, wmax[w]);
        g_qf[((size_t)h * NTOK + n0 + r) * MF + t] = RATIO * (expf(acc[r] - diag[r] - mx) + 1e-4f);
        __syncthreads();
    }
}

// ---------------- FAVOR+ key features pass 1 ----------------
__global__ __launch_bounds__(256) void featk1_kernel(const float* __restrict__ proj) {
    int h = blockIdx.x, n0 = blockIdx.y * 32, t = threadIdx.x;
    extern __shared__ float sm[];
    float* projT = sm;
    float* xs = sm + MF * DH;
    float* diag = xs + 32 * DH;
    for (int i = t; i < MF * DH; i += 256) { int m = i >> 6, d = i & 63; projT[d * MF + m] = proj[i]; }
    for (int i = t; i < 32 * DH; i += 256) {
        int r = i >> 6, d = i & 63;
        xs[i] = g_k[(n0 + r) * DIM + h * DH + d] * DNORM;
    }
    __syncthreads();
    if (t < 32) {
        float s = 0.f;
        for (int d = 0; d < DH; d++) { float v = xs[t * DH + d]; s += v * v; }
        diag[t] = 0.5f * s;
        g_diagk[h * NTOK + n0 + t] = diag[t];
    }
    __syncthreads();
    float acc[32];
    #pragma unroll
    for (int r = 0; r < 32; r++) acc[r] = 0.f;
    for (int d = 0; d < DH; d++) {
        float p = projT[d * MF + t];
        #pragma unroll
        for (int r = 0; r < 32; r++) acc[r] += xs[r * DH + d] * p;
    }
    float lmax = -1e30f;
    #pragma unroll
    for (int r = 0; r < 32; r++) {
        g_kf[((size_t)h * NTOK + n0 + r) * MF + t] = acc[r];
        lmax = fmaxf(lmax, acc[r]);
    }
    for (int off = 16; off; off >>= 1) lmax = fmaxf(lmax, __shfl_xor_sync(0xffffffffu, lmax, off));
    __shared__ float wmax[8];
    int lane = t & 31, wid = t >> 5;
    if (lane == 0) wmax[wid] = lmax;
    __syncthreads();
    if (t == 0) {
        float mx = wmax[0];
        #pragma unroll
        for (int w = 1; w < 8; w++) mx = fmaxf(mx, wmax[w]);
        atomicMaxFloat(&g_maxk[h], mx);
    }
}

// ---------------- key features pass 2: exp + mask (in place) ----------------
__global__ void featk2_kernel(const float* __restrict__ methy) {
    int i = blockIdx.x * blockDim.x + threadIdx.x;
    int n = (i / MF) & (NTOK - 1);
    int h = i / (NTOK * MF);
    float xd = g_kf[i];
    float m = (methy[n] != 0.0f) ? 1.0f : 0.0f;
    g_kf[i] = RATIO * (expf(xd - g_diagk[h * NTOK + n] - g_maxk[h]) + 1e-4f) * m;
}

// ---------------- k_sum ----------------
__global__ __launch_bounds__(256) void ksum_kernel() {
    int h = blockIdx.x, t = threadIdx.x;
    int n0 = blockIdx.y * 256;
    float s = 0.f;
    for (int n = n0; n < n0 + 256; n++) s += g_kf[((size_t)h * NTOK + n) * MF + t];
    atomicAdd(&g_ksum[h * MF + t], s);
}

// ---------------- ctx[h,m,d] = sum_n kf[h,n,m] * v[h,n,d] ----------------
__global__ __launch_bounds__(256) void ctx_kernel() {
    int h = blockIdx.x, t = threadIdx.x;
    int n0 = blockIdx.y * 256;
    __shared__ float kfs[8 * 256];
    __shared__ float4 vs4[8 * 16];
    float acc[DH];
    #pragma unroll
    for (int d = 0; d < DH; d++) acc[d] = 0.f;
    for (int c = 0; c < 256; c += 8) {
        for (int i = t; i < 8 * 256; i += 256) {
            int r = i >> 8, m = i & 255;
            kfs[i] = g_kf[((size_t)h * NTOK + n0 + c + r) * MF + m];
        }
        if (t < 128) {
            int r = t >> 4, d4 = t & 15;
            vs4[r * 16 + d4] = *(const float4*)&g_v[(n0 + c + r) * DIM + h * DH + d4 * 4];
        }
        __syncthreads();
        #pragma unroll
        for (int r = 0; r < 8; r++) {
            float kv = kfs[r * 256 + t];
            #pragma unroll
            for (int d4 = 0; d4 < 16; d4++) {
                float4 vv = vs4[r * 16 + d4];
                acc[d4 * 4 + 0] += kv * vv.x;
                acc[d4 * 4 + 1] += kv * vv.y;
                acc[d4 * 4 + 2] += kv * vv.z;
                acc[d4 * 4 + 3] += kv * vv.w;
            }
        }
        __syncthreads();
    }
    #pragma unroll
    for (int d = 0; d < DH; d++) atomicAdd(&g_ctx[(size_t)h * MF * DH + t * DH + d], acc[d]);
}

// ---------------- o = (qf @ ctx) / (qf . k_sum) ----------------
__global__ __launch_bounds__(256) void attnout_kernel() {
    int h = blockIdx.x, t = threadIdx.x;
    int n0 = blockIdx.y * 64;
    extern __shared__ float sm[];
    float* ctxs = sm;
    float* ks = sm + MF * DH;
    float* qfs = ks + MF;
    for (int i = t; i < MF * DH; i += 256) ctxs[i] = g_ctx[(size_t)h * MF * DH + i];
    ks[t] = g_ksum[h * MF + t];
    __syncthreads();
    int r = t >> 6, d = t & 63;
    for (int rr = 0; rr < 64; rr += 4) {
        for (int i = t; i < 4 * MF; i += 256)
            qfs[i] = g_qf[((size_t)h * NTOK + n0 + rr + (i >> 8)) * MF + (i & 255)];
        __syncthreads();
        float acc = 0.f, den = 0.f;
        const float* qrow = &qfs[r * MF];
        #pragma unroll 8
        for (int m = 0; m < MF; m++) {
            float qv = qrow[m];
            acc += qv * ctxs[m * DH + d];
            den += qv * ks[m];
        }
        g_attn[(n0 + rr + r) * DIM + h * DH + d] = acc / den;
        __syncthreads();
    }
}

// ---------------- output head ----------------
__global__ __launch_bounds__(128) void wout_kernel(const float* __restrict__ Wout,
                                                   const float* __restrict__ bout,
                                                   float* __restrict__ out) {
    int n = blockIdx.x, t = threadIdx.x;
    __shared__ float xs[DIM];
    for (int i = t; i < DIM; i += 128) xs[i] = g_h[n * DIM + i];
    __syncthreads();
    if (t < VOCAB) {
        float acc = bout[t];
        for (int k = 0; k < DIM; k++) acc += xs[k] * Wout[k * VOCAB + t];
        out[n * VOCAB + t] = acc;
    }
}

// ---------------- host ----------------
extern "C" void kernel_launch(void* const* d_in, const int* in_sizes, int n_in,
                              void* d_out, int out_size) {
    const float* methy = (const float*)d_in[0];
    const int* chromo = (const int*)d_in[1];
    const int* pos    = (const int*)d_in[2];
    const float* mt = (const float*)d_in[3];
    const float* ct = (const float*)d_in[4];
    const float* pt = (const float*)d_in[5];
    const float* ln1g = (const float*)d_in[6];
    const float* ln1b = (const float*)d_in[7];
    const float* ln2g = (const float*)d_in[8];
    const float* ln2b = (const float*)d_in[9];
    const float* Wq = (const float*)d_in[10];
    const float* Wk = (const float*)d_in[11];
    const float* Wv = (const float*)d_in[12];
    const float* Wo = (const float*)d_in[13];
    const float* bo = (const float*)d_in[14];
    const float* W1 = (const float*)d_in[15];
    const float* b1 = (const float*)d_in[16];
    const float* W2 = (const float*)d_in[17];
    const float* b2 = (const float*)d_in[18];
    const float* proj = (const float*)d_in[19];
    const float* nfg = (const float*)d_in[20];
    const float* nfb = (const float*)d_in[21];
    const float* Wout = (const float*)d_in[22];
    const float* bout = (const float*)d_in[23];
    float* out = (float*)d_out;

    float *px, *ph, *pq, *pk, *pv, *pattn, *pff;
    cudaGetSymbolAddress((void**)&px, g_x);
    cudaGetSymbolAddress((void**)&ph, g_h);
    cudaGetSymbolAddress((void**)&pq, g_q);
    cudaGetSymbolAddress((void**)&pk, g_k);
    cudaGetSymbolAddress((void**)&pv, g_v);
    cudaGetSymbolAddress((void**)&pattn, g_attn);
    cudaGetSymbolAddress((void**)&pff, g_ff);

    const int FEAT_SMEM = (MF * DH + 32 * DH + 32) * sizeof(float);
    const int ATT_SMEM  = (MF * DH + MF + 4 * MF) * sizeof(float);
    const int GEMM_SMEM = 2 * (AELE + BELE) * sizeof(float);   // 71680
    cudaFuncSetAttribute(featq_kernel,  cudaFuncAttributeMaxDynamicSharedMemorySize, FEAT_SMEM);
    cudaFuncSetAttribute(featk1_kernel, cudaFuncAttributeMaxDynamicSharedMemorySize, FEAT_SMEM);
    cudaFuncSetAttribute(attnout_kernel, cudaFuncAttributeMaxDynamicSharedMemorySize, ATT_SMEM);
    cudaFuncSetAttribute(tgemm_kernel,  cudaFuncAttributeMaxDynamicSharedMemorySize, GEMM_SMEM);

    embed_kernel<<<NTOK, 256>>>(methy, chromo, pos, mt, ct, pt);

    dim3 g768(DIM / BN, NTOK / BM);     // (6, 32)
    dim3 gff(FF / BN, NTOK / BM);       // (24, 32)

    for (int l = 0; l < DEPTH; l++) {
        const float* pj = proj + (size_t)l * MF * DH;
        // --- attention ---
        ln_kernel<<<NTOK, 256>>>(px, ln1g + l * DIM, ln1b + l * DIM, ph);
        tgemm_kernel<<<g768, 256, GEMM_SMEM>>>(ph, Wq + (size_t)l * DIM * DIM, nullptr, nullptr, pq, DIM, DIM, 0);
        tgemm_kernel<<<g768, 256, GEMM_SMEM>>>(ph, Wk + (size_t)l * DIM * DIM, nullptr, nullptr, pk, DIM, DIM, 0);
        tgemm_kernel<<<g768, 256, GEMM_SMEM>>>(ph, Wv + (size_t)l * DIM * DIM, nullptr, nullptr, pv, DIM, DIM, 0);
        init_kernel<<<64, 256>>>();
        featq_kernel<<<dim3(HEADS, NTOK / 32), 256, FEAT_SMEM>>>(pj);
        featk1_kernel<<<dim3(HEADS, NTOK / 32), 256, FEAT_SMEM>>>(pj);
        featk2_kernel<<<HEADS * NTOK * MF / 256, 256>>>(methy);
        ksum_kernel<<<dim3(HEADS, NTOK / 256), 256>>>();
        ctx_kernel<<<dim3(HEADS, 16), 256>>>();
        attnout_kernel<<<dim3(HEADS, NTOK / 64), 256, ATT_SMEM>>>();
        tgemm_kernel<<<g768, 256, GEMM_SMEM>>>(pattn, Wo + (size_t)l * DIM * DIM, bo + l * DIM, px, px, DIM, DIM, 0);
        // --- FFN ---
        ln_kernel<<<NTOK, 256>>>(px, ln2g + l * DIM, ln2b + l * DIM, ph);
        tgemm_kernel<<<gff, 256, GEMM_SMEM>>>(ph, W1 + (size_t)l * DIM * FF, b1 + l * FF, nullptr, pff, FF, DIM, 1);
        tgemm_kernel<<<g768, 256, GEMM_SMEM>>>(pff, W2 + (size_t)l * FF * DIM, b2 + l * DIM, px, px, DIM, FF, 0);
    }

    ln_kernel<<<NTOK, 256>>>(px, nfg, nfb, ph);
    wout_kernel<<<NTOK, 128>>>(Wout, bout, out);
}

// round 3
// speedup vs baseline: 1.8133x; 1.1815x over previous
#include <cuda_runtime.h>
#include <math.h>
#include <stdint.h>

#define NTOK 4096
#define DIM 768
#define DEPTH 6
#define HEADS 12
#define DH 64
#define FF 3072
#define MF 256
#define VOCAB 102
#define DNORM 0.35355339059327373f   /* 64^-0.25 */
#define RATIO 0.0625f                /* 256^-0.5 */

// ---------------- scratch (device globals, no allocation) ----------------
__device__ float g_x[NTOK * DIM];
__device__ float g_h[NTOK * DIM];
__device__ float g_q[NTOK * DIM];
__device__ float g_k[NTOK * DIM];
__device__ float g_v[NTOK * DIM];
__device__ float g_attn[NTOK * DIM];
__device__ float g_ff[NTOK * FF];
__device__ float g_qf[HEADS * NTOK * MF];
__device__ float g_kf[HEADS * NTOK * MF];
__device__ float g_diagk[HEADS * NTOK];
__device__ float g_maxk[HEADS];
__device__ float g_ksum[HEADS * MF];
__device__ float g_ctx[HEADS * MF * DH];

// ---------------- helpers ----------------
__device__ __forceinline__ void atomicMaxFloat(float* addr, float val) {
    int* ia = (int*)addr;
    int old = *ia;
    while (val > __int_as_float(old)) {
        int assumed = old;
        old = atomicCAS(ia, assumed, __float_as_int(val));
        if (old == assumed) break;
    }
}

__device__ __forceinline__ float gelu_tanh(float u) {
    return 0.5f * u * (1.0f + tanhf(0.7978845608028654f * (u + 0.044715f * u * u * u)));
}

__device__ __forceinline__ float to_tf32(float x) {
    float r;
    asm("cvt.rna.tf32.f32 %0, %1;" : "=f"(r) : "f"(x));
    return r;
}

__device__ __forceinline__ void mma8(float* c, const uint32_t* a, const uint32_t* b) {
    asm volatile(
        "mma.sync.aligned.m16n8k8.row.col.f32.tf32.tf32.f32 "
        "{%0,%1,%2,%3}, {%4,%5,%6,%7}, {%8,%9}, {%0,%1,%2,%3};"
        : "+f"(c[0]), "+f"(c[1]), "+f"(c[2]), "+f"(c[3])
        : "r"(a[0]), "r"(a[1]), "r"(a[2]), "r"(a[3]), "r"(b[0]), "r"(b[1]));
}

// ---------------- embedding + bucketize ----------------
__global__ void embed_kernel(const float* __restrict__ methy,
                             const int* __restrict__ chromo,
                             const int* __restrict__ pos,
                             const float* __restrict__ mt,
                             const float* __restrict__ ct,
                             const float* __restrict__ pt) {
    int n = blockIdx.x;
    float x = methy[n];
    int idx = (x > -2.0f) + (x > -1.0f);
    #pragma unroll 4
    for (int i = 0; i < 100; i++) idx += ((float)i * 0.01f < x) ? 1 : 0;
    int c = chromo[n], p = pos[n];
    const float* mrow = mt + (size_t)idx * DIM;
    const float* prow = pt + (size_t)p * DIM;
    const float* crow = ct + (size_t)c * DIM;
    for (int d = threadIdx.x; d < DIM; d += blockDim.x)
        g_x[n * DIM + d] = mrow[d] + prow[d] + crow[d];
}

// ---------------- layernorm ----------------
__global__ __launch_bounds__(256) void ln_kernel(const float* __restrict__ in,
                                                 const float* __restrict__ g,
                                                 const float* __restrict__ b,
                                                 float* __restrict__ out) {
    int n = blockIdx.x, t = threadIdx.x;
    __shared__ float red[256];
    float v[3];
    float s = 0.f;
    #pragma unroll
    for (int i = 0; i < 3; i++) { v[i] = in[n * DIM + t + i * 256]; s += v[i]; }
    red[t] = s; __syncthreads();
    for (int off = 128; off > 0; off >>= 1) { if (t < off) red[t] += red[t + off]; __syncthreads(); }
    float mu = red[0] * (1.0f / DIM);
    __syncthreads();
    float s2 = 0.f;
    #pragma unroll
    for (int i = 0; i < 3; i++) { float d = v[i] - mu; s2 += d * d; }
    red[t] = s2; __syncthreads();
    for (int off = 128; off > 0; off >>= 1) { if (t < off) red[t] += red[t + off]; __syncthreads(); }
    float rstd = rsqrtf(red[0] * (1.0f / DIM) + 1e-5f);
    #pragma unroll
    for (int i = 0; i < 3; i++) {
        int d = t + i * 256;
        out[n * DIM + d] = (v[i] - mu) * rstd * g[d] + b[d];
    }
}

// ---------------- TF32 tensor-core GEMM 128x128x16, 2 CTA/SM --------------
#define BM 128
#define BN 128
#define BK 16
#define ASTR 20   /* BK+4 pad */
#define BSTR 136  /* BN+8 pad */
#define AELE (BM * ASTR)  /* 2560 */
#define BELE (BK * BSTR)  /* 2176 */

__global__ __launch_bounds__(256, 2) void tgemm_kernel(const float* __restrict__ A,
                                                       const float* __restrict__ B,
                                                       const float* __restrict__ bias,
                                                       const float* __restrict__ resid,
                                                       float* __restrict__ C,
                                                       int Nn, int Kk, int act) {
    __shared__ float Asm[2][AELE];
    __shared__ float Bsm[2][BELE];

    int t = threadIdx.x;
    int rb = blockIdx.y * BM, cb = blockIdx.x * BN;
    int lane = t & 31, wid = t >> 5;
    int warp_m = (wid & 1) * 64, warp_n = (wid >> 1) * 32;
    int q = lane & 3, g = lane >> 2;

    // global load indices
    int ar = t >> 2;          // 0..63, rows ar, ar+64
    int ac = (t & 3) * 4;     // 0,4,8,12
    int br = t >> 5;          // 0..7, rows br, br+8
    int bc = (t & 31) * 4;

    float4 ta[2], tb[2];

    const float* Abase = A + (size_t)(rb + ar) * Kk + ac;
    const float* Bbase = B + (size_t)br * Nn + cb + bc;

    // prologue
    #pragma unroll
    for (int i = 0; i < 2; i++) ta[i] = *(const float4*)(Abase + (size_t)(64 * i) * Kk);
    #pragma unroll
    for (int i = 0; i < 2; i++) tb[i] = *(const float4*)(Bbase + (size_t)(8 * i) * Nn);
    #pragma unroll
    for (int i = 0; i < 2; i++) {
        float4 v = ta[i];
        *(float4*)&Asm[0][(ar + 64 * i) * ASTR + ac] =
            make_float4(to_tf32(v.x), to_tf32(v.y), to_tf32(v.z), to_tf32(v.w));
        float4 u = tb[i];
        *(float4*)&Bsm[0][(br + 8 * i) * BSTR + bc] =
            make_float4(to_tf32(u.x), to_tf32(u.y), to_tf32(u.z), to_tf32(u.w));
    }
    __syncthreads();

    float acc[4][4][4];
    #pragma unroll
    for (int mt = 0; mt < 4; mt++)
        #pragma unroll
        for (int nt = 0; nt < 4; nt++)
            #pragma unroll
            for (int e = 0; e < 4; e++) acc[mt][nt][e] = 0.f;

    int niter = Kk / BK;
    int cur = 0;
    for (int it = 0; it < niter; it++) {
        if (it + 1 < niter) {
            size_t k0n = (size_t)(it + 1) * BK;
            #pragma unroll
            for (int i = 0; i < 2; i++) ta[i] = *(const float4*)(Abase + (size_t)(64 * i) * Kk + k0n);
            #pragma unroll
            for (int i = 0; i < 2; i++) tb[i] = *(const float4*)(Bbase + ((size_t)(8 * i) + k0n) * Nn);
        }
        const float* as = Asm[cur];
        const float* bs = Bsm[cur];
        #pragma unroll
        for (int kk = 0; kk < 2; kk++) {
            int k = kk * 8;
            uint32_t af[4][4], bf[4][2];
            #pragma unroll
            for (int mt = 0; mt < 4; mt++) {
                int m = warp_m + mt * 16 + g;
                af[mt][0] = __float_as_uint(as[m * ASTR + k + q]);
                af[mt][1] = __float_as_uint(as[(m + 8) * ASTR + k + q]);
                af[mt][2] = __float_as_uint(as[m * ASTR + k + q + 4]);
                af[mt][3] = __float_as_uint(as[(m + 8) * ASTR + k + q + 4]);
            }
            #pragma unroll
            for (int nt = 0; nt < 4; nt++) {
                int n = warp_n + nt * 8 + g;
                bf[nt][0] = __float_as_uint(bs[(k + q) * BSTR + n]);
                bf[nt][1] = __float_as_uint(bs[(k + 4 + q) * BSTR + n]);
            }
            #pragma unroll
            for (int mt = 0; mt < 4; mt++)
                #pragma unroll
                for (int nt = 0; nt < 4; nt++)
                    mma8(acc[mt][nt], af[mt], bf[nt]);
        }
        if (it + 1 < niter) {
            #pragma unroll
            for (int i = 0; i < 2; i++) {
                float4 v = ta[i];
                *(float4*)&Asm[cur ^ 1][(ar + 64 * i) * ASTR + ac] =
                    make_float4(to_tf32(v.x), to_tf32(v.y), to_tf32(v.z), to_tf32(v.w));
                float4 u = tb[i];
                *(float4*)&Bsm[cur ^ 1][(br + 8 * i) * BSTR + bc] =
                    make_float4(to_tf32(u.x), to_tf32(u.y), to_tf32(u.z), to_tf32(u.w));
            }
        }
        __syncthreads();
        cur ^= 1;
    }

    // epilogue
    #pragma unroll
    for (int mt = 0; mt < 4; mt++) {
        #pragma unroll
        for (int nt = 0; nt < 4; nt++) {
            #pragma unroll
            for (int e = 0; e < 4; e++) {
                int row = rb + warp_m + mt * 16 + g + (e >> 1) * 8;
                int col = cb + warp_n + nt * 8 + q * 2 + (e & 1);
                float val = acc[mt][nt][e];
                if (bias) val += bias[col];
                if (act) val = gelu_tanh(val);
                if (resid) val += resid[(size_t)row * Nn + col];
                C[(size_t)row * Nn + col] = val;
            }
        }
    }
}

// ---------------- per-layer init ----------------
__global__ void init_kernel() {
    int i = blockIdx.x * blockDim.x + threadIdx.x;
    if (i < HEADS) g_maxk[i] = -1e30f;
    if (i < HEADS * MF) g_ksum[i] = 0.f;
    for (int j = i; j < HEADS * MF * DH; j += gridDim.x * blockDim.x) g_ctx[j] = 0.f;
}

// ---------------- FAVOR+ query features (3 barriers total) ----------------
// dyn smem: projT[256*64] + xs[32*64] + diag[32] + xd[32*256] + rmax[32]
__global__ __launch_bounds__(256) void featq_kernel(const float* __restrict__ proj) {
    int h = blockIdx.x, n0 = blockIdx.y * 32, t = threadIdx.x;
    extern __shared__ float sm[];
    float* projT = sm;                   // [d][m]
    float* xs = sm + MF * DH;            // [r][d]
    float* diag = xs + 32 * DH;          // [32]
    float* xd = diag + 32;               // [r][m]
    float* rmax = xd + 32 * MF;          // [32]
    for (int i = t; i < MF * DH; i += 256) { int m = i >> 6, d = i & 63; projT[d * MF + m] = proj[i]; }
    for (int i = t; i < 32 * DH; i += 256) {
        int r = i >> 6, d = i & 63;
        xs[i] = g_q[(n0 + r) * DIM + h * DH + d] * DNORM;
    }
    __syncthreads();
    if (t < 32) {
        float s = 0.f;
        for (int d = 0; d < DH; d++) { float v = xs[t * DH + d]; s += v * v; }
        diag[t] = 0.5f * s;
    }
    float acc[32];
    #pragma unroll
    for (int r = 0; r < 32; r++) acc[r] = 0.f;
    for (int d = 0; d < DH; d++) {
        float p = projT[d * MF + t];
        #pragma unroll
        for (int r = 0; r < 32; r++) acc[r] += xs[r * DH + d] * p;
    }
    #pragma unroll
    for (int r = 0; r < 32; r++) xd[r * MF + t] = acc[r];
    __syncthreads();
    int lane = t & 31, w = t >> 5;
    #pragma unroll
    for (int rr = 0; rr < 4; rr++) {
        int r = w * 4 + rr;
        float v = -1e30f;
        #pragma unroll
        for (int j = 0; j < 8; j++) v = fmaxf(v, xd[r * MF + lane + 32 * j]);
        for (int off = 16; off; off >>= 1) v = fmaxf(v, __shfl_xor_sync(0xffffffffu, v, off));
        if (lane == 0) rmax[r] = v;
    }
    __syncthreads();
    #pragma unroll
    for (int r = 0; r < 32; r++)
        g_qf[((size_t)h * NTOK + n0 + r) * MF + t] = RATIO * (expf(acc[r] - diag[r] - rmax[r]) + 1e-4f);
}

// ---------------- FAVOR+ key features pass 1 ----------------
__global__ __launch_bounds__(256) void featk1_kernel(const float* __restrict__ proj) {
    int h = blockIdx.x, n0 = blockIdx.y * 32, t = threadIdx.x;
    extern __shared__ float sm[];
    float* projT = sm;
    float* xs = sm + MF * DH;
    float* diag = xs + 32 * DH;
    for (int i = t; i < MF * DH; i += 256) { int m = i >> 6, d = i & 63; projT[d * MF + m] = proj[i]; }
    for (int i = t; i < 32 * DH; i += 256) {
        int r = i >> 6, d = i & 63;
        xs[i] = g_k[(n0 + r) * DIM + h * DH + d] * DNORM;
    }
    __syncthreads();
    if (t < 32) {
        float s = 0.f;
        for (int d = 0; d < DH; d++) { float v = xs[t * DH + d]; s += v * v; }
        diag[t] = 0.5f * s;
        g_diagk[h * NTOK + n0 + t] = diag[t];
    }
    __syncthreads();
    float acc[32];
    #pragma unroll
    for (int r = 0; r < 32; r++) acc[r] = 0.f;
    for (int d = 0; d < DH; d++) {
        float p = projT[d * MF + t];
        #pragma unroll
        for (int r = 0; r < 32; r++) acc[r] += xs[r * DH + d] * p;
    }
    float lmax = -1e30f;
    #pragma unroll
    for (int r = 0; r < 32; r++) {
        g_kf[((size_t)h * NTOK + n0 + r) * MF + t] = acc[r];
        lmax = fmaxf(lmax, acc[r]);
    }
    for (int off = 16; off; off >>= 1) lmax = fmaxf(lmax, __shfl_xor_sync(0xffffffffu, lmax, off));
    __shared__ float wmax[8];
    int lane = t & 31, wid = t >> 5;
    if (lane == 0) wmax[wid] = lmax;
    __syncthreads();
    if (t == 0) {
        float mx = wmax[0];
        #pragma unroll
        for (int w = 1; w < 8; w++) mx = fmaxf(mx, wmax[w]);
        atomicMaxFloat(&g_maxk[h], mx);
    }
}

// ---------------- key features pass 2 ----------------
__global__ void featk2_kernel(const float* __restrict__ methy) {
    int i = blockIdx.x * blockDim.x + threadIdx.x;
    int n = (i / MF) & (NTOK - 1);
    int h = i / (NTOK * MF);
    float xd = g_kf[i];
    float m = (methy[n] != 0.0f) ? 1.0f : 0.0f;
    g_kf[i] = RATIO * (expf(xd - g_diagk[h * NTOK + n] - g_maxk[h]) + 1e-4f) * m;
}

// ---------------- k_sum ----------------
__global__ __launch_bounds__(256) void ksum_kernel() {
    int h = blockIdx.x, t = threadIdx.x;
    int n0 = blockIdx.y * 256;
    float s = 0.f;
    for (int n = n0; n < n0 + 256; n++) s += g_kf[((size_t)h * NTOK + n) * MF + t];
    atomicAdd(&g_ksum[h * MF + t], s);
}

// ---------------- ctx ----------------
__global__ __launch_bounds__(256) void ctx_kernel() {
    int h = blockIdx.x, t = threadIdx.x;
    int n0 = blockIdx.y * 256;
    __shared__ float kfs[8 * 256];
    __shared__ float4 vs4[8 * 16];
    float acc[DH];
    #pragma unroll
    for (int d = 0; d < DH; d++) acc[d] = 0.f;
    for (int c = 0; c < 256; c += 8) {
        for (int i = t; i < 8 * 256; i += 256) {
            int r = i >> 8, m = i & 255;
            kfs[i] = g_kf[((size_t)h * NTOK + n0 + c + r) * MF + m];
        }
        if (t < 128) {
            int r = t >> 4, d4 = t & 15;
            vs4[r * 16 + d4] = *(const float4*)&g_v[(n0 + c + r) * DIM + h * DH + d4 * 4];
        }
        __syncthreads();
        #pragma unroll
        for (int r = 0; r < 8; r++) {
            float kv = kfs[r * 256 + t];
            #pragma unroll
            for (int d4 = 0; d4 < 16; d4++) {
                float4 vv = vs4[r * 16 + d4];
                acc[d4 * 4 + 0] += kv * vv.x;
                acc[d4 * 4 + 1] += kv * vv.y;
                acc[d4 * 4 + 2] += kv * vv.z;
                acc[d4 * 4 + 3] += kv * vv.w;
            }
        }
        __syncthreads();
    }
    #pragma unroll
    for (int d = 0; d < DH; d++) atomicAdd(&g_ctx[(size_t)h * MF * DH + t * DH + d], acc[d]);
}

// ---------------- o = (qf @ ctx) / (qf . k_sum) ----------------
__global__ __launch_bounds__(256) void attnout_kernel() {
    int h = blockIdx.x, t = threadIdx.x;
    int n0 = blockIdx.y * 64;
    extern __shared__ float sm[];
    float* ctxs = sm;
    float* ks = sm + MF * DH;
    float* qfs = ks + MF;
    for (int i = t; i < MF * DH; i += 256) ctxs[i] = g_ctx[(size_t)h * MF * DH + i];
    ks[t] = g_ksum[h * MF + t];
    __syncthreads();
    int r = t >> 6, d = t & 63;
    for (int rr = 0; rr < 64; rr += 4) {
        for (int i = t; i < 4 * MF; i += 256)
            qfs[i] = g_qf[((size_t)h * NTOK + n0 + rr + (i >> 8)) * MF + (i & 255)];
        __syncthreads();
        float acc = 0.f, den = 0.f;
        const float* qrow = &qfs[r * MF];
        #pragma unroll 8
        for (int m = 0; m < MF; m++) {
            float qv = qrow[m];
            acc += qv * ctxs[m * DH + d];
            den += qv * ks[m];
        }
        g_attn[(n0 + rr + r) * DIM + h * DH + d] = acc / den;
        __syncthreads();
    }
}

// ---------------- output head ----------------
__global__ __launch_bounds__(128) void wout_kernel(const float* __restrict__ Wout,
                                                   const float* __restrict__ bout,
                                                   float* __restrict__ out) {
    int n = blockIdx.x, t = threadIdx.x;
    __shared__ float xs[DIM];
    for (int i = t; i < DIM; i += 128) xs[i] = g_h[n * DIM + i];
    __syncthreads();
    if (t < VOCAB) {
        float acc = bout[t];
        for (int k = 0; k < DIM; k++) acc += xs[k] * Wout[k * VOCAB + t];
        out[n * VOCAB + t] = acc;
    }
}

// ---------------- host ----------------
extern "C" void kernel_launch(void* const* d_in, const int* in_sizes, int n_in,
                              void* d_out, int out_size) {
    const float* methy = (const float*)d_in[0];
    const int* chromo = (const int*)d_in[1];
    const int* pos    = (const int*)d_in[2];
    const float* mt = (const float*)d_in[3];
    const float* ct = (const float*)d_in[4];
    const float* pt = (const float*)d_in[5];
    const float* ln1g = (const float*)d_in[6];
    const float* ln1b = (const float*)d_in[7];
    const float* ln2g = (const float*)d_in[8];
    const float* ln2b = (const float*)d_in[9];
    const float* Wq = (const float*)d_in[10];
    const float* Wk = (const float*)d_in[11];
    const float* Wv = (const float*)d_in[12];
    const float* Wo = (const float*)d_in[13];
    const float* bo = (const float*)d_in[14];
    const float* W1 = (const float*)d_in[15];
    const float* b1 = (const float*)d_in[16];
    const float* W2 = (const float*)d_in[17];
    const float* b2 = (const float*)d_in[18];
    const float* proj = (const float*)d_in[19];
    const float* nfg = (const float*)d_in[20];
    const float* nfb = (const float*)d_in[21];
    const float* Wout = (const float*)d_in[22];
    const float* bout = (const float*)d_in[23];
    float* out = (float*)d_out;

    float *px, *ph, *pq, *pk, *pv, *pattn, *pff;
    cudaGetSymbolAddress((void**)&px, g_x);
    cudaGetSymbolAddress((void**)&ph, g_h);
    cudaGetSymbolAddress((void**)&pq, g_q);
    cudaGetSymbolAddress((void**)&pk, g_k);
    cudaGetSymbolAddress((void**)&pv, g_v);
    cudaGetSymbolAddress((void**)&pattn, g_attn);
    cudaGetSymbolAddress((void**)&pff, g_ff);

    const int FEATQ_SMEM = (MF * DH + 32 * DH + 32 + 32 * MF + 32) * sizeof(float); // 106,752
    const int FEATK_SMEM = (MF * DH + 32 * DH + 32) * sizeof(float);                // 73,856
    const int ATT_SMEM   = (MF * DH + MF + 4 * MF) * sizeof(float);
    cudaFuncSetAttribute(featq_kernel,  cudaFuncAttributeMaxDynamicSharedMemorySize, FEATQ_SMEM);
    cudaFuncSetAttribute(featk1_kernel, cudaFuncAttributeMaxDynamicSharedMemorySize, FEATK_SMEM);
    cudaFuncSetAttribute(attnout_kernel, cudaFuncAttributeMaxDynamicSharedMemorySize, ATT_SMEM);

    embed_kernel<<<NTOK, 256>>>(methy, chromo, pos, mt, ct, pt);

    dim3 g768(DIM / BN, NTOK / BM);     // (6, 32)
    dim3 gff(FF / BN, NTOK / BM);       // (24, 32)

    for (int l = 0; l < DEPTH; l++) {
        const float* pj = proj + (size_t)l * MF * DH;
        // --- attention ---
        ln_kernel<<<NTOK, 256>>>(px, ln1g + l * DIM, ln1b + l * DIM, ph);
        tgemm_kernel<<<g768, 256>>>(ph, Wq + (size_t)l * DIM * DIM, nullptr, nullptr, pq, DIM, DIM, 0);
        tgemm_kernel<<<g768, 256>>>(ph, Wk + (size_t)l * DIM * DIM, nullptr, nullptr, pk, DIM, DIM, 0);
        tgemm_kernel<<<g768, 256>>>(ph, Wv + (size_t)l * DIM * DIM, nullptr, nullptr, pv, DIM, DIM, 0);
        init_kernel<<<64, 256>>>();
        featq_kernel<<<dim3(HEADS, NTOK / 32), 256, FEATQ_SMEM>>>(pj);
        featk1_kernel<<<dim3(HEADS, NTOK / 32), 256, FEATK_SMEM>>>(pj);
        featk2_kernel<<<HEADS * NTOK * MF / 256, 256>>>(methy);
        ksum_kernel<<<dim3(HEADS, NTOK / 256), 256>>>();
        ctx_kernel<<<dim3(HEADS, 16), 256>>>();
        attnout_kernel<<<dim3(HEADS, NTOK / 64), 256, ATT_SMEM>>>();
        tgemm_kernel<<<g768, 256>>>(pattn, Wo + (size_t)l * DIM * DIM, bo + l * DIM, px, px, DIM, DIM, 0);
        // --- FFN ---
        ln_kernel<<<NTOK, 256>>>(px, ln2g + l * DIM, ln2b + l * DIM, ph);
        tgemm_kernel<<<gff, 256>>>(ph, W1 + (size_t)l * DIM * FF, b1 + l * FF, nullptr, pff, FF, DIM, 1);
        tgemm_kernel<<<g768, 256>>>(pff, W2 + (size_t)l * FF * DIM, b2 + l * DIM, px, px, DIM, FF, 0);
    }

    ln_kernel<<<NTOK, 256>>>(px, nfg, nfb, ph);
    wout_kernel<<<NTOK, 128>>>(Wout, bout, out);
}

// round 4
// speedup vs baseline: 2.0378x; 1.1238x over previous
#include <cuda_runtime.h>
#include <math.h>
#include <stdint.h>

#define NTOK 4096
#define DIM 768
#define DEPTH 6
#define HEADS 12
#define DH 64
#define FF 3072
#define MF 256
#define VOCAB 102
#define DNORM 0.35355339059327373f   /* 64^-0.25 */
#define RATIO 0.0625f                /* 256^-0.5 */

// ---------------- scratch (device globals, no allocation) ----------------
__device__ float g_x[NTOK * DIM];
__device__ float g_h[NTOK * DIM];
__device__ float g_q[NTOK * DIM];
__device__ float g_k[NTOK * DIM];
__device__ float g_v[NTOK * DIM];
__device__ float g_attn[NTOK * DIM];
__device__ float g_ff[NTOK * FF];
__device__ float g_qf[HEADS * NTOK * MF];
__device__ float g_kf[HEADS * NTOK * MF];
__device__ float g_diagk[HEADS * NTOK];
__device__ float g_maxk[HEADS];
__device__ float g_ksum[HEADS * MF];
__device__ float g_ctx[HEADS * MF * DH];

// ---------------- helpers ----------------
__device__ __forceinline__ void atomicMaxFloat(float* addr, float val) {
    int* ia = (int*)addr;
    int old = *ia;
    while (val > __int_as_float(old)) {
        int assumed = old;
        old = atomicCAS(ia, assumed, __float_as_int(val));
        if (old == assumed) break;
    }
}

__device__ __forceinline__ float gelu_tanh(float u) {
    return 0.5f * u * (1.0f + tanhf(0.7978845608028654f * (u + 0.044715f * u * u * u)));
}

__device__ __forceinline__ uint32_t to_tf32u(float x) {
    float r;
    asm("cvt.rna.tf32.f32 %0, %1;" : "=f"(r) : "f"(x));
    return __float_as_uint(r);
}

__device__ __forceinline__ void mma8(float* c, const uint32_t* a, const uint32_t* b) {
    asm volatile(
        "mma.sync.aligned.m16n8k8.row.col.f32.tf32.tf32.f32 "
        "{%0,%1,%2,%3}, {%4,%5,%6,%7}, {%8,%9}, {%0,%1,%2,%3};"
        : "+f"(c[0]), "+f"(c[1]), "+f"(c[2]), "+f"(c[3])
        : "r"(a[0]), "r"(a[1]), "r"(a[2]), "r"(a[3]), "r"(b[0]), "r"(b[1]));
}

__device__ __forceinline__ void cp_async16(uint32_t dst, const float* src) {
    asm volatile("cp.async.cg.shared.global [%0], [%1], 16;" :: "r"(dst), "l"(src));
}
__device__ __forceinline__ void cp_commit() {
    asm volatile("cp.async.commit_group;");
}
__device__ __forceinline__ void cp_wait1() {
    asm volatile("cp.async.wait_group 1;");
}
__device__ __forceinline__ void cp_wait0() {
    asm volatile("cp.async.wait_group 0;");
}

// ---------------- embedding + bucketize ----------------
__global__ void embed_kernel(const float* __restrict__ methy,
                             const int* __restrict__ chromo,
                             const int* __restrict__ pos,
                             const float* __restrict__ mt,
                             const float* __restrict__ ct,
                             const float* __restrict__ pt) {
    int n = blockIdx.x;
    float x = methy[n];
    int idx = (x > -2.0f) + (x > -1.0f);
    #pragma unroll 4
    for (int i = 0; i < 100; i++) idx += ((float)i * 0.01f < x) ? 1 : 0;
    int c = chromo[n], p = pos[n];
    const float* mrow = mt + (size_t)idx * DIM;
    const float* prow = pt + (size_t)p * DIM;
    const float* crow = ct + (size_t)c * DIM;
    for (int d = threadIdx.x; d < DIM; d += blockDim.x)
        g_x[n * DIM + d] = mrow[d] + prow[d] + crow[d];
}

// ---------------- layernorm ----------------
__global__ __launch_bounds__(256) void ln_kernel(const float* __restrict__ in,
                                                 const float* __restrict__ g,
                                                 const float* __restrict__ b,
                                                 float* __restrict__ out) {
    int n = blockIdx.x, t = threadIdx.x;
    __shared__ float red[256];
    float v[3];
    float s = 0.f;
    #pragma unroll
    for (int i = 0; i < 3; i++) { v[i] = in[n * DIM + t + i * 256]; s += v[i]; }
    red[t] = s; __syncthreads();
    for (int off = 128; off > 0; off >>= 1) { if (t < off) red[t] += red[t + off]; __syncthreads(); }
    float mu = red[0] * (1.0f / DIM);
    __syncthreads();
    float s2 = 0.f;
    #pragma unroll
    for (int i = 0; i < 3; i++) { float d = v[i] - mu; s2 += d * d; }
    red[t] = s2; __syncthreads();
    for (int off = 128; off > 0; off >>= 1) { if (t < off) red[t] += red[t + off]; __syncthreads(); }
    float rstd = rsqrtf(red[0] * (1.0f / DIM) + 1e-5f);
    #pragma unroll
    for (int i = 0; i < 3; i++) {
        int d = t + i * 256;
        out[n * DIM + d] = (v[i] - mu) * rstd * g[d] + b[d];
    }
}

// ---------------- TF32 GEMM 128x128x32, cp.async 3-stage, z-fused ----------
#define BM 128
#define BN 128
#define BK 32
#define ASTR 36   /* BK+4 */
#define BSTR 136  /* BN+8 */
#define AELE (BM * ASTR)  /* 4608 */
#define BELE (BK * BSTR)  /* 4352 */
#define STAGES 3

__global__ __launch_bounds__(256, 2) void tgemm_kernel(const float* __restrict__ A,
                                                       const float* __restrict__ B0,
                                                       const float* __restrict__ B1,
                                                       const float* __restrict__ B2,
                                                       const float* __restrict__ bias,
                                                       const float* __restrict__ resid,
                                                       float* __restrict__ C0,
                                                       float* __restrict__ C1,
                                                       float* __restrict__ C2,
                                                       int Nn, int Kk, int act) {
    extern __shared__ float sm[];
    int z = blockIdx.z;
    const float* B = (z == 0) ? B0 : ((z == 1) ? B1 : B2);
    float* C = (z == 0) ? C0 : ((z == 1) ? C1 : C2);

    int t = threadIdx.x;
    int rb = blockIdx.y * BM, cb = blockIdx.x * BN;
    int lane = t & 31, wid = t >> 5;
    int warp_m = (wid & 1) * 64, warp_n = (wid >> 1) * 32;
    int q = lane & 3, g = lane >> 2;

    // copy indices: A 128x32 (1024 float4), B 32x128 (1024 float4), 4 each
    int ar = t >> 3, ac = (t & 7) * 4;      // rows ar+32i
    int br = t >> 5, bc = (t & 31) * 4;     // rows br+8i

    const float* Abase = A + (size_t)(rb + ar) * Kk + ac;
    const float* Bbase = B + (size_t)br * Nn + cb + bc;

    uint32_t smA = (uint32_t)__cvta_generic_to_shared(sm);
    uint32_t smB = smA + STAGES * AELE * 4;
    // per-thread smem dst offsets (bytes)
    uint32_t adst = smA + (uint32_t)((ar * ASTR + ac) * 4);
    uint32_t bdst = smB + (uint32_t)((br * BSTR + bc) * 4);

    int niter = Kk / BK;

    // prologue: issue stages 0 and 1
    #pragma unroll
    for (int s = 0; s < 2; s++) {
        if (s < niter) {
            size_t k0 = (size_t)s * BK;
            #pragma unroll
            for (int i = 0; i < 4; i++)
                cp_async16(adst + (uint32_t)(s * AELE * 4 + i * 32 * ASTR * 4),
                           Abase + (size_t)(32 * i) * Kk + k0);
            #pragma unroll
            for (int i = 0; i < 4; i++)
                cp_async16(bdst + (uint32_t)(s * BELE * 4 + i * 8 * BSTR * 4),
                           Bbase + ((size_t)(8 * i) + k0) * Nn);
        }
        cp_commit();
    }

    float acc[4][4][4];
    #pragma unroll
    for (int mt = 0; mt < 4; mt++)
        #pragma unroll
        for (int nt = 0; nt < 4; nt++)
            #pragma unroll
            for (int e = 0; e < 4; e++) acc[mt][nt][e] = 0.f;

    for (int it = 0; it < niter; it++) {
        if (it + 1 < niter) cp_wait1(); else cp_wait0();
        __syncthreads();
        // issue stage it+2
        if (it + 2 < niter) {
            int s = (it + 2) % STAGES;
            size_t k0 = (size_t)(it + 2) * BK;
            #pragma unroll
            for (int i = 0; i < 4; i++)
                cp_async16(adst + (uint32_t)(s * AELE * 4 + i * 32 * ASTR * 4),
                           Abase + (size_t)(32 * i) * Kk + k0);
            #pragma unroll
            for (int i = 0; i < 4; i++)
                cp_async16(bdst + (uint32_t)(s * BELE * 4 + i * 8 * BSTR * 4),
                           Bbase + ((size_t)(8 * i) + k0) * Nn);
        }
        cp_commit();

        const float* as = sm + (it % STAGES) * AELE;
        const float* bs = sm + STAGES * AELE + (it % STAGES) * BELE;
        #pragma unroll
        for (int kk = 0; kk < 4; kk++) {
            int k = kk * 8;
            uint32_t af[4][4], bf[4][2];
            #pragma unroll
            for (int mt = 0; mt < 4; mt++) {
                int m = warp_m + mt * 16 + g;
                af[mt][0] = to_tf32u(as[m * ASTR + k + q]);
                af[mt][1] = to_tf32u(as[(m + 8) * ASTR + k + q]);
                af[mt][2] = to_tf32u(as[m * ASTR + k + q + 4]);
                af[mt][3] = to_tf32u(as[(m + 8) * ASTR + k + q + 4]);
            }
            #pragma unroll
            for (int nt = 0; nt < 4; nt++) {
                int n = warp_n + nt * 8 + g;
                bf[nt][0] = to_tf32u(bs[(k + q) * BSTR + n]);
                bf[nt][1] = to_tf32u(bs[(k + 4 + q) * BSTR + n]);
            }
            #pragma unroll
            for (int mt = 0; mt < 4; mt++)
                #pragma unroll
                for (int nt = 0; nt < 4; nt++)
                    mma8(acc[mt][nt], af[mt], bf[nt]);
        }
        __syncthreads();
    }

    // epilogue
    #pragma unroll
    for (int mt = 0; mt < 4; mt++) {
        #pragma unroll
        for (int nt = 0; nt < 4; nt++) {
            #pragma unroll
            for (int e = 0; e < 4; e++) {
                int row = rb + warp_m + mt * 16 + g + (e >> 1) * 8;
                int col = cb + warp_n + nt * 8 + q * 2 + (e & 1);
                float val = acc[mt][nt][e];
                if (bias) val += bias[col];
                if (act) val = gelu_tanh(val);
                if (resid) val += resid[(size_t)row * Nn + col];
                C[(size_t)row * Nn + col] = val;
            }
        }
    }
}

// ---------------- per-layer init ----------------
__global__ void init_kernel() {
    int i = blockIdx.x * blockDim.x + threadIdx.x;
    if (i < HEADS) g_maxk[i] = -1e30f;
    if (i < HEADS * MF) g_ksum[i] = 0.f;
    for (int j = i; j < HEADS * MF * DH; j += gridDim.x * blockDim.x) g_ctx[j] = 0.f;
}

// ---------------- FAVOR+ query features ----------------
__global__ __launch_bounds__(256) void featq_kernel(const float* __restrict__ proj) {
    int h = blockIdx.x, n0 = blockIdx.y * 32, t = threadIdx.x;
    extern __shared__ float sm[];
    float* projT = sm;                   // [d][m]
    float* xs = sm + MF * DH;            // [r][d]
    float* diag = xs + 32 * DH;          // [32]
    float* xd = diag + 32;               // [r][m]
    float* rmax = xd + 32 * MF;          // [32]
    for (int i = t; i < MF * DH; i += 256) { int m = i >> 6, d = i & 63; projT[d * MF + m] = proj[i]; }
    for (int i = t; i < 32 * DH; i += 256) {
        int r = i >> 6, d = i & 63;
        xs[i] = g_q[(n0 + r) * DIM + h * DH + d] * DNORM;
    }
    __syncthreads();
    if (t < 32) {
        float s = 0.f;
        for (int d = 0; d < DH; d++) { float v = xs[t * DH + d]; s += v * v; }
        diag[t] = 0.5f * s;
    }
    float acc[32];
    #pragma unroll
    for (int r = 0; r < 32; r++) acc[r] = 0.f;
    for (int d = 0; d < DH; d++) {
        float p = projT[d * MF + t];
        #pragma unroll
        for (int r = 0; r < 32; r++) acc[r] += xs[r * DH + d] * p;
    }
    #pragma unroll
    for (int r = 0; r < 32; r++) xd[r * MF + t] = acc[r];
    __syncthreads();
    int lane = t & 31, w = t >> 5;
    #pragma unroll
    for (int rr = 0; rr < 4; rr++) {
        int r = w * 4 + rr;
        float v = -1e30f;
        #pragma unroll
        for (int j = 0; j < 8; j++) v = fmaxf(v, xd[r * MF + lane + 32 * j]);
        for (int off = 16; off; off >>= 1) v = fmaxf(v, __shfl_xor_sync(0xffffffffu, v, off));
        if (lane == 0) rmax[r] = v;
    }
    __syncthreads();
    #pragma unroll
    for (int r = 0; r < 32; r++)
        g_qf[((size_t)h * NTOK + n0 + r) * MF + t] = RATIO * (expf(acc[r] - diag[r] - rmax[r]) + 1e-4f);
}

// ---------------- FAVOR+ key features pass 1 ----------------
__global__ __launch_bounds__(256) void featk1_kernel(const float* __restrict__ proj) {
    int h = blockIdx.x, n0 = blockIdx.y * 32, t = threadIdx.x;
    extern __shared__ float sm[];
    float* projT = sm;
    float* xs = sm + MF * DH;
    float* diag = xs + 32 * DH;
    for (int i = t; i < MF * DH; i += 256) { int m = i >> 6, d = i & 63; projT[d * MF + m] = proj[i]; }
    for (int i = t; i < 32 * DH; i += 256) {
        int r = i >> 6, d = i & 63;
        xs[i] = g_k[(n0 + r) * DIM + h * DH + d] * DNORM;
    }
    __syncthreads();
    if (t < 32) {
        float s = 0.f;
        for (int d = 0; d < DH; d++) { float v = xs[t * DH + d]; s += v * v; }
        diag[t] = 0.5f * s;
        g_diagk[h * NTOK + n0 + t] = diag[t];
    }
    __syncthreads();
    float acc[32];
    #pragma unroll
    for (int r = 0; r < 32; r++) acc[r] = 0.f;
    for (int d = 0; d < DH; d++) {
        float p = projT[d * MF + t];
        #pragma unroll
        for (int r = 0; r < 32; r++) acc[r] += xs[r * DH + d] * p;
    }
    float lmax = -1e30f;
    #pragma unroll
    for (int r = 0; r < 32; r++) {
        g_kf[((size_t)h * NTOK + n0 + r) * MF + t] = acc[r];
        lmax = fmaxf(lmax, acc[r]);
    }
    for (int off = 16; off; off >>= 1) lmax = fmaxf(lmax, __shfl_xor_sync(0xffffffffu, lmax, off));
    __shared__ float wmax[8];
    int lane = t & 31, wid = t >> 5;
    if (lane == 0) wmax[wid] = lmax;
    __syncthreads();
    if (t == 0) {
        float mx = wmax[0];
        #pragma unroll
        for (int w = 1; w < 8; w++) mx = fmaxf(mx, wmax[w]);
        atomicMaxFloat(&g_maxk[h], mx);
    }
}

// ---------------- key features pass 2 ----------------
__global__ void featk2_kernel(const float* __restrict__ methy) {
    int i = blockIdx.x * blockDim.x + threadIdx.x;
    int n = (i / MF) & (NTOK - 1);
    int h = i / (NTOK * MF);
    float xd = g_kf[i];
    float m = (methy[n] != 0.0f) ? 1.0f : 0.0f;
    g_kf[i] = RATIO * (expf(xd - g_diagk[h * NTOK + n] - g_maxk[h]) + 1e-4f) * m;
}

// ---------------- k_sum ----------------
__global__ __launch_bounds__(256) void ksum_kernel() {
    int h = blockIdx.x, t = threadIdx.x;
    int n0 = blockIdx.y * 256;
    float s = 0.f;
    for (int n = n0; n < n0 + 256; n++) s += g_kf[((size_t)h * NTOK + n) * MF + t];
    atomicAdd(&g_ksum[h * MF + t], s);
}

// ---------------- ctx ----------------
__global__ __launch_bounds__(256) void ctx_kernel() {
    int h = blockIdx.x, t = threadIdx.x;
    int n0 = blockIdx.y * 256;
    __shared__ float kfs[8 * 256];
    __shared__ float4 vs4[8 * 16];
    float acc[DH];
    #pragma unroll
    for (int d = 0; d < DH; d++) acc[d] = 0.f;
    for (int c = 0; c < 256; c += 8) {
        for (int i = t; i < 8 * 256; i += 256) {
            int r = i >> 8, m = i & 255;
            kfs[i] = g_kf[((size_t)h * NTOK + n0 + c + r) * MF + m];
        }
        if (t < 128) {
            int r = t >> 4, d4 = t & 15;
            vs4[r * 16 + d4] = *(const float4*)&g_v[(n0 + c + r) * DIM + h * DH + d4 * 4];
        }
        __syncthreads();
        #pragma unroll
        for (int r = 0; r < 8; r++) {
            float kv = kfs[r * 256 + t];
            #pragma unroll
            for (int d4 = 0; d4 < 16; d4++) {
                float4 vv = vs4[r * 16 + d4];
                acc[d4 * 4 + 0] += kv * vv.x;
                acc[d4 * 4 + 1] += kv * vv.y;
                acc[d4 * 4 + 2] += kv * vv.z;
                acc[d4 * 4 + 3] += kv * vv.w;
            }
        }
        __syncthreads();
    }
    #pragma unroll
    for (int d = 0; d < DH; d++) atomicAdd(&g_ctx[(size_t)h * MF * DH + t * DH + d], acc[d]);
}

// ---------------- o = (qf @ ctx) / (qf . k_sum) ----------------
__global__ __launch_bounds__(256) void attnout_kernel() {
    int h = blockIdx.x, t = threadIdx.x;
    int n0 = blockIdx.y * 64;
    extern __shared__ float sm[];
    float* ctxs = sm;
    float* ks = sm + MF * DH;
    float* qfs = ks + MF;
    for (int i = t; i < MF * DH; i += 256) ctxs[i] = g_ctx[(size_t)h * MF * DH + i];
    ks[t] = g_ksum[h * MF + t];
    __syncthreads();
    int r = t >> 6, d = t & 63;
    for (int rr = 0; rr < 64; rr += 4) {
        for (int i = t; i < 4 * MF; i += 256)
            qfs[i] = g_qf[((size_t)h * NTOK + n0 + rr + (i >> 8)) * MF + (i & 255)];
        __syncthreads();
        float acc = 0.f, den = 0.f;
        const float* qrow = &qfs[r * MF];
        #pragma unroll 8
        for (int m = 0; m < MF; m++) {
            float qv = qrow[m];
            acc += qv * ctxs[m * DH + d];
            den += qv * ks[m];
        }
        g_attn[(n0 + rr + r) * DIM + h * DH + d] = acc / den;
        __syncthreads();
    }
}

// ---------------- output head ----------------
__global__ __launch_bounds__(128) void wout_kernel(const float* __restrict__ Wout,
                                                   const float* __restrict__ bout,
                                                   float* __restrict__ out) {
    int n = blockIdx.x, t = threadIdx.x;
    __shared__ float xs[DIM];
    for (int i = t; i < DIM; i += 128) xs[i] = g_h[n * DIM + i];
    __syncthreads();
    if (t < VOCAB) {
        float acc = bout[t];
        for (int k = 0; k < DIM; k++) acc += xs[k] * Wout[k * VOCAB + t];
        out[n * VOCAB + t] = acc;
    }
}

// ---------------- host ----------------
extern "C" void kernel_launch(void* const* d_in, const int* in_sizes, int n_in,
                              void* d_out, int out_size) {
    const float* methy = (const float*)d_in[0];
    const int* chromo = (const int*)d_in[1];
    const int* pos    = (const int*)d_in[2];
    const float* mt = (const float*)d_in[3];
    const float* ct = (const float*)d_in[4];
    const float* pt = (const float*)d_in[5];
    const float* ln1g = (const float*)d_in[6];
    const float* ln1b = (const float*)d_in[7];
    const float* ln2g = (const float*)d_in[8];
    const float* ln2b = (const float*)d_in[9];
    const float* Wq = (const float*)d_in[10];
    const float* Wk = (const float*)d_in[11];
    const float* Wv = (const float*)d_in[12];
    const float* Wo = (const float*)d_in[13];
    const float* bo = (const float*)d_in[14];
    const float* W1 = (const float*)d_in[15];
    const float* b1 = (const float*)d_in[16];
    const float* W2 = (const float*)d_in[17];
    const float* b2 = (const float*)d_in[18];
    const float* proj = (const float*)d_in[19];
    const float* nfg = (const float*)d_in[20];
    const float* nfb = (const float*)d_in[21];
    const float* Wout = (const float*)d_in[22];
    const float* bout = (const float*)d_in[23];
    float* out = (float*)d_out;

    float *px, *ph, *pq, *pk, *pv, *pattn, *pff;
    cudaGetSymbolAddress((void**)&px, g_x);
    cudaGetSymbolAddress((void**)&ph, g_h);
    cudaGetSymbolAddress((void**)&pq, g_q);
    cudaGetSymbolAddress((void**)&pk, g_k);
    cudaGetSymbolAddress((void**)&pv, g_v);
    cudaGetSymbolAddress((void**)&pattn, g_attn);
    cudaGetSymbolAddress((void**)&pff, g_ff);

    const int FEATQ_SMEM = (MF * DH + 32 * DH + 32 + 32 * MF + 32) * sizeof(float);
    const int FEATK_SMEM = (MF * DH + 32 * DH + 32) * sizeof(float);
    const int ATT_SMEM   = (MF * DH + MF + 4 * MF) * sizeof(float);
    const int GEMM_SMEM  = STAGES * (AELE + BELE) * sizeof(float);   // 107,520
    cudaFuncSetAttribute(featq_kernel,  cudaFuncAttributeMaxDynamicSharedMemorySize, FEATQ_SMEM);
    cudaFuncSetAttribute(featk1_kernel, cudaFuncAttributeMaxDynamicSharedMemorySize, FEATK_SMEM);
    cudaFuncSetAttribute(attnout_kernel, cudaFuncAttributeMaxDynamicSharedMemorySize, ATT_SMEM);
    cudaFuncSetAttribute(tgemm_kernel,  cudaFuncAttributeMaxDynamicSharedMemorySize, GEMM_SMEM);

    embed_kernel<<<NTOK, 256>>>(methy, chromo, pos, mt, ct, pt);

    dim3 gqkv(DIM / BN, NTOK / BM, 3);  // (6, 32, 3)
    dim3 g768(DIM / BN, NTOK / BM, 1);  // (6, 32)
    dim3 gff(FF / BN, NTOK / BM, 1);    // (24, 32)

    for (int l = 0; l < DEPTH; l++) {
        const float* pj = proj + (size_t)l * MF * DH;
        // --- attention ---
        ln_kernel<<<NTOK, 256>>>(px, ln1g + l * DIM, ln1b + l * DIM, ph);
        tgemm_kernel<<<gqkv, 256, GEMM_SMEM>>>(ph,
            Wq + (size_t)l * DIM * DIM, Wk + (size_t)l * DIM * DIM, Wv + (size_t)l * DIM * DIM,
            nullptr, nullptr, pq, pk, pv, DIM, DIM, 0);
        init_kernel<<<64, 256>>>();
        featq_kernel<<<dim3(HEADS, NTOK / 32), 256, FEATQ_SMEM>>>(pj);
        featk1_kernel<<<dim3(HEADS, NTOK / 32), 256, FEATK_SMEM>>>(pj);
        featk2_kernel<<<HEADS * NTOK * MF / 256, 256>>>(methy);
        ksum_kernel<<<dim3(HEADS, NTOK / 256), 256>>>();
        ctx_kernel<<<dim3(HEADS, 16), 256>>>();
        attnout_kernel<<<dim3(HEADS, NTOK / 64), 256, ATT_SMEM>>>();
        tgemm_kernel<<<g768, 256, GEMM_SMEM>>>(pattn,
            Wo + (size_t)l * DIM * DIM, nullptr, nullptr,
            bo + l * DIM, px, px, nullptr, nullptr, DIM, DIM, 0);
        // --- FFN ---
        ln_kernel<<<NTOK, 256>>>(px, ln2g + l * DIM, ln2b + l * DIM, ph);
        tgemm_kernel<<<gff, 256, GEMM_SMEM>>>(ph,
            W1 + (size_t)l * DIM * FF, nullptr, nullptr,
            b1 + l * FF, nullptr, pff, nullptr, nullptr, FF, DIM, 1);
        tgemm_kernel<<<g768, 256, GEMM_SMEM>>>(pff,
            W2 + (size_t)l * FF * DIM, nullptr, nullptr,
            b2 + l * DIM, px, px, nullptr, nullptr, DIM, FF, 0);
    }

    ln_kernel<<<NTOK, 256>>>(px, nfg, nfb, ph);
    wout_kernel<<<NTOK, 128>>>(Wout, bout, out);
}

// round 6
// speedup vs baseline: 2.1694x; 1.0646x over previous
#include <cuda_runtime.h>
#include <math.h>
#include <stdint.h>

#define NTOK 4096
#define DIM 768
#define DEPTH 6
#define HEADS 12
#define DH 64
#define FF 3072
#define MF 256
#define VOCAB 102
#define DNORM 0.35355339059327373f   /* 64^-0.25 */
#define RATIO 0.0625f                /* 256^-0.5 */

// ---------------- scratch (device globals, no allocation) ----------------
__device__ float g_x[NTOK * DIM];
__device__ float g_h[NTOK * DIM];
__device__ float g_q[NTOK * DIM];
__device__ float g_k[NTOK * DIM];
__device__ float g_v[NTOK * DIM];
__device__ float g_attn[NTOK * DIM];
__device__ float g_ff[NTOK * FF];
__device__ float g_qf[HEADS * NTOK * MF];
__device__ float g_kf[HEADS * NTOK * MF];   // holds xd from featk1; exp applied on the fly in ctx
__device__ float g_diagk[HEADS * NTOK];
__device__ float g_maxk[HEADS];
__device__ float g_ksum[HEADS * MF];
__device__ float g_ctx[HEADS * MF * DH];

// ---------------- helpers ----------------
__device__ __forceinline__ void atomicMaxFloat(float* addr, float val) {
    int* ia = (int*)addr;
    int old = *ia;
    while (val > __int_as_float(old)) {
        int assumed = old;
        old = atomicCAS(ia, assumed, __float_as_int(val));
        if (old == assumed) break;
    }
}

__device__ __forceinline__ float tanh_fast(float x) {
    float r;
    asm("tanh.approx.f32 %0, %1;" : "=f"(r) : "f"(x));
    return r;
}

__device__ __forceinline__ float gelu_tanh(float u) {
    return 0.5f * u * (1.0f + tanh_fast(0.7978845608028654f * (u + 0.044715f * u * u * u)));
}

__device__ __forceinline__ uint32_t to_tf32u(float x) {
    float r;
    asm("cvt.rna.tf32.f32 %0, %1;" : "=f"(r) : "f"(x));
    return __float_as_uint(r);
}

__device__ __forceinline__ void mma8(float* c, const uint32_t* a, const uint32_t* b) {
    asm volatile(
        "mma.sync.aligned.m16n8k8.row.col.f32.tf32.tf32.f32 "
        "{%0,%1,%2,%3}, {%4,%5,%6,%7}, {%8,%9}, {%0,%1,%2,%3};"
        : "+f"(c[0]), "+f"(c[1]), "+f"(c[2]), "+f"(c[3])
        : "r"(a[0]), "r"(a[1]), "r"(a[2]), "r"(a[3]), "r"(b[0]), "r"(b[1]));
}

__device__ __forceinline__ void cp_async16(uint32_t dst, const float* src) {
    asm volatile("cp.async.cg.shared.global [%0], [%1], 16;" :: "r"(dst), "l"(src));
}
__device__ __forceinline__ void cp_commit() {
    asm volatile("cp.async.commit_group;");
}
__device__ __forceinline__ void cp_wait1() {
    asm volatile("cp.async.wait_group 1;");
}
__device__ __forceinline__ void cp_wait0() {
    asm volatile("cp.async.wait_group 0;");
}

// ---------------- embedding + bucketize ----------------
__global__ void embed_kernel(const float* __restrict__ methy,
                             const int* __restrict__ chromo,
                             const int* __restrict__ pos,
                             const float* __restrict__ mt,
                             const float* __restrict__ ct,
                             const float* __restrict__ pt) {
    int n = blockIdx.x;
    float x = methy[n];
    int idx = (x > -2.0f) + (x > -1.0f);
    #pragma unroll 4
    for (int i = 0; i < 100; i++) idx += ((float)i * 0.01f < x) ? 1 : 0;
    int c = chromo[n], p = pos[n];
    const float* mrow = mt + (size_t)idx * DIM;
    const float* prow = pt + (size_t)p * DIM;
    const float* crow = ct + (size_t)c * DIM;
    for (int d = threadIdx.x; d < DIM; d += blockDim.x)
        g_x[n * DIM + d] = mrow[d] + prow[d] + crow[d];
}

// ---------------- layernorm ----------------
__global__ __launch_bounds__(256) void ln_kernel(const float* __restrict__ in,
                                                 const float* __restrict__ g,
                                                 const float* __restrict__ b,
                                                 float* __restrict__ out) {
    int n = blockIdx.x, t = threadIdx.x;
    __shared__ float red[256];
    float v[3];
    float s = 0.f;
    #pragma unroll
    for (int i = 0; i < 3; i++) { v[i] = in[n * DIM + t + i * 256]; s += v[i]; }
    red[t] = s; __syncthreads();
    for (int off = 128; off > 0; off >>= 1) { if (t < off) red[t] += red[t + off]; __syncthreads(); }
    float mu = red[0] * (1.0f / DIM);
    __syncthreads();
    float s2 = 0.f;
    #pragma unroll
    for (int i = 0; i < 3; i++) { float d = v[i] - mu; s2 += d * d; }
    red[t] = s2; __syncthreads();
    for (int off = 128; off > 0; off >>= 1) { if (t < off) red[t] += red[t + off]; __syncthreads(); }
    float rstd = rsqrtf(red[0] * (1.0f / DIM) + 1e-5f);
    #pragma unroll
    for (int i = 0; i < 3; i++) {
        int d = t + i * 256;
        out[n * DIM + d] = (v[i] - mu) * rstd * g[d] + b[d];
    }
}

// ---------------- TF32 GEMM 128x128x32, cp.async 3-stage, z-fused/split-K --
#define BM 128
#define BN 128
#define BK 32
#define ASTR 36   /* BK+4 */
#define BSTR 136  /* BN+8 */
#define AELE (BM * ASTR)
#define BELE (BK * BSTR)
#define STAGES 3

__global__ __launch_bounds__(256, 2) void tgemm_kernel(const float* __restrict__ A,
                                                       const float* __restrict__ B0,
                                                       const float* __restrict__ B1,
                                                       const float* __restrict__ B2,
                                                       const float* __restrict__ bias,
                                                       const float* __restrict__ resid,
                                                       float* __restrict__ C0,
                                                       float* __restrict__ C1,
                                                       float* __restrict__ C2,
                                                       int Nn, int Kk, int act, int splitk) {
    extern __shared__ float sm[];
    int z = blockIdx.z;
    const float* B = B0;
    float* C = C0;
    int koff = 0, Keff = Kk;
    if (splitk > 1) {
        Keff = Kk / splitk;
        koff = z * Keff;
    } else {
        B = (z == 0) ? B0 : ((z == 1) ? B1 : B2);
        C = (z == 0) ? C0 : ((z == 1) ? C1 : C2);
    }

    int t = threadIdx.x;
    int rb = blockIdx.y * BM, cb = blockIdx.x * BN;
    int lane = t & 31, wid = t >> 5;
    int warp_m = (wid & 1) * 64, warp_n = (wid >> 1) * 32;
    int q = lane & 3, g = lane >> 2;

    int ar = t >> 3, ac = (t & 7) * 4;
    int br = t >> 5, bc = (t & 31) * 4;

    const float* Abase = A + (size_t)(rb + ar) * Kk + ac + koff;
    const float* Bbase = B + (size_t)(br + koff) * Nn + cb + bc;

    uint32_t smA = (uint32_t)__cvta_generic_to_shared(sm);
    uint32_t smB = smA + STAGES * AELE * 4;
    uint32_t adst = smA + (uint32_t)((ar * ASTR + ac) * 4);
    uint32_t bdst = smB + (uint32_t)((br * BSTR + bc) * 4);

    int niter = Keff / BK;

    #pragma unroll
    for (int s = 0; s < 2; s++) {
        if (s < niter) {
            size_t k0 = (size_t)s * BK;
            #pragma unroll
            for (int i = 0; i < 4; i++)
                cp_async16(adst + (uint32_t)(s * AELE * 4 + i * 32 * ASTR * 4),
                           Abase + (size_t)(32 * i) * Kk + k0);
            #pragma unroll
            for (int i = 0; i < 4; i++)
                cp_async16(bdst + (uint32_t)(s * BELE * 4 + i * 8 * BSTR * 4),
                           Bbase + ((size_t)(8 * i) + k0) * Nn);
        }
        cp_commit();
    }

    float acc[4][4][4];
    #pragma unroll
    for (int mt = 0; mt < 4; mt++)
        #pragma unroll
        for (int nt = 0; nt < 4; nt++)
            #pragma unroll
            for (int e = 0; e < 4; e++) acc[mt][nt][e] = 0.f;

    for (int it = 0; it < niter; it++) {
        if (it + 1 < niter) cp_wait1(); else cp_wait0();
        __syncthreads();
        if (it + 2 < niter) {
            int s = (it + 2) % STAGES;
            size_t k0 = (size_t)(it + 2) * BK;
            #pragma unroll
            for (int i = 0; i < 4; i++)
                cp_async16(adst + (uint32_t)(s * AELE * 4 + i * 32 * ASTR * 4),
                           Abase + (size_t)(32 * i) * Kk + k0);
            #pragma unroll
            for (int i = 0; i < 4; i++)
                cp_async16(bdst + (uint32_t)(s * BELE * 4 + i * 8 * BSTR * 4),
                           Bbase + ((size_t)(8 * i) + k0) * Nn);
        }
        cp_commit();

        const float* as = sm + (it % STAGES) * AELE;
        const float* bs = sm + STAGES * AELE + (it % STAGES) * BELE;
        #pragma unroll
        for (int kk = 0; kk < 4; kk++) {
            int k = kk * 8;
            uint32_t af[4][4], bf[4][2];
            #pragma unroll
            for (int mt = 0; mt < 4; mt++) {
                int m = warp_m + mt * 16 + g;
                af[mt][0] = to_tf32u(as[m * ASTR + k + q]);
                af[mt][1] = to_tf32u(as[(m + 8) * ASTR + k + q]);
                af[mt][2] = to_tf32u(as[m * ASTR + k + q + 4]);
                af[mt][3] = to_tf32u(as[(m + 8) * ASTR + k + q + 4]);
            }
            #pragma unroll
            for (int nt = 0; nt < 4; nt++) {
                int n = warp_n + nt * 8 + g;
                bf[nt][0] = to_tf32u(bs[(k + q) * BSTR + n]);
                bf[nt][1] = to_tf32u(bs[(k + 4 + q) * BSTR + n]);
            }
            #pragma unroll
            for (int mt = 0; mt < 4; mt++)
                #pragma unroll
                for (int nt = 0; nt < 4; nt++)
                    mma8(acc[mt][nt], af[mt], bf[nt]);
        }
    }
    __syncthreads();

    // epilogue
    if (splitk > 1) {
        #pragma unroll
        for (int mt = 0; mt < 4; mt++)
            #pragma unroll
            for (int nt = 0; nt < 4; nt++)
                #pragma unroll
                for (int e = 0; e < 4; e++) {
                    int row = rb + warp_m + mt * 16 + g + (e >> 1) * 8;
                    int col = cb + warp_n + nt * 8 + q * 2 + (e & 1);
                    float val = acc[mt][nt][e];
                    if (bias && z == 0) val += bias[col];
                    atomicAdd(&C[(size_t)row * Nn + col], val);
                }
    } else {
        #pragma unroll
        for (int mt = 0; mt < 4; mt++)
            #pragma unroll
            for (int nt = 0; nt < 4; nt++)
                #pragma unroll
                for (int e = 0; e < 4; e++) {
                    int row = rb + warp_m + mt * 16 + g + (e >> 1) * 8;
                    int col = cb + warp_n + nt * 8 + q * 2 + (e & 1);
                    float val = acc[mt][nt][e];
                    if (bias) val += bias[col];
                    if (act) val = gelu_tanh(val);
                    if (resid) val += resid[(size_t)row * Nn + col];
                    C[(size_t)row * Nn + col] = val;
                }
    }
}

// ---------------- per-layer init ----------------
__global__ void init_kernel() {
    int i = blockIdx.x * blockDim.x + threadIdx.x;
    if (i < HEADS) g_maxk[i] = -1e30f;
    if (i < HEADS * MF) g_ksum[i] = 0.f;
    for (int j = i; j < HEADS * MF * DH; j += gridDim.x * blockDim.x) g_ctx[j] = 0.f;
}

// ---------------- FAVOR+ query features ----------------
__global__ __launch_bounds__(256) void featq_kernel(const float* __restrict__ proj) {
    int h = blockIdx.x, n0 = blockIdx.y * 32, t = threadIdx.x;
    extern __shared__ float sm[];
    float* projT = sm;                   // [d][m]
    float* xs = sm + MF * DH;            // [r][d]
    float* diag = xs + 32 * DH;          // [32]
    float* xd = diag + 32;               // [r][m]
    float* rmax = xd + 32 * MF;          // [32]
    for (int i = t; i < MF * DH; i += 256) { int m = i >> 6, d = i & 63; projT[d * MF + m] = proj[i]; }
    for (int i = t; i < 32 * DH; i += 256) {
        int r = i >> 6, d = i & 63;
        xs[i] = g_q[(n0 + r) * DIM + h * DH + d] * DNORM;
    }
    __syncthreads();
    if (t < 32) {
        float s = 0.f;
        for (int d = 0; d < DH; d++) { float v = xs[t * DH + d]; s += v * v; }
        diag[t] = 0.5f * s;
    }
    float acc[32];
    #pragma unroll
    for (int r = 0; r < 32; r++) acc[r] = 0.f;
    for (int d = 0; d < DH; d++) {
        float p = projT[d * MF + t];
        #pragma unroll
        for (int r = 0; r < 32; r++) acc[r] += xs[r * DH + d] * p;
    }
    #pragma unroll
    for (int r = 0; r < 32; r++) xd[r * MF + t] = acc[r];
    __syncthreads();
    int lane = t & 31, w = t >> 5;
    #pragma unroll
    for (int rr = 0; rr < 4; rr++) {
        int r = w * 4 + rr;
        float v = -1e30f;
        #pragma unroll
        for (int j = 0; j < 8; j++) v = fmaxf(v, xd[r * MF + lane + 32 * j]);
        for (int off = 16; off; off >>= 1) v = fmaxf(v, __shfl_xor_sync(0xffffffffu, v, off));
        if (lane == 0) rmax[r] = v;
    }
    __syncthreads();
    #pragma unroll
    for (int r = 0; r < 32; r++)
        g_qf[((size_t)h * NTOK + n0 + r) * MF + t] = RATIO * (expf(acc[r] - diag[r] - rmax[r]) + 1e-4f);
}

// ---------------- FAVOR+ key features pass 1 (xd + diag + head max) -------
__global__ __launch_bounds__(256) void featk1_kernel(const float* __restrict__ proj) {
    int h = blockIdx.x, n0 = blockIdx.y * 32, t = threadIdx.x;
    extern __shared__ float sm[];
    float* projT = sm;
    float* xs = sm + MF * DH;
    float* diag = xs + 32 * DH;
    for (int i = t; i < MF * DH; i += 256) { int m = i >> 6, d = i & 63; projT[d * MF + m] = proj[i]; }
    for (int i = t; i < 32 * DH; i += 256) {
        int r = i >> 6, d = i & 63;
        xs[i] = g_k[(n0 + r) * DIM + h * DH + d] * DNORM;
    }
    __syncthreads();
    if (t < 32) {
        float s = 0.f;
        for (int d = 0; d < DH; d++) { float v = xs[t * DH + d]; s += v * v; }
        diag[t] = 0.5f * s;
        g_diagk[h * NTOK + n0 + t] = diag[t];
    }
    __syncthreads();
    float acc[32];
    #pragma unroll
    for (int r = 0; r < 32; r++) acc[r] = 0.f;
    for (int d = 0; d < DH; d++) {
        float p = projT[d * MF + t];
        #pragma unroll
        for (int r = 0; r < 32; r++) acc[r] += xs[r * DH + d] * p;
    }
    float lmax = -1e30f;
    #pragma unroll
    for (int r = 0; r < 32; r++) {
        g_kf[((size_t)h * NTOK + n0 + r) * MF + t] = acc[r];
        lmax = fmaxf(lmax, acc[r]);
    }
    for (int off = 16; off; off >>= 1) lmax = fmaxf(lmax, __shfl_xor_sync(0xffffffffu, lmax, off));
    __shared__ float wmax[8];
    int lane = t & 31, wid = t >> 5;
    if (lane == 0) wmax[wid] = lmax;
    __syncthreads();
    if (t == 0) {
        float mx = wmax[0];
        #pragma unroll
        for (int w = 1; w < 8; w++) mx = fmaxf(mx, wmax[w]);
        atomicMaxFloat(&g_maxk[h], mx);
    }
}

// ---------------- fused: kf=exp(...)*mask ; ksum += kf ; ctx += kf^T v ----
__global__ __launch_bounds__(256) void ctx_kernel(const float* __restrict__ methy) {
    int h = blockIdx.x, t = threadIdx.x;
    int n0 = blockIdx.y * 256;
    __shared__ float kfs[8 * 256];
    __shared__ float4 vs4[8 * 16];
    float acc[DH];
    #pragma unroll
    for (int d = 0; d < DH; d++) acc[d] = 0.f;
    float ksacc = 0.f;
    float mk = g_maxk[h];
    for (int c = 0; c < 256; c += 8) {
        #pragma unroll
        for (int j = 0; j < 8; j++) {
            int n = n0 + c + j;
            float xd = g_kf[((size_t)h * NTOK + n) * MF + t];
            float msk = (methy[n] != 0.0f) ? 1.0f : 0.0f;
            kfs[j * 256 + t] = RATIO * (expf(xd - g_diagk[h * NTOK + n] - mk) + 1e-4f) * msk;
        }
        if (t < 128) {
            int r = t >> 4, d4 = t & 15;
            vs4[r * 16 + d4] = *(const float4*)&g_v[(n0 + c + r) * DIM + h * DH + d4 * 4];
        }
        __syncthreads();
        #pragma unroll
        for (int r = 0; r < 8; r++) {
            float kv = kfs[r * 256 + t];
            ksacc += kv;
            #pragma unroll
            for (int d4 = 0; d4 < 16; d4++) {
                float4 vv = vs4[r * 16 + d4];
                acc[d4 * 4 + 0] += kv * vv.x;
                acc[d4 * 4 + 1] += kv * vv.y;
                acc[d4 * 4 + 2] += kv * vv.z;
                acc[d4 * 4 + 3] += kv * vv.w;
            }
        }
        __syncthreads();
    }
    atomicAdd(&g_ksum[h * MF + t], ksacc);
    #pragma unroll
    for (int d = 0; d < DH; d++) atomicAdd(&g_ctx[(size_t)h * MF * DH + t * DH + d], acc[d]);
}

// ---------------- o = (qf @ ctx) / (qf . k_sum) ----------------
__global__ __launch_bounds__(256) void attnout_kernel() {
    int h = blockIdx.x, t = threadIdx.x;
    int n0 = blockIdx.y * 64;
    extern __shared__ float sm[];
    float* ctxs = sm;
    float* ks = sm + MF * DH;
    float* qfs = ks + MF;
    for (int i = t; i < MF * DH; i += 256) ctxs[i] = g_ctx[(size_t)h * MF * DH + i];
    ks[t] = g_ksum[h * MF + t];
    __syncthreads();
    int r = t >> 6, d = t & 63;
    for (int rr = 0; rr < 64; rr += 4) {
        for (int i = t; i < 4 * MF; i += 256)
            qfs[i] = g_qf[((size_t)h * NTOK + n0 + rr + (i >> 8)) * MF + (i & 255)];
        __syncthreads();
        float acc = 0.f, den = 0.f;
        const float* qrow = &qfs[r * MF];
        #pragma unroll 8
        for (int m = 0; m < MF; m++) {
            float qv = qrow[m];
            acc += qv * ctxs[m * DH + d];
            den += qv * ks[m];
        }
        g_attn[(n0 + rr + r) * DIM + h * DH + d] = acc / den;
        __syncthreads();
    }
}

// ---------------- output head ----------------
__global__ __launch_bounds__(128) void wout_kernel(const float* __restrict__ Wout,
                                                   const float* __restrict__ bout,
                                                   float* __restrict__ out) {
    int n = blockIdx.x, t = threadIdx.x;
    __shared__ float xs[DIM];
    for (int i = t; i < DIM; i += 128) xs[i] = g_h[n * DIM + i];
    __syncthreads();
    if (t < VOCAB) {
        float acc = bout[t];
        for (int k = 0; k < DIM; k++) acc += xs[k] * Wout[k * VOCAB + t];
        out[n * VOCAB + t] = acc;
    }
}

// ---------------- host ----------------
extern "C" void kernel_launch(void* const* d_in, const int* in_sizes, int n_in,
                              void* d_out, int out_size) {
    const float* methy = (const float*)d_in[0];
    const int* chromo = (const int*)d_in[1];
    const int* pos    = (const int*)d_in[2];
    const float* mt = (const float*)d_in[3];
    const float* ct = (const float*)d_in[4];
    const float* pt = (const float*)d_in[5];
    const float* ln1g = (const float*)d_in[6];
    const float* ln1b = (const float*)d_in[7];
    const float* ln2g = (const float*)d_in[8];
    const float* ln2b = (const float*)d_in[9];
    const float* Wq = (const float*)d_in[10];
    const float* Wk = (const float*)d_in[11];
    const float* Wv = (const float*)d_in[12];
    const float* Wo = (const float*)d_in[13];
    const float* bo = (const float*)d_in[14];
    const float* W1 = (const float*)d_in[15];
    const float* b1 = (const float*)d_in[16];
    const float* W2 = (const float*)d_in[17];
    const float* b2 = (const float*)d_in[18];
    const float* proj = (const float*)d_in[19];
    const float* nfg = (const float*)d_in[20];
    const float* nfb = (const float*)d_in[21];
    const float* Wout = (const float*)d_in[22];
    const float* bout = (const float*)d_in[23];
    float* out = (float*)d_out;

    float *px, *ph, *pq, *pk, *pv, *pattn, *pff;
    cudaGetSymbolAddress((void**)&px, g_x);
    cudaGetSymbolAddress((void**)&ph, g_h);
    cudaGetSymbolAddress((void**)&pq, g_q);
    cudaGetSymbolAddress((void**)&pk, g_k);
    cudaGetSymbolAddress((void**)&pv, g_v);
    cudaGetSymbolAddress((void**)&pattn, g_attn);
    cudaGetSymbolAddress((void**)&pff, g_ff);

    const int FEATQ_SMEM = (MF * DH + 32 * DH + 32 + 32 * MF + 32) * sizeof(float);
    const int FEATK_SMEM = (MF * DH + 32 * DH + 32) * sizeof(float);
    const int ATT_SMEM   = (MF * DH + MF + 4 * MF) * sizeof(float);
    const int GEMM_SMEM  = STAGES * (AELE + BELE) * sizeof(float);   // 107,520
    cudaFuncSetAttribute(featq_kernel,  cudaFuncAttributeMaxDynamicSharedMemorySize, FEATQ_SMEM);
    cudaFuncSetAttribute(featk1_kernel, cudaFuncAttributeMaxDynamicSharedMemorySize, FEATK_SMEM);
    cudaFuncSetAttribute(attnout_kernel, cudaFuncAttributeMaxDynamicSharedMemorySize, ATT_SMEM);
    cudaFuncSetAttribute(tgemm_kernel,  cudaFuncAttributeMaxDynamicSharedMemorySize, GEMM_SMEM);

    embed_kernel<<<NTOK, 256>>>(methy, chromo, pos, mt, ct, pt);

    dim3 gqkv(DIM / BN, NTOK / BM, 3);  // (6, 32, 3)
    dim3 gsk(DIM / BN, NTOK / BM, 2);   // (6, 32, 2) split-K
    dim3 gff(FF / BN, NTOK / BM, 1);    // (24, 32)

    for (int l = 0; l < DEPTH; l++) {
        const float* pj = proj + (size_t)l * MF * DH;
        // --- attention ---
        ln_kernel<<<NTOK, 256>>>(px, ln1g + l * DIM, ln1b + l * DIM, ph);
        tgemm_kernel<<<gqkv, 256, GEMM_SMEM>>>(ph,
            Wq + (size_t)l * DIM * DIM, Wk + (size_t)l * DIM * DIM, Wv + (size_t)l * DIM * DIM,
            nullptr, nullptr, pq, pk, pv, DIM, DIM, 0, 1);
        init_kernel<<<64, 256>>>();
        featq_kernel<<<dim3(HEADS, NTOK / 32), 256, FEATQ_SMEM>>>(pj);
        featk1_kernel<<<dim3(HEADS, NTOK / 32), 256, FEATK_SMEM>>>(pj);
        ctx_kernel<<<dim3(HEADS, 16), 256>>>(methy);
        attnout_kernel<<<dim3(HEADS, NTOK / 64), 256, ATT_SMEM>>>();
        // Wo: split-K=2, atomicAdd into px (residual already present)
        tgemm_kernel<<<gsk, 256, GEMM_SMEM>>>(pattn,
            Wo + (size_t)l * DIM * DIM, nullptr, nullptr,
            bo + l * DIM, nullptr, px, nullptr, nullptr, DIM, DIM, 0, 2);
        // --- FFN ---
        ln_kernel<<<NTOK, 256>>>(px, ln2g + l * DIM, ln2b + l * DIM, ph);
        tgemm_kernel<<<gff, 256, GEMM_SMEM>>>(ph,
            W1 + (size_t)l * DIM * FF, nullptr, nullptr,
            b1 + l * FF, nullptr, pff, nullptr, nullptr, FF, DIM, 1, 1);
        // W2: split-K=2, atomicAdd into px
        tgemm_kernel<<<gsk, 256, GEMM_SMEM>>>(pff,
            W2 + (size_t)l * FF * DIM, nullptr, nullptr,
            b2 + l * DIM, nullptr, px, nullptr, nullptr, DIM, FF, 0, 2);
    }

    ln_kernel<<<NTOK, 256>>>(px, nfg, nfb, ph);
    wout_kernel<<<NTOK, 128>>>(Wout, bout, out);
}

// round 7
// speedup vs baseline: 2.8646x; 1.3205x over previous
#include <cuda_runtime.h>
#include <math.h>
#include <stdint.h>

#define NTOK 4096
#define DIM 768
#define DEPTH 6
#define HEADS 12
#define DH 64
#define FF 3072
#define MF 256
#define VOCAB 102
#define DNORM 0.35355339059327373f   /* 64^-0.25 */
#define RATIO 0.0625f                /* 256^-0.5 */

// ---------------- scratch (device globals, no allocation) ----------------
__device__ float g_x[NTOK * DIM];
__device__ float g_h[NTOK * DIM];
__device__ float g_q[NTOK * DIM];
__device__ float g_k[NTOK * DIM];
__device__ float g_v[NTOK * DIM];
__device__ float g_attn[NTOK * DIM];
__device__ float g_ff[NTOK * FF];
__device__ float g_qf[HEADS * NTOK * MF];   // raw xd; exp applied in attnout
__device__ float g_kf[HEADS * NTOK * MF];   // raw xd; exp applied in ctx
__device__ float g_diagq[HEADS * NTOK];
__device__ float g_diagk[HEADS * NTOK];
__device__ float g_maxq[HEADS * NTOK];
__device__ float g_maxk[HEADS];
__device__ float g_ksum[HEADS * MF];
__device__ float g_ctx[HEADS * MF * DH];

// ---------------- helpers ----------------
__device__ __forceinline__ void atomicMaxFloat(float* addr, float val) {
    int* ia = (int*)addr;
    int old = *ia;
    while (val > __int_as_float(old)) {
        int assumed = old;
        old = atomicCAS(ia, assumed, __float_as_int(val));
        if (old == assumed) break;
    }
}

__device__ __forceinline__ float tanh_fast(float x) {
    float r;
    asm("tanh.approx.f32 %0, %1;" : "=f"(r) : "f"(x));
    return r;
}

__device__ __forceinline__ float gelu_tanh(float u) {
    return 0.5f * u * (1.0f + tanh_fast(0.7978845608028654f * (u + 0.044715f * u * u * u)));
}

__device__ __forceinline__ uint32_t to_tf32u(float x) {
    float r;
    asm("cvt.rna.tf32.f32 %0, %1;" : "=f"(r) : "f"(x));
    return __float_as_uint(r);
}

__device__ __forceinline__ void mma8(float* c, const uint32_t* a, const uint32_t* b) {
    asm volatile(
        "mma.sync.aligned.m16n8k8.row.col.f32.tf32.tf32.f32 "
        "{%0,%1,%2,%3}, {%4,%5,%6,%7}, {%8,%9}, {%0,%1,%2,%3};"
        : "+f"(c[0]), "+f"(c[1]), "+f"(c[2]), "+f"(c[3])
        : "r"(a[0]), "r"(a[1]), "r"(a[2]), "r"(a[3]), "r"(b[0]), "r"(b[1]));
}

__device__ __forceinline__ void cp_async16(uint32_t dst, const float* src) {
    asm volatile("cp.async.cg.shared.global [%0], [%1], 16;" :: "r"(dst), "l"(src));
}
__device__ __forceinline__ void cp_commit() {
    asm volatile("cp.async.commit_group;");
}
__device__ __forceinline__ void cp_wait1() {
    asm volatile("cp.async.wait_group 1;");
}
__device__ __forceinline__ void cp_wait0() {
    asm volatile("cp.async.wait_group 0;");
}

// ---------------- embedding + bucketize ----------------
__global__ void embed_kernel(const float* __restrict__ methy,
                             const int* __restrict__ chromo,
                             const int* __restrict__ pos,
                             const float* __restrict__ mt,
                             const float* __restrict__ ct,
                             const float* __restrict__ pt) {
    int n = blockIdx.x;
    float x = methy[n];
    int idx = (x > -2.0f) + (x > -1.0f);
    #pragma unroll 4
    for (int i = 0; i < 100; i++) idx += ((float)i * 0.01f < x) ? 1 : 0;
    int c = chromo[n], p = pos[n];
    const float* mrow = mt + (size_t)idx * DIM;
    const float* prow = pt + (size_t)p * DIM;
    const float* crow = ct + (size_t)c * DIM;
    for (int d = threadIdx.x; d < DIM; d += blockDim.x)
        g_x[n * DIM + d] = mrow[d] + prow[d] + crow[d];
}

// ---------------- layernorm ----------------
__global__ __launch_bounds__(256) void ln_kernel(const float* __restrict__ in,
                                                 const float* __restrict__ g,
                                                 const float* __restrict__ b,
                                                 float* __restrict__ out) {
    int n = blockIdx.x, t = threadIdx.x;
    __shared__ float red[256];
    float v[3];
    float s = 0.f;
    #pragma unroll
    for (int i = 0; i < 3; i++) { v[i] = in[n * DIM + t + i * 256]; s += v[i]; }
    red[t] = s; __syncthreads();
    for (int off = 128; off > 0; off >>= 1) { if (t < off) red[t] += red[t + off]; __syncthreads(); }
    float mu = red[0] * (1.0f / DIM);
    __syncthreads();
    float s2 = 0.f;
    #pragma unroll
    for (int i = 0; i < 3; i++) { float d = v[i] - mu; s2 += d * d; }
    red[t] = s2; __syncthreads();
    for (int off = 128; off > 0; off >>= 1) { if (t < off) red[t] += red[t + off]; __syncthreads(); }
    float rstd = rsqrtf(red[0] * (1.0f / DIM) + 1e-5f);
    #pragma unroll
    for (int i = 0; i < 3; i++) {
        int d = t + i * 256;
        out[n * DIM + d] = (v[i] - mu) * rstd * g[d] + b[d];
    }
}

// ---------------- TF32 GEMM 128x128x32, cp.async 3-stage, z-fused/split-K --
#define BM 128
#define BN 128
#define BK 32
#define ASTR 36   /* BK+4 */
#define BSTR 136  /* BN+8 */
#define AELE (BM * ASTR)
#define BELE (BK * BSTR)
#define STAGES 3

__global__ __launch_bounds__(256, 2) void tgemm_kernel(const float* __restrict__ A,
                                                       const float* __restrict__ B0,
                                                       const float* __restrict__ B1,
                                                       const float* __restrict__ B2,
                                                       const float* __restrict__ bias,
                                                       const float* __restrict__ resid,
                                                       float* __restrict__ C0,
                                                       float* __restrict__ C1,
                                                       float* __restrict__ C2,
                                                       int Nn, int Kk, int act, int splitk) {
    extern __shared__ float sm[];
    int z = blockIdx.z;
    const float* B = B0;
    float* C = C0;
    int koff = 0, Keff = Kk;
    if (splitk > 1) {
        Keff = Kk / splitk;
        koff = z * Keff;
    } else {
        B = (z == 0) ? B0 : ((z == 1) ? B1 : B2);
        C = (z == 0) ? C0 : ((z == 1) ? C1 : C2);
    }

    int t = threadIdx.x;
    int rb = blockIdx.y * BM, cb = blockIdx.x * BN;
    int lane = t & 31, wid = t >> 5;
    int warp_m = (wid & 1) * 64, warp_n = (wid >> 1) * 32;
    int q = lane & 3, g = lane >> 2;

    int ar = t >> 3, ac = (t & 7) * 4;
    int br = t >> 5, bc = (t & 31) * 4;

    const float* Abase = A + (size_t)(rb + ar) * Kk + ac + koff;
    const float* Bbase = B + (size_t)(br + koff) * Nn + cb + bc;

    uint32_t smA = (uint32_t)__cvta_generic_to_shared(sm);
    uint32_t smB = smA + STAGES * AELE * 4;
    uint32_t adst = smA + (uint32_t)((ar * ASTR + ac) * 4);
    uint32_t bdst = smB + (uint32_t)((br * BSTR + bc) * 4);

    int niter = Keff / BK;

    #pragma unroll
    for (int s = 0; s < 2; s++) {
        if (s < niter) {
            size_t k0 = (size_t)s * BK;
            #pragma unroll
            for (int i = 0; i < 4; i++)
                cp_async16(adst + (uint32_t)(s * AELE * 4 + i * 32 * ASTR * 4),
                           Abase + (size_t)(32 * i) * Kk + k0);
            #pragma unroll
            for (int i = 0; i < 4; i++)
                cp_async16(bdst + (uint32_t)(s * BELE * 4 + i * 8 * BSTR * 4),
                           Bbase + ((size_t)(8 * i) + k0) * Nn);
        }
        cp_commit();
    }

    float acc[4][4][4];
    #pragma unroll
    for (int mt = 0; mt < 4; mt++)
        #pragma unroll
        for (int nt = 0; nt < 4; nt++)
            #pragma unroll
            for (int e = 0; e < 4; e++) acc[mt][nt][e] = 0.f;

    for (int it = 0; it < niter; it++) {
        if (it + 1 < niter) cp_wait1(); else cp_wait0();
        __syncthreads();
        if (it + 2 < niter) {
            int s = (it + 2) % STAGES;
            size_t k0 = (size_t)(it + 2) * BK;
            #pragma unroll
            for (int i = 0; i < 4; i++)
                cp_async16(adst + (uint32_t)(s * AELE * 4 + i * 32 * ASTR * 4),
                           Abase + (size_t)(32 * i) * Kk + k0);
            #pragma unroll
            for (int i = 0; i < 4; i++)
                cp_async16(bdst + (uint32_t)(s * BELE * 4 + i * 8 * BSTR * 4),
                           Bbase + ((size_t)(8 * i) + k0) * Nn);
        }
        cp_commit();

        const float* as = sm + (it % STAGES) * AELE;
        const float* bs = sm + STAGES * AELE + (it % STAGES) * BELE;
        #pragma unroll
        for (int kk = 0; kk < 4; kk++) {
            int k = kk * 8;
            uint32_t af[4][4], bf[4][2];
            #pragma unroll
            for (int mt = 0; mt < 4; mt++) {
                int m = warp_m + mt * 16 + g;
                af[mt][0] = to_tf32u(as[m * ASTR + k + q]);
                af[mt][1] = to_tf32u(as[(m + 8) * ASTR + k + q]);
                af[mt][2] = to_tf32u(as[m * ASTR + k + q + 4]);
                af[mt][3] = to_tf32u(as[(m + 8) * ASTR + k + q + 4]);
            }
            #pragma unroll
            for (int nt = 0; nt < 4; nt++) {
                int n = warp_n + nt * 8 + g;
                bf[nt][0] = to_tf32u(bs[(k + q) * BSTR + n]);
                bf[nt][1] = to_tf32u(bs[(k + 4 + q) * BSTR + n]);
            }
            #pragma unroll
            for (int mt = 0; mt < 4; mt++)
                #pragma unroll
                for (int nt = 0; nt < 4; nt++)
                    mma8(acc[mt][nt], af[mt], bf[nt]);
        }
    }
    __syncthreads();

    // epilogue
    if (splitk > 1) {
        #pragma unroll
        for (int mt = 0; mt < 4; mt++)
            #pragma unroll
            for (int nt = 0; nt < 4; nt++)
                #pragma unroll
                for (int e = 0; e < 4; e++) {
                    int row = rb + warp_m + mt * 16 + g + (e >> 1) * 8;
                    int col = cb + warp_n + nt * 8 + q * 2 + (e & 1);
                    float val = acc[mt][nt][e];
                    if (bias && z == 0) val += bias[col];
                    atomicAdd(&C[(size_t)row * Nn + col], val);
                }
    } else {
        #pragma unroll
        for (int mt = 0; mt < 4; mt++)
            #pragma unroll
            for (int nt = 0; nt < 4; nt++)
                #pragma unroll
                for (int e = 0; e < 4; e++) {
                    int row = rb + warp_m + mt * 16 + g + (e >> 1) * 8;
                    int col = cb + warp_n + nt * 8 + q * 2 + (e & 1);
                    float val = acc[mt][nt][e];
                    if (bias) val += bias[col];
                    if (act) val = gelu_tanh(val);
                    if (resid) val += resid[(size_t)row * Nn + col];
                    C[(size_t)row * Nn + col] = val;
                }
    }
}

// ---------------- per-layer init ----------------
__global__ void init_kernel() {
    int i = blockIdx.x * blockDim.x + threadIdx.x;
    int nt = gridDim.x * blockDim.x;
    if (i < HEADS) g_maxk[i] = -1e30f;
    if (i < HEADS * MF) g_ksum[i] = 0.f;
    for (int j = i; j < HEADS * NTOK; j += nt) g_maxq[j] = -1e30f;
    for (int j = i; j < HEADS * MF * DH; j += nt) g_ctx[j] = 0.f;
}

// ---------------- diag: 0.5*|x*DNORM|^2 per (head,row) for q and k --------
__global__ __launch_bounds__(384) void diag_kernel() {
    int n = blockIdx.x;
    int w = threadIdx.x >> 5, lane = threadIdx.x & 31;
    const float dn2 = DNORM * DNORM;
    float a = g_q[n * DIM + w * DH + lane];
    float b = g_q[n * DIM + w * DH + lane + 32];
    float s = a * a + b * b;
    for (int off = 16; off; off >>= 1) s += __shfl_xor_sync(0xffffffffu, s, off);
    if (lane == 0) g_diagq[w * NTOK + n] = 0.5f * dn2 * s;
    a = g_k[n * DIM + w * DH + lane];
    b = g_k[n * DIM + w * DH + lane + 32];
    s = a * a + b * b;
    for (int off = 16; off; off >>= 1) s += __shfl_xor_sync(0xffffffffu, s, off);
    if (lane == 0) g_diagk[w * NTOK + n] = 0.5f * dn2 * s;
}

// ---------------- feature GEMM: xd[h,n,m] = (x*DNORM) . proj[m] -----------
// grid (2 m-halves, 32 n-tiles, HEADS*2), 256 thr. K=64, single smem load.
#define FSA 68    /* 64+4 */
#define FSB 136   /* 128+8 */
__global__ __launch_bounds__(256, 2) void featgemm_kernel(const float* __restrict__ proj) {
    extern __shared__ float sm[];
    float* As = sm;                 // [128][FSA]
    float* Bs = sm + 128 * FSA;     // [64][FSB]
    int hk = blockIdx.z, h = hk >> 1, isK = hk & 1;
    const float* X = isK ? g_k : g_q;
    float* dst = isK ? g_kf : g_qf;
    int n0 = blockIdx.y * 128, m0 = blockIdx.x * 128;
    int t = threadIdx.x, lane = t & 31, wid = t >> 5;
    int warp_m = (wid & 1) * 64, warp_n = (wid >> 1) * 32;
    int q = lane & 3, g = lane >> 2;

    #pragma unroll
    for (int j = 0; j < 8; j++) {
        int i = t + j * 256;
        int row = i >> 4, c = (i & 15) * 4;
        float4 v = *(const float4*)&X[(size_t)(n0 + row) * DIM + h * DH + c];
        *(float4*)&As[row * FSA + c] = v;
    }
    for (int i = t; i < 128 * 64; i += 256) {
        int m = i >> 6, d = i & 63;
        Bs[d * FSB + m] = proj[(size_t)(m0 + m) * DH + d] * DNORM;
    }
    __syncthreads();

    float acc[4][4][4];
    #pragma unroll
    for (int mt = 0; mt < 4; mt++)
        #pragma unroll
        for (int nt = 0; nt < 4; nt++)
            #pragma unroll
            for (int e = 0; e < 4; e++) acc[mt][nt][e] = 0.f;

    #pragma unroll
    for (int kk = 0; kk < 8; kk++) {
        int k = kk * 8;
        uint32_t af[4][4], bf[4][2];
        #pragma unroll
        for (int mt = 0; mt < 4; mt++) {
            int m = warp_m + mt * 16 + g;
            af[mt][0] = to_tf32u(As[m * FSA + k + q]);
            af[mt][1] = to_tf32u(As[(m + 8) * FSA + k + q]);
            af[mt][2] = to_tf32u(As[m * FSA + k + q + 4]);
            af[mt][3] = to_tf32u(As[(m + 8) * FSA + k + q + 4]);
        }
        #pragma unroll
        for (int nt = 0; nt < 4; nt++) {
            int n = warp_n + nt * 8 + g;
            bf[nt][0] = to_tf32u(Bs[(k + q) * FSB + n]);
            bf[nt][1] = to_tf32u(Bs[(k + 4 + q) * FSB + n]);
        }
        #pragma unroll
        for (int mt = 0; mt < 4; mt++)
            #pragma unroll
            for (int nt = 0; nt < 4; nt++)
                mma8(acc[mt][nt], af[mt], bf[nt]);
    }

    // store raw xd + reductions
    #pragma unroll
    for (int mt = 0; mt < 4; mt++)
        #pragma unroll
        for (int nt = 0; nt < 4; nt++)
            #pragma unroll
            for (int e = 0; e < 4; e++) {
                int row = warp_m + mt * 16 + g + (e >> 1) * 8;
                int col = warp_n + nt * 8 + q * 2 + (e & 1);
                dst[((size_t)h * NTOK + n0 + row) * MF + m0 + col] = acc[mt][nt][e];
            }
    if (!isK) {
        // per-row max over this block's 128 m-columns
        #pragma unroll
        for (int mt = 0; mt < 4; mt++)
            #pragma unroll
            for (int eh = 0; eh < 2; eh++) {
                float v = -1e30f;
                #pragma unroll
                for (int nt = 0; nt < 4; nt++) {
                    v = fmaxf(v, acc[mt][nt][eh * 2]);
                    v = fmaxf(v, acc[mt][nt][eh * 2 + 1]);
                }
                v = fmaxf(v, __shfl_xor_sync(0xffffffffu, v, 1));
                v = fmaxf(v, __shfl_xor_sync(0xffffffffu, v, 2));
                if (q == 0)
                    atomicMaxFloat(&g_maxq[h * NTOK + n0 + warp_m + mt * 16 + g + eh * 8], v);
            }
    } else {
        float v = -1e30f;
        #pragma unroll
        for (int mt = 0; mt < 4; mt++)
            #pragma unroll
            for (int nt = 0; nt < 4; nt++)
                #pragma unroll
                for (int e = 0; e < 4; e++) v = fmaxf(v, acc[mt][nt][e]);
        for (int off = 16; off; off >>= 1) v = fmaxf(v, __shfl_xor_sync(0xffffffffu, v, off));
        if (lane == 0) atomicMaxFloat(&g_maxk[h], v);
    }
}

// ---------------- fused: kf=exp(...)*mask ; ksum += kf ; ctx += kf^T v ----
__global__ __launch_bounds__(256) void ctx_kernel(const float* __restrict__ methy) {
    int h = blockIdx.x, t = threadIdx.x;
    int n0 = blockIdx.y * 256;
    __shared__ float kfs[8 * 256];
    __shared__ float4 vs4[8 * 16];
    float acc[DH];
    #pragma unroll
    for (int d = 0; d < DH; d++) acc[d] = 0.f;
    float ksacc = 0.f;
    float mk = g_maxk[h];
    for (int c = 0; c < 256; c += 8) {
        #pragma unroll
        for (int j = 0; j < 8; j++) {
            int n = n0 + c + j;
            float xd = g_kf[((size_t)h * NTOK + n) * MF + t];
            float msk = (methy[n] != 0.0f) ? 1.0f : 0.0f;
            kfs[j * 256 + t] = RATIO * (expf(xd - g_diagk[h * NTOK + n] - mk) + 1e-4f) * msk;
        }
        if (t < 128) {
            int r = t >> 4, d4 = t & 15;
            vs4[r * 16 + d4] = *(const float4*)&g_v[(n0 + c + r) * DIM + h * DH + d4 * 4];
        }
        __syncthreads();
        #pragma unroll
        for (int r = 0; r < 8; r++) {
            float kv = kfs[r * 256 + t];
            ksacc += kv;
            #pragma unroll
            for (int d4 = 0; d4 < 16; d4++) {
                float4 vv = vs4[r * 16 + d4];
                acc[d4 * 4 + 0] += kv * vv.x;
                acc[d4 * 4 + 1] += kv * vv.y;
                acc[d4 * 4 + 2] += kv * vv.z;
                acc[d4 * 4 + 3] += kv * vv.w;
            }
        }
        __syncthreads();
    }
    atomicAdd(&g_ksum[h * MF + t], ksacc);
    #pragma unroll
    for (int d = 0; d < DH; d++) atomicAdd(&g_ctx[(size_t)h * MF * DH + t * DH + d], acc[d]);
}

// ---------------- o = (qf @ ctx) / (qf . k_sum), exp applied on load ------
__global__ __launch_bounds__(256) void attnout_kernel() {
    int h = blockIdx.x, t = threadIdx.x;
    int n0 = blockIdx.y * 64;
    extern __shared__ float sm[];
    float* ctxs = sm;
    float* ks = sm + MF * DH;
    float* qfs = ks + MF;
    for (int i = t; i < MF * DH; i += 256) ctxs[i] = g_ctx[(size_t)h * MF * DH + i];
    ks[t] = g_ksum[h * MF + t];
    __syncthreads();
    int r = t >> 6, d = t & 63;
    for (int rr = 0; rr < 64; rr += 4) {
        for (int i = t; i < 4 * MF; i += 256) {
            int n = n0 + rr + (i >> 8);
            float xd = g_qf[((size_t)h * NTOK + n) * MF + (i & 255)];
            qfs[i] = RATIO * (expf(xd - g_diagq[h * NTOK + n] - g_maxq[h * NTOK + n]) + 1e-4f);
        }
        __syncthreads();
        float acc = 0.f, den = 0.f;
        const float* qrow = &qfs[r * MF];
        #pragma unroll 8
        for (int m = 0; m < MF; m++) {
            float qv = qrow[m];
            acc += qv * ctxs[m * DH + d];
            den += qv * ks[m];
        }
        g_attn[(n0 + rr + r) * DIM + h * DH + d] = acc / den;
        __syncthreads();
    }
}

// ---------------- output head ----------------
__global__ __launch_bounds__(128) void wout_kernel(const float* __restrict__ Wout,
                                                   const float* __restrict__ bout,
                                                   float* __restrict__ out) {
    int n = blockIdx.x, t = threadIdx.x;
    __shared__ float xs[DIM];
    for (int i = t; i < DIM; i += 128) xs[i] = g_h[n * DIM + i];
    __syncthreads();
    if (t < VOCAB) {
        float acc = bout[t];
        for (int k = 0; k < DIM; k++) acc += xs[k] * Wout[k * VOCAB + t];
        out[n * VOCAB + t] = acc;
    }
}

// ---------------- host ----------------
extern "C" void kernel_launch(void* const* d_in, const int* in_sizes, int n_in,
                              void* d_out, int out_size) {
    const float* methy = (const float*)d_in[0];
    const int* chromo = (const int*)d_in[1];
    const int* pos    = (const int*)d_in[2];
    const float* mt = (const float*)d_in[3];
    const float* ct = (const float*)d_in[4];
    const float* pt = (const float*)d_in[5];
    const float* ln1g = (const float*)d_in[6];
    const float* ln1b = (const float*)d_in[7];
    const float* ln2g = (const float*)d_in[8];
    const float* ln2b = (const float*)d_in[9];
    const float* Wq = (const float*)d_in[10];
    const float* Wk = (const float*)d_in[11];
    const float* Wv = (const float*)d_in[12];
    const float* Wo = (const float*)d_in[13];
    const float* bo = (const float*)d_in[14];
    const float* W1 = (const float*)d_in[15];
    const float* b1 = (const float*)d_in[16];
    const float* W2 = (const float*)d_in[17];
    const float* b2 = (const float*)d_in[18];
    const float* proj = (const float*)d_in[19];
    const float* nfg = (const float*)d_in[20];
    const float* nfb = (const float*)d_in[21];
    const float* Wout = (const float*)d_in[22];
    const float* bout = (const float*)d_in[23];
    float* out = (float*)d_out;

    float *px, *ph, *pq, *pk, *pv, *pattn, *pff;
    cudaGetSymbolAddress((void**)&px, g_x);
    cudaGetSymbolAddress((void**)&ph, g_h);
    cudaGetSymbolAddress((void**)&pq, g_q);
    cudaGetSymbolAddress((void**)&pk, g_k);
    cudaGetSymbolAddress((void**)&pv, g_v);
    cudaGetSymbolAddress((void**)&pattn, g_attn);
    cudaGetSymbolAddress((void**)&pff, g_ff);

    const int ATT_SMEM   = (MF * DH + MF + 4 * MF) * sizeof(float);
    const int GEMM_SMEM  = STAGES * (AELE + BELE) * sizeof(float);   // 107,520
    const int FEAT_SMEM  = (128 * FSA + 64 * FSB) * sizeof(float);   // 69,632
    cudaFuncSetAttribute(attnout_kernel, cudaFuncAttributeMaxDynamicSharedMemorySize, ATT_SMEM);
    cudaFuncSetAttribute(tgemm_kernel,  cudaFuncAttributeMaxDynamicSharedMemorySize, GEMM_SMEM);
    cudaFuncSetAttribute(featgemm_kernel, cudaFuncAttributeMaxDynamicSharedMemorySize, FEAT_SMEM);

    embed_kernel<<<NTOK, 256>>>(methy, chromo, pos, mt, ct, pt);

    dim3 gqkv(DIM / BN, NTOK / BM, 3);   // (6, 32, 3)
    dim3 gsk(DIM / BN, NTOK / BM, 2);    // (6, 32, 2) split-K
    dim3 gff(FF / BN, NTOK / BM, 1);     // (24, 32)
    dim3 gfeat(2, 32, HEADS * 2);        // (2, 32, 24)

    for (int l = 0; l < DEPTH; l++) {
        const float* pj = proj + (size_t)l * MF * DH;
        // --- attention ---
        ln_kernel<<<NTOK, 256>>>(px, ln1g + l * DIM, ln1b + l * DIM, ph);
        tgemm_kernel<<<gqkv, 256, GEMM_SMEM>>>(ph,
            Wq + (size_t)l * DIM * DIM, Wk + (size_t)l * DIM * DIM, Wv + (size_t)l * DIM * DIM,
            nullptr, nullptr, pq, pk, pv, DIM, DIM, 0, 1);
        init_kernel<<<96, 256>>>();
        diag_kernel<<<NTOK, 384>>>();
        featgemm_kernel<<<gfeat, 256, FEAT_SMEM>>>(pj);
        ctx_kernel<<<dim3(HEADS, 16), 256>>>(methy);
        attnout_kernel<<<dim3(HEADS, NTOK / 64), 256, ATT_SMEM>>>();
        tgemm_kernel<<<gsk, 256, GEMM_SMEM>>>(pattn,
            Wo + (size_t)l * DIM * DIM, nullptr, nullptr,
            bo + l * DIM, nullptr, px, nullptr, nullptr, DIM, DIM, 0, 2);
        // --- FFN ---
        ln_kernel<<<NTOK, 256>>>(px, ln2g + l * DIM, ln2b + l * DIM, ph);
        tgemm_kernel<<<gff, 256, GEMM_SMEM>>>(ph,
            W1 + (size_t)l * DIM * FF, nullptr, nullptr,
            b1 + l * FF, nullptr, pff, nullptr, nullptr, FF, DIM, 1, 1);
        tgemm_kernel<<<gsk, 256, GEMM_SMEM>>>(pff,
            W2 + (size_t)l * FF * DIM, nullptr, nullptr,
            b2 + l * DIM, nullptr, px, nullptr, nullptr, DIM, FF, 0, 2);
    }

    ln_kernel<<<NTOK, 256>>>(px, nfg, nfb, ph);
    wout_kernel<<<NTOK, 128>>>(Wout, bout, out);
}

// round 8
// speedup vs baseline: 4.0229x; 1.4043x over previous
#include <cuda_runtime.h>
#include <math.h>
#include <stdint.h>

#define NTOK 4096
#define DIM 768
#define DEPTH 6
#define HEADS 12
#define DH 64
#define FF 3072
#define MF 256
#define VOCAB 102
#define DNORM 0.35355339059327373f   /* 64^-0.25 */
#define RATIO 0.0625f                /* 256^-0.5 */

// ---------------- scratch (device globals, no allocation) ----------------
__device__ float g_x[NTOK * DIM];
__device__ float g_h[NTOK * DIM];
__device__ float g_q[NTOK * DIM];
__device__ float g_k[NTOK * DIM];
__device__ float g_v[NTOK * DIM];
__device__ float g_attn[NTOK * DIM];
__device__ float g_ff[NTOK * FF];
__device__ float g_qf[HEADS * NTOK * MF];   // raw xd; exp applied in attngemm staging
__device__ float g_kf[HEADS * NTOK * MF];   // raw xd; exp applied in ctxgemm staging
__device__ float g_diagq[HEADS * NTOK];
__device__ float g_diagk[HEADS * NTOK];
__device__ float g_maxq[HEADS * NTOK];
__device__ float g_maxk[HEADS];
__device__ float g_ksum[HEADS * MF];
__device__ float g_ctx[HEADS * MF * DH];

// ---------------- helpers ----------------
__device__ __forceinline__ void atomicMaxFloat(float* addr, float val) {
    int* ia = (int*)addr;
    int old = *ia;
    while (val > __int_as_float(old)) {
        int assumed = old;
        old = atomicCAS(ia, assumed, __float_as_int(val));
        if (old == assumed) break;
    }
}

__device__ __forceinline__ float tanh_fast(float x) {
    float r;
    asm("tanh.approx.f32 %0, %1;" : "=f"(r) : "f"(x));
    return r;
}

__device__ __forceinline__ float gelu_tanh(float u) {
    return 0.5f * u * (1.0f + tanh_fast(0.7978845608028654f * (u + 0.044715f * u * u * u)));
}

__device__ __forceinline__ uint32_t to_tf32u(float x) {
    float r;
    asm("cvt.rna.tf32.f32 %0, %1;" : "=f"(r) : "f"(x));
    return __float_as_uint(r);
}

__device__ __forceinline__ void mma8(float* c, const uint32_t* a, const uint32_t* b) {
    asm volatile(
        "mma.sync.aligned.m16n8k8.row.col.f32.tf32.tf32.f32 "
        "{%0,%1,%2,%3}, {%4,%5,%6,%7}, {%8,%9}, {%0,%1,%2,%3};"
        : "+f"(c[0]), "+f"(c[1]), "+f"(c[2]), "+f"(c[3])
        : "r"(a[0]), "r"(a[1]), "r"(a[2]), "r"(a[3]), "r"(b[0]), "r"(b[1]));
}

__device__ __forceinline__ void cp_async16(uint32_t dst, const float* src) {
    asm volatile("cp.async.cg.shared.global [%0], [%1], 16;" :: "r"(dst), "l"(src));
}
__device__ __forceinline__ void cp_commit() {
    asm volatile("cp.async.commit_group;");
}
__device__ __forceinline__ void cp_wait1() {
    asm volatile("cp.async.wait_group 1;");
}
__device__ __forceinline__ void cp_wait0() {
    asm volatile("cp.async.wait_group 0;");
}

// ---------------- embedding + bucketize ----------------
__global__ void embed_kernel(const float* __restrict__ methy,
                             const int* __restrict__ chromo,
                             const int* __restrict__ pos,
                             const float* __restrict__ mt,
                             const float* __restrict__ ct,
                             const float* __restrict__ pt) {
    int n = blockIdx.x;
    float x = methy[n];
    int idx = (x > -2.0f) + (x > -1.0f);
    #pragma unroll 4
    for (int i = 0; i < 100; i++) idx += ((float)i * 0.01f < x) ? 1 : 0;
    int c = chromo[n], p = pos[n];
    const float* mrow = mt + (size_t)idx * DIM;
    const float* prow = pt + (size_t)p * DIM;
    const float* crow = ct + (size_t)c * DIM;
    for (int d = threadIdx.x; d < DIM; d += blockDim.x)
        g_x[n * DIM + d] = mrow[d] + prow[d] + crow[d];
}

// ---------------- layernorm ----------------
__global__ __launch_bounds__(256) void ln_kernel(const float* __restrict__ in,
                                                 const float* __restrict__ g,
                                                 const float* __restrict__ b,
                                                 float* __restrict__ out) {
    int n = blockIdx.x, t = threadIdx.x;
    __shared__ float red[256];
    float v[3];
    float s = 0.f;
    #pragma unroll
    for (int i = 0; i < 3; i++) { v[i] = in[n * DIM + t + i * 256]; s += v[i]; }
    red[t] = s; __syncthreads();
    for (int off = 128; off > 0; off >>= 1) { if (t < off) red[t] += red[t + off]; __syncthreads(); }
    float mu = red[0] * (1.0f / DIM);
    __syncthreads();
    float s2 = 0.f;
    #pragma unroll
    for (int i = 0; i < 3; i++) { float d = v[i] - mu; s2 += d * d; }
    red[t] = s2; __syncthreads();
    for (int off = 128; off > 0; off >>= 1) { if (t < off) red[t] += red[t + off]; __syncthreads(); }
    float rstd = rsqrtf(red[0] * (1.0f / DIM) + 1e-5f);
    #pragma unroll
    for (int i = 0; i < 3; i++) {
        int d = t + i * 256;
        out[n * DIM + d] = (v[i] - mu) * rstd * g[d] + b[d];
    }
}

// ---------------- TF32 GEMM 128x128x32, cp.async 3-stage, z-fused/split-K --
#define BM 128
#define BN 128
#define BK 32
#define ASTR 36   /* BK+4 */
#define BSTR 136  /* BN+8 */
#define AELE (BM * ASTR)
#define BELE (BK * BSTR)
#define STAGES 3

__global__ __launch_bounds__(256, 2) void tgemm_kernel(const float* __restrict__ A,
                                                       const float* __restrict__ B0,
                                                       const float* __restrict__ B1,
                                                       const float* __restrict__ B2,
                                                       const float* __restrict__ bias,
                                                       const float* __restrict__ resid,
                                                       float* __restrict__ C0,
                                                       float* __restrict__ C1,
                                                       float* __restrict__ C2,
                                                       int Nn, int Kk, int act, int splitk) {
    extern __shared__ float sm[];
    int z = blockIdx.z;
    const float* B = B0;
    float* C = C0;
    int koff = 0, Keff = Kk;
    if (splitk > 1) {
        Keff = Kk / splitk;
        koff = z * Keff;
    } else {
        B = (z == 0) ? B0 : ((z == 1) ? B1 : B2);
        C = (z == 0) ? C0 : ((z == 1) ? C1 : C2);
    }

    int t = threadIdx.x;
    int rb = blockIdx.y * BM, cb = blockIdx.x * BN;
    int lane = t & 31, wid = t >> 5;
    int warp_m = (wid & 1) * 64, warp_n = (wid >> 1) * 32;
    int q = lane & 3, g = lane >> 2;

    int ar = t >> 3, ac = (t & 7) * 4;
    int br = t >> 5, bc = (t & 31) * 4;

    const float* Abase = A + (size_t)(rb + ar) * Kk + ac + koff;
    const float* Bbase = B + (size_t)(br + koff) * Nn + cb + bc;

    uint32_t smA = (uint32_t)__cvta_generic_to_shared(sm);
    uint32_t smB = smA + STAGES * AELE * 4;
    uint32_t adst = smA + (uint32_t)((ar * ASTR + ac) * 4);
    uint32_t bdst = smB + (uint32_t)((br * BSTR + bc) * 4);

    int niter = Keff / BK;

    #pragma unroll
    for (int s = 0; s < 2; s++) {
        if (s < niter) {
            size_t k0 = (size_t)s * BK;
            #pragma unroll
            for (int i = 0; i < 4; i++)
                cp_async16(adst + (uint32_t)(s * AELE * 4 + i * 32 * ASTR * 4),
                           Abase + (size_t)(32 * i) * Kk + k0);
            #pragma unroll
            for (int i = 0; i < 4; i++)
                cp_async16(bdst + (uint32_t)(s * BELE * 4 + i * 8 * BSTR * 4),
                           Bbase + ((size_t)(8 * i) + k0) * Nn);
        }
        cp_commit();
    }

    float acc[4][4][4];
    #pragma unroll
    for (int mt = 0; mt < 4; mt++)
        #pragma unroll
        for (int nt = 0; nt < 4; nt++)
            #pragma unroll
            for (int e = 0; e < 4; e++) acc[mt][nt][e] = 0.f;

    for (int it = 0; it < niter; it++) {
        if (it + 1 < niter) cp_wait1(); else cp_wait0();
        __syncthreads();
        if (it + 2 < niter) {
            int s = (it + 2) % STAGES;
            size_t k0 = (size_t)(it + 2) * BK;
            #pragma unroll
            for (int i = 0; i < 4; i++)
                cp_async16(adst + (uint32_t)(s * AELE * 4 + i * 32 * ASTR * 4),
                           Abase + (size_t)(32 * i) * Kk + k0);
            #pragma unroll
            for (int i = 0; i < 4; i++)
                cp_async16(bdst + (uint32_t)(s * BELE * 4 + i * 8 * BSTR * 4),
                           Bbase + ((size_t)(8 * i) + k0) * Nn);
        }
        cp_commit();

        const float* as = sm + (it % STAGES) * AELE;
        const float* bs = sm + STAGES * AELE + (it % STAGES) * BELE;
        #pragma unroll
        for (int kk = 0; kk < 4; kk++) {
            int k = kk * 8;
            uint32_t af[4][4], bf[4][2];
            #pragma unroll
            for (int mt = 0; mt < 4; mt++) {
                int m = warp_m + mt * 16 + g;
                af[mt][0] = to_tf32u(as[m * ASTR + k + q]);
                af[mt][1] = to_tf32u(as[(m + 8) * ASTR + k + q]);
                af[mt][2] = to_tf32u(as[m * ASTR + k + q + 4]);
                af[mt][3] = to_tf32u(as[(m + 8) * ASTR + k + q + 4]);
            }
            #pragma unroll
            for (int nt = 0; nt < 4; nt++) {
                int n = warp_n + nt * 8 + g;
                bf[nt][0] = to_tf32u(bs[(k + q) * BSTR + n]);
                bf[nt][1] = to_tf32u(bs[(k + 4 + q) * BSTR + n]);
            }
            #pragma unroll
            for (int mt = 0; mt < 4; mt++)
                #pragma unroll
                for (int nt = 0; nt < 4; nt++)
                    mma8(acc[mt][nt], af[mt], bf[nt]);
        }
    }
    __syncthreads();

    // epilogue
    if (splitk > 1) {
        #pragma unroll
        for (int mt = 0; mt < 4; mt++)
            #pragma unroll
            for (int nt = 0; nt < 4; nt++)
                #pragma unroll
                for (int e = 0; e < 4; e++) {
                    int row = rb + warp_m + mt * 16 + g + (e >> 1) * 8;
                    int col = cb + warp_n + nt * 8 + q * 2 + (e & 1);
                    float val = acc[mt][nt][e];
                    if (bias && z == 0) val += bias[col];
                    atomicAdd(&C[(size_t)row * Nn + col], val);
                }
    } else {
        #pragma unroll
        for (int mt = 0; mt < 4; mt++)
            #pragma unroll
            for (int nt = 0; nt < 4; nt++)
                #pragma unroll
                for (int e = 0; e < 4; e++) {
                    int row = rb + warp_m + mt * 16 + g + (e >> 1) * 8;
                    int col = cb + warp_n + nt * 8 + q * 2 + (e & 1);
                    float val = acc[mt][nt][e];
                    if (bias) val += bias[col];
                    if (act) val = gelu_tanh(val);
                    if (resid) val += resid[(size_t)row * Nn + col];
                    C[(size_t)row * Nn + col] = val;
                }
    }
}

// ---------------- per-layer init ----------------
__global__ void init_kernel() {
    int i = blockIdx.x * blockDim.x + threadIdx.x;
    int nt = gridDim.x * blockDim.x;
    if (i < HEADS) g_maxk[i] = -1e30f;
    if (i < HEADS * MF) g_ksum[i] = 0.f;
    for (int j = i; j < HEADS * NTOK; j += nt) g_maxq[j] = -1e30f;
    for (int j = i; j < HEADS * MF * DH; j += nt) g_ctx[j] = 0.f;
}

// ---------------- diag: 0.5*|x*DNORM|^2 per (head,row) for q and k --------
__global__ __launch_bounds__(384) void diag_kernel() {
    int n = blockIdx.x;
    int w = threadIdx.x >> 5, lane = threadIdx.x & 31;
    const float dn2 = DNORM * DNORM;
    float a = g_q[n * DIM + w * DH + lane];
    float b = g_q[n * DIM + w * DH + lane + 32];
    float s = a * a + b * b;
    for (int off = 16; off; off >>= 1) s += __shfl_xor_sync(0xffffffffu, s, off);
    if (lane == 0) g_diagq[w * NTOK + n] = 0.5f * dn2 * s;
    a = g_k[n * DIM + w * DH + lane];
    b = g_k[n * DIM + w * DH + lane + 32];
    s = a * a + b * b;
    for (int off = 16; off; off >>= 1) s += __shfl_xor_sync(0xffffffffu, s, off);
    if (lane == 0) g_diagk[w * NTOK + n] = 0.5f * dn2 * s;
}

// ---------------- feature GEMM: xd[h,n,m] = (x*DNORM) . proj[m] -----------
#define FSA 68    /* 64+4 */
#define FSB 136   /* 128+8 */
__global__ __launch_bounds__(256, 2) void featgemm_kernel(const float* __restrict__ proj) {
    extern __shared__ float sm[];
    float* As = sm;                 // [128][FSA]
    float* Bs = sm + 128 * FSA;     // [64][FSB]
    int hk = blockIdx.z, h = hk >> 1, isK = hk & 1;
    const float* X = isK ? g_k : g_q;
    float* dst = isK ? g_kf : g_qf;
    int n0 = blockIdx.y * 128, m0 = blockIdx.x * 128;
    int t = threadIdx.x, lane = t & 31, wid = t >> 5;
    int warp_m = (wid & 1) * 64, warp_n = (wid >> 1) * 32;
    int q = lane & 3, g = lane >> 2;

    #pragma unroll
    for (int j = 0; j < 8; j++) {
        int i = t + j * 256;
        int row = i >> 4, c = (i & 15) * 4;
        float4 v = *(const float4*)&X[(size_t)(n0 + row) * DIM + h * DH + c];
        *(float4*)&As[row * FSA + c] = v;
    }
    for (int i = t; i < 128 * 64; i += 256) {
        int m = i >> 6, d = i & 63;
        Bs[d * FSB + m] = proj[(size_t)(m0 + m) * DH + d] * DNORM;
    }
    __syncthreads();

    float acc[4][4][4];
    #pragma unroll
    for (int mt = 0; mt < 4; mt++)
        #pragma unroll
        for (int nt = 0; nt < 4; nt++)
            #pragma unroll
            for (int e = 0; e < 4; e++) acc[mt][nt][e] = 0.f;

    #pragma unroll
    for (int kk = 0; kk < 8; kk++) {
        int k = kk * 8;
        uint32_t af[4][4], bf[4][2];
        #pragma unroll
        for (int mt = 0; mt < 4; mt++) {
            int m = warp_m + mt * 16 + g;
            af[mt][0] = to_tf32u(As[m * FSA + k + q]);
            af[mt][1] = to_tf32u(As[(m + 8) * FSA + k + q]);
            af[mt][2] = to_tf32u(As[m * FSA + k + q + 4]);
            af[mt][3] = to_tf32u(As[(m + 8) * FSA + k + q + 4]);
        }
        #pragma unroll
        for (int nt = 0; nt < 4; nt++) {
            int n = warp_n + nt * 8 + g;
            bf[nt][0] = to_tf32u(Bs[(k + q) * FSB + n]);
            bf[nt][1] = to_tf32u(Bs[(k + 4 + q) * FSB + n]);
        }
        #pragma unroll
        for (int mt = 0; mt < 4; mt++)
            #pragma unroll
            for (int nt = 0; nt < 4; nt++)
                mma8(acc[mt][nt], af[mt], bf[nt]);
    }

    #pragma unroll
    for (int mt = 0; mt < 4; mt++)
        #pragma unroll
        for (int nt = 0; nt < 4; nt++)
            #pragma unroll
            for (int e = 0; e < 4; e++) {
                int row = warp_m + mt * 16 + g + (e >> 1) * 8;
                int col = warp_n + nt * 8 + q * 2 + (e & 1);
                dst[((size_t)h * NTOK + n0 + row) * MF + m0 + col] = acc[mt][nt][e];
            }
    if (!isK) {
        #pragma unroll
        for (int mt = 0; mt < 4; mt++)
            #pragma unroll
            for (int eh = 0; eh < 2; eh++) {
                float v = -1e30f;
                #pragma unroll
                for (int nt = 0; nt < 4; nt++) {
                    v = fmaxf(v, acc[mt][nt][eh * 2]);
                    v = fmaxf(v, acc[mt][nt][eh * 2 + 1]);
                }
                v = fmaxf(v, __shfl_xor_sync(0xffffffffu, v, 1));
                v = fmaxf(v, __shfl_xor_sync(0xffffffffu, v, 2));
                if (q == 0)
                    atomicMaxFloat(&g_maxq[h * NTOK + n0 + warp_m + mt * 16 + g + eh * 8], v);
            }
    } else {
        float v = -1e30f;
        #pragma unroll
        for (int mt = 0; mt < 4; mt++)
            #pragma unroll
            for (int nt = 0; nt < 4; nt++)
                #pragma unroll
                for (int e = 0; e < 4; e++) v = fmaxf(v, acc[mt][nt][e]);
        for (int off = 16; off; off >>= 1) v = fmaxf(v, __shfl_xor_sync(0xffffffffu, v, off));
        if (lane == 0) atomicMaxFloat(&g_maxk[h], v);
    }
}

// ---------------- ctx GEMM: ctx[m,d] += kf^T v, ksum += col sums ----------
// grid (HEADS, 2 m-tiles, 8 n-splits). kf exp'd at staging (once per element).
#define CSA 136   /* 128 m + 8 pad */
#define CSB 72    /* 64 d + 8 pad */
__global__ __launch_bounds__(256) void ctxgemm_kernel(const float* __restrict__ methy) {
    __shared__ float As[32 * CSA];   // [k(token)][m]
    __shared__ float Bs[32 * CSB];   // [k(token)][d]
    int h = blockIdx.x, m0 = blockIdx.y * 128, nbase = blockIdx.z * 512;
    int t = threadIdx.x, lane = t & 31, wid = t >> 5;
    int warp_m = (wid & 3) * 32, warp_n = (wid >> 2) * 32;
    int q = lane & 3, g = lane >> 2;
    float mk = g_maxk[h];
    int sr = t >> 3;            // staging row 0..31
    int sc = (t & 7) * 4;       // staging col base

    float acc[2][4][4];
    #pragma unroll
    for (int mt = 0; mt < 2; mt++)
        #pragma unroll
        for (int nt = 0; nt < 4; nt++)
            #pragma unroll
            for (int e = 0; e < 4; e++) acc[mt][nt][e] = 0.f;
    float ksacc[16];
    #pragma unroll
    for (int i = 0; i < 16; i++) ksacc[i] = 0.f;

    for (int c = 0; c < 512; c += 32) {
        int n = nbase + c + sr;
        float dgk = g_diagk[h * NTOK + n];
        float msk = (methy[n] != 0.0f) ? 1.0f : 0.0f;
        const float* src = &g_kf[((size_t)h * NTOK + n) * MF + m0];
        #pragma unroll
        for (int j = 0; j < 4; j++) {
            int col = sc + 32 * j;
            float4 v = *(const float4*)&src[col];
            float4 w;
            w.x = RATIO * (expf(v.x - dgk - mk) + 1e-4f) * msk;
            w.y = RATIO * (expf(v.y - dgk - mk) + 1e-4f) * msk;
            w.z = RATIO * (expf(v.z - dgk - mk) + 1e-4f) * msk;
            w.w = RATIO * (expf(v.w - dgk - mk) + 1e-4f) * msk;
            *(float4*)&As[sr * CSA + col] = w;
            ksacc[j * 4 + 0] += w.x; ksacc[j * 4 + 1] += w.y;
            ksacc[j * 4 + 2] += w.z; ksacc[j * 4 + 3] += w.w;
        }
        #pragma unroll
        for (int j = 0; j < 2; j++) {
            int fi = t * 2 + j;
            int row = fi >> 4, col = (fi & 15) * 4;
            *(float4*)&Bs[row * CSB + col] =
                *(const float4*)&g_v[(size_t)(nbase + c + row) * DIM + h * DH + col];
        }
        __syncthreads();
        #pragma unroll
        for (int kk = 0; kk < 4; kk++) {
            int k = kk * 8;
            uint32_t af[2][4], bf[4][2];
            #pragma unroll
            for (int mt = 0; mt < 2; mt++) {
                int m = warp_m + mt * 16 + g;
                af[mt][0] = to_tf32u(As[(k + q) * CSA + m]);
                af[mt][1] = to_tf32u(As[(k + q) * CSA + m + 8]);
                af[mt][2] = to_tf32u(As[(k + 4 + q) * CSA + m]);
                af[mt][3] = to_tf32u(As[(k + 4 + q) * CSA + m + 8]);
            }
            #pragma unroll
            for (int nt = 0; nt < 4; nt++) {
                int n2 = warp_n + nt * 8 + g;
                bf[nt][0] = to_tf32u(Bs[(k + q) * CSB + n2]);
                bf[nt][1] = to_tf32u(Bs[(k + 4 + q) * CSB + n2]);
            }
            #pragma unroll
            for (int mt = 0; mt < 2; mt++)
                #pragma unroll
                for (int nt = 0; nt < 4; nt++)
                    mma8(acc[mt][nt], af[mt], bf[nt]);
        }
        __syncthreads();
    }

    // ksum reduce via As reuse
    #pragma unroll
    for (int j = 0; j < 4; j++) {
        int col = sc + 32 * j;
        *(float4*)&As[sr * CSA + col] = make_float4(ksacc[j*4], ksacc[j*4+1], ksacc[j*4+2], ksacc[j*4+3]);
    }
    __syncthreads();
    if (t < 128) {
        float s = 0.f;
        #pragma unroll
        for (int r = 0; r < 32; r++) s += As[r * CSA + t];
        atomicAdd(&g_ksum[h * MF + m0 + t], s);
    }
    // ctx epilogue
    #pragma unroll
    for (int mt = 0; mt < 2; mt++)
        #pragma unroll
        for (int nt = 0; nt < 4; nt++)
            #pragma unroll
            for (int e = 0; e < 4; e++) {
                int m = m0 + warp_m + mt * 16 + g + (e >> 1) * 8;
                int d = warp_n + nt * 8 + q * 2 + (e & 1);
                atomicAdd(&g_ctx[(size_t)h * MF * DH + m * DH + d], acc[mt][nt][e]);
            }
}

// ---------------- attn GEMM: o[n,d] = (qf @ ctx)[n,d] / (qf . ksum)[n] ----
// grid (HEADS, 32 n-tiles). qf exp'd at staging; den accumulated fp32.
__global__ __launch_bounds__(256) void attngemm_kernel() {
    __shared__ float As[128 * 36];   // [n row][k chunk 32]
    __shared__ float Bs[32 * CSB];   // [k(m)][d]
    __shared__ float ksums[MF];
    __shared__ float dens[128];
    int h = blockIdx.x, n0 = blockIdx.y * 128;
    int t = threadIdx.x, lane = t & 31, wid = t >> 5;
    int warp_m = (wid & 3) * 32, warp_n = (wid >> 2) * 32;
    int q = lane & 3, g = lane >> 2;

    ksums[t] = g_ksum[h * MF + t];
    __syncthreads();

    int sr = t >> 1;                 // staging row 0..127
    int n = n0 + sr;
    float dq = g_diagq[h * NTOK + n];
    float mq = g_maxq[h * NTOK + n];
    float denp = 0.f;

    float acc[2][4][4];
    #pragma unroll
    for (int mt = 0; mt < 2; mt++)
        #pragma unroll
        for (int nt = 0; nt < 4; nt++)
            #pragma unroll
            for (int e = 0; e < 4; e++) acc[mt][nt][e] = 0.f;

    for (int c = 0; c < 256; c += 32) {
        const float* src = &g_qf[((size_t)h * NTOK + n) * MF + c];
        #pragma unroll
        for (int j = 0; j < 4; j++) {
            int col = ((t & 1) * 4 + j) * 4;
            float4 v = *(const float4*)&src[col];
            float4 w;
            w.x = RATIO * (expf(v.x - dq - mq) + 1e-4f);
            w.y = RATIO * (expf(v.y - dq - mq) + 1e-4f);
            w.z = RATIO * (expf(v.z - dq - mq) + 1e-4f);
            w.w = RATIO * (expf(v.w - dq - mq) + 1e-4f);
            *(float4*)&As[sr * 36 + col] = w;
            denp += w.x * ksums[c + col] + w.y * ksums[c + col + 1]
                  + w.z * ksums[c + col + 2] + w.w * ksums[c + col + 3];
        }
        #pragma unroll
        for (int j = 0; j < 2; j++) {
            int fi = t * 2 + j;
            int row = fi >> 4, col = (fi & 15) * 4;
            *(float4*)&Bs[row * CSB + col] =
                *(const float4*)&g_ctx[(size_t)h * MF * DH + (size_t)(c + row) * DH + col];
        }
        __syncthreads();
        #pragma unroll
        for (int kk = 0; kk < 4; kk++) {
            int k = kk * 8;
            uint32_t af[2][4], bf[4][2];
            #pragma unroll
            for (int mt = 0; mt < 2; mt++) {
                int m = warp_m + mt * 16 + g;
                af[mt][0] = to_tf32u(As[m * 36 + k + q]);
                af[mt][1] = to_tf32u(As[(m + 8) * 36 + k + q]);
                af[mt][2] = to_tf32u(As[m * 36 + k + q + 4]);
                af[mt][3] = to_tf32u(As[(m + 8) * 36 + k + q + 4]);
            }
            #pragma unroll
            for (int nt = 0; nt < 4; nt++) {
                int n2 = warp_n + nt * 8 + g;
                bf[nt][0] = to_tf32u(Bs[(k + q) * CSB + n2]);
                bf[nt][1] = to_tf32u(Bs[(k + 4 + q) * CSB + n2]);
            }
            #pragma unroll
            for (int mt = 0; mt < 2; mt++)
                #pragma unroll
                for (int nt = 0; nt < 4; nt++)
                    mma8(acc[mt][nt], af[mt], bf[nt]);
        }
        __syncthreads();
    }

    denp += __shfl_xor_sync(0xffffffffu, denp, 1);
    if ((t & 1) == 0) dens[sr] = denp;
    __syncthreads();

    #pragma unroll
    for (int mt = 0; mt < 2; mt++)
        #pragma unroll
        for (int nt = 0; nt < 4; nt++)
            #pragma unroll
            for (int e = 0; e < 4; e++) {
                int row = warp_m + mt * 16 + g + (e >> 1) * 8;
                int d = warp_n + nt * 8 + q * 2 + (e & 1);
                g_attn[(size_t)(n0 + row) * DIM + h * DH + d] = acc[mt][nt][e] / dens[row];
            }
}

// ---------------- output head ----------------
__global__ __launch_bounds__(128) void wout_kernel(const float* __restrict__ Wout,
                                                   const float* __restrict__ bout,
                                                   float* __restrict__ out) {
    int n = blockIdx.x, t = threadIdx.x;
    __shared__ float xs[DIM];
    for (int i = t; i < DIM; i += 128) xs[i] = g_h[n * DIM + i];
    __syncthreads();
    if (t < VOCAB) {
        float acc = bout[t];
        for (int k = 0; k < DIM; k++) acc += xs[k] * Wout[k * VOCAB + t];
        out[n * VOCAB + t] = acc;
    }
}

// ---------------- host ----------------
extern "C" void kernel_launch(void* const* d_in, const int* in_sizes, int n_in,
                              void* d_out, int out_size) {
    const float* methy = (const float*)d_in[0];
    const int* chromo = (const int*)d_in[1];
    const int* pos    = (const int*)d_in[2];
    const float* mt = (const float*)d_in[3];
    const float* ct = (const float*)d_in[4];
    const float* pt = (const float*)d_in[5];
    const float* ln1g = (const float*)d_in[6];
    const float* ln1b = (const float*)d_in[7];
    const float* ln2g = (const float*)d_in[8];
    const float* ln2b = (const float*)d_in[9];
    const float* Wq = (const float*)d_in[10];
    const float* Wk = (const float*)d_in[11];
    const float* Wv = (const float*)d_in[12];
    const float* Wo = (const float*)d_in[13];
    const float* bo = (const float*)d_in[14];
    const float* W1 = (const float*)d_in[15];
    const float* b1 = (const float*)d_in[16];
    const float* W2 = (const float*)d_in[17];
    const float* b2 = (const float*)d_in[18];
    const float* proj = (const float*)d_in[19];
    const float* nfg = (const float*)d_in[20];
    const float* nfb = (const float*)d_in[21];
    const float* Wout = (const float*)d_in[22];
    const float* bout = (const float*)d_in[23];
    float* out = (float*)d_out;

    float *px, *ph, *pq, *pk, *pv, *pattn, *pff;
    cudaGetSymbolAddress((void**)&px, g_x);
    cudaGetSymbolAddress((void**)&ph, g_h);
    cudaGetSymbolAddress((void**)&pq, g_q);
    cudaGetSymbolAddress((void**)&pk, g_k);
    cudaGetSymbolAddress((void**)&pv, g_v);
    cudaGetSymbolAddress((void**)&pattn, g_attn);
    cudaGetSymbolAddress((void**)&pff, g_ff);

    const int GEMM_SMEM  = STAGES * (AELE + BELE) * sizeof(float);   // 107,520
    const int FEAT_SMEM  = (128 * FSA + 64 * FSB) * sizeof(float);   // 69,632
    cudaFuncSetAttribute(tgemm_kernel,  cudaFuncAttributeMaxDynamicSharedMemorySize, GEMM_SMEM);
    cudaFuncSetAttribute(featgemm_kernel, cudaFuncAttributeMaxDynamicSharedMemorySize, FEAT_SMEM);

    embed_kernel<<<NTOK, 256>>>(methy, chromo, pos, mt, ct, pt);

    dim3 gqkv(DIM / BN, NTOK / BM, 3);   // (6, 32, 3)
    dim3 gsk(DIM / BN, NTOK / BM, 2);    // (6, 32, 2) split-K
    dim3 gff(FF / BN, NTOK / BM, 1);     // (24, 32)
    dim3 gfeat(2, 32, HEADS * 2);        // (2, 32, 24)
    dim3 gctx(HEADS, 2, 8);              // (12, 2, 8)
    dim3 gattn(HEADS, NTOK / 128);       // (12, 32)

    for (int l = 0; l < DEPTH; l++) {
        const float* pj = proj + (size_t)l * MF * DH;
        // --- attention ---
        ln_kernel<<<NTOK, 256>>>(px, ln1g + l * DIM, ln1b + l * DIM, ph);
        tgemm_kernel<<<gqkv, 256, GEMM_SMEM>>>(ph,
            Wq + (size_t)l * DIM * DIM, Wk + (size_t)l * DIM * DIM, Wv + (size_t)l * DIM * DIM,
            nullptr, nullptr, pq, pk, pv, DIM, DIM, 0, 1);
        init_kernel<<<96, 256>>>();
        diag_kernel<<<NTOK, 384>>>();
        featgemm_kernel<<<gfeat, 256, FEAT_SMEM>>>(pj);
        ctxgemm_kernel<<<gctx, 256>>>(methy);
        attngemm_kernel<<<gattn, 256>>>();
        tgemm_kernel<<<gsk, 256, GEMM_SMEM>>>(pattn,
            Wo + (size_t)l * DIM * DIM, nullptr, nullptr,
            bo + l * DIM, nullptr, px, nullptr, nullptr, DIM, DIM, 0, 2);
        // --- FFN ---
        ln_kernel<<<NTOK, 256>>>(px, ln2g + l * DIM, ln2b + l * DIM, ph);
        tgemm_kernel<<<gff, 256, GEMM_SMEM>>>(ph,
            W1 + (size_t)l * DIM * FF, nullptr, nullptr,
            b1 + l * FF, nullptr, pff, nullptr, nullptr, FF, DIM, 1, 1);
        tgemm_kernel<<<gsk, 256, GEMM_SMEM>>>(pff,
            W2 + (size_t)l * FF * DIM, nullptr, nullptr,
            b2 + l * DIM, nullptr, px, nullptr, nullptr, DIM, FF, 0, 2);
    }

    ln_kernel<<<NTOK, 256>>>(px, nfg, nfb, ph);
    wout_kernel<<<NTOK, 128>>>(Wout, bout, out);
}

// round 10
// speedup vs baseline: 4.2263x; 1.0506x over previous
#include <cuda_runtime.h>
#include <math.h>
#include <stdint.h>

#define NTOK 4096
#define DIM 768
#define DEPTH 6
#define HEADS 12
#define DH 64
#define FF 3072
#define MF 256
#define VOCAB 102
#define DNORM 0.35355339059327373f   /* 64^-0.25 */
#define RATIO 0.0625f                /* 256^-0.5 */

// ---------------- scratch (device globals, no allocation) ----------------
__device__ float g_x[NTOK * DIM];
__device__ float g_h[NTOK * DIM];
__device__ float g_q[NTOK * DIM];
__device__ float g_k[NTOK * DIM];
__device__ float g_v[NTOK * DIM];
__device__ float g_attn[NTOK * DIM];
__device__ float g_ff[NTOK * FF];
__device__ float g_qf[HEADS * NTOK * MF];     // raw xd; exp applied in attngemm staging
__device__ float g_kf[HEADS * NTOK * MF];     // raw xd; exp applied in ctxgemm staging
__device__ float g_diagq[HEADS * NTOK];
__device__ float g_diagk[HEADS * NTOK];
__device__ float g_maxq2[2 * HEADS * NTOK];   // per m-half row max (block-wide reduced)
__device__ float g_maxk2[HEADS * 64];         // per (n-tile, m-half) block max
__device__ float g_ksum[HEADS * MF];
__device__ float g_ctx[HEADS * MF * DH];
__device__ float g_ctxp[8 * HEADS * MF * DH]; // per-z-slice ctx partials
__device__ float g_ksump[8 * HEADS * MF];     // per-z-slice ksum partials

// ---------------- helpers ----------------
__device__ __forceinline__ float tanh_fast(float x) {
    float r;
    asm("tanh.approx.f32 %0, %1;" : "=f"(r) : "f"(x));
    return r;
}

__device__ __forceinline__ float gelu_tanh(float u) {
    return 0.5f * u * (1.0f + tanh_fast(0.7978845608028654f * (u + 0.044715f * u * u * u)));
}

__device__ __forceinline__ uint32_t to_tf32u(float x) {
    float r;
    asm("cvt.rna.tf32.f32 %0, %1;" : "=f"(r) : "f"(x));
    return __float_as_uint(r);
}

__device__ __forceinline__ void mma8(float* c, const uint32_t* a, const uint32_t* b) {
    asm volatile(
        "mma.sync.aligned.m16n8k8.row.col.f32.tf32.tf32.f32 "
        "{%0,%1,%2,%3}, {%4,%5,%6,%7}, {%8,%9}, {%0,%1,%2,%3};"
        : "+f"(c[0]), "+f"(c[1]), "+f"(c[2]), "+f"(c[3])
        : "r"(a[0]), "r"(a[1]), "r"(a[2]), "r"(a[3]), "r"(b[0]), "r"(b[1]));
}

__device__ __forceinline__ void cp_async16(uint32_t dst, const float* src) {
    asm volatile("cp.async.cg.shared.global [%0], [%1], 16;" :: "r"(dst), "l"(src));
}
__device__ __forceinline__ void cp_commit() {
    asm volatile("cp.async.commit_group;");
}
__device__ __forceinline__ void cp_wait1() {
    asm volatile("cp.async.wait_group 1;");
}
__device__ __forceinline__ void cp_wait0() {
    asm volatile("cp.async.wait_group 0;");
}

// ---------------- embedding + bucketize ----------------
__global__ void embed_kernel(const float* __restrict__ methy,
                             const int* __restrict__ chromo,
                             const int* __restrict__ pos,
                             const float* __restrict__ mt,
                             const float* __restrict__ ct,
                             const float* __restrict__ pt) {
    int n = blockIdx.x;
    float x = methy[n];
    int idx = (x > -2.0f) + (x > -1.0f);
    #pragma unroll 4
    for (int i = 0; i < 100; i++) idx += ((float)i * 0.01f < x) ? 1 : 0;
    int c = chromo[n], p = pos[n];
    const float* mrow = mt + (size_t)idx * DIM;
    const float* prow = pt + (size_t)p * DIM;
    const float* crow = ct + (size_t)c * DIM;
    for (int d = threadIdx.x; d < DIM; d += blockDim.x)
        g_x[n * DIM + d] = mrow[d] + prow[d] + crow[d];
}

// ---------------- layernorm ----------------
__global__ __launch_bounds__(256) void ln_kernel(const float* __restrict__ in,
                                                 const float* __restrict__ g,
                                                 const float* __restrict__ b,
                                                 float* __restrict__ out) {
    int n = blockIdx.x, t = threadIdx.x;
    __shared__ float red[256];
    float v[3];
    float s = 0.f;
    #pragma unroll
    for (int i = 0; i < 3; i++) { v[i] = in[n * DIM + t + i * 256]; s += v[i]; }
    red[t] = s; __syncthreads();
    for (int off = 128; off > 0; off >>= 1) { if (t < off) red[t] += red[t + off]; __syncthreads(); }
    float mu = red[0] * (1.0f / DIM);
    __syncthreads();
    float s2 = 0.f;
    #pragma unroll
    for (int i = 0; i < 3; i++) { float d = v[i] - mu; s2 += d * d; }
    red[t] = s2; __syncthreads();
    for (int off = 128; off > 0; off >>= 1) { if (t < off) red[t] += red[t + off]; __syncthreads(); }
    float rstd = rsqrtf(red[0] * (1.0f / DIM) + 1e-5f);
    #pragma unroll
    for (int i = 0; i < 3; i++) {
        int d = t + i * 256;
        out[n * DIM + d] = (v[i] - mu) * rstd * g[d] + b[d];
    }
}

// ---------------- TF32 GEMM 128x128x32, cp.async 3-stage, z-fused/split-K --
#define BM 128
#define BN 128
#define BK 32
#define ASTR 36   /* BK+4 */
#define BSTR 136  /* BN+8 */
#define AELE (BM * ASTR)
#define BELE (BK * BSTR)
#define STAGES 3

__global__ __launch_bounds__(256, 2) void tgemm_kernel(const float* __restrict__ A,
                                                       const float* __restrict__ B0,
                                                       const float* __restrict__ B1,
                                                       const float* __restrict__ B2,
                                                       const float* __restrict__ bias,
                                                       const float* __restrict__ resid,
                                                       float* __restrict__ C0,
                                                       float* __restrict__ C1,
                                                       float* __restrict__ C2,
                                                       int Nn, int Kk, int act, int splitk) {
    extern __shared__ float sm[];
    int z = blockIdx.z;
    const float* B = B0;
    float* C = C0;
    int koff = 0, Keff = Kk;
    if (splitk > 1) {
        Keff = Kk / splitk;
        koff = z * Keff;
    } else {
        B = (z == 0) ? B0 : ((z == 1) ? B1 : B2);
        C = (z == 0) ? C0 : ((z == 1) ? C1 : C2);
    }

    int t = threadIdx.x;
    int rb = blockIdx.y * BM, cb = blockIdx.x * BN;
    int lane = t & 31, wid = t >> 5;
    int warp_m = (wid & 1) * 64, warp_n = (wid >> 1) * 32;
    int q = lane & 3, g = lane >> 2;

    int ar = t >> 3, ac = (t & 7) * 4;
    int br = t >> 5, bc = (t & 31) * 4;

    const float* Abase = A + (size_t)(rb + ar) * Kk + ac + koff;
    const float* Bbase = B + (size_t)(br + koff) * Nn + cb + bc;

    uint32_t smA = (uint32_t)__cvta_generic_to_shared(sm);
    uint32_t smB = smA + STAGES * AELE * 4;
    uint32_t adst = smA + (uint32_t)((ar * ASTR + ac) * 4);
    uint32_t bdst = smB + (uint32_t)((br * BSTR + bc) * 4);

    int niter = Keff / BK;

    #pragma unroll
    for (int s = 0; s < 2; s++) {
        if (s < niter) {
            size_t k0 = (size_t)s * BK;
            #pragma unroll
            for (int i = 0; i < 4; i++)
                cp_async16(adst + (uint32_t)(s * AELE * 4 + i * 32 * ASTR * 4),
                           Abase + (size_t)(32 * i) * Kk + k0);
            #pragma unroll
            for (int i = 0; i < 4; i++)
                cp_async16(bdst + (uint32_t)(s * BELE * 4 + i * 8 * BSTR * 4),
                           Bbase + ((size_t)(8 * i) + k0) * Nn);
        }
        cp_commit();
    }

    float acc[4][4][4];
    #pragma unroll
    for (int mt = 0; mt < 4; mt++)
        #pragma unroll
        for (int nt = 0; nt < 4; nt++)
            #pragma unroll
            for (int e = 0; e < 4; e++) acc[mt][nt][e] = 0.f;

    for (int it = 0; it < niter; it++) {
        if (it + 1 < niter) cp_wait1(); else cp_wait0();
        __syncthreads();
        if (it + 2 < niter) {
            int s = (it + 2) % STAGES;
            size_t k0 = (size_t)(it + 2) * BK;
            #pragma unroll
            for (int i = 0; i < 4; i++)
                cp_async16(adst + (uint32_t)(s * AELE * 4 + i * 32 * ASTR * 4),
                           Abase + (size_t)(32 * i) * Kk + k0);
            #pragma unroll
            for (int i = 0; i < 4; i++)
                cp_async16(bdst + (uint32_t)(s * BELE * 4 + i * 8 * BSTR * 4),
                           Bbase + ((size_t)(8 * i) + k0) * Nn);
        }
        cp_commit();

        const float* as = sm + (it % STAGES) * AELE;
        const float* bs = sm + STAGES * AELE + (it % STAGES) * BELE;
        #pragma unroll
        for (int kk = 0; kk < 4; kk++) {
            int k = kk * 8;
            uint32_t af[4][4], bf[4][2];
            #pragma unroll
            for (int mt = 0; mt < 4; mt++) {
                int m = warp_m + mt * 16 + g;
                af[mt][0] = to_tf32u(as[m * ASTR + k + q]);
                af[mt][1] = to_tf32u(as[(m + 8) * ASTR + k + q]);
                af[mt][2] = to_tf32u(as[m * ASTR + k + q + 4]);
                af[mt][3] = to_tf32u(as[(m + 8) * ASTR + k + q + 4]);
            }
            #pragma unroll
            for (int nt = 0; nt < 4; nt++) {
                int n = warp_n + nt * 8 + g;
                bf[nt][0] = to_tf32u(bs[(k + q) * BSTR + n]);
                bf[nt][1] = to_tf32u(bs[(k + 4 + q) * BSTR + n]);
            }
            #pragma unroll
            for (int mt = 0; mt < 4; mt++)
                #pragma unroll
                for (int nt = 0; nt < 4; nt++)
                    mma8(acc[mt][nt], af[mt], bf[nt]);
        }
    }
    __syncthreads();

    // epilogue
    if (splitk > 1) {
        #pragma unroll
        for (int mt = 0; mt < 4; mt++)
            #pragma unroll
            for (int nt = 0; nt < 4; nt++)
                #pragma unroll
                for (int e = 0; e < 4; e++) {
                    int row = rb + warp_m + mt * 16 + g + (e >> 1) * 8;
                    int col = cb + warp_n + nt * 8 + q * 2 + (e & 1);
                    float val = acc[mt][nt][e];
                    if (bias && z == 0) val += bias[col];
                    atomicAdd(&C[(size_t)row * Nn + col], val);
                }
    } else {
        #pragma unroll
        for (int mt = 0; mt < 4; mt++)
            #pragma unroll
            for (int nt = 0; nt < 4; nt++)
                #pragma unroll
                for (int e = 0; e < 4; e++) {
                    int row = rb + warp_m + mt * 16 + g + (e >> 1) * 8;
                    int col = cb + warp_n + nt * 8 + q * 2 + (e & 1);
                    float val = acc[mt][nt][e];
                    if (bias) val += bias[col];
                    if (act) val = gelu_tanh(val);
                    if (resid) val += resid[(size_t)row * Nn + col];
                    C[(size_t)row * Nn + col] = val;
                }
    }
}

// ---------------- feature GEMM: xd[h,n,m] = (x*DNORM) . proj[m] -----------
// Also computes diag (m-half 0 blocks) and block-reduced maxes (no atomics).
#define FSA 68    /* 64+4 */
#define FSB 136   /* 128+8 */
__global__ __launch_bounds__(256, 2) void featgemm_kernel(const float* __restrict__ proj) {
    extern __shared__ float sm[];
    float* As = sm;                 // [128][FSA] raw x
    float* Bs = sm + 128 * FSA;     // [64][FSB]  proj^T * DNORM
    __shared__ float wred[8];
    __shared__ float redq[4][128];  // per n-warp-group row maxes
    int hk = blockIdx.z, h = hk >> 1, isK = hk & 1;
    const float* X = isK ? g_k : g_q;
    float* dst = isK ? g_kf : g_qf;
    int n0 = blockIdx.y * 128, m0 = blockIdx.x * 128;
    int t = threadIdx.x, lane = t & 31, wid = t >> 5;
    int warp_m = (wid & 1) * 64, warp_n = (wid >> 1) * 32;
    int q = lane & 3, g = lane >> 2;

    #pragma unroll
    for (int j = 0; j < 8; j++) {
        int i = t + j * 256;
        int row = i >> 4, c = (i & 15) * 4;
        float4 v = *(const float4*)&X[(size_t)(n0 + row) * DIM + h * DH + c];
        *(float4*)&As[row * FSA + c] = v;
    }
    for (int i = t; i < 128 * 64; i += 256) {
        int m = i >> 6, d = i & 63;
        Bs[d * FSB + m] = proj[(size_t)(m0 + m) * DH + d] * DNORM;
    }
    __syncthreads();

    float acc[4][4][4];
    #pragma unroll
    for (int mt = 0; mt < 4; mt++)
        #pragma unroll
        for (int nt = 0; nt < 4; nt++)
            #pragma unroll
            for (int e = 0; e < 4; e++) acc[mt][nt][e] = 0.f;

    #pragma unroll
    for (int kk = 0; kk < 8; kk++) {
        int k = kk * 8;
        uint32_t af[4][4], bf[4][2];
        #pragma unroll
        for (int mt = 0; mt < 4; mt++) {
            int m = warp_m + mt * 16 + g;
            af[mt][0] = to_tf32u(As[m * FSA + k + q]);
            af[mt][1] = to_tf32u(As[(m + 8) * FSA + k + q]);
            af[mt][2] = to_tf32u(As[m * FSA + k + q + 4]);
            af[mt][3] = to_tf32u(As[(m + 8) * FSA + k + q + 4]);
        }
        #pragma unroll
        for (int nt = 0; nt < 4; nt++) {
            int n = warp_n + nt * 8 + g;
            bf[nt][0] = to_tf32u(Bs[(k + q) * FSB + n]);
            bf[nt][1] = to_tf32u(Bs[(k + 4 + q) * FSB + n]);
        }
        #pragma unroll
        for (int mt = 0; mt < 4; mt++)
            #pragma unroll
            for (int nt = 0; nt < 4; nt++)
                mma8(acc[mt][nt], af[mt], bf[nt]);
    }

    // diag from As (raw x), only one m-half needs to do it
    if (blockIdx.x == 0 && t < 128) {
        float s = 0.f;
        #pragma unroll
        for (int d = 0; d < DH; d++) { float v = As[t * FSA + d]; s += v * v; }
        float* dg = isK ? g_diagk : g_diagq;
        dg[h * NTOK + n0 + t] = 0.5f * (DNORM * DNORM) * s;
    }

    // store raw xd
    #pragma unroll
    for (int mt = 0; mt < 4; mt++)
        #pragma unroll
        for (int nt = 0; nt < 4; nt++)
            #pragma unroll
            for (int e = 0; e < 4; e++) {
                int row = warp_m + mt * 16 + g + (e >> 1) * 8;
                int col = warp_n + nt * 8 + q * 2 + (e & 1);
                dst[((size_t)h * NTOK + n0 + row) * MF + m0 + col] = acc[mt][nt][e];
            }

    if (!isK) {
        // per-row max: warp partial (32 cols) -> smem -> cross-warp reduce (128 cols)
        #pragma unroll
        for (int mt = 0; mt < 4; mt++)
            #pragma unroll
            for (int eh = 0; eh < 2; eh++) {
                float v = -1e30f;
                #pragma unroll
                for (int nt = 0; nt < 4; nt++) {
                    v = fmaxf(v, acc[mt][nt][eh * 2]);
                    v = fmaxf(v, acc[mt][nt][eh * 2 + 1]);
                }
                v = fmaxf(v, __shfl_xor_sync(0xffffffffu, v, 1));
                v = fmaxf(v, __shfl_xor_sync(0xffffffffu, v, 2));
                if (q == 0)
                    redq[wid >> 1][warp_m + mt * 16 + g + eh * 8] = v;
            }
        __syncthreads();
        if (t < 128) {
            float v = fmaxf(fmaxf(redq[0][t], redq[1][t]), fmaxf(redq[2][t], redq[3][t]));
            g_maxq2[(size_t)blockIdx.x * HEADS * NTOK + h * NTOK + n0 + t] = v;
        }
    } else {
        // per-block max -> direct store
        float v = -1e30f;
        #pragma unroll
        for (int mt = 0; mt < 4; mt++)
            #pragma unroll
            for (int nt = 0; nt < 4; nt++)
                #pragma unroll
                for (int e = 0; e < 4; e++) v = fmaxf(v, acc[mt][nt][e]);
        for (int off = 16; off; off >>= 1) v = fmaxf(v, __shfl_xor_sync(0xffffffffu, v, off));
        if (lane == 0) wred[wid] = v;
        __syncthreads();
        if (t == 0) {
            float mx = wred[0];
            #pragma unroll
            for (int w = 1; w < 8; w++) mx = fmaxf(mx, wred[w]);
            g_maxk2[h * 64 + blockIdx.y * 2 + blockIdx.x] = mx;
        }
    }
}

// ---------------- ctx GEMM: ctxp[z][m,d] = kf^T v, ksump = col sums -------
#define CSA 136   /* 128 m + 8 pad */
#define CSB 72    /* 64 d + 8 pad */
__global__ __launch_bounds__(256) void ctxgemm_kernel(const float* __restrict__ methy) {
    __shared__ float As[32 * CSA];   // [k(token)][m]
    __shared__ float Bs[32 * CSB];   // [k(token)][d]
    __shared__ float mkred[64];
    int h = blockIdx.x, m0 = blockIdx.y * 128, zs = blockIdx.z;
    int nbase = zs * 512;
    int t = threadIdx.x, lane = t & 31, wid = t >> 5;
    int warp_m = (wid & 3) * 32, warp_n = (wid >> 2) * 32;
    int q = lane & 3, g = lane >> 2;

    if (t < 64) mkred[t] = g_maxk2[h * 64 + t];
    __syncthreads();
    float mk = mkred[0];
    #pragma unroll
    for (int i = 1; i < 64; i++) mk = fmaxf(mk, mkred[i]);

    int sr = t >> 3;            // staging row 0..31
    int sc = (t & 7) * 4;       // staging col base

    float acc[2][4][4];
    #pragma unroll
    for (int mt = 0; mt < 2; mt++)
        #pragma unroll
        for (int nt = 0; nt < 4; nt++)
            #pragma unroll
            for (int e = 0; e < 4; e++) acc[mt][nt][e] = 0.f;
    float ksacc[16];
    #pragma unroll
    for (int i = 0; i < 16; i++) ksacc[i] = 0.f;

    for (int c = 0; c < 512; c += 32) {
        int n = nbase + c + sr;
        float dgk = g_diagk[h * NTOK + n];
        float msk = (methy[n] != 0.0f) ? 1.0f : 0.0f;
        const float* src = &g_kf[((size_t)h * NTOK + n) * MF + m0];
        #pragma unroll
        for (int j = 0; j < 4; j++) {
            int col = sc + 32 * j;
            float4 v = *(const float4*)&src[col];
            float4 w;
            w.x = RATIO * (expf(v.x - dgk - mk) + 1e-4f) * msk;
            w.y = RATIO * (expf(v.y - dgk - mk) + 1e-4f) * msk;
            w.z = RATIO * (expf(v.z - dgk - mk) + 1e-4f) * msk;
            w.w = RATIO * (expf(v.w - dgk - mk) + 1e-4f) * msk;
            *(float4*)&As[sr * CSA + col] = w;
            ksacc[j * 4 + 0] += w.x; ksacc[j * 4 + 1] += w.y;
            ksacc[j * 4 + 2] += w.z; ksacc[j * 4 + 3] += w.w;
        }
        #pragma unroll
        for (int j = 0; j < 2; j++) {
            int fi = t * 2 + j;
            int row = fi >> 4, col = (fi & 15) * 4;
            *(float4*)&Bs[row * CSB + col] =
                *(const float4*)&g_v[(size_t)(nbase + c + row) * DIM + h * DH + col];
        }
        __syncthreads();
        #pragma unroll
        for (int kk = 0; kk < 4; kk++) {
            int k = kk * 8;
            uint32_t af[2][4], bf[4][2];
            #pragma unroll
            for (int mt = 0; mt < 2; mt++) {
                int m = warp_m + mt * 16 + g;
                af[mt][0] = to_tf32u(As[(k + q) * CSA + m]);
                af[mt][1] = to_tf32u(As[(k + q) * CSA + m + 8]);
                af[mt][2] = to_tf32u(As[(k + 4 + q) * CSA + m]);
                af[mt][3] = to_tf32u(As[(k + 4 + q) * CSA + m + 8]);
            }
            #pragma unroll
            for (int nt = 0; nt < 4; nt++) {
                int n2 = warp_n + nt * 8 + g;
                bf[nt][0] = to_tf32u(Bs[(k + q) * CSB + n2]);
                bf[nt][1] = to_tf32u(Bs[(k + 4 + q) * CSB + n2]);
            }
            #pragma unroll
            for (int mt = 0; mt < 2; mt++)
                #pragma unroll
                for (int nt = 0; nt < 4; nt++)
                    mma8(acc[mt][nt], af[mt], bf[nt]);
        }
        __syncthreads();
    }

    // ksum reduce via As reuse -> plain store to partial slice
    #pragma unroll
    for (int j = 0; j < 4; j++) {
        int col = sc + 32 * j;
        *(float4*)&As[sr * CSA + col] = make_float4(ksacc[j*4], ksacc[j*4+1], ksacc[j*4+2], ksacc[j*4+3]);
    }
    __syncthreads();
    if (t < 128) {
        float s = 0.f;
        #pragma unroll
        for (int r = 0; r < 32; r++) s += As[r * CSA + t];
        g_ksump[((size_t)zs * HEADS + h) * MF + m0 + t] = s;
    }
    // ctx epilogue: plain store to partial slice
    float* ctxp = &g_ctxp[((size_t)zs * HEADS + h) * MF * DH];
    #pragma unroll
    for (int mt = 0; mt < 2; mt++)
        #pragma unroll
        for (int nt = 0; nt < 4; nt++)
            #pragma unroll
            for (int e = 0; e < 4; e++) {
                int m = m0 + warp_m + mt * 16 + g + (e >> 1) * 8;
                int d = warp_n + nt * 8 + q * 2 + (e & 1);
                ctxp[(size_t)m * DH + d] = acc[mt][nt][e];
            }
}

// ---------------- reduce partials: ctx, ksum ----------------
__global__ __launch_bounds__(256) void reduce_kernel() {
    int i = blockIdx.x * 256 + threadIdx.x;
    int nt = gridDim.x * 256;
    for (int j = i; j < HEADS * MF * DH; j += nt) {
        float s = 0.f;
        #pragma unroll
        for (int z = 0; z < 8; z++) s += g_ctxp[(size_t)z * HEADS * MF * DH + j];
        g_ctx[j] = s;
    }
    for (int j = i; j < HEADS * MF; j += nt) {
        float s = 0.f;
        #pragma unroll
        for (int z = 0; z < 8; z++) s += g_ksump[(size_t)z * HEADS * MF + j];
        g_ksum[j] = s;
    }
}

// ---------------- attn GEMM: o[n,d] = (qf @ ctx)[n,d] / (qf . ksum)[n] ----
__global__ __launch_bounds__(256) void attngemm_kernel() {
    __shared__ float As[128 * 36];   // [n row][k chunk 32]
    __shared__ float Bs[32 * CSB];   // [k(m)][d]
    __shared__ float ksums[MF];
    __shared__ float dens[128];
    int h = blockIdx.x, n0 = blockIdx.y * 128;
    int t = threadIdx.x, lane = t & 31, wid = t >> 5;
    int warp_m = (wid & 3) * 32, warp_n = (wid >> 2) * 32;
    int q = lane & 3, g = lane >> 2;

    ksums[t] = g_ksum[h * MF + t];
    __syncthreads();

    int sr = t >> 1;                 // staging row 0..127
    int n = n0 + sr;
    float dq = g_diagq[h * NTOK + n];
    float mq = fmaxf(g_maxq2[h * NTOK + n], g_maxq2[(size_t)HEADS * NTOK + h * NTOK + n]);
    float denp = 0.f;

    float acc[2][4][4];
    #pragma unroll
    for (int mt = 0; mt < 2; mt++)
        #pragma unroll
        for (int nt = 0; nt < 4; nt++)
            #pragma unroll
            for (int e = 0; e < 4; e++) acc[mt][nt][e] = 0.f;

    for (int c = 0; c < 256; c += 32) {
        const float* src = &g_qf[((size_t)h * NTOK + n) * MF + c];
        #pragma unroll
        for (int j = 0; j < 4; j++) {
            int col = ((t & 1) * 4 + j) * 4;
            float4 v = *(const float4*)&src[col];
            float4 w;
            w.x = RATIO * (expf(v.x - dq - mq) + 1e-4f);
            w.y = RATIO * (expf(v.y - dq - mq) + 1e-4f);
            w.z = RATIO * (expf(v.z - dq - mq) + 1e-4f);
            w.w = RATIO * (expf(v.w - dq - mq) + 1e-4f);
            *(float4*)&As[sr * 36 + col] = w;
            denp += w.x * ksums[c + col] + w.y * ksums[c + col + 1]
                  + w.z * ksums[c + col + 2] + w.w * ksums[c + col + 3];
        }
        #pragma unroll
        for (int j = 0; j < 2; j++) {
            int fi = t * 2 + j;
            int row = fi >> 4, col = (fi & 15) * 4;
            *(float4*)&Bs[row * CSB + col] =
                *(const float4*)&g_ctx[(size_t)h * MF * DH + (size_t)(c + row) * DH + col];
        }
        __syncthreads();
        #pragma unroll
        for (int kk = 0; kk < 4; kk++) {
            int k = kk * 8;
            uint32_t af[2][4], bf[4][2];
            #pragma unroll
            for (int mt = 0; mt < 2; mt++) {
                int m = warp_m + mt * 16 + g;
                af[mt][0] = to_tf32u(As[m * 36 + k + q]);
                af[mt][1] = to_tf32u(As[(m + 8) * 36 + k + q]);
                af[mt][2] = to_tf32u(As[m * 36 + k + q + 4]);
                af[mt][3] = to_tf32u(As[(m + 8) * 36 + k + q + 4]);
            }
            #pragma unroll
            for (int nt = 0; nt < 4; nt++) {
                int n2 = warp_n + nt * 8 + g;
                bf[nt][0] = to_tf32u(Bs[(k + q) * CSB + n2]);
                bf[nt][1] = to_tf32u(Bs[(k + 4 + q) * CSB + n2]);
            }
            #pragma unroll
            for (int mt = 0; mt < 2; mt++)
                #pragma unroll
                for (int nt = 0; nt < 4; nt++)
                    mma8(acc[mt][nt], af[mt], bf[nt]);
        }
        __syncthreads();
    }

    denp += __shfl_xor_sync(0xffffffffu, denp, 1);
    if ((t & 1) == 0) dens[sr] = denp;
    __syncthreads();

    #pragma unroll
    for (int mt = 0; mt < 2; mt++)
        #pragma unroll
        for (int nt = 0; nt < 4; nt++)
            #pragma unroll
            for (int e = 0; e < 4; e++) {
                int row = warp_m + mt * 16 + g + (e >> 1) * 8;
                int d = warp_n + nt * 8 + q * 2 + (e & 1);
                g_attn[(size_t)(n0 + row) * DIM + h * DH + d] = acc[mt][nt][e] / dens[row];
            }
}

// ---------------- output head ----------------
__global__ __launch_bounds__(128) void wout_kernel(const float* __restrict__ Wout,
                                                   const float* __restrict__ bout,
                                                   float* __restrict__ out) {
    int n = blockIdx.x, t = threadIdx.x;
    __shared__ float xs[DIM];
    for (int i = t; i < DIM; i += 128) xs[i] = g_h[n * DIM + i];
    __syncthreads();
    if (t < VOCAB) {
        float acc = bout[t];
        for (int k = 0; k < DIM; k++) acc += xs[k] * Wout[k * VOCAB + t];
        out[n * VOCAB + t] = acc;
    }
}

// ---------------- host ----------------
extern "C" void kernel_launch(void* const* d_in, const int* in_sizes, int n_in,
                              void* d_out, int out_size) {
    const float* methy = (const float*)d_in[0];
    const int* chromo = (const int*)d_in[1];
    const int* pos    = (const int*)d_in[2];
    const float* mt = (const float*)d_in[3];
    const float* ct = (const float*)d_in[4];
    const float* pt = (const float*)d_in[5];
    const float* ln1g = (const float*)d_in[6];
    const float* ln1b = (const float*)d_in[7];
    const float* ln2g = (const float*)d_in[8];
    const float* ln2b = (const float*)d_in[9];
    const float* Wq = (const float*)d_in[10];
    const float* Wk = (const float*)d_in[11];
    const float* Wv = (const float*)d_in[12];
    const float* Wo = (const float*)d_in[13];
    const float* bo = (const float*)d_in[14];
    const float* W1 = (const float*)d_in[15];
    const float* b1 = (const float*)d_in[16];
    const float* W2 = (const float*)d_in[17];
    const float* b2 = (const float*)d_in[18];
    const float* proj = (const float*)d_in[19];
    const float* nfg = (const float*)d_in[20];
    const float* nfb = (const float*)d_in[21];
    const float* Wout = (const float*)d_in[22];
    const float* bout = (const float*)d_in[23];
    float* out = (float*)d_out;

    float *px, *ph, *pq, *pk, *pv, *pattn, *pff;
    cudaGetSymbolAddress((void**)&px, g_x);
    cudaGetSymbolAddress((void**)&ph, g_h);
    cudaGetSymbolAddress((void**)&pq, g_q);
    cudaGetSymbolAddress((void**)&pk, g_k);
    cudaGetSymbolAddress((void**)&pv, g_v);
    cudaGetSymbolAddress((void**)&pattn, g_attn);
    cudaGetSymbolAddress((void**)&pff, g_ff);

    const int GEMM_SMEM  = STAGES * (AELE + BELE) * sizeof(float);   // 107,520
    const int FEAT_SMEM  = (128 * FSA + 64 * FSB) * sizeof(float);   // 69,632
    cudaFuncSetAttribute(tgemm_kernel,  cudaFuncAttributeMaxDynamicSharedMemorySize, GEMM_SMEM);
    cudaFuncSetAttribute(featgemm_kernel, cudaFuncAttributeMaxDynamicSharedMemorySize, FEAT_SMEM);

    embed_kernel<<<NTOK, 256>>>(methy, chromo, pos, mt, ct, pt);

    dim3 gqkv(DIM / BN, NTOK / BM, 3);   // (6, 32, 3)
    dim3 gsk3(DIM / BN, NTOK / BM, 3);   // (6, 32, 3) split-K=3
    dim3 gff(FF / BN, NTOK / BM, 1);     // (24, 32)
    dim3 gfeat(2, 32, HEADS * 2);        // (2, 32, 24)
    dim3 gctx(HEADS, 2, 8);              // (12, 2, 8)
    dim3 gattn(HEADS, NTOK / 128);       // (12, 32)

    for (int l = 0; l < DEPTH; l++) {
        const float* pj = proj + (size_t)l * MF * DH;
        // --- attention ---
        ln_kernel<<<NTOK, 256>>>(px, ln1g + l * DIM, ln1b + l * DIM, ph);
        tgemm_kernel<<<gqkv, 256, GEMM_SMEM>>>(ph,
            Wq + (size_t)l * DIM * DIM, Wk + (size_t)l * DIM * DIM, Wv + (size_t)l * DIM * DIM,
            nullptr, nullptr, pq, pk, pv, DIM, DIM, 0, 1);
        featgemm_kernel<<<gfeat, 256, FEAT_SMEM>>>(pj);
        ctxgemm_kernel<<<gctx, 256>>>(methy);
        reduce_kernel<<<192, 256>>>();
        attngemm_kernel<<<gattn, 256>>>();
        tgemm_kernel<<<gsk3, 256, GEMM_SMEM>>>(pattn,
            Wo + (size_t)l * DIM * DIM, nullptr, nullptr,
            bo + l * DIM, nullptr, px, nullptr, nullptr, DIM, DIM, 0, 3);
        // --- FFN ---
        ln_kernel<<<NTOK, 256>>>(px, ln2g + l * DIM, ln2b + l * DIM, ph);
        tgemm_kernel<<<gff, 256, GEMM_SMEM>>>(ph,
            W1 + (size_t)l * DIM * FF, nullptr, nullptr,
            b1 + l * FF, nullptr, pff, nullptr, nullptr, FF, DIM, 1, 1);
        tgemm_kernel<<<gsk3, 256, GEMM_SMEM>>>(pff,
            W2 + (size_t)l * FF * DIM, nullptr, nullptr,
            b2 + l * DIM, nullptr, px, nullptr, nullptr, DIM, FF, 0, 3);
    }

    ln_kernel<<<NTOK, 256>>>(px, nfg, nfb, ph);
    wout_kernel<<<NTOK, 128>>>(Wout, bout, out);
}

// round 11
// speedup vs baseline: 5.7732x; 1.3660x over previous
#include <cuda_runtime.h>
#include <cuda_fp16.h>
#include <math.h>
#include <stdint.h>

#define NTOK 4096
#define DIM 768
#define DEPTH 6
#define HEADS 12
#define DH 64
#define FF 3072
#define MF 256
#define VOCAB 102
#define DNORM 0.35355339059327373f   /* 64^-0.25 */
#define RATIO 0.0625f                /* 256^-0.5 */

// per-layer half-weight offsets (in halves)
#define LOFF 7077888
#define WOQ 0
#define WOK 589824
#define WOV 1179648
#define WOO 1769472
#define WO1 2359296
#define WO2 4718592

// ---------------- scratch (device globals, no allocation) ----------------
__device__ float g_x[NTOK * DIM];
__device__ float g_h[NTOK * DIM];
__device__ __align__(16) __half g_hh[NTOK * DIM];
__device__ float g_q[NTOK * DIM];
__device__ float g_k[NTOK * DIM];
__device__ float g_v[NTOK * DIM];
__device__ __align__(16) __half g_attnh[NTOK * DIM];
__device__ __align__(16) __half g_ffh[NTOK * FF];
__device__ __align__(16) __half g_wh[(size_t)DEPTH * LOFF];
__device__ float g_qf[HEADS * NTOK * MF];     // raw xd
__device__ float g_kf[HEADS * NTOK * MF];     // raw xd
__device__ float g_diagq[HEADS * NTOK];
__device__ float g_diagk[HEADS * NTOK];
__device__ float g_maxq2[2 * HEADS * NTOK];
__device__ float g_maxk2[HEADS * 64];
__device__ float g_ksum[HEADS * MF];
__device__ float g_ctx[HEADS * MF * DH];
__device__ float g_ctxp[8 * HEADS * MF * DH];
__device__ float g_ksump[8 * HEADS * MF];

// ---------------- helpers ----------------
__device__ __forceinline__ float tanh_fast(float x) {
    float r;
    asm("tanh.approx.f32 %0, %1;" : "=f"(r) : "f"(x));
    return r;
}

__device__ __forceinline__ float gelu_tanh(float u) {
    return 0.5f * u * (1.0f + tanh_fast(0.7978845608028654f * (u + 0.044715f * u * u * u)));
}

__device__ __forceinline__ uint32_t to_tf32u(float x) {
    float r;
    asm("cvt.rna.tf32.f32 %0, %1;" : "=f"(r) : "f"(x));
    return __float_as_uint(r);
}

__device__ __forceinline__ void mma8(float* c, const uint32_t* a, const uint32_t* b) {
    asm volatile(
        "mma.sync.aligned.m16n8k8.row.col.f32.tf32.tf32.f32 "
        "{%0,%1,%2,%3}, {%4,%5,%6,%7}, {%8,%9}, {%0,%1,%2,%3};"
        : "+f"(c[0]), "+f"(c[1]), "+f"(c[2]), "+f"(c[3])
        : "r"(a[0]), "r"(a[1]), "r"(a[2]), "r"(a[3]), "r"(b[0]), "r"(b[1]));
}

__device__ __forceinline__ void mma16(float* c, const uint32_t* a, const uint32_t* b) {
    asm volatile(
        "mma.sync.aligned.m16n8k16.row.col.f32.f16.f16.f32 "
        "{%0,%1,%2,%3}, {%4,%5,%6,%7}, {%8,%9}, {%0,%1,%2,%3};"
        : "+f"(c[0]), "+f"(c[1]), "+f"(c[2]), "+f"(c[3])
        : "r"(a[0]), "r"(a[1]), "r"(a[2]), "r"(a[3]), "r"(b[0]), "r"(b[1]));
}

__device__ __forceinline__ void cp_async16(uint32_t dst, const void* src) {
    asm volatile("cp.async.cg.shared.global [%0], [%1], 16;" :: "r"(dst), "l"(src));
}
__device__ __forceinline__ void cp_commit() { asm volatile("cp.async.commit_group;"); }
__device__ __forceinline__ void cp_wait1() { asm volatile("cp.async.wait_group 1;"); }
__device__ __forceinline__ void cp_wait0() { asm volatile("cp.async.wait_group 0;"); }

// ---------------- weight convert + transpose: W[K][N]f32 -> Wt[N][K]h -----
__global__ __launch_bounds__(256) void wconv_kernel(const float* __restrict__ Wq,
                                                    const float* __restrict__ Wk,
                                                    const float* __restrict__ Wv,
                                                    const float* __restrict__ Wo,
                                                    const float* __restrict__ W1,
                                                    const float* __restrict__ W2) {
    int mat = blockIdx.z % 6, l = blockIdx.z / 6;
    int K = (mat == 5) ? FF : DIM;
    int N = (mat == 4) ? FF : DIM;
    int n0 = blockIdx.x * 32, k0 = blockIdx.y * 32;
    if (n0 >= N || k0 >= K) return;
    const float* srcs[6] = {Wq, Wk, Wv, Wo, W1, W2};
    const size_t offs[6] = {WOQ, WOK, WOV, WOO, WO1, WO2};
    const float* src = srcs[mat] + (size_t)l * K * N;
    __half* dst = g_wh + (size_t)l * LOFF + offs[mat];
    __shared__ float tile[32][33];
    int tx = threadIdx.x & 31, ty = threadIdx.x >> 5;   // 32x8
    #pragma unroll
    for (int i = 0; i < 4; i++)
        tile[ty + i * 8][tx] = src[(size_t)(k0 + ty + i * 8) * N + n0 + tx];
    __syncthreads();
    #pragma unroll
    for (int i = 0; i < 4; i++)
        dst[(size_t)(n0 + ty + i * 8) * K + k0 + tx] = __float2half(tile[tx][ty + i * 8]);
}

// ---------------- embedding + bucketize ----------------
__global__ void embed_kernel(const float* __restrict__ methy,
                             const int* __restrict__ chromo,
                             const int* __restrict__ pos,
                             const float* __restrict__ mt,
                             const float* __restrict__ ct,
                             const float* __restrict__ pt) {
    int n = blockIdx.x;
    float x = methy[n];
    int idx = (x > -2.0f) + (x > -1.0f);
    #pragma unroll 4
    for (int i = 0; i < 100; i++) idx += ((float)i * 0.01f < x) ? 1 : 0;
    int c = chromo[n], p = pos[n];
    const float* mrow = mt + (size_t)idx * DIM;
    const float* prow = pt + (size_t)p * DIM;
    const float* crow = ct + (size_t)c * DIM;
    for (int d = threadIdx.x; d < DIM; d += blockDim.x)
        g_x[n * DIM + d] = mrow[d] + prow[d] + crow[d];
}

// ---------------- layernorm (writes fp32 + half) ----------------
__global__ __launch_bounds__(256) void ln_kernel(const float* __restrict__ in,
                                                 const float* __restrict__ g,
                                                 const float* __restrict__ b,
                                                 float* __restrict__ out,
                                                 __half* __restrict__ outh) {
    int n = blockIdx.x, t = threadIdx.x;
    __shared__ float red[256];
    float v[3];
    float s = 0.f;
    #pragma unroll
    for (int i = 0; i < 3; i++) { v[i] = in[n * DIM + t + i * 256]; s += v[i]; }
    red[t] = s; __syncthreads();
    for (int off = 128; off > 0; off >>= 1) { if (t < off) red[t] += red[t + off]; __syncthreads(); }
    float mu = red[0] * (1.0f / DIM);
    __syncthreads();
    float s2 = 0.f;
    #pragma unroll
    for (int i = 0; i < 3; i++) { float d = v[i] - mu; s2 += d * d; }
    red[t] = s2; __syncthreads();
    for (int off = 128; off > 0; off >>= 1) { if (t < off) red[t] += red[t + off]; __syncthreads(); }
    float rstd = rsqrtf(red[0] * (1.0f / DIM) + 1e-5f);
    #pragma unroll
    for (int i = 0; i < 3; i++) {
        int d = t + i * 256;
        float o = (v[i] - mu) * rstd * g[d] + b[d];
        out[n * DIM + d] = o;
        outh[n * DIM + d] = __float2half(o);
    }
}

// ---------------- FP16 GEMM 128x128x64h, cp.async 3-stage -----------------
// A [M,K] half row-major, Bt [N,K] half row-major (pre-transposed weights).
#define BKH 64
#define SAH 72            /* halves stride; 36 words */
#define HAELE (128 * SAH) /* 9216 halves per stage */
#define HSTAGES 3

__global__ __launch_bounds__(256, 2) void tgemm_h(const __half* __restrict__ A,
                                                  const __half* __restrict__ B0,
                                                  const __half* __restrict__ B1,
                                                  const __half* __restrict__ B2,
                                                  const float* __restrict__ bias,
                                                  float* __restrict__ C0,
                                                  float* __restrict__ C1,
                                                  float* __restrict__ C2,
                                                  int Nn, int Kk, int act, int splitk,
                                                  int outhalf) {
    extern __shared__ __half hsm[];
    int z = blockIdx.z;
    const __half* B = B0;
    float* C = C0;
    int koff = 0, Keff = Kk;
    if (splitk > 1) {
        Keff = Kk / splitk;
        koff = z * Keff;
    } else {
        B = (z == 0) ? B0 : ((z == 1) ? B1 : B2);
        C = (z == 0) ? C0 : ((z == 1) ? C1 : C2);
    }

    int t = threadIdx.x;
    int rb = blockIdx.y * 128, cb = blockIdx.x * 128;
    int lane = t & 31, wid = t >> 5;
    int warp_m = (wid & 1) * 64, warp_n = (wid >> 1) * 32;
    int q = lane & 3, g = lane >> 2;

    int tr = t >> 3;           // 0..31, rows tr+32i
    int tc = (t & 7) * 8;      // halves

    const __half* Abase = A + (size_t)(rb + tr) * Kk + koff + tc;
    const __half* Bbase = B + (size_t)(cb + tr) * Kk + koff + tc;

    uint32_t smA = (uint32_t)__cvta_generic_to_shared(hsm);
    uint32_t smB = smA + HSTAGES * HAELE * 2;
    uint32_t adst = smA + (uint32_t)((tr * SAH + tc) * 2);
    uint32_t bdst = smB + (uint32_t)((tr * SAH + tc) * 2);

    int niter = Keff / BKH;

    #pragma unroll
    for (int s = 0; s < 2; s++) {
        if (s < niter) {
            size_t k0 = (size_t)s * BKH;
            #pragma unroll
            for (int i = 0; i < 4; i++)
                cp_async16(adst + (uint32_t)(s * HAELE * 2 + i * 32 * SAH * 2),
                           Abase + (size_t)(32 * i) * Kk + k0);
            #pragma unroll
            for (int i = 0; i < 4; i++)
                cp_async16(bdst + (uint32_t)(s * HAELE * 2 + i * 32 * SAH * 2),
                           Bbase + (size_t)(32 * i) * Kk + k0);
        }
        cp_commit();
    }

    float acc[4][4][4];
    #pragma unroll
    for (int mt = 0; mt < 4; mt++)
        #pragma unroll
        for (int nt = 0; nt < 4; nt++)
            #pragma unroll
            for (int e = 0; e < 4; e++) acc[mt][nt][e] = 0.f;

    for (int it = 0; it < niter; it++) {
        if (it + 1 < niter) cp_wait1(); else cp_wait0();
        __syncthreads();
        if (it + 2 < niter) {
            int s = (it + 2) % HSTAGES;
            size_t k0 = (size_t)(it + 2) * BKH;
            #pragma unroll
            for (int i = 0; i < 4; i++)
                cp_async16(adst + (uint32_t)(s * HAELE * 2 + i * 32 * SAH * 2),
                           Abase + (size_t)(32 * i) * Kk + k0);
            #pragma unroll
            for (int i = 0; i < 4; i++)
                cp_async16(bdst + (uint32_t)(s * HAELE * 2 + i * 32 * SAH * 2),
                           Bbase + (size_t)(32 * i) * Kk + k0);
        }
        cp_commit();

        const uint32_t* asw = (const uint32_t*)(hsm + (it % HSTAGES) * HAELE);
        const uint32_t* bsw = (const uint32_t*)(hsm + HSTAGES * HAELE + (it % HSTAGES) * HAELE);
        #pragma unroll
        for (int ks = 0; ks < 4; ks++) {
            int k0w = ks * 8;
            uint32_t af[4][4], bf[4][2];
            #pragma unroll
            for (int mt = 0; mt < 4; mt++) {
                int m = warp_m + mt * 16 + g;
                af[mt][0] = asw[m * 36 + k0w + q];
                af[mt][1] = asw[(m + 8) * 36 + k0w + q];
                af[mt][2] = asw[m * 36 + k0w + q + 4];
                af[mt][3] = asw[(m + 8) * 36 + k0w + q + 4];
            }
            #pragma unroll
            for (int nt = 0; nt < 4; nt++) {
                int n = warp_n + nt * 8 + g;
                bf[nt][0] = bsw[n * 36 + k0w + q];
                bf[nt][1] = bsw[n * 36 + k0w + q + 4];
            }
            #pragma unroll
            for (int mt = 0; mt < 4; mt++)
                #pragma unroll
                for (int nt = 0; nt < 4; nt++)
                    mma16(acc[mt][nt], af[mt], bf[nt]);
        }
    }
    __syncthreads();

    // epilogue
    if (splitk > 1) {
        #pragma unroll
        for (int mt = 0; mt < 4; mt++)
            #pragma unroll
            for (int nt = 0; nt < 4; nt++)
                #pragma unroll
                for (int e = 0; e < 4; e++) {
                    int row = rb + warp_m + mt * 16 + g + (e >> 1) * 8;
                    int col = cb + warp_n + nt * 8 + q * 2 + (e & 1);
                    float val = acc[mt][nt][e];
                    if (bias && z == 0) val += bias[col];
                    atomicAdd(&C[(size_t)row * Nn + col], val);
                }
    } else {
        #pragma unroll
        for (int mt = 0; mt < 4; mt++)
            #pragma unroll
            for (int nt = 0; nt < 4; nt++)
                #pragma unroll
                for (int e = 0; e < 4; e++) {
                    int row = rb + warp_m + mt * 16 + g + (e >> 1) * 8;
                    int col = cb + warp_n + nt * 8 + q * 2 + (e & 1);
                    float val = acc[mt][nt][e];
                    if (bias) val += bias[col];
                    if (act) val = gelu_tanh(val);
                    if (outhalf) ((__half*)C)[(size_t)row * Nn + col] = __float2half(val);
                    else C[(size_t)row * Nn + col] = val;
                }
    }
}

// ---------------- feature GEMM (tf32, unchanged math) ----------------------
#define FSA 68
#define FSB 136
__global__ __launch_bounds__(256, 2) void featgemm_kernel(const float* __restrict__ proj) {
    extern __shared__ float sm[];
    float* As = sm;
    float* Bs = sm + 128 * FSA;
    __shared__ float wred[8];
    __shared__ float redq[4][128];
    int hk = blockIdx.z, h = hk >> 1, isK = hk & 1;
    const float* X = isK ? g_k : g_q;
    float* dst = isK ? g_kf : g_qf;
    int n0 = blockIdx.y * 128, m0 = blockIdx.x * 128;
    int t = threadIdx.x, lane = t & 31, wid = t >> 5;
    int warp_m = (wid & 1) * 64, warp_n = (wid >> 1) * 32;
    int q = lane & 3, g = lane >> 2;

    #pragma unroll
    for (int j = 0; j < 8; j++) {
        int i = t + j * 256;
        int row = i >> 4, c = (i & 15) * 4;
        float4 v = *(const float4*)&X[(size_t)(n0 + row) * DIM + h * DH + c];
        *(float4*)&As[row * FSA + c] = v;
    }
    for (int i = t; i < 128 * 64; i += 256) {
        int m = i >> 6, d = i & 63;
        Bs[d * FSB + m] = proj[(size_t)(m0 + m) * DH + d] * DNORM;
    }
    __syncthreads();

    float acc[4][4][4];
    #pragma unroll
    for (int mt = 0; mt < 4; mt++)
        #pragma unroll
        for (int nt = 0; nt < 4; nt++)
            #pragma unroll
            for (int e = 0; e < 4; e++) acc[mt][nt][e] = 0.f;

    #pragma unroll
    for (int kk = 0; kk < 8; kk++) {
        int k = kk * 8;
        uint32_t af[4][4], bf[4][2];
        #pragma unroll
        for (int mt = 0; mt < 4; mt++) {
            int m = warp_m + mt * 16 + g;
            af[mt][0] = to_tf32u(As[m * FSA + k + q]);
            af[mt][1] = to_tf32u(As[(m + 8) * FSA + k + q]);
            af[mt][2] = to_tf32u(As[m * FSA + k + q + 4]);
            af[mt][3] = to_tf32u(As[(m + 8) * FSA + k + q + 4]);
        }
        #pragma unroll
        for (int nt = 0; nt < 4; nt++) {
            int n = warp_n + nt * 8 + g;
            bf[nt][0] = to_tf32u(Bs[(k + q) * FSB + n]);
            bf[nt][1] = to_tf32u(Bs[(k + 4 + q) * FSB + n]);
        }
        #pragma unroll
        for (int mt = 0; mt < 4; mt++)
            #pragma unroll
            for (int nt = 0; nt < 4; nt++)
                mma8(acc[mt][nt], af[mt], bf[nt]);
    }

    if (blockIdx.x == 0 && t < 128) {
        float s = 0.f;
        #pragma unroll
        for (int d = 0; d < DH; d++) { float v = As[t * FSA + d]; s += v * v; }
        float* dg = isK ? g_diagk : g_diagq;
        dg[h * NTOK + n0 + t] = 0.5f * (DNORM * DNORM) * s;
    }

    #pragma unroll
    for (int mt = 0; mt < 4; mt++)
        #pragma unroll
        for (int nt = 0; nt < 4; nt++)
            #pragma unroll
            for (int e = 0; e < 4; e++) {
                int row = warp_m + mt * 16 + g + (e >> 1) * 8;
                int col = warp_n + nt * 8 + q * 2 + (e & 1);
                dst[((size_t)h * NTOK + n0 + row) * MF + m0 + col] = acc[mt][nt][e];
            }

    if (!isK) {
        #pragma unroll
        for (int mt = 0; mt < 4; mt++)
            #pragma unroll
            for (int eh = 0; eh < 2; eh++) {
                float v = -1e30f;
                #pragma unroll
                for (int nt = 0; nt < 4; nt++) {
                    v = fmaxf(v, acc[mt][nt][eh * 2]);
                    v = fmaxf(v, acc[mt][nt][eh * 2 + 1]);
                }
                v = fmaxf(v, __shfl_xor_sync(0xffffffffu, v, 1));
                v = fmaxf(v, __shfl_xor_sync(0xffffffffu, v, 2));
                if (q == 0)
                    redq[wid >> 1][warp_m + mt * 16 + g + eh * 8] = v;
            }
        __syncthreads();
        if (t < 128) {
            float v = fmaxf(fmaxf(redq[0][t], redq[1][t]), fmaxf(redq[2][t], redq[3][t]));
            g_maxq2[(size_t)blockIdx.x * HEADS * NTOK + h * NTOK + n0 + t] = v;
        }
    } else {
        float v = -1e30f;
        #pragma unroll
        for (int mt = 0; mt < 4; mt++)
            #pragma unroll
            for (int nt = 0; nt < 4; nt++)
                #pragma unroll
                for (int e = 0; e < 4; e++) v = fmaxf(v, acc[mt][nt][e]);
        for (int off = 16; off; off >>= 1) v = fmaxf(v, __shfl_xor_sync(0xffffffffu, v, off));
        if (lane == 0) wred[wid] = v;
        __syncthreads();
        if (t == 0) {
            float mx = wred[0];
            #pragma unroll
            for (int w = 1; w < 8; w++) mx = fmaxf(mx, wred[w]);
            g_maxk2[h * 64 + blockIdx.y * 2 + blockIdx.x] = mx;
        }
    }
}

// ---------------- ctx GEMM (tf32, partials) ----------------
#define CSA 136
#define CSB 72
__global__ __launch_bounds__(256) void ctxgemm_kernel(const float* __restrict__ methy) {
    __shared__ float As[32 * CSA];
    __shared__ float Bs[32 * CSB];
    __shared__ float mkred[64];
    int h = blockIdx.x, m0 = blockIdx.y * 128, zs = blockIdx.z;
    int nbase = zs * 512;
    int t = threadIdx.x, lane = t & 31, wid = t >> 5;
    int warp_m = (wid & 3) * 32, warp_n = (wid >> 2) * 32;
    int q = lane & 3, g = lane >> 2;

    if (t < 64) mkred[t] = g_maxk2[h * 64 + t];
    __syncthreads();
    float mk = mkred[0];
    #pragma unroll
    for (int i = 1; i < 64; i++) mk = fmaxf(mk, mkred[i]);

    int sr = t >> 3;
    int sc = (t & 7) * 4;

    float acc[2][4][4];
    #pragma unroll
    for (int mt = 0; mt < 2; mt++)
        #pragma unroll
        for (int nt = 0; nt < 4; nt++)
            #pragma unroll
            for (int e = 0; e < 4; e++) acc[mt][nt][e] = 0.f;
    float ksacc[16];
    #pragma unroll
    for (int i = 0; i < 16; i++) ksacc[i] = 0.f;

    for (int c = 0; c < 512; c += 32) {
        int n = nbase + c + sr;
        float dgk = g_diagk[h * NTOK + n];
        float msk = (methy[n] != 0.0f) ? 1.0f : 0.0f;
        const float* src = &g_kf[((size_t)h * NTOK + n) * MF + m0];
        #pragma unroll
        for (int j = 0; j < 4; j++) {
            int col = sc + 32 * j;
            float4 v = *(const float4*)&src[col];
            float4 w;
            w.x = RATIO * (expf(v.x - dgk - mk) + 1e-4f) * msk;
            w.y = RATIO * (expf(v.y - dgk - mk) + 1e-4f) * msk;
            w.z = RATIO * (expf(v.z - dgk - mk) + 1e-4f) * msk;
            w.w = RATIO * (expf(v.w - dgk - mk) + 1e-4f) * msk;
            *(float4*)&As[sr * CSA + col] = w;
            ksacc[j * 4 + 0] += w.x; ksacc[j * 4 + 1] += w.y;
            ksacc[j * 4 + 2] += w.z; ksacc[j * 4 + 3] += w.w;
        }
        #pragma unroll
        for (int j = 0; j < 2; j++) {
            int fi = t * 2 + j;
            int row = fi >> 4, col = (fi & 15) * 4;
            *(float4*)&Bs[row * CSB + col] =
                *(const float4*)&g_v[(size_t)(nbase + c + row) * DIM + h * DH + col];
        }
        __syncthreads();
        #pragma unroll
        for (int kk = 0; kk < 4; kk++) {
            int k = kk * 8;
            uint32_t af[2][4], bf[4][2];
            #pragma unroll
            for (int mt = 0; mt < 2; mt++) {
                int m = warp_m + mt * 16 + g;
                af[mt][0] = to_tf32u(As[(k + q) * CSA + m]);
                af[mt][1] = to_tf32u(As[(k + q) * CSA + m + 8]);
                af[mt][2] = to_tf32u(As[(k + 4 + q) * CSA + m]);
                af[mt][3] = to_tf32u(As[(k + 4 + q) * CSA + m + 8]);
            }
            #pragma unroll
            for (int nt = 0; nt < 4; nt++) {
                int n2 = warp_n + nt * 8 + g;
                bf[nt][0] = to_tf32u(Bs[(k + q) * CSB + n2]);
                bf[nt][1] = to_tf32u(Bs[(k + 4 + q) * CSB + n2]);
            }
            #pragma unroll
            for (int mt = 0; mt < 2; mt++)
                #pragma unroll
                for (int nt = 0; nt < 4; nt++)
                    mma8(acc[mt][nt], af[mt], bf[nt]);
        }
        __syncthreads();
    }

    #pragma unroll
    for (int j = 0; j < 4; j++) {
        int col = sc + 32 * j;
        *(float4*)&As[sr * CSA + col] = make_float4(ksacc[j*4], ksacc[j*4+1], ksacc[j*4+2], ksacc[j*4+3]);
    }
    __syncthreads();
    if (t < 128) {
        float s = 0.f;
        #pragma unroll
        for (int r = 0; r < 32; r++) s += As[r * CSA + t];
        g_ksump[((size_t)zs * HEADS + h) * MF + m0 + t] = s;
    }
    float* ctxp = &g_ctxp[((size_t)zs * HEADS + h) * MF * DH];
    #pragma unroll
    for (int mt = 0; mt < 2; mt++)
        #pragma unroll
        for (int nt = 0; nt < 4; nt++)
            #pragma unroll
            for (int e = 0; e < 4; e++) {
                int m = m0 + warp_m + mt * 16 + g + (e >> 1) * 8;
                int d = warp_n + nt * 8 + q * 2 + (e & 1);
                ctxp[(size_t)m * DH + d] = acc[mt][nt][e];
            }
}

// ---------------- reduce partials ----------------
__global__ __launch_bounds__(256) void reduce_kernel() {
    int i = blockIdx.x * 256 + threadIdx.x;
    int nt = gridDim.x * 256;
    for (int j = i; j < HEADS * MF * DH; j += nt) {
        float s = 0.f;
        #pragma unroll
        for (int z = 0; z < 8; z++) s += g_ctxp[(size_t)z * HEADS * MF * DH + j];
        g_ctx[j] = s;
    }
    for (int j = i; j < HEADS * MF; j += nt) {
        float s = 0.f;
        #pragma unroll
        for (int z = 0; z < 8; z++) s += g_ksump[(size_t)z * HEADS * MF + j];
        g_ksum[j] = s;
    }
}

// ---------------- attn GEMM (tf32), writes half output --------------------
__global__ __launch_bounds__(256) void attngemm_kernel() {
    __shared__ float As[128 * 36];
    __shared__ float Bs[32 * CSB];
    __shared__ float ksums[MF];
    __shared__ float dens[128];
    int h = blockIdx.x, n0 = blockIdx.y * 128;
    int t = threadIdx.x, lane = t & 31, wid = t >> 5;
    int warp_m = (wid & 3) * 32, warp_n = (wid >> 2) * 32;
    int q = lane & 3, g = lane >> 2;

    ksums[t] = g_ksum[h * MF + t];
    __syncthreads();

    int sr = t >> 1;
    int n = n0 + sr;
    float dq = g_diagq[h * NTOK + n];
    float mq = fmaxf(g_maxq2[h * NTOK + n], g_maxq2[(size_t)HEADS * NTOK + h * NTOK + n]);
    float denp = 0.f;

    float acc[2][4][4];
    #pragma unroll
    for (int mt = 0; mt < 2; mt++)
        #pragma unroll
        for (int nt = 0; nt < 4; nt++)
            #pragma unroll
            for (int e = 0; e < 4; e++) acc[mt][nt][e] = 0.f;

    for (int c = 0; c < 256; c += 32) {
        const float* src = &g_qf[((size_t)h * NTOK + n) * MF + c];
        #pragma unroll
        for (int j = 0; j < 4; j++) {
            int col = ((t & 1) * 4 + j) * 4;
            float4 v = *(const float4*)&src[col];
            float4 w;
            w.x = RATIO * (expf(v.x - dq - mq) + 1e-4f);
            w.y = RATIO * (expf(v.y - dq - mq) + 1e-4f);
            w.z = RATIO * (expf(v.z - dq - mq) + 1e-4f);
            w.w = RATIO * (expf(v.w - dq - mq) + 1e-4f);
            *(float4*)&As[sr * 36 + col] = w;
            denp += w.x * ksums[c + col] + w.y * ksums[c + col + 1]
                  + w.z * ksums[c + col + 2] + w.w * ksums[c + col + 3];
        }
        #pragma unroll
        for (int j = 0; j < 2; j++) {
            int fi = t * 2 + j;
            int row = fi >> 4, col = (fi & 15) * 4;
            *(float4*)&Bs[row * CSB + col] =
                *(const float4*)&g_ctx[(size_t)h * MF * DH + (size_t)(c + row) * DH + col];
        }
        __syncthreads();
        #pragma unroll
        for (int kk = 0; kk < 4; kk++) {
            int k = kk * 8;
            uint32_t af[2][4], bf[4][2];
            #pragma unroll
            for (int mt = 0; mt < 2; mt++) {
                int m = warp_m + mt * 16 + g;
                af[mt][0] = to_tf32u(As[m * 36 + k + q]);
                af[mt][1] = to_tf32u(As[(m + 8) * 36 + k + q]);
                af[mt][2] = to_tf32u(As[m * 36 + k + q + 4]);
                af[mt][3] = to_tf32u(As[(m + 8) * 36 + k + q + 4]);
            }
            #pragma unroll
            for (int nt = 0; nt < 4; nt++) {
                int n2 = warp_n + nt * 8 + g;
                bf[nt][0] = to_tf32u(Bs[(k + q) * CSB + n2]);
                bf[nt][1] = to_tf32u(Bs[(k + 4 + q) * CSB + n2]);
            }
            #pragma unroll
            for (int mt = 0; mt < 2; mt++)
                #pragma unroll
                for (int nt = 0; nt < 4; nt++)
                    mma8(acc[mt][nt], af[mt], bf[nt]);
        }
        __syncthreads();
    }

    denp += __shfl_xor_sync(0xffffffffu, denp, 1);
    if ((t & 1) == 0) dens[sr] = denp;
    __syncthreads();

    #pragma unroll
    for (int mt = 0; mt < 2; mt++)
        #pragma unroll
        for (int nt = 0; nt < 4; nt++)
            #pragma unroll
            for (int e = 0; e < 4; e++) {
                int row = warp_m + mt * 16 + g + (e >> 1) * 8;
                int d = warp_n + nt * 8 + q * 2 + (e & 1);
                g_attnh[(size_t)(n0 + row) * DIM + h * DH + d] =
                    __float2half(acc[mt][nt][e] / dens[row]);
            }
}

// ---------------- output head ----------------
__global__ __launch_bounds__(128) void wout_kernel(const float* __restrict__ Wout,
                                                   const float* __restrict__ bout,
                                                   float* __restrict__ out) {
    int n = blockIdx.x, t = threadIdx.x;
    __shared__ float xs[DIM];
    for (int i = t; i < DIM; i += 128) xs[i] = g_h[n * DIM + i];
    __syncthreads();
    if (t < VOCAB) {
        float acc = bout[t];
        for (int k = 0; k < DIM; k++) acc += xs[k] * Wout[k * VOCAB + t];
        out[n * VOCAB + t] = acc;
    }
}

// ---------------- host ----------------
extern "C" void kernel_launch(void* const* d_in, const int* in_sizes, int n_in,
                              void* d_out, int out_size) {
    const float* methy = (const float*)d_in[0];
    const int* chromo = (const int*)d_in[1];
    const int* pos    = (const int*)d_in[2];
    const float* mt = (const float*)d_in[3];
    const float* ct = (const float*)d_in[4];
    const float* pt = (const float*)d_in[5];
    const float* ln1g = (const float*)d_in[6];
    const float* ln1b = (const float*)d_in[7];
    const float* ln2g = (const float*)d_in[8];
    const float* ln2b = (const float*)d_in[9];
    const float* Wq = (const float*)d_in[10];
    const float* Wk = (const float*)d_in[11];
    const float* Wv = (const float*)d_in[12];
    const float* Wo = (const float*)d_in[13];
    const float* bo = (const float*)d_in[14];
    const float* W1 = (const float*)d_in[15];
    const float* b1 = (const float*)d_in[16];
    const float* W2 = (const float*)d_in[17];
    const float* b2 = (const float*)d_in[18];
    const float* proj = (const float*)d_in[19];
    const float* nfg = (const float*)d_in[20];
    const float* nfb = (const float*)d_in[21];
    const float* Wout = (const float*)d_in[22];
    const float* bout = (const float*)d_in[23];
    float* out = (float*)d_out;

    float *px, *ph, *pq, *pk, *pv;
    __half *phh, *pattnh, *pffh, *pwh;
    cudaGetSymbolAddress((void**)&px, g_x);
    cudaGetSymbolAddress((void**)&ph, g_h);
    cudaGetSymbolAddress((void**)&phh, g_hh);
    cudaGetSymbolAddress((void**)&pq, g_q);
    cudaGetSymbolAddress((void**)&pk, g_k);
    cudaGetSymbolAddress((void**)&pv, g_v);
    cudaGetSymbolAddress((void**)&pattnh, g_attnh);
    cudaGetSymbolAddress((void**)&pffh, g_ffh);
    cudaGetSymbolAddress((void**)&pwh, g_wh);

    const int GEMMH_SMEM = HSTAGES * 2 * HAELE * 2;                  // 110,592
    const int FEAT_SMEM  = (128 * FSA + 64 * FSB) * sizeof(float);   // 69,632
    cudaFuncSetAttribute(tgemm_h, cudaFuncAttributeMaxDynamicSharedMemorySize, GEMMH_SMEM);
    cudaFuncSetAttribute(featgemm_kernel, cudaFuncAttributeMaxDynamicSharedMemorySize, FEAT_SMEM);

    wconv_kernel<<<dim3(96, 96, 36), 256>>>(Wq, Wk, Wv, Wo, W1, W2);
    embed_kernel<<<NTOK, 256>>>(methy, chromo, pos, mt, ct, pt);

    dim3 gqkv(DIM / 128, NTOK / 128, 3);
    dim3 gsk3(DIM / 128, NTOK / 128, 3);
    dim3 gff(FF / 128, NTOK / 128, 1);
    dim3 gfeat(2, 32, HEADS * 2);
    dim3 gctx(HEADS, 2, 8);
    dim3 gattn(HEADS, NTOK / 128);

    for (int l = 0; l < DEPTH; l++) {
        const float* pj = proj + (size_t)l * MF * DH;
        const __half* wl = pwh + (size_t)l * LOFF;
        // --- attention ---
        ln_kernel<<<NTOK, 256>>>(px, ln1g + l * DIM, ln1b + l * DIM, ph, phh);
        tgemm_h<<<gqkv, 256, GEMMH_SMEM>>>(phh,
            wl + WOQ, wl + WOK, wl + WOV,
            nullptr, pq, pk, pv, DIM, DIM, 0, 1, 0);
        featgemm_kernel<<<gfeat, 256, FEAT_SMEM>>>(pj);
        ctxgemm_kernel<<<gctx, 256>>>(methy);
        reduce_kernel<<<192, 256>>>();
        attngemm_kernel<<<gattn, 256>>>();
        tgemm_h<<<gsk3, 256, GEMMH_SMEM>>>(pattnh,
            wl + WOO, nullptr, nullptr,
            bo + l * DIM, px, nullptr, nullptr, DIM, DIM, 0, 3, 0);
        // --- FFN ---
        ln_kernel<<<NTOK, 256>>>(px, ln2g + l * DIM, ln2b + l * DIM, ph, phh);
        tgemm_h<<<gff, 256, GEMMH_SMEM>>>(phh,
            wl + WO1, nullptr, nullptr,
            b1 + l * FF, (float*)pffh, nullptr, nullptr, FF, DIM, 1, 1, 1);
        tgemm_h<<<gsk3, 256, GEMMH_SMEM>>>(pffh,
            wl + WO2, nullptr, nullptr,
            b2 + l * DIM, px, nullptr, nullptr, DIM, FF, 0, 3, 0);
    }

    ln_kernel<<<NTOK, 256>>>(px, nfg, nfb, ph, phh);
    wout_kernel<<<NTOK, 128>>>(Wout, bout, out);
}

// round 12
// speedup vs baseline: 5.8658x; 1.0160x over previous
#include <cuda_runtime.h>
#include <cuda_fp16.h>
#include <math.h>
#include <stdint.h>

#define NTOK 4096
#define DIM 768
#define DEPTH 6
#define HEADS 12
#define DH 64
#define FF 3072
#define MF 256
#define VOCAB 102
#define DNORM 0.35355339059327373f   /* 64^-0.25 */
#define RATIO 0.0625f                /* 256^-0.5 */

// per-layer half-weight offsets (in halves)
#define LOFF 7077888
#define WOQ 0
#define WOK 589824
#define WOV 1179648
#define WOO 1769472
#define WO1 2359296
#define WO2 4718592

// ---------------- scratch (device globals, no allocation) ----------------
__device__ float g_x[NTOK * DIM];
__device__ float g_h[NTOK * DIM];
__device__ __align__(16) __half g_hh[NTOK * DIM];
__device__ float g_q[NTOK * DIM];
__device__ float g_k[NTOK * DIM];
__device__ float g_v[NTOK * DIM];
__device__ __align__(16) __half g_attnh[NTOK * DIM];
__device__ __align__(16) __half g_ffh[NTOK * FF];
__device__ __align__(16) __half g_wh[(size_t)DEPTH * LOFF];
__device__ float g_qf[HEADS * NTOK * MF];     // raw xd
__device__ float g_kf[HEADS * NTOK * MF];     // raw xd
__device__ float g_diagq[HEADS * NTOK];
__device__ float g_diagk[HEADS * NTOK];
__device__ float g_maxq2[2 * HEADS * NTOK];
__device__ float g_maxk2[HEADS * 64];
__device__ float g_ksum[HEADS * MF];
__device__ float g_ctx[HEADS * MF * DH];
__device__ float g_ctxp[8 * HEADS * MF * DH];
__device__ float g_ksump[8 * HEADS * MF];

// ---------------- helpers ----------------
__device__ __forceinline__ float tanh_fast(float x) {
    float r;
    asm("tanh.approx.f32 %0, %1;" : "=f"(r) : "f"(x));
    return r;
}

__device__ __forceinline__ float gelu_tanh(float u) {
    return 0.5f * u * (1.0f + tanh_fast(0.7978845608028654f * (u + 0.044715f * u * u * u)));
}

__device__ __forceinline__ uint32_t to_tf32u(float x) {
    float r;
    asm("cvt.rna.tf32.f32 %0, %1;" : "=f"(r) : "f"(x));
    return __float_as_uint(r);
}

__device__ __forceinline__ void mma8(float* c, const uint32_t* a, const uint32_t* b) {
    asm volatile(
        "mma.sync.aligned.m16n8k8.row.col.f32.tf32.tf32.f32 "
        "{%0,%1,%2,%3}, {%4,%5,%6,%7}, {%8,%9}, {%0,%1,%2,%3};"
        : "+f"(c[0]), "+f"(c[1]), "+f"(c[2]), "+f"(c[3])
        : "r"(a[0]), "r"(a[1]), "r"(a[2]), "r"(a[3]), "r"(b[0]), "r"(b[1]));
}

__device__ __forceinline__ void mma16(float* c, const uint32_t* a, const uint32_t* b) {
    asm volatile(
        "mma.sync.aligned.m16n8k16.row.col.f32.f16.f16.f32 "
        "{%0,%1,%2,%3}, {%4,%5,%6,%7}, {%8,%9}, {%0,%1,%2,%3};"
        : "+f"(c[0]), "+f"(c[1]), "+f"(c[2]), "+f"(c[3])
        : "r"(a[0]), "r"(a[1]), "r"(a[2]), "r"(a[3]), "r"(b[0]), "r"(b[1]));
}

__device__ __forceinline__ void ldsm4(uint32_t* r, uint32_t addr) {
    asm volatile("ldmatrix.sync.aligned.m8n8.x4.shared.b16 {%0,%1,%2,%3}, [%4];"
        : "=r"(r[0]), "=r"(r[1]), "=r"(r[2]), "=r"(r[3]) : "r"(addr));
}

__device__ __forceinline__ void cp_async16(uint32_t dst, const void* src) {
    asm volatile("cp.async.cg.shared.global [%0], [%1], 16;" :: "r"(dst), "l"(src));
}
__device__ __forceinline__ void cp_commit() { asm volatile("cp.async.commit_group;"); }
__device__ __forceinline__ void cp_wait1() { asm volatile("cp.async.wait_group 1;"); }
__device__ __forceinline__ void cp_wait0() { asm volatile("cp.async.wait_group 0;"); }

// ---------------- weight convert + transpose: W[K][N]f32 -> Wt[N][K]h -----
__global__ __launch_bounds__(256) void wconv_kernel(const float* __restrict__ Wq,
                                                    const float* __restrict__ Wk,
                                                    const float* __restrict__ Wv,
                                                    const float* __restrict__ Wo,
                                                    const float* __restrict__ W1,
                                                    const float* __restrict__ W2) {
    int mat = blockIdx.z % 6, l = blockIdx.z / 6;
    int K = (mat == 5) ? FF : DIM;
    int N = (mat == 4) ? FF : DIM;
    int n0 = blockIdx.x * 32, k0 = blockIdx.y * 32;
    if (n0 >= N || k0 >= K) return;
    const float* srcs[6] = {Wq, Wk, Wv, Wo, W1, W2};
    const size_t offs[6] = {WOQ, WOK, WOV, WOO, WO1, WO2};
    const float* src = srcs[mat] + (size_t)l * K * N;
    __half* dst = g_wh + (size_t)l * LOFF + offs[mat];
    __shared__ float tile[32][33];
    int tx = threadIdx.x & 31, ty = threadIdx.x >> 5;   // 32x8
    #pragma unroll
    for (int i = 0; i < 4; i++)
        tile[ty + i * 8][tx] = src[(size_t)(k0 + ty + i * 8) * N + n0 + tx];
    __syncthreads();
    #pragma unroll
    for (int i = 0; i < 4; i++)
        dst[(size_t)(n0 + ty + i * 8) * K + k0 + tx] = __float2half(tile[tx][ty + i * 8]);
}

// ---------------- embedding + bucketize ----------------
__global__ void embed_kernel(const float* __restrict__ methy,
                             const int* __restrict__ chromo,
                             const int* __restrict__ pos,
                             const float* __restrict__ mt,
                             const float* __restrict__ ct,
                             const float* __restrict__ pt) {
    int n = blockIdx.x;
    float x = methy[n];
    int idx = (x > -2.0f) + (x > -1.0f);
    #pragma unroll 4
    for (int i = 0; i < 100; i++) idx += ((float)i * 0.01f < x) ? 1 : 0;
    int c = chromo[n], p = pos[n];
    const float* mrow = mt + (size_t)idx * DIM;
    const float* prow = pt + (size_t)p * DIM;
    const float* crow = ct + (size_t)c * DIM;
    for (int d = threadIdx.x; d < DIM; d += blockDim.x)
        g_x[n * DIM + d] = mrow[d] + prow[d] + crow[d];
}

// ---------------- layernorm (writes fp32 + half) ----------------
__global__ __launch_bounds__(256) void ln_kernel(const float* __restrict__ in,
                                                 const float* __restrict__ g,
                                                 const float* __restrict__ b,
                                                 float* __restrict__ out,
                                                 __half* __restrict__ outh) {
    int n = blockIdx.x, t = threadIdx.x;
    __shared__ float red[256];
    float v[3];
    float s = 0.f;
    #pragma unroll
    for (int i = 0; i < 3; i++) { v[i] = in[n * DIM + t + i * 256]; s += v[i]; }
    red[t] = s; __syncthreads();
    for (int off = 128; off > 0; off >>= 1) { if (t < off) red[t] += red[t + off]; __syncthreads(); }
    float mu = red[0] * (1.0f / DIM);
    __syncthreads();
    float s2 = 0.f;
    #pragma unroll
    for (int i = 0; i < 3; i++) { float d = v[i] - mu; s2 += d * d; }
    red[t] = s2; __syncthreads();
    for (int off = 128; off > 0; off >>= 1) { if (t < off) red[t] += red[t + off]; __syncthreads(); }
    float rstd = rsqrtf(red[0] * (1.0f / DIM) + 1e-5f);
    #pragma unroll
    for (int i = 0; i < 3; i++) {
        int d = t + i * 256;
        float o = (v[i] - mu) * rstd * g[d] + b[d];
        out[n * DIM + d] = o;
        outh[n * DIM + d] = __float2half(o);
    }
}

// ---------------- FP16 GEMM 128x128x64h, cp.async 3-stage, ldmatrix -------
// A [M,K] half row-major, Bt [N,K] half row-major (pre-transposed weights).
#define BKH 64
#define SAH 72            /* halves stride; 36 words */
#define HAELE (128 * SAH) /* 9216 halves per stage */
#define HSTAGES 3

__global__ __launch_bounds__(256, 2) void tgemm_h(const __half* __restrict__ A,
                                                  const __half* __restrict__ B0,
                                                  const __half* __restrict__ B1,
                                                  const __half* __restrict__ B2,
                                                  const float* __restrict__ bias,
                                                  float* __restrict__ C0,
                                                  float* __restrict__ C1,
                                                  float* __restrict__ C2,
                                                  int Nn, int Kk, int act, int splitk,
                                                  int outhalf) {
    extern __shared__ __half hsm[];
    int z = blockIdx.z;
    const __half* B = B0;
    float* C = C0;
    int koff = 0, Keff = Kk;
    if (splitk > 1) {
        Keff = Kk / splitk;
        koff = z * Keff;
    } else {
        B = (z == 0) ? B0 : ((z == 1) ? B1 : B2);
        C = (z == 0) ? C0 : ((z == 1) ? C1 : C2);
    }

    int t = threadIdx.x;
    int rb = blockIdx.y * 128, cb = blockIdx.x * 128;
    int lane = t & 31, wid = t >> 5;
    int warp_m = (wid & 1) * 64, warp_n = (wid >> 1) * 32;
    int q = lane & 3, g = lane >> 2;

    int tr = t >> 3;           // 0..31, rows tr+32i
    int tc = (t & 7) * 8;      // halves

    const __half* Abase = A + (size_t)(rb + tr) * Kk + koff + tc;
    const __half* Bbase = B + (size_t)(cb + tr) * Kk + koff + tc;

    uint32_t smA = (uint32_t)__cvta_generic_to_shared(hsm);
    uint32_t smB = smA + HSTAGES * HAELE * 2;
    uint32_t adst = smA + (uint32_t)((tr * SAH + tc) * 2);
    uint32_t bdst = smB + (uint32_t)((tr * SAH + tc) * 2);

    // ldmatrix per-lane base offsets (bytes within a stage)
    uint32_t aoff[4], boff[2];
    {
        int r = (lane & 7) + ((lane >> 3) & 1) * 8;
        int kh = (lane >> 4) * 8;
        #pragma unroll
        for (int mt = 0; mt < 4; mt++)
            aoff[mt] = (uint32_t)(((warp_m + mt * 16 + r) * SAH + kh) * 2);
        int rn = lane & 7;
        int khb = ((lane >> 3) & 1) * 8;
        int pb = lane >> 4;
        #pragma unroll
        for (int p = 0; p < 2; p++)
            boff[p] = (uint32_t)(((warp_n + (p * 2 + pb) * 8 + rn) * SAH + khb) * 2);
    }

    int niter = Keff / BKH;

    #pragma unroll
    for (int s = 0; s < 2; s++) {
        if (s < niter) {
            size_t k0 = (size_t)s * BKH;
            #pragma unroll
            for (int i = 0; i < 4; i++)
                cp_async16(adst + (uint32_t)(s * HAELE * 2 + i * 32 * SAH * 2),
                           Abase + (size_t)(32 * i) * Kk + k0);
            #pragma unroll
            for (int i = 0; i < 4; i++)
                cp_async16(bdst + (uint32_t)(s * HAELE * 2 + i * 32 * SAH * 2),
                           Bbase + (size_t)(32 * i) * Kk + k0);
        }
        cp_commit();
    }

    float acc[4][4][4];
    #pragma unroll
    for (int mt = 0; mt < 4; mt++)
        #pragma unroll
        for (int nt = 0; nt < 4; nt++)
            #pragma unroll
            for (int e = 0; e < 4; e++) acc[mt][nt][e] = 0.f;

    for (int it = 0; it < niter; it++) {
        if (it + 1 < niter) cp_wait1(); else cp_wait0();
        __syncthreads();
        if (it + 2 < niter) {
            int s = (it + 2) % HSTAGES;
            size_t k0 = (size_t)(it + 2) * BKH;
            #pragma unroll
            for (int i = 0; i < 4; i++)
                cp_async16(adst + (uint32_t)(s * HAELE * 2 + i * 32 * SAH * 2),
                           Abase + (size_t)(32 * i) * Kk + k0);
            #pragma unroll
            for (int i = 0; i < 4; i++)
                cp_async16(bdst + (uint32_t)(s * HAELE * 2 + i * 32 * SAH * 2),
                           Bbase + (size_t)(32 * i) * Kk + k0);
        }
        cp_commit();

        uint32_t sa = smA + (uint32_t)((it % HSTAGES) * HAELE * 2);
        uint32_t sb = smB + (uint32_t)((it % HSTAGES) * HAELE * 2);
        #pragma unroll
        for (int ks = 0; ks < 4; ks++) {
            uint32_t kbyte = (uint32_t)(ks * 32);   // 16 halves
            uint32_t af[4][4], bfr[2][4];
            #pragma unroll
            for (int mt = 0; mt < 4; mt++) ldsm4(af[mt], sa + aoff[mt] + kbyte);
            #pragma unroll
            for (int p = 0; p < 2; p++) ldsm4(bfr[p], sb + boff[p] + kbyte);
            #pragma unroll
            for (int mt = 0; mt < 4; mt++)
                #pragma unroll
                for (int nt = 0; nt < 4; nt++)
                    mma16(acc[mt][nt], af[mt], &bfr[nt >> 1][(nt & 1) * 2]);
        }
    }
    __syncthreads();

    // epilogue
    if (splitk > 1) {
        #pragma unroll
        for (int mt = 0; mt < 4; mt++)
            #pragma unroll
            for (int nt = 0; nt < 4; nt++)
                #pragma unroll
                for (int e = 0; e < 4; e++) {
                    int row = rb + warp_m + mt * 16 + g + (e >> 1) * 8;
                    int col = cb + warp_n + nt * 8 + q * 2 + (e & 1);
                    float val = acc[mt][nt][e];
                    if (bias && z == 0) val += bias[col];
                    atomicAdd(&C[(size_t)row * Nn + col], val);
                }
    } else {
        #pragma unroll
        for (int mt = 0; mt < 4; mt++)
            #pragma unroll
            for (int nt = 0; nt < 4; nt++)
                #pragma unroll
                for (int e = 0; e < 4; e++) {
                    int row = rb + warp_m + mt * 16 + g + (e >> 1) * 8;
                    int col = cb + warp_n + nt * 8 + q * 2 + (e & 1);
                    float val = acc[mt][nt][e];
                    if (bias) val += bias[col];
                    if (act) val = gelu_tanh(val);
                    if (outhalf) ((__half*)C)[(size_t)row * Nn + col] = __float2half(val);
                    else C[(size_t)row * Nn + col] = val;
                }
    }
}

// ---------------- feature GEMM fp16: xd[h,n,m] = (x*DNORM) . proj[m] ------
// A = x half-staged [128 n][64 d], B = proj*DNORM [128 m][64 d]; diag fp32.
#define FSH 72   /* halves stride, 36 words */
__global__ __launch_bounds__(256, 2) void featgemm_kernel(const float* __restrict__ proj) {
    __shared__ __half As[128 * FSH];
    __shared__ __half Bs[128 * FSH];
    __shared__ float diagacc[128];
    __shared__ float wred[8];
    __shared__ float redq[4][128];
    int hk = blockIdx.z, h = hk >> 1, isK = hk & 1;
    const float* X = isK ? g_k : g_q;
    float* dst = isK ? g_kf : g_qf;
    int n0 = blockIdx.y * 128, m0 = blockIdx.x * 128;
    int t = threadIdx.x, lane = t & 31, wid = t >> 5;
    int warp_m = (wid & 1) * 64, warp_n = (wid >> 1) * 32;
    int q = lane & 3, g = lane >> 2;
    bool dodiag = (blockIdx.x == 0);

    if (t < 128) diagacc[t] = 0.f;
    __syncthreads();

    #pragma unroll
    for (int j = 0; j < 8; j++) {
        int i = t + j * 256;
        int row = i >> 4, c = (i & 15) * 4;
        float4 v = *(const float4*)&X[(size_t)(n0 + row) * DIM + h * DH + c];
        __half2 lo = __floats2half2_rn(v.x, v.y);
        __half2 hi = __floats2half2_rn(v.z, v.w);
        *(__half2*)&As[row * FSH + c] = lo;
        *(__half2*)&As[row * FSH + c + 2] = hi;
        if (dodiag)
            atomicAdd(&diagacc[row], v.x * v.x + v.y * v.y + v.z * v.z + v.w * v.w);
    }
    #pragma unroll
    for (int j = 0; j < 8; j++) {
        int i = t + j * 256;
        int m = i >> 4, d = (i & 15) * 4;
        float4 v = *(const float4*)&proj[(size_t)(m0 + m) * DH + d];
        *(__half2*)&Bs[m * FSH + d] = __floats2half2_rn(v.x * DNORM, v.y * DNORM);
        *(__half2*)&Bs[m * FSH + d + 2] = __floats2half2_rn(v.z * DNORM, v.w * DNORM);
    }
    __syncthreads();

    float acc[4][4][4];
    #pragma unroll
    for (int mt = 0; mt < 4; mt++)
        #pragma unroll
        for (int nt = 0; nt < 4; nt++)
            #pragma unroll
            for (int e = 0; e < 4; e++) acc[mt][nt][e] = 0.f;

    const uint32_t* asw = (const uint32_t*)As;
    const uint32_t* bsw = (const uint32_t*)Bs;
    #pragma unroll
    for (int ks = 0; ks < 4; ks++) {
        int k0w = ks * 8;
        uint32_t af[4][4], bf[4][2];
        #pragma unroll
        for (int mt = 0; mt < 4; mt++) {
            int m = warp_m + mt * 16 + g;
            af[mt][0] = asw[m * 36 + k0w + q];
            af[mt][1] = asw[(m + 8) * 36 + k0w + q];
            af[mt][2] = asw[m * 36 + k0w + q + 4];
            af[mt][3] = asw[(m + 8) * 36 + k0w + q + 4];
        }
        #pragma unroll
        for (int nt = 0; nt < 4; nt++) {
            int n = warp_n + nt * 8 + g;
            bf[nt][0] = bsw[n * 36 + k0w + q];
            bf[nt][1] = bsw[n * 36 + k0w + q + 4];
        }
        #pragma unroll
        for (int mt = 0; mt < 4; mt++)
            #pragma unroll
            for (int nt = 0; nt < 4; nt++)
                mma16(acc[mt][nt], af[mt], bf[nt]);
    }

    if (dodiag && t < 128) {
        float* dg = isK ? g_diagk : g_diagq;
        dg[h * NTOK + n0 + t] = 0.5f * (DNORM * DNORM) * diagacc[t];
    }

    // store raw xd
    #pragma unroll
    for (int mt = 0; mt < 4; mt++)
        #pragma unroll
        for (int nt = 0; nt < 4; nt++)
            #pragma unroll
            for (int e = 0; e < 4; e++) {
                int row = warp_m + mt * 16 + g + (e >> 1) * 8;
                int col = warp_n + nt * 8 + q * 2 + (e & 1);
                dst[((size_t)h * NTOK + n0 + row) * MF + m0 + col] = acc[mt][nt][e];
            }

    if (!isK) {
        #pragma unroll
        for (int mt = 0; mt < 4; mt++)
            #pragma unroll
            for (int eh = 0; eh < 2; eh++) {
                float v = -1e30f;
                #pragma unroll
                for (int nt = 0; nt < 4; nt++) {
                    v = fmaxf(v, acc[mt][nt][eh * 2]);
                    v = fmaxf(v, acc[mt][nt][eh * 2 + 1]);
                }
                v = fmaxf(v, __shfl_xor_sync(0xffffffffu, v, 1));
                v = fmaxf(v, __shfl_xor_sync(0xffffffffu, v, 2));
                if (q == 0)
                    redq[wid >> 1][warp_m + mt * 16 + g + eh * 8] = v;
            }
        __syncthreads();
        if (t < 128) {
            float v = fmaxf(fmaxf(redq[0][t], redq[1][t]), fmaxf(redq[2][t], redq[3][t]));
            g_maxq2[(size_t)blockIdx.x * HEADS * NTOK + h * NTOK + n0 + t] = v;
        }
    } else {
        float v = -1e30f;
        #pragma unroll
        for (int mt = 0; mt < 4; mt++)
            #pragma unroll
            for (int nt = 0; nt < 4; nt++)
                #pragma unroll
                for (int e = 0; e < 4; e++) v = fmaxf(v, acc[mt][nt][e]);
        for (int off = 16; off; off >>= 1) v = fmaxf(v, __shfl_xor_sync(0xffffffffu, v, off));
        if (lane == 0) wred[wid] = v;
        __syncthreads();
        if (t == 0) {
            float mx = wred[0];
            #pragma unroll
            for (int w = 1; w < 8; w++) mx = fmaxf(mx, wred[w]);
            g_maxk2[h * 64 + blockIdx.y * 2 + blockIdx.x] = mx;
        }
    }
}

// ---------------- ctx GEMM (tf32, partials) ----------------
#define CSA 136
#define CSB 72
__global__ __launch_bounds__(256) void ctxgemm_kernel(const float* __restrict__ methy) {
    __shared__ float As[32 * CSA];
    __shared__ float Bs[32 * CSB];
    __shared__ float mkred[64];
    int h = blockIdx.x, m0 = blockIdx.y * 128, zs = blockIdx.z;
    int nbase = zs * 512;
    int t = threadIdx.x, lane = t & 31, wid = t >> 5;
    int warp_m = (wid & 3) * 32, warp_n = (wid >> 2) * 32;
    int q = lane & 3, g = lane >> 2;

    if (t < 64) mkred[t] = g_maxk2[h * 64 + t];
    __syncthreads();
    float mk = mkred[0];
    #pragma unroll
    for (int i = 1; i < 64; i++) mk = fmaxf(mk, mkred[i]);

    int sr = t >> 3;
    int sc = (t & 7) * 4;

    float acc[2][4][4];
    #pragma unroll
    for (int mt = 0; mt < 2; mt++)
        #pragma unroll
        for (int nt = 0; nt < 4; nt++)
            #pragma unroll
            for (int e = 0; e < 4; e++) acc[mt][nt][e] = 0.f;
    float ksacc[16];
    #pragma unroll
    for (int i = 0; i < 16; i++) ksacc[i] = 0.f;

    for (int c = 0; c < 512; c += 32) {
        int n = nbase + c + sr;
        float dgk = g_diagk[h * NTOK + n];
        float msk = (methy[n] != 0.0f) ? 1.0f : 0.0f;
        const float* src = &g_kf[((size_t)h * NTOK + n) * MF + m0];
        #pragma unroll
        for (int j = 0; j < 4; j++) {
            int col = sc + 32 * j;
            float4 v = *(const float4*)&src[col];
            float4 w;
            w.x = RATIO * (expf(v.x - dgk - mk) + 1e-4f) * msk;
            w.y = RATIO * (expf(v.y - dgk - mk) + 1e-4f) * msk;
            w.z = RATIO * (expf(v.z - dgk - mk) + 1e-4f) * msk;
            w.w = RATIO * (expf(v.w - dgk - mk) + 1e-4f) * msk;
            *(float4*)&As[sr * CSA + col] = w;
            ksacc[j * 4 + 0] += w.x; ksacc[j * 4 + 1] += w.y;
            ksacc[j * 4 + 2] += w.z; ksacc[j * 4 + 3] += w.w;
        }
        #pragma unroll
        for (int j = 0; j < 2; j++) {
            int fi = t * 2 + j;
            int row = fi >> 4, col = (fi & 15) * 4;
            *(float4*)&Bs[row * CSB + col] =
                *(const float4*)&g_v[(size_t)(nbase + c + row) * DIM + h * DH + col];
        }
        __syncthreads();
        #pragma unroll
        for (int kk = 0; kk < 4; kk++) {
            int k = kk * 8;
            uint32_t af[2][4], bf[4][2];
            #pragma unroll
            for (int mt = 0; mt < 2; mt++) {
                int m = warp_m + mt * 16 + g;
                af[mt][0] = to_tf32u(As[(k + q) * CSA + m]);
                af[mt][1] = to_tf32u(As[(k + q) * CSA + m + 8]);
                af[mt][2] = to_tf32u(As[(k + 4 + q) * CSA + m]);
                af[mt][3] = to_tf32u(As[(k + 4 + q) * CSA + m + 8]);
            }
            #pragma unroll
            for (int nt = 0; nt < 4; nt++) {
                int n2 = warp_n + nt * 8 + g;
                bf[nt][0] = to_tf32u(Bs[(k + q) * CSB + n2]);
                bf[nt][1] = to_tf32u(Bs[(k + 4 + q) * CSB + n2]);
            }
            #pragma unroll
            for (int mt = 0; mt < 2; mt++)
                #pragma unroll
                for (int nt = 0; nt < 4; nt++)
                    mma8(acc[mt][nt], af[mt], bf[nt]);
        }
        __syncthreads();
    }

    #pragma unroll
    for (int j = 0; j < 4; j++) {
        int col = sc + 32 * j;
        *(float4*)&As[sr * CSA + col] = make_float4(ksacc[j*4], ksacc[j*4+1], ksacc[j*4+2], ksacc[j*4+3]);
    }
    __syncthreads();
    if (t < 128) {
        float s = 0.f;
        #pragma unroll
        for (int r = 0; r < 32; r++) s += As[r * CSA + t];
        g_ksump[((size_t)zs * HEADS + h) * MF + m0 + t] = s;
    }
    float* ctxp = &g_ctxp[((size_t)zs * HEADS + h) * MF * DH];
    #pragma unroll
    for (int mt = 0; mt < 2; mt++)
        #pragma unroll
        for (int nt = 0; nt < 4; nt++)
            #pragma unroll
            for (int e = 0; e < 4; e++) {
                int m = m0 + warp_m + mt * 16 + g + (e >> 1) * 8;
                int d = warp_n + nt * 8 + q * 2 + (e & 1);
                ctxp[(size_t)m * DH + d] = acc[mt][nt][e];
            }
}

// ---------------- reduce partials ----------------
__global__ __launch_bounds__(256) void reduce_kernel() {
    int i = blockIdx.x * 256 + threadIdx.x;
    int nt = gridDim.x * 256;
    for (int j = i; j < HEADS * MF * DH; j += nt) {
        float s = 0.f;
        #pragma unroll
        for (int z = 0; z < 8; z++) s += g_ctxp[(size_t)z * HEADS * MF * DH + j];
        g_ctx[j] = s;
    }
    for (int j = i; j < HEADS * MF; j += nt) {
        float s = 0.f;
        #pragma unroll
        for (int z = 0; z < 8; z++) s += g_ksump[(size_t)z * HEADS * MF + j];
        g_ksum[j] = s;
    }
}

// ---------------- attn GEMM (tf32), writes half output --------------------
__global__ __launch_bounds__(256) void attngemm_kernel() {
    __shared__ float As[128 * 36];
    __shared__ float Bs[32 * CSB];
    __shared__ float ksums[MF];
    __shared__ float dens[128];
    int h = blockIdx.x, n0 = blockIdx.y * 128;
    int t = threadIdx.x, lane = t & 31, wid = t >> 5;
    int warp_m = (wid & 3) * 32, warp_n = (wid >> 2) * 32;
    int q = lane & 3, g = lane >> 2;

    ksums[t] = g_ksum[h * MF + t];
    __syncthreads();

    int sr = t >> 1;
    int n = n0 + sr;
    float dq = g_diagq[h * NTOK + n];
    float mq = fmaxf(g_maxq2[h * NTOK + n], g_maxq2[(size_t)HEADS * NTOK + h * NTOK + n]);
    float denp = 0.f;

    float acc[2][4][4];
    #pragma unroll
    for (int mt = 0; mt < 2; mt++)
        #pragma unroll
        for (int nt = 0; nt < 4; nt++)
            #pragma unroll
            for (int e = 0; e < 4; e++) acc[mt][nt][e] = 0.f;

    for (int c = 0; c < 256; c += 32) {
        const float* src = &g_qf[((size_t)h * NTOK + n) * MF + c];
        #pragma unroll
        for (int j = 0; j < 4; j++) {
            int col = ((t & 1) * 4 + j) * 4;
            float4 v = *(const float4*)&src[col];
            float4 w;
            w.x = RATIO * (expf(v.x - dq - mq) + 1e-4f);
            w.y = RATIO * (expf(v.y - dq - mq) + 1e-4f);
            w.z = RATIO * (expf(v.z - dq - mq) + 1e-4f);
            w.w = RATIO * (expf(v.w - dq - mq) + 1e-4f);
            *(float4*)&As[sr * 36 + col] = w;
            denp += w.x * ksums[c + col] + w.y * ksums[c + col + 1]
                  + w.z * ksums[c + col + 2] + w.w * ksums[c + col + 3];
        }
        #pragma unroll
        for (int j = 0; j < 2; j++) {
            int fi = t * 2 + j;
            int row = fi >> 4, col = (fi & 15) * 4;
            *(float4*)&Bs[row * CSB + col] =
                *(const float4*)&g_ctx[(size_t)h * MF * DH + (size_t)(c + row) * DH + col];
        }
        __syncthreads();
        #pragma unroll
        for (int kk = 0; kk < 4; kk++) {
            int k = kk * 8;
            uint32_t af[2][4], bf[4][2];
            #pragma unroll
            for (int mt = 0; mt < 2; mt++) {
                int m = warp_m + mt * 16 + g;
                af[mt][0] = to_tf32u(As[m * 36 + k + q]);
                af[mt][1] = to_tf32u(As[(m + 8) * 36 + k + q]);
                af[mt][2] = to_tf32u(As[m * 36 + k + q + 4]);
                af[mt][3] = to_tf32u(As[(m + 8) * 36 + k + q + 4]);
            }
            #pragma unroll
            for (int nt = 0; nt < 4; nt++) {
                int n2 = warp_n + nt * 8 + g;
                bf[nt][0] = to_tf32u(Bs[(k + q) * CSB + n2]);
                bf[nt][1] = to_tf32u(Bs[(k + 4 + q) * CSB + n2]);
            }
            #pragma unroll
            for (int mt = 0; mt < 2; mt++)
                #pragma unroll
                for (int nt = 0; nt < 4; nt++)
                    mma8(acc[mt][nt], af[mt], bf[nt]);
        }
        __syncthreads();
    }

    denp += __shfl_xor_sync(0xffffffffu, denp, 1);
    if ((t & 1) == 0) dens[sr] = denp;
    __syncthreads();

    #pragma unroll
    for (int mt = 0; mt < 2; mt++)
        #pragma unroll
        for (int nt = 0; nt < 4; nt++)
            #pragma unroll
            for (int e = 0; e < 4; e++) {
                int row = warp_m + mt * 16 + g + (e >> 1) * 8;
                int d = warp_n + nt * 8 + q * 2 + (e & 1);
                g_attnh[(size_t)(n0 + row) * DIM + h * DH + d] =
                    __float2half(acc[mt][nt][e] / dens[row]);
            }
}

// ---------------- output head ----------------
__global__ __launch_bounds__(128) void wout_kernel(const float* __restrict__ Wout,
                                                   const float* __restrict__ bout,
                                                   float* __restrict__ out) {
    int n = blockIdx.x, t = threadIdx.x;
    __shared__ float xs[DIM];
    for (int i = t; i < DIM; i += 128) xs[i] = g_h[n * DIM + i];
    __syncthreads();
    if (t < VOCAB) {
        float acc = bout[t];
        for (int k = 0; k < DIM; k++) acc += xs[k] * Wout[k * VOCAB + t];
        out[n * VOCAB + t] = acc;
    }
}

// ---------------- host ----------------
extern "C" void kernel_launch(void* const* d_in, const int* in_sizes, int n_in,
                              void* d_out, int out_size) {
    const float* methy = (const float*)d_in[0];
    const int* chromo = (const int*)d_in[1];
    const int* pos    = (const int*)d_in[2];
    const float* mt = (const float*)d_in[3];
    const float* ct = (const float*)d_in[4];
    const float* pt = (const float*)d_in[5];
    const float* ln1g = (const float*)d_in[6];
    const float* ln1b = (const float*)d_in[7];
    const float* ln2g = (const float*)d_in[8];
    const float* ln2b = (const float*)d_in[9];
    const float* Wq = (const float*)d_in[10];
    const float* Wk = (const float*)d_in[11];
    const float* Wv = (const float*)d_in[12];
    const float* Wo = (const float*)d_in[13];
    const float* bo = (const float*)d_in[14];
    const float* W1 = (const float*)d_in[15];
    const float* b1 = (const float*)d_in[16];
    const float* W2 = (const float*)d_in[17];
    const float* b2 = (const float*)d_in[18];
    const float* proj = (const float*)d_in[19];
    const float* nfg = (const float*)d_in[20];
    const float* nfb = (const float*)d_in[21];
    const float* Wout = (const float*)d_in[22];
    const float* bout = (const float*)d_in[23];
    float* out = (float*)d_out;

    float *px, *ph, *pq, *pk, *pv;
    __half *phh, *pattnh, *pffh, *pwh;
    cudaGetSymbolAddress((void**)&px, g_x);
    cudaGetSymbolAddress((void**)&ph, g_h);
    cudaGetSymbolAddress((void**)&phh, g_hh);
    cudaGetSymbolAddress((void**)&pq, g_q);
    cudaGetSymbolAddress((void**)&pk, g_k);
    cudaGetSymbolAddress((void**)&pv, g_v);
    cudaGetSymbolAddress((void**)&pattnh, g_attnh);
    cudaGetSymbolAddress((void**)&pffh, g_ffh);
    cudaGetSymbolAddress((void**)&pwh, g_wh);

    const int GEMMH_SMEM = HSTAGES * 2 * HAELE * 2;                  // 110,592
    cudaFuncSetAttribute(tgemm_h, cudaFuncAttributeMaxDynamicSharedMemorySize, GEMMH_SMEM);

    wconv_kernel<<<dim3(96, 96, 36), 256>>>(Wq, Wk, Wv, Wo, W1, W2);
    embed_kernel<<<NTOK, 256>>>(methy, chromo, pos, mt, ct, pt);

    dim3 gqkv(DIM / 128, NTOK / 128, 3);
    dim3 gsk3(DIM / 128, NTOK / 128, 3);
    dim3 gff(FF / 128, NTOK / 128, 1);
    dim3 gfeat(2, 32, HEADS * 2);
    dim3 gctx(HEADS, 2, 8);
    dim3 gattn(HEADS, NTOK / 128);

    for (int l = 0; l < DEPTH; l++) {
        const float* pj = proj + (size_t)l * MF * DH;
        const __half* wl = pwh + (size_t)l * LOFF;
        // --- attention ---
        ln_kernel<<<NTOK, 256>>>(px, ln1g + l * DIM, ln1b + l * DIM, ph, phh);
        tgemm_h<<<gqkv, 256, GEMMH_SMEM>>>(phh,
            wl + WOQ, wl + WOK, wl + WOV,
            nullptr, pq, pk, pv, DIM, DIM, 0, 1, 0);
        featgemm_kernel<<<gfeat, 256>>>(pj);
        ctxgemm_kernel<<<gctx, 256>>>(methy);
        reduce_kernel<<<192, 256>>>();
        attngemm_kernel<<<gattn, 256>>>();
        tgemm_h<<<gsk3, 256, GEMMH_SMEM>>>(pattnh,
            wl + WOO, nullptr, nullptr,
            bo + l * DIM, px, nullptr, nullptr, DIM, DIM, 0, 3, 0);
        // --- FFN ---
        ln_kernel<<<NTOK, 256>>>(px, ln2g + l * DIM, ln2b + l * DIM, ph, phh);
        tgemm_h<<<gff, 256, GEMMH_SMEM>>>(phh,
            wl + WO1, nullptr, nullptr,
            b1 + l * FF, (float*)pffh, nullptr, nullptr, FF, DIM, 1, 1, 1);
        tgemm_h<<<gsk3, 256, GEMMH_SMEM>>>(pffh,
            wl + WO2, nullptr, nullptr,
            b2 + l * DIM, px, nullptr, nullptr, DIM, FF, 0, 3, 0);
    }

    ln_kernel<<<NTOK, 256>>>(px, nfg, nfb, ph, phh);
    wout_kernel<<<NTOK, 128>>>(Wout, bout, out);
}

// round 13
// speedup vs baseline: 6.8742x; 1.1719x over previous
#include <cuda_runtime.h>
#include <cuda_fp16.h>
#include <math.h>
#include <stdint.h>

#define NTOK 4096
#define DIM 768
#define DEPTH 6
#define HEADS 12
#define DH 64
#define FF 3072
#define MF 256
#define VOCAB 102
#define DNORM 0.35355339059327373f   /* 64^-0.25 */
#define RATIO 0.0625f                /* 256^-0.5 */
#define L2E 1.4426950408889634f

// per-layer half-weight offsets (in halves)
#define LOFF 7077888
#define WOQ 0
#define WOK 589824
#define WOV 1179648
#define WOO 1769472
#define WO1 2359296
#define WO2 4718592

// ---------------- scratch (device globals, no allocation) ----------------
__device__ float g_x[NTOK * DIM];
__device__ float g_h[NTOK * DIM];
__device__ __align__(16) __half g_hh[NTOK * DIM];
__device__ float g_q[NTOK * DIM];
__device__ float g_k[NTOK * DIM];
__device__ float g_v[NTOK * DIM];
__device__ __align__(16) __half g_attnh[NTOK * DIM];
__device__ __align__(16) __half g_ffh[NTOK * FF];
__device__ __align__(16) __half g_wh[(size_t)DEPTH * LOFF];
__device__ float g_qf[HEADS * NTOK * MF];     // raw xd
__device__ float g_kf[HEADS * NTOK * MF];     // raw xd
__device__ float g_diagq[HEADS * NTOK];
__device__ float g_diagk[HEADS * NTOK];
__device__ float g_maxq2[2 * HEADS * NTOK];
__device__ float g_maxk2[HEADS * 64];
__device__ float g_ksum[HEADS * MF];
__device__ float g_ctx[HEADS * MF * DH];
__device__ float g_ctxp[8 * HEADS * MF * DH];
__device__ float g_ksump[8 * HEADS * MF];

// ---------------- helpers ----------------
__device__ __forceinline__ float tanh_fast(float x) {
    float r;
    asm("tanh.approx.f32 %0, %1;" : "=f"(r) : "f"(x));
    return r;
}

__device__ __forceinline__ float ex2f(float y) {
    float r;
    asm("ex2.approx.f32 %0, %1;" : "=f"(r) : "f"(y));
    return r;
}

__device__ __forceinline__ float gelu_tanh(float u) {
    return 0.5f * u * (1.0f + tanh_fast(0.7978845608028654f * (u + 0.044715f * u * u * u)));
}

__device__ __forceinline__ uint32_t to_tf32u(float x) {
    float r;
    asm("cvt.rna.tf32.f32 %0, %1;" : "=f"(r) : "f"(x));
    return __float_as_uint(r);
}

__device__ __forceinline__ void mma8(float* c, const uint32_t* a, const uint32_t* b) {
    asm volatile(
        "mma.sync.aligned.m16n8k8.row.col.f32.tf32.tf32.f32 "
        "{%0,%1,%2,%3}, {%4,%5,%6,%7}, {%8,%9}, {%0,%1,%2,%3};"
        : "+f"(c[0]), "+f"(c[1]), "+f"(c[2]), "+f"(c[3])
        : "r"(a[0]), "r"(a[1]), "r"(a[2]), "r"(a[3]), "r"(b[0]), "r"(b[1]));
}

__device__ __forceinline__ void mma16(float* c, const uint32_t* a, const uint32_t* b) {
    asm volatile(
        "mma.sync.aligned.m16n8k16.row.col.f32.f16.f16.f32 "
        "{%0,%1,%2,%3}, {%4,%5,%6,%7}, {%8,%9}, {%0,%1,%2,%3};"
        : "+f"(c[0]), "+f"(c[1]), "+f"(c[2]), "+f"(c[3])
        : "r"(a[0]), "r"(a[1]), "r"(a[2]), "r"(a[3]), "r"(b[0]), "r"(b[1]));
}

__device__ __forceinline__ void ldsm4(uint32_t* r, uint32_t addr) {
    asm volatile("ldmatrix.sync.aligned.m8n8.x4.shared.b16 {%0,%1,%2,%3}, [%4];"
        : "=r"(r[0]), "=r"(r[1]), "=r"(r[2]), "=r"(r[3]) : "r"(addr));
}

__device__ __forceinline__ void cp_async16(uint32_t dst, const void* src) {
    asm volatile("cp.async.cg.shared.global [%0], [%1], 16;" :: "r"(dst), "l"(src));
}
__device__ __forceinline__ void cp_commit() { asm volatile("cp.async.commit_group;"); }
__device__ __forceinline__ void cp_wait1() { asm volatile("cp.async.wait_group 1;"); }
__device__ __forceinline__ void cp_wait0() { asm volatile("cp.async.wait_group 0;"); }

// ---------------- weight convert + transpose helpers ----------------------
__device__ __forceinline__ void wtile_transpose(const float* src, __half* dst,
                                                int K, int N, int k0, int n0) {
    __shared__ float tile[32][33];
    int tx = threadIdx.x & 31, ty = threadIdx.x >> 5;   // 32x8
    #pragma unroll
    for (int i = 0; i < 4; i++)
        tile[ty + i * 8][tx] = src[(size_t)(k0 + ty + i * 8) * N + n0 + tx];
    __syncthreads();
    #pragma unroll
    for (int i = 0; i < 4; i++)
        dst[(size_t)(n0 + ty + i * 8) * K + k0 + tx] = __float2half(tile[tx][ty + i * 8]);
}

// square 768x768 mats: Q,K,V,Wo. grid (24,24, DEPTH*4)
__global__ __launch_bounds__(256) void wconv_sq(const float* __restrict__ Wq,
                                                const float* __restrict__ Wk,
                                                const float* __restrict__ Wv,
                                                const float* __restrict__ Wo) {
    int zz = blockIdx.z, l = zz >> 2, mat = zz & 3;
    const float* srcs[4] = {Wq, Wk, Wv, Wo};
    const size_t offs[4] = {WOQ, WOK, WOV, WOO};
    wtile_transpose(srcs[mat] + (size_t)l * DIM * DIM,
                    g_wh + (size_t)l * LOFF + offs[mat],
                    DIM, DIM, blockIdx.y * 32, blockIdx.x * 32);
}

// FF mats: W1 [768,3072], W2 [3072,768]. grid (2304, DEPTH, 2)
__global__ __launch_bounds__(256) void wconv_ff(const float* __restrict__ W1,
                                                const float* __restrict__ W2) {
    int l = blockIdx.y, mat = blockIdx.z, f = blockIdx.x;
    int K, N, n0, k0;
    size_t off;
    const float* src;
    if (mat == 0) { K = DIM; N = FF;  n0 = (f % 96) * 32; k0 = (f / 96) * 32; off = WO1; src = W1; }
    else          { K = FF;  N = DIM; n0 = (f % 24) * 32; k0 = (f / 24) * 32; off = WO2; src = W2; }
    wtile_transpose(src + (size_t)l * K * N,
                    g_wh + (size_t)l * LOFF + off, K, N, k0, n0);
}

// ---------------- embedding + bucketize ----------------
__global__ void embed_kernel(const float* __restrict__ methy,
                             const int* __restrict__ chromo,
                             const int* __restrict__ pos,
                             const float* __restrict__ mt,
                             const float* __restrict__ ct,
                             const float* __restrict__ pt) {
    int n = blockIdx.x;
    float x = methy[n];
    int idx = (x > -2.0f) + (x > -1.0f);
    #pragma unroll 4
    for (int i = 0; i < 100; i++) idx += ((float)i * 0.01f < x) ? 1 : 0;
    int c = chromo[n], p = pos[n];
    const float* mrow = mt + (size_t)idx * DIM;
    const float* prow = pt + (size_t)p * DIM;
    const float* crow = ct + (size_t)c * DIM;
    for (int d = threadIdx.x; d < DIM; d += blockDim.x)
        g_x[n * DIM + d] = mrow[d] + prow[d] + crow[d];
}

// ---------------- layernorm (writes fp32 + half) ----------------
__global__ __launch_bounds__(256) void ln_kernel(const float* __restrict__ in,
                                                 const float* __restrict__ g,
                                                 const float* __restrict__ b,
                                                 float* __restrict__ out,
                                                 __half* __restrict__ outh) {
    int n = blockIdx.x, t = threadIdx.x;
    __shared__ float red[256];
    float v[3];
    float s = 0.f;
    #pragma unroll
    for (int i = 0; i < 3; i++) { v[i] = in[n * DIM + t + i * 256]; s += v[i]; }
    red[t] = s; __syncthreads();
    for (int off = 128; off > 0; off >>= 1) { if (t < off) red[t] += red[t + off]; __syncthreads(); }
    float mu = red[0] * (1.0f / DIM);
    __syncthreads();
    float s2 = 0.f;
    #pragma unroll
    for (int i = 0; i < 3; i++) { float d = v[i] - mu; s2 += d * d; }
    red[t] = s2; __syncthreads();
    for (int off = 128; off > 0; off >>= 1) { if (t < off) red[t] += red[t + off]; __syncthreads(); }
    float rstd = rsqrtf(red[0] * (1.0f / DIM) + 1e-5f);
    #pragma unroll
    for (int i = 0; i < 3; i++) {
        int d = t + i * 256;
        float o = (v[i] - mu) * rstd * g[d] + b[d];
        out[n * DIM + d] = o;
        outh[n * DIM + d] = __float2half(o);
    }
}

// ---------------- FP16 GEMM 128x128x64h, cp.async 3-stage, ldmatrix -------
#define BKH 64
#define SAH 72            /* halves stride; 36 words */
#define HAELE (128 * SAH)
#define HSTAGES 3

__global__ __launch_bounds__(256, 2) void tgemm_h(const __half* __restrict__ A,
                                                  const __half* __restrict__ B0,
                                                  const __half* __restrict__ B1,
                                                  const __half* __restrict__ B2,
                                                  const float* __restrict__ bias,
                                                  float* __restrict__ C0,
                                                  float* __restrict__ C1,
                                                  float* __restrict__ C2,
                                                  int Nn, int Kk, int act, int splitk,
                                                  int outhalf) {
    extern __shared__ __half hsm[];
    int z = blockIdx.z;
    const __half* B = B0;
    float* C = C0;
    int koff = 0, Keff = Kk;
    if (splitk > 1) {
        Keff = Kk / splitk;
        koff = z * Keff;
    } else {
        B = (z == 0) ? B0 : ((z == 1) ? B1 : B2);
        C = (z == 0) ? C0 : ((z == 1) ? C1 : C2);
    }

    int t = threadIdx.x;
    int rb = blockIdx.y * 128, cb = blockIdx.x * 128;
    int lane = t & 31, wid = t >> 5;
    int warp_m = (wid & 1) * 64, warp_n = (wid >> 1) * 32;
    int q = lane & 3, g = lane >> 2;

    int tr = t >> 3;
    int tc = (t & 7) * 8;

    const __half* Abase = A + (size_t)(rb + tr) * Kk + koff + tc;
    const __half* Bbase = B + (size_t)(cb + tr) * Kk + koff + tc;

    uint32_t smA = (uint32_t)__cvta_generic_to_shared(hsm);
    uint32_t smB = smA + HSTAGES * HAELE * 2;
    uint32_t adst = smA + (uint32_t)((tr * SAH + tc) * 2);
    uint32_t bdst = smB + (uint32_t)((tr * SAH + tc) * 2);

    uint32_t aoff[4], boff[2];
    {
        int r = (lane & 7) + ((lane >> 3) & 1) * 8;
        int kh = (lane >> 4) * 8;
        #pragma unroll
        for (int mt = 0; mt < 4; mt++)
            aoff[mt] = (uint32_t)(((warp_m + mt * 16 + r) * SAH + kh) * 2);
        int rn = lane & 7;
        int khb = ((lane >> 3) & 1) * 8;
        int pb = lane >> 4;
        #pragma unroll
        for (int p = 0; p < 2; p++)
            boff[p] = (uint32_t)(((warp_n + (p * 2 + pb) * 8 + rn) * SAH + khb) * 2);
    }

    int niter = Keff / BKH;

    #pragma unroll
    for (int s = 0; s < 2; s++) {
        if (s < niter) {
            size_t k0 = (size_t)s * BKH;
            #pragma unroll
            for (int i = 0; i < 4; i++)
                cp_async16(adst + (uint32_t)(s * HAELE * 2 + i * 32 * SAH * 2),
                           Abase + (size_t)(32 * i) * Kk + k0);
            #pragma unroll
            for (int i = 0; i < 4; i++)
                cp_async16(bdst + (uint32_t)(s * HAELE * 2 + i * 32 * SAH * 2),
                           Bbase + (size_t)(32 * i) * Kk + k0);
        }
        cp_commit();
    }

    float acc[4][4][4];
    #pragma unroll
    for (int mt = 0; mt < 4; mt++)
        #pragma unroll
        for (int nt = 0; nt < 4; nt++)
            #pragma unroll
            for (int e = 0; e < 4; e++) acc[mt][nt][e] = 0.f;

    for (int it = 0; it < niter; it++) {
        if (it + 1 < niter) cp_wait1(); else cp_wait0();
        __syncthreads();
        if (it + 2 < niter) {
            int s = (it + 2) % HSTAGES;
            size_t k0 = (size_t)(it + 2) * BKH;
            #pragma unroll
            for (int i = 0; i < 4; i++)
                cp_async16(adst + (uint32_t)(s * HAELE * 2 + i * 32 * SAH * 2),
                           Abase + (size_t)(32 * i) * Kk + k0);
            #pragma unroll
            for (int i = 0; i < 4; i++)
                cp_async16(bdst + (uint32_t)(s * HAELE * 2 + i * 32 * SAH * 2),
                           Bbase + (size_t)(32 * i) * Kk + k0);
        }
        cp_commit();

        uint32_t sa = smA + (uint32_t)((it % HSTAGES) * HAELE * 2);
        uint32_t sb = smB + (uint32_t)((it % HSTAGES) * HAELE * 2);
        #pragma unroll
        for (int ks = 0; ks < 4; ks++) {
            uint32_t kbyte = (uint32_t)(ks * 32);
            uint32_t af[4][4], bfr[2][4];
            #pragma unroll
            for (int mt = 0; mt < 4; mt++) ldsm4(af[mt], sa + aoff[mt] + kbyte);
            #pragma unroll
            for (int p = 0; p < 2; p++) ldsm4(bfr[p], sb + boff[p] + kbyte);
            #pragma unroll
            for (int mt = 0; mt < 4; mt++)
                #pragma unroll
                for (int nt = 0; nt < 4; nt++)
                    mma16(acc[mt][nt], af[mt], &bfr[nt >> 1][(nt & 1) * 2]);
        }
    }
    __syncthreads();

    // epilogue
    if (splitk > 1) {
        #pragma unroll
        for (int mt = 0; mt < 4; mt++)
            #pragma unroll
            for (int nt = 0; nt < 4; nt++)
                #pragma unroll
                for (int e = 0; e < 4; e++) {
                    int row = rb + warp_m + mt * 16 + g + (e >> 1) * 8;
                    int col = cb + warp_n + nt * 8 + q * 2 + (e & 1);
                    float val = acc[mt][nt][e];
                    if (bias && z == 0) val += bias[col];
                    atomicAdd(&C[(size_t)row * Nn + col], val);
                }
    } else {
        #pragma unroll
        for (int mt = 0; mt < 4; mt++)
            #pragma unroll
            for (int nt = 0; nt < 4; nt++)
                #pragma unroll
                for (int eh = 0; eh < 2; eh++) {
                    int row = rb + warp_m + mt * 16 + g + eh * 8;
                    int col = cb + warp_n + nt * 8 + q * 2;
                    float v0 = acc[mt][nt][eh * 2];
                    float v1 = acc[mt][nt][eh * 2 + 1];
                    if (bias) { v0 += bias[col]; v1 += bias[col + 1]; }
                    if (act) { v0 = gelu_tanh(v0); v1 = gelu_tanh(v1); }
                    if (outhalf)
                        *(__half2*)&((__half*)C)[(size_t)row * Nn + col] = __floats2half2_rn(v0, v1);
                    else
                        *(float2*)&C[(size_t)row * Nn + col] = make_float2(v0, v1);
                }
    }
}

// ---------------- feature GEMM fp16 ----------------
#define FSH 72
__global__ __launch_bounds__(256, 2) void featgemm_kernel(const float* __restrict__ proj) {
    __shared__ __half As[128 * FSH];
    __shared__ __half Bs[128 * FSH];
    __shared__ float diagacc[128];
    __shared__ float wred[8];
    __shared__ float redq[4][128];
    int hk = blockIdx.z, h = hk >> 1, isK = hk & 1;
    const float* X = isK ? g_k : g_q;
    float* dst = isK ? g_kf : g_qf;
    int n0 = blockIdx.y * 128, m0 = blockIdx.x * 128;
    int t = threadIdx.x, lane = t & 31, wid = t >> 5;
    int warp_m = (wid & 1) * 64, warp_n = (wid >> 1) * 32;
    int q = lane & 3, g = lane >> 2;
    bool dodiag = (blockIdx.x == 0);

    if (t < 128) diagacc[t] = 0.f;
    __syncthreads();

    #pragma unroll
    for (int j = 0; j < 8; j++) {
        int i = t + j * 256;
        int row = i >> 4, c = (i & 15) * 4;
        float4 v = *(const float4*)&X[(size_t)(n0 + row) * DIM + h * DH + c];
        *(__half2*)&As[row * FSH + c] = __floats2half2_rn(v.x, v.y);
        *(__half2*)&As[row * FSH + c + 2] = __floats2half2_rn(v.z, v.w);
        if (dodiag)
            atomicAdd(&diagacc[row], v.x * v.x + v.y * v.y + v.z * v.z + v.w * v.w);
    }
    #pragma unroll
    for (int j = 0; j < 8; j++) {
        int i = t + j * 256;
        int m = i >> 4, d = (i & 15) * 4;
        float4 v = *(const float4*)&proj[(size_t)(m0 + m) * DH + d];
        *(__half2*)&Bs[m * FSH + d] = __floats2half2_rn(v.x * DNORM, v.y * DNORM);
        *(__half2*)&Bs[m * FSH + d + 2] = __floats2half2_rn(v.z * DNORM, v.w * DNORM);
    }
    __syncthreads();

    float acc[4][4][4];
    #pragma unroll
    for (int mt = 0; mt < 4; mt++)
        #pragma unroll
        for (int nt = 0; nt < 4; nt++)
            #pragma unroll
            for (int e = 0; e < 4; e++) acc[mt][nt][e] = 0.f;

    const uint32_t* asw = (const uint32_t*)As;
    const uint32_t* bsw = (const uint32_t*)Bs;
    #pragma unroll
    for (int ks = 0; ks < 4; ks++) {
        int k0w = ks * 8;
        uint32_t af[4][4], bf[4][2];
        #pragma unroll
        for (int mt = 0; mt < 4; mt++) {
            int m = warp_m + mt * 16 + g;
            af[mt][0] = asw[m * 36 + k0w + q];
            af[mt][1] = asw[(m + 8) * 36 + k0w + q];
            af[mt][2] = asw[m * 36 + k0w + q + 4];
            af[mt][3] = asw[(m + 8) * 36 + k0w + q + 4];
        }
        #pragma unroll
        for (int nt = 0; nt < 4; nt++) {
            int n = warp_n + nt * 8 + g;
            bf[nt][0] = bsw[n * 36 + k0w + q];
            bf[nt][1] = bsw[n * 36 + k0w + q + 4];
        }
        #pragma unroll
        for (int mt = 0; mt < 4; mt++)
            #pragma unroll
            for (int nt = 0; nt < 4; nt++)
                mma16(acc[mt][nt], af[mt], bf[nt]);
    }

    if (dodiag && t < 128) {
        float* dg = isK ? g_diagk : g_diagq;
        dg[h * NTOK + n0 + t] = 0.5f * (DNORM * DNORM) * diagacc[t];
    }

    #pragma unroll
    for (int mt = 0; mt < 4; mt++)
        #pragma unroll
        for (int nt = 0; nt < 4; nt++)
            #pragma unroll
            for (int e = 0; e < 4; e++) {
                int row = warp_m + mt * 16 + g + (e >> 1) * 8;
                int col = warp_n + nt * 8 + q * 2 + (e & 1);
                dst[((size_t)h * NTOK + n0 + row) * MF + m0 + col] = acc[mt][nt][e];
            }

    if (!isK) {
        #pragma unroll
        for (int mt = 0; mt < 4; mt++)
            #pragma unroll
            for (int eh = 0; eh < 2; eh++) {
                float v = -1e30f;
                #pragma unroll
                for (int nt = 0; nt < 4; nt++) {
                    v = fmaxf(v, acc[mt][nt][eh * 2]);
                    v = fmaxf(v, acc[mt][nt][eh * 2 + 1]);
                }
                v = fmaxf(v, __shfl_xor_sync(0xffffffffu, v, 1));
                v = fmaxf(v, __shfl_xor_sync(0xffffffffu, v, 2));
                if (q == 0)
                    redq[wid >> 1][warp_m + mt * 16 + g + eh * 8] = v;
            }
        __syncthreads();
        if (t < 128) {
            float v = fmaxf(fmaxf(redq[0][t], redq[1][t]), fmaxf(redq[2][t], redq[3][t]));
            g_maxq2[(size_t)blockIdx.x * HEADS * NTOK + h * NTOK + n0 + t] = v;
        }
    } else {
        float v = -1e30f;
        #pragma unroll
        for (int mt = 0; mt < 4; mt++)
            #pragma unroll
            for (int nt = 0; nt < 4; nt++)
                #pragma unroll
                for (int e = 0; e < 4; e++) v = fmaxf(v, acc[mt][nt][e]);
        for (int off = 16; off; off >>= 1) v = fmaxf(v, __shfl_xor_sync(0xffffffffu, v, off));
        if (lane == 0) wred[wid] = v;
        __syncthreads();
        if (t == 0) {
            float mx = wred[0];
            #pragma unroll
            for (int w = 1; w < 8; w++) mx = fmaxf(mx, wred[w]);
            g_maxk2[h * 64 + blockIdx.y * 2 + blockIdx.x] = mx;
        }
    }
}

// ---------------- ctx GEMM (tf32, partials, fast exp) ----------------
#define CSA 136
#define CSB 72
__global__ __launch_bounds__(256) void ctxgemm_kernel(const float* __restrict__ methy) {
    __shared__ float As[32 * CSA];
    __shared__ float Bs[32 * CSB];
    __shared__ float mkred[64];
    int h = blockIdx.x, m0 = blockIdx.y * 128, zs = blockIdx.z;
    int nbase = zs * 512;
    int t = threadIdx.x, lane = t & 31, wid = t >> 5;
    int warp_m = (wid & 3) * 32, warp_n = (wid >> 2) * 32;
    int q = lane & 3, g = lane >> 2;

    if (t < 64) mkred[t] = g_maxk2[h * 64 + t];
    __syncthreads();
    float mk = mkred[0];
    #pragma unroll
    for (int i = 1; i < 64; i++) mk = fmaxf(mk, mkred[i]);

    int sr = t >> 3;
    int sc = (t & 7) * 4;

    float acc[2][4][4];
    #pragma unroll
    for (int mt = 0; mt < 2; mt++)
        #pragma unroll
        for (int nt = 0; nt < 4; nt++)
            #pragma unroll
            for (int e = 0; e < 4; e++) acc[mt][nt][e] = 0.f;
    float ksacc[16];
    #pragma unroll
    for (int i = 0; i < 16; i++) ksacc[i] = 0.f;

    for (int c = 0; c < 512; c += 32) {
        int n = nbase + c + sr;
        float cc = (g_diagk[h * NTOK + n] + mk) * L2E;
        float msk = (methy[n] != 0.0f) ? RATIO : 0.0f;
        const float* src = &g_kf[((size_t)h * NTOK + n) * MF + m0];
        #pragma unroll
        for (int j = 0; j < 4; j++) {
            int col = sc + 32 * j;
            float4 v = *(const float4*)&src[col];
            float4 w;
            w.x = (ex2f(fmaf(v.x, L2E, -cc)) + 1e-4f) * msk;
            w.y = (ex2f(fmaf(v.y, L2E, -cc)) + 1e-4f) * msk;
            w.z = (ex2f(fmaf(v.z, L2E, -cc)) + 1e-4f) * msk;
            w.w = (ex2f(fmaf(v.w, L2E, -cc)) + 1e-4f) * msk;
            *(float4*)&As[sr * CSA + col] = w;
            ksacc[j * 4 + 0] += w.x; ksacc[j * 4 + 1] += w.y;
            ksacc[j * 4 + 2] += w.z; ksacc[j * 4 + 3] += w.w;
        }
        #pragma unroll
        for (int j = 0; j < 2; j++) {
            int fi = t * 2 + j;
            int row = fi >> 4, col = (fi & 15) * 4;
            *(float4*)&Bs[row * CSB + col] =
                *(const float4*)&g_v[(size_t)(nbase + c + row) * DIM + h * DH + col];
        }
        __syncthreads();
        #pragma unroll
        for (int kk = 0; kk < 4; kk++) {
            int k = kk * 8;
            uint32_t af[2][4], bf[4][2];
            #pragma unroll
            for (int mt = 0; mt < 2; mt++) {
                int m = warp_m + mt * 16 + g;
                af[mt][0] = to_tf32u(As[(k + q) * CSA + m]);
                af[mt][1] = to_tf32u(As[(k + q) * CSA + m + 8]);
                af[mt][2] = to_tf32u(As[(k + 4 + q) * CSA + m]);
                af[mt][3] = to_tf32u(As[(k + 4 + q) * CSA + m + 8]);
            }
            #pragma unroll
            for (int nt = 0; nt < 4; nt++) {
                int n2 = warp_n + nt * 8 + g;
                bf[nt][0] = to_tf32u(Bs[(k + q) * CSB + n2]);
                bf[nt][1] = to_tf32u(Bs[(k + 4 + q) * CSB + n2]);
            }
            #pragma unroll
            for (int mt = 0; mt < 2; mt++)
                #pragma unroll
                for (int nt = 0; nt < 4; nt++)
                    mma8(acc[mt][nt], af[mt], bf[nt]);
        }
        __syncthreads();
    }

    #pragma unroll
    for (int j = 0; j < 4; j++) {
        int col = sc + 32 * j;
        *(float4*)&As[sr * CSA + col] = make_float4(ksacc[j*4], ksacc[j*4+1], ksacc[j*4+2], ksacc[j*4+3]);
    }
    __syncthreads();
    if (t < 128) {
        float s = 0.f;
        #pragma unroll
        for (int r = 0; r < 32; r++) s += As[r * CSA + t];
        g_ksump[((size_t)zs * HEADS + h) * MF + m0 + t] = s;
    }
    float* ctxp = &g_ctxp[((size_t)zs * HEADS + h) * MF * DH];
    #pragma unroll
    for (int mt = 0; mt < 2; mt++)
        #pragma unroll
        for (int nt = 0; nt < 4; nt++)
            #pragma unroll
            for (int e = 0; e < 4; e++) {
                int m = m0 + warp_m + mt * 16 + g + (e >> 1) * 8;
                int d = warp_n + nt * 8 + q * 2 + (e & 1);
                ctxp[(size_t)m * DH + d] = acc[mt][nt][e];
            }
}

// ---------------- reduce partials ----------------
__global__ __launch_bounds__(256) void reduce_kernel() {
    int i = blockIdx.x * 256 + threadIdx.x;
    int nt = gridDim.x * 256;
    for (int j = i; j < HEADS * MF * DH; j += nt) {
        float s = 0.f;
        #pragma unroll
        for (int z = 0; z < 8; z++) s += g_ctxp[(size_t)z * HEADS * MF * DH + j];
        g_ctx[j] = s;
    }
    for (int j = i; j < HEADS * MF; j += nt) {
        float s = 0.f;
        #pragma unroll
        for (int z = 0; z < 8; z++) s += g_ksump[(size_t)z * HEADS * MF + j];
        g_ksum[j] = s;
    }
}

// ---------------- attn GEMM (tf32, fast exp), half output -----------------
__global__ __launch_bounds__(256) void attngemm_kernel() {
    __shared__ float As[128 * 36];
    __shared__ float Bs[32 * CSB];
    __shared__ float ksums[MF];
    __shared__ float dens[128];
    int h = blockIdx.x, n0 = blockIdx.y * 128;
    int t = threadIdx.x, lane = t & 31, wid = t >> 5;
    int warp_m = (wid & 3) * 32, warp_n = (wid >> 2) * 32;
    int q = lane & 3, g = lane >> 2;

    ksums[t] = g_ksum[h * MF + t];
    __syncthreads();

    int sr = t >> 1;
    int n = n0 + sr;
    float mq = fmaxf(g_maxq2[h * NTOK + n], g_maxq2[(size_t)HEADS * NTOK + h * NTOK + n]);
    float cc = (g_diagq[h * NTOK + n] + mq) * L2E;
    float denp = 0.f;

    float acc[2][4][4];
    #pragma unroll
    for (int mt = 0; mt < 2; mt++)
        #pragma unroll
        for (int nt = 0; nt < 4; nt++)
            #pragma unroll
            for (int e = 0; e < 4; e++) acc[mt][nt][e] = 0.f;

    for (int c = 0; c < 256; c += 32) {
        const float* src = &g_qf[((size_t)h * NTOK + n) * MF + c];
        #pragma unroll
        for (int j = 0; j < 4; j++) {
            int col = ((t & 1) * 4 + j) * 4;
            float4 v = *(const float4*)&src[col];
            float4 w;
            w.x = RATIO * (ex2f(fmaf(v.x, L2E, -cc)) + 1e-4f);
            w.y = RATIO * (ex2f(fmaf(v.y, L2E, -cc)) + 1e-4f);
            w.z = RATIO * (ex2f(fmaf(v.z, L2E, -cc)) + 1e-4f);
            w.w = RATIO * (ex2f(fmaf(v.w, L2E, -cc)) + 1e-4f);
            *(float4*)&As[sr * 36 + col] = w;
            denp += w.x * ksums[c + col] + w.y * ksums[c + col + 1]
                  + w.z * ksums[c + col + 2] + w.w * ksums[c + col + 3];
        }
        #pragma unroll
        for (int j = 0; j < 2; j++) {
            int fi = t * 2 + j;
            int row = fi >> 4, col = (fi & 15) * 4;
            *(float4*)&Bs[row * CSB + col] =
                *(const float4*)&g_ctx[(size_t)h * MF * DH + (size_t)(c + row) * DH + col];
        }
        __syncthreads();
        #pragma unroll
        for (int kk = 0; kk < 4; kk++) {
            int k = kk * 8;
            uint32_t af[2][4], bf[4][2];
            #pragma unroll
            for (int mt = 0; mt < 2; mt++) {
                int m = warp_m + mt * 16 + g;
                af[mt][0] = to_tf32u(As[m * 36 + k + q]);
                af[mt][1] = to_tf32u(As[(m + 8) * 36 + k + q]);
                af[mt][2] = to_tf32u(As[m * 36 + k + q + 4]);
                af[mt][3] = to_tf32u(As[(m + 8) * 36 + k + q + 4]);
            }
            #pragma unroll
            for (int nt = 0; nt < 4; nt++) {
                int n2 = warp_n + nt * 8 + g;
                bf[nt][0] = to_tf32u(Bs[(k + q) * CSB + n2]);
                bf[nt][1] = to_tf32u(Bs[(k + 4 + q) * CSB + n2]);
            }
            #pragma unroll
            for (int mt = 0; mt < 2; mt++)
                #pragma unroll
                for (int nt = 0; nt < 4; nt++)
                    mma8(acc[mt][nt], af[mt], bf[nt]);
        }
        __syncthreads();
    }

    denp += __shfl_xor_sync(0xffffffffu, denp, 1);
    if ((t & 1) == 0) dens[sr] = denp;
    __syncthreads();

    #pragma unroll
    for (int mt = 0; mt < 2; mt++)
        #pragma unroll
        for (int nt = 0; nt < 4; nt++)
            #pragma unroll
            for (int e = 0; e < 4; e++) {
                int row = warp_m + mt * 16 + g + (e >> 1) * 8;
                int d = warp_n + nt * 8 + q * 2 + (e & 1);
                g_attnh[(size_t)(n0 + row) * DIM + h * DH + d] =
                    __float2half(acc[mt][nt][e] / dens[row]);
            }
}

// ---------------- output head ----------------
__global__ __launch_bounds__(128) void wout_kernel(const float* __restrict__ Wout,
                                                   const float* __restrict__ bout,
                                                   float* __restrict__ out) {
    int n = blockIdx.x, t = threadIdx.x;
    __shared__ float xs[DIM];
    for (int i = t; i < DIM; i += 128) xs[i] = g_h[n * DIM + i];
    __syncthreads();
    if (t < VOCAB) {
        float acc = bout[t];
        for (int k = 0; k < DIM; k++) acc += xs[k] * Wout[k * VOCAB + t];
        out[n * VOCAB + t] = acc;
    }
}

// ---------------- host ----------------
extern "C" void kernel_launch(void* const* d_in, const int* in_sizes, int n_in,
                              void* d_out, int out_size) {
    const float* methy = (const float*)d_in[0];
    const int* chromo = (const int*)d_in[1];
    const int* pos    = (const int*)d_in[2];
    const float* mt = (const float*)d_in[3];
    const float* ct = (const float*)d_in[4];
    const float* pt = (const float*)d_in[5];
    const float* ln1g = (const float*)d_in[6];
    const float* ln1b = (const float*)d_in[7];
    const float* ln2g = (const float*)d_in[8];
    const float* ln2b = (const float*)d_in[9];
    const float* Wq = (const float*)d_in[10];
    const float* Wk = (const float*)d_in[11];
    const float* Wv = (const float*)d_in[12];
    const float* Wo = (const float*)d_in[13];
    const float* bo = (const float*)d_in[14];
    const float* W1 = (const float*)d_in[15];
    const float* b1 = (const float*)d_in[16];
    const float* W2 = (const float*)d_in[17];
    const float* b2 = (const float*)d_in[18];
    const float* proj = (const float*)d_in[19];
    const float* nfg = (const float*)d_in[20];
    const float* nfb = (const float*)d_in[21];
    const float* Wout = (const float*)d_in[22];
    const float* bout = (const float*)d_in[23];
    float* out = (float*)d_out;

    float *px, *ph, *pq, *pk, *pv;
    __half *phh, *pattnh, *pffh, *pwh;
    cudaGetSymbolAddress((void**)&px, g_x);
    cudaGetSymbolAddress((void**)&ph, g_h);
    cudaGetSymbolAddress((void**)&phh, g_hh);
    cudaGetSymbolAddress((void**)&pq, g_q);
    cudaGetSymbolAddress((void**)&pk, g_k);
    cudaGetSymbolAddress((void**)&pv, g_v);
    cudaGetSymbolAddress((void**)&pattnh, g_attnh);
    cudaGetSymbolAddress((void**)&pffh, g_ffh);
    cudaGetSymbolAddress((void**)&pwh, g_wh);

    const int GEMMH_SMEM = HSTAGES * 2 * HAELE * 2;                  // 110,592
    cudaFuncSetAttribute(tgemm_h, cudaFuncAttributeMaxDynamicSharedMemorySize, GEMMH_SMEM);

    wconv_sq<<<dim3(24, 24, DEPTH * 4), 256>>>(Wq, Wk, Wv, Wo);
    wconv_ff<<<dim3(2304, DEPTH, 2), 256>>>(W1, W2);
    embed_kernel<<<NTOK, 256>>>(methy, chromo, pos, mt, ct, pt);

    dim3 gqkv(DIM / 128, NTOK / 128, 3);
    dim3 gsk3(DIM / 128, NTOK / 128, 3);
    dim3 gff(FF / 128, NTOK / 128, 1);
    dim3 gfeat(2, 32, HEADS * 2);
    dim3 gctx(HEADS, 2, 8);
    dim3 gattn(HEADS, NTOK / 128);

    for (int l = 0; l < DEPTH; l++) {
        const float* pj = proj + (size_t)l * MF * DH;
        const __half* wl = pwh + (size_t)l * LOFF;
        // --- attention ---
        ln_kernel<<<NTOK, 256>>>(px, ln1g + l * DIM, ln1b + l * DIM, ph, phh);
        tgemm_h<<<gqkv, 256, GEMMH_SMEM>>>(phh,
            wl + WOQ, wl + WOK, wl + WOV,
            nullptr, pq, pk, pv, DIM, DIM, 0, 1, 0);
        featgemm_kernel<<<gfeat, 256>>>(pj);
        ctxgemm_kernel<<<gctx, 256>>>(methy);
        reduce_kernel<<<192, 256>>>();
        attngemm_kernel<<<gattn, 256>>>();
        tgemm_h<<<gsk3, 256, GEMMH_SMEM>>>(pattnh,
            wl + WOO, nullptr, nullptr,
            bo + l * DIM, px, nullptr, nullptr, DIM, DIM, 0, 3, 0);
        // --- FFN ---
        ln_kernel<<<NTOK, 256>>>(px, ln2g + l * DIM, ln2b + l * DIM, ph, phh);
        tgemm_h<<<gff, 256, GEMMH_SMEM>>>(phh,
            wl + WO1, nullptr, nullptr,
            b1 + l * FF, (float*)pffh, nullptr, nullptr, FF, DIM, 1, 1, 1);
        tgemm_h<<<gsk3, 256, GEMMH_SMEM>>>(pffh,
            wl + WO2, nullptr, nullptr,
            b2 + l * DIM, px, nullptr, nullptr, DIM, FF, 0, 3, 0);
    }

    ln_kernel<<<NTOK, 256>>>(px, nfg, nfb, ph, phh);
    wout_kernel<<<NTOK, 128>>>(Wout, bout, out);
}

// round 14
// speedup vs baseline: 7.0496x; 1.0255x over previous
#include <cuda_runtime.h>
#include <cuda_fp16.h>
#include <math.h>
#include <stdint.h>

#define NTOK 4096
#define DIM 768
#define DEPTH 6
#define HEADS 12
#define DH 64
#define FF 3072
#define MF 256
#define VOCAB 102
#define DNORM 0.35355339059327373f   /* 64^-0.25 */
#define RATIO 0.0625f                /* 256^-0.5 */
#define L2E 1.4426950408889634f

// per-layer half-weight offsets (in halves)
#define LOFF 7077888
#define WOQ 0
#define WOK 589824
#define WOV 1179648
#define WOO 1769472
#define WO1 2359296
#define WO2 4718592

// ---------------- scratch (device globals, no allocation) ----------------
__device__ float g_x[NTOK * DIM];
__device__ float g_h[NTOK * DIM];
__device__ __align__(16) __half g_hh[NTOK * DIM];
__device__ float g_q[NTOK * DIM];
__device__ float g_k[NTOK * DIM];
__device__ float g_v[NTOK * DIM];
__device__ __align__(16) __half g_attnh[NTOK * DIM];
__device__ __align__(16) __half g_ffh[NTOK * FF];
__device__ __align__(16) __half g_wh[(size_t)DEPTH * LOFF];
__device__ float g_qf[HEADS * NTOK * MF];     // raw xd
__device__ float g_kf[HEADS * NTOK * MF];     // raw xd
__device__ float g_diagq[HEADS * NTOK];
__device__ float g_diagk[HEADS * NTOK];
__device__ float g_maxq2[2 * HEADS * NTOK];
__device__ float g_maxk2[HEADS * 64];
__device__ float g_ksum[HEADS * MF];
__device__ float g_ctx[HEADS * MF * DH];
__device__ float g_ctxp[8 * HEADS * MF * DH];
__device__ float g_ksump[8 * HEADS * MF];

// ---------------- helpers ----------------
__device__ __forceinline__ float tanh_fast(float x) {
    float r;
    asm("tanh.approx.f32 %0, %1;" : "=f"(r) : "f"(x));
    return r;
}

__device__ __forceinline__ float ex2f(float y) {
    float r;
    asm("ex2.approx.f32 %0, %1;" : "=f"(r) : "f"(y));
    return r;
}

__device__ __forceinline__ float gelu_tanh(float u) {
    return 0.5f * u * (1.0f + tanh_fast(0.7978845608028654f * (u + 0.044715f * u * u * u)));
}

__device__ __forceinline__ uint32_t to_tf32u(float x) {
    float r;
    asm("cvt.rna.tf32.f32 %0, %1;" : "=f"(r) : "f"(x));
    return __float_as_uint(r);
}

__device__ __forceinline__ void mma8(float* c, const uint32_t* a, const uint32_t* b) {
    asm volatile(
        "mma.sync.aligned.m16n8k8.row.col.f32.tf32.tf32.f32 "
        "{%0,%1,%2,%3}, {%4,%5,%6,%7}, {%8,%9}, {%0,%1,%2,%3};"
        : "+f"(c[0]), "+f"(c[1]), "+f"(c[2]), "+f"(c[3])
        : "r"(a[0]), "r"(a[1]), "r"(a[2]), "r"(a[3]), "r"(b[0]), "r"(b[1]));
}

__device__ __forceinline__ void mma16(float* c, const uint32_t* a, const uint32_t* b) {
    asm volatile(
        "mma.sync.aligned.m16n8k16.row.col.f32.f16.f16.f32 "
        "{%0,%1,%2,%3}, {%4,%5,%6,%7}, {%8,%9}, {%0,%1,%2,%3};"
        : "+f"(c[0]), "+f"(c[1]), "+f"(c[2]), "+f"(c[3])
        : "r"(a[0]), "r"(a[1]), "r"(a[2]), "r"(a[3]), "r"(b[0]), "r"(b[1]));
}

__device__ __forceinline__ void ldsm4(uint32_t* r, uint32_t addr) {
    asm volatile("ldmatrix.sync.aligned.m8n8.x4.shared.b16 {%0,%1,%2,%3}, [%4];"
        : "=r"(r[0]), "=r"(r[1]), "=r"(r[2]), "=r"(r[3]) : "r"(addr));
}

__device__ __forceinline__ void cp_async16(uint32_t dst, const void* src) {
    asm volatile("cp.async.cg.shared.global [%0], [%1], 16;" :: "r"(dst), "l"(src));
}
__device__ __forceinline__ void cp_commit() { asm volatile("cp.async.commit_group;"); }
__device__ __forceinline__ void cp_wait1() { asm volatile("cp.async.wait_group 1;"); }
__device__ __forceinline__ void cp_wait0() { asm volatile("cp.async.wait_group 0;"); }

// ---------------- weight convert + transpose helpers ----------------------
__device__ __forceinline__ void wtile_transpose(const float* src, __half* dst,
                                                int K, int N, int k0, int n0) {
    __shared__ float tile[32][33];
    int tx = threadIdx.x & 31, ty = threadIdx.x >> 5;   // 32x8
    #pragma unroll
    for (int i = 0; i < 4; i++)
        tile[ty + i * 8][tx] = src[(size_t)(k0 + ty + i * 8) * N + n0 + tx];
    __syncthreads();
    #pragma unroll
    for (int i = 0; i < 4; i++)
        dst[(size_t)(n0 + ty + i * 8) * K + k0 + tx] = __float2half(tile[tx][ty + i * 8]);
}

__global__ __launch_bounds__(256) void wconv_sq(const float* __restrict__ Wq,
                                                const float* __restrict__ Wk,
                                                const float* __restrict__ Wv,
                                                const float* __restrict__ Wo) {
    int zz = blockIdx.z, l = zz >> 2, mat = zz & 3;
    const float* srcs[4] = {Wq, Wk, Wv, Wo};
    const size_t offs[4] = {WOQ, WOK, WOV, WOO};
    wtile_transpose(srcs[mat] + (size_t)l * DIM * DIM,
                    g_wh + (size_t)l * LOFF + offs[mat],
                    DIM, DIM, blockIdx.y * 32, blockIdx.x * 32);
}

__global__ __launch_bounds__(256) void wconv_ff(const float* __restrict__ W1,
                                                const float* __restrict__ W2) {
    int l = blockIdx.y, mat = blockIdx.z, f = blockIdx.x;
    int K, N, n0, k0;
    size_t off;
    const float* src;
    if (mat == 0) { K = DIM; N = FF;  n0 = (f % 96) * 32; k0 = (f / 96) * 32; off = WO1; src = W1; }
    else          { K = FF;  N = DIM; n0 = (f % 24) * 32; k0 = (f / 24) * 32; off = WO2; src = W2; }
    wtile_transpose(src + (size_t)l * K * N,
                    g_wh + (size_t)l * LOFF + off, K, N, k0, n0);
}

// ---------------- embedding + bucketize ----------------
__global__ void embed_kernel(const float* __restrict__ methy,
                             const int* __restrict__ chromo,
                             const int* __restrict__ pos,
                             const float* __restrict__ mt,
                             const float* __restrict__ ct,
                             const float* __restrict__ pt) {
    int n = blockIdx.x;
    float x = methy[n];
    int idx = (x > -2.0f) + (x > -1.0f);
    #pragma unroll 4
    for (int i = 0; i < 100; i++) idx += ((float)i * 0.01f < x) ? 1 : 0;
    int c = chromo[n], p = pos[n];
    const float* mrow = mt + (size_t)idx * DIM;
    const float* prow = pt + (size_t)p * DIM;
    const float* crow = ct + (size_t)c * DIM;
    for (int d = threadIdx.x; d < DIM; d += blockDim.x)
        g_x[n * DIM + d] = mrow[d] + prow[d] + crow[d];
}

// ---------------- layernorm: 192 thr, float4, shfl reductions -------------
__global__ __launch_bounds__(192) void ln_kernel(const float* __restrict__ in,
                                                 const float* __restrict__ g,
                                                 const float* __restrict__ b,
                                                 float* __restrict__ out,
                                                 __half* __restrict__ outh) {
    int n = blockIdx.x, t = threadIdx.x;
    int lane = t & 31, wid = t >> 5;
    __shared__ float ws[6], ws2[6];
    float4 v = *(const float4*)&in[(size_t)n * DIM + t * 4];
    float s = v.x + v.y + v.z + v.w;
    for (int off = 16; off; off >>= 1) s += __shfl_xor_sync(0xffffffffu, s, off);
    if (lane == 0) ws[wid] = s;
    __syncthreads();
    float mu = (ws[0] + ws[1] + ws[2] + ws[3] + ws[4] + ws[5]) * (1.0f / DIM);
    float dx = v.x - mu, dy = v.y - mu, dz = v.z - mu, dw = v.w - mu;
    float s2 = dx * dx + dy * dy + dz * dz + dw * dw;
    for (int off = 16; off; off >>= 1) s2 += __shfl_xor_sync(0xffffffffu, s2, off);
    if (lane == 0) ws2[wid] = s2;
    __syncthreads();
    float rstd = rsqrtf((ws2[0] + ws2[1] + ws2[2] + ws2[3] + ws2[4] + ws2[5]) * (1.0f / DIM) + 1e-5f);
    float4 gg = *(const float4*)&g[t * 4];
    float4 bb = *(const float4*)&b[t * 4];
    float4 o;
    o.x = dx * rstd * gg.x + bb.x;
    o.y = dy * rstd * gg.y + bb.y;
    o.z = dz * rstd * gg.z + bb.z;
    o.w = dw * rstd * gg.w + bb.w;
    *(float4*)&out[(size_t)n * DIM + t * 4] = o;
    __half2 h0 = __floats2half2_rn(o.x, o.y);
    __half2 h1 = __floats2half2_rn(o.z, o.w);
    *(__half2*)&outh[(size_t)n * DIM + t * 4] = h0;
    *(__half2*)&outh[(size_t)n * DIM + t * 4 + 2] = h1;
}

// ---------------- FP16 GEMM 128x128x64h, cp.async 3-stage, ldmatrix -------
#define BKH 64
#define SAH 72
#define HAELE (128 * SAH)
#define HSTAGES 3

__global__ __launch_bounds__(256, 2) void tgemm_h(const __half* __restrict__ A,
                                                  const __half* __restrict__ B0,
                                                  const __half* __restrict__ B1,
                                                  const __half* __restrict__ B2,
                                                  const float* __restrict__ bias,
                                                  float* __restrict__ C0,
                                                  float* __restrict__ C1,
                                                  float* __restrict__ C2,
                                                  int Nn, int Kk, int act, int splitk,
                                                  int outhalf) {
    extern __shared__ __half hsm[];
    int z = blockIdx.z;
    const __half* B = B0;
    float* C = C0;
    int koff = 0, Keff = Kk;
    if (splitk > 1) {
        Keff = Kk / splitk;
        koff = z * Keff;
    } else {
        B = (z == 0) ? B0 : ((z == 1) ? B1 : B2);
        C = (z == 0) ? C0 : ((z == 1) ? C1 : C2);
    }

    int t = threadIdx.x;
    int rb = blockIdx.y * 128, cb = blockIdx.x * 128;
    int lane = t & 31, wid = t >> 5;
    int warp_m = (wid & 1) * 64, warp_n = (wid >> 1) * 32;
    int q = lane & 3, g = lane >> 2;

    int tr = t >> 3;
    int tc = (t & 7) * 8;

    const __half* Abase = A + (size_t)(rb + tr) * Kk + koff + tc;
    const __half* Bbase = B + (size_t)(cb + tr) * Kk + koff + tc;

    uint32_t smA = (uint32_t)__cvta_generic_to_shared(hsm);
    uint32_t smB = smA + HSTAGES * HAELE * 2;
    uint32_t adst = smA + (uint32_t)((tr * SAH + tc) * 2);
    uint32_t bdst = smB + (uint32_t)((tr * SAH + tc) * 2);

    uint32_t aoff[4], boff[2];
    {
        int r = (lane & 7) + ((lane >> 3) & 1) * 8;
        int kh = (lane >> 4) * 8;
        #pragma unroll
        for (int mt = 0; mt < 4; mt++)
            aoff[mt] = (uint32_t)(((warp_m + mt * 16 + r) * SAH + kh) * 2);
        int rn = lane & 7;
        int khb = ((lane >> 3) & 1) * 8;
        int pb = lane >> 4;
        #pragma unroll
        for (int p = 0; p < 2; p++)
            boff[p] = (uint32_t)(((warp_n + (p * 2 + pb) * 8 + rn) * SAH + khb) * 2);
    }

    int niter = Keff / BKH;

    #pragma unroll
    for (int s = 0; s < 2; s++) {
        if (s < niter) {
            size_t k0 = (size_t)s * BKH;
            #pragma unroll
            for (int i = 0; i < 4; i++)
                cp_async16(adst + (uint32_t)(s * HAELE * 2 + i * 32 * SAH * 2),
                           Abase + (size_t)(32 * i) * Kk + k0);
            #pragma unroll
            for (int i = 0; i < 4; i++)
                cp_async16(bdst + (uint32_t)(s * HAELE * 2 + i * 32 * SAH * 2),
                           Bbase + (size_t)(32 * i) * Kk + k0);
        }
        cp_commit();
    }

    float acc[4][4][4];
    #pragma unroll
    for (int mt = 0; mt < 4; mt++)
        #pragma unroll
        for (int nt = 0; nt < 4; nt++)
            #pragma unroll
            for (int e = 0; e < 4; e++) acc[mt][nt][e] = 0.f;

    for (int it = 0; it < niter; it++) {
        if (it + 1 < niter) cp_wait1(); else cp_wait0();
        __syncthreads();
        if (it + 2 < niter) {
            int s = (it + 2) % HSTAGES;
            size_t k0 = (size_t)(it + 2) * BKH;
            #pragma unroll
            for (int i = 0; i < 4; i++)
                cp_async16(adst + (uint32_t)(s * HAELE * 2 + i * 32 * SAH * 2),
                           Abase + (size_t)(32 * i) * Kk + k0);
            #pragma unroll
            for (int i = 0; i < 4; i++)
                cp_async16(bdst + (uint32_t)(s * HAELE * 2 + i * 32 * SAH * 2),
                           Bbase + (size_t)(32 * i) * Kk + k0);
        }
        cp_commit();

        uint32_t sa = smA + (uint32_t)((it % HSTAGES) * HAELE * 2);
        uint32_t sb = smB + (uint32_t)((it % HSTAGES) * HAELE * 2);
        #pragma unroll
        for (int ks = 0; ks < 4; ks++) {
            uint32_t kbyte = (uint32_t)(ks * 32);
            uint32_t af[4][4], bfr[2][4];
            #pragma unroll
            for (int mt = 0; mt < 4; mt++) ldsm4(af[mt], sa + aoff[mt] + kbyte);
            #pragma unroll
            for (int p = 0; p < 2; p++) ldsm4(bfr[p], sb + boff[p] + kbyte);
            #pragma unroll
            for (int mt = 0; mt < 4; mt++)
                #pragma unroll
                for (int nt = 0; nt < 4; nt++)
                    mma16(acc[mt][nt], af[mt], &bfr[nt >> 1][(nt & 1) * 2]);
        }
    }
    __syncthreads();

    // epilogue
    if (splitk > 1) {
        #pragma unroll
        for (int mt = 0; mt < 4; mt++)
            #pragma unroll
            for (int nt = 0; nt < 4; nt++)
                #pragma unroll
                for (int e = 0; e < 4; e++) {
                    int row = rb + warp_m + mt * 16 + g + (e >> 1) * 8;
                    int col = cb + warp_n + nt * 8 + q * 2 + (e & 1);
                    float val = acc[mt][nt][e];
                    if (bias && z == 0) val += bias[col];
                    atomicAdd(&C[(size_t)row * Nn + col], val);
                }
    } else {
        #pragma unroll
        for (int mt = 0; mt < 4; mt++)
            #pragma unroll
            for (int nt = 0; nt < 4; nt++)
                #pragma unroll
                for (int eh = 0; eh < 2; eh++) {
                    int row = rb + warp_m + mt * 16 + g + eh * 8;
                    int col = cb + warp_n + nt * 8 + q * 2;
                    float v0 = acc[mt][nt][eh * 2];
                    float v1 = acc[mt][nt][eh * 2 + 1];
                    if (bias) { v0 += bias[col]; v1 += bias[col + 1]; }
                    if (act) { v0 = gelu_tanh(v0); v1 = gelu_tanh(v1); }
                    if (outhalf)
                        *(__half2*)&((__half*)C)[(size_t)row * Nn + col] = __floats2half2_rn(v0, v1);
                    else
                        *(float2*)&C[(size_t)row * Nn + col] = make_float2(v0, v1);
                }
    }
}

// ---------------- feature GEMM fp16 ----------------
#define FSH 72
__global__ __launch_bounds__(256, 2) void featgemm_kernel(const float* __restrict__ proj) {
    __shared__ __half As[128 * FSH];
    __shared__ __half Bs[128 * FSH];
    __shared__ float diagacc[128];
    __shared__ float wred[8];
    __shared__ float redq[4][128];
    int hk = blockIdx.z, h = hk >> 1, isK = hk & 1;
    const float* X = isK ? g_k : g_q;
    float* dst = isK ? g_kf : g_qf;
    int n0 = blockIdx.y * 128, m0 = blockIdx.x * 128;
    int t = threadIdx.x, lane = t & 31, wid = t >> 5;
    int warp_m = (wid & 1) * 64, warp_n = (wid >> 1) * 32;
    int q = lane & 3, g = lane >> 2;
    bool dodiag = (blockIdx.x == 0);

    if (t < 128) diagacc[t] = 0.f;
    __syncthreads();

    #pragma unroll
    for (int j = 0; j < 8; j++) {
        int i = t + j * 256;
        int row = i >> 4, c = (i & 15) * 4;
        float4 v = *(const float4*)&X[(size_t)(n0 + row) * DIM + h * DH + c];
        *(__half2*)&As[row * FSH + c] = __floats2half2_rn(v.x, v.y);
        *(__half2*)&As[row * FSH + c + 2] = __floats2half2_rn(v.z, v.w);
        if (dodiag)
            atomicAdd(&diagacc[row], v.x * v.x + v.y * v.y + v.z * v.z + v.w * v.w);
    }
    #pragma unroll
    for (int j = 0; j < 8; j++) {
        int i = t + j * 256;
        int m = i >> 4, d = (i & 15) * 4;
        float4 v = *(const float4*)&proj[(size_t)(m0 + m) * DH + d];
        *(__half2*)&Bs[m * FSH + d] = __floats2half2_rn(v.x * DNORM, v.y * DNORM);
        *(__half2*)&Bs[m * FSH + d + 2] = __floats2half2_rn(v.z * DNORM, v.w * DNORM);
    }
    __syncthreads();

    float acc[4][4][4];
    #pragma unroll
    for (int mt = 0; mt < 4; mt++)
        #pragma unroll
        for (int nt = 0; nt < 4; nt++)
            #pragma unroll
            for (int e = 0; e < 4; e++) acc[mt][nt][e] = 0.f;

    const uint32_t* asw = (const uint32_t*)As;
    const uint32_t* bsw = (const uint32_t*)Bs;
    #pragma unroll
    for (int ks = 0; ks < 4; ks++) {
        int k0w = ks * 8;
        uint32_t af[4][4], bf[4][2];
        #pragma unroll
        for (int mt = 0; mt < 4; mt++) {
            int m = warp_m + mt * 16 + g;
            af[mt][0] = asw[m * 36 + k0w + q];
            af[mt][1] = asw[(m + 8) * 36 + k0w + q];
            af[mt][2] = asw[m * 36 + k0w + q + 4];
            af[mt][3] = asw[(m + 8) * 36 + k0w + q + 4];
        }
        #pragma unroll
        for (int nt = 0; nt < 4; nt++) {
            int n = warp_n + nt * 8 + g;
            bf[nt][0] = bsw[n * 36 + k0w + q];
            bf[nt][1] = bsw[n * 36 + k0w + q + 4];
        }
        #pragma unroll
        for (int mt = 0; mt < 4; mt++)
            #pragma unroll
            for (int nt = 0; nt < 4; nt++)
                mma16(acc[mt][nt], af[mt], bf[nt]);
    }

    if (dodiag && t < 128) {
        float* dg = isK ? g_diagk : g_diagq;
        dg[h * NTOK + n0 + t] = 0.5f * (DNORM * DNORM) * diagacc[t];
    }

    #pragma unroll
    for (int mt = 0; mt < 4; mt++)
        #pragma unroll
        for (int nt = 0; nt < 4; nt++)
            #pragma unroll
            for (int e = 0; e < 4; e++) {
                int row = warp_m + mt * 16 + g + (e >> 1) * 8;
                int col = warp_n + nt * 8 + q * 2 + (e & 1);
                dst[((size_t)h * NTOK + n0 + row) * MF + m0 + col] = acc[mt][nt][e];
            }

    if (!isK) {
        #pragma unroll
        for (int mt = 0; mt < 4; mt++)
            #pragma unroll
            for (int eh = 0; eh < 2; eh++) {
                float v = -1e30f;
                #pragma unroll
                for (int nt = 0; nt < 4; nt++) {
                    v = fmaxf(v, acc[mt][nt][eh * 2]);
                    v = fmaxf(v, acc[mt][nt][eh * 2 + 1]);
                }
                v = fmaxf(v, __shfl_xor_sync(0xffffffffu, v, 1));
                v = fmaxf(v, __shfl_xor_sync(0xffffffffu, v, 2));
                if (q == 0)
                    redq[wid >> 1][warp_m + mt * 16 + g + eh * 8] = v;
            }
        __syncthreads();
        if (t < 128) {
            float v = fmaxf(fmaxf(redq[0][t], redq[1][t]), fmaxf(redq[2][t], redq[3][t]));
            g_maxq2[(size_t)blockIdx.x * HEADS * NTOK + h * NTOK + n0 + t] = v;
        }
    } else {
        float v = -1e30f;
        #pragma unroll
        for (int mt = 0; mt < 4; mt++)
            #pragma unroll
            for (int nt = 0; nt < 4; nt++)
                #pragma unroll
                for (int e = 0; e < 4; e++) v = fmaxf(v, acc[mt][nt][e]);
        for (int off = 16; off; off >>= 1) v = fmaxf(v, __shfl_xor_sync(0xffffffffu, v, off));
        if (lane == 0) wred[wid] = v;
        __syncthreads();
        if (t == 0) {
            float mx = wred[0];
            #pragma unroll
            for (int w = 1; w < 8; w++) mx = fmaxf(mx, wred[w]);
            g_maxk2[h * 64 + blockIdx.y * 2 + blockIdx.x] = mx;
        }
    }
}

// ---------------- ctx GEMM (tf32, partials, fast exp) ----------------
#define CSA 136
#define CSB 72
__global__ __launch_bounds__(256) void ctxgemm_kernel(const float* __restrict__ methy) {
    __shared__ float As[32 * CSA];
    __shared__ float Bs[32 * CSB];
    __shared__ float mkred[64];
    int h = blockIdx.x, m0 = blockIdx.y * 128, zs = blockIdx.z;
    int nbase = zs * 512;
    int t = threadIdx.x, lane = t & 31, wid = t >> 5;
    int warp_m = (wid & 3) * 32, warp_n = (wid >> 2) * 32;
    int q = lane & 3, g = lane >> 2;

    if (t < 64) mkred[t] = g_maxk2[h * 64 + t];
    __syncthreads();
    float mk = mkred[0];
    #pragma unroll
    for (int i = 1; i < 64; i++) mk = fmaxf(mk, mkred[i]);

    int sr = t >> 3;
    int sc = (t & 7) * 4;

    float acc[2][4][4];
    #pragma unroll
    for (int mt = 0; mt < 2; mt++)
        #pragma unroll
        for (int nt = 0; nt < 4; nt++)
            #pragma unroll
            for (int e = 0; e < 4; e++) acc[mt][nt][e] = 0.f;
    float ksacc[16];
    #pragma unroll
    for (int i = 0; i < 16; i++) ksacc[i] = 0.f;

    for (int c = 0; c < 512; c += 32) {
        int n = nbase + c + sr;
        float cc = (g_diagk[h * NTOK + n] + mk) * L2E;
        float msk = (methy[n] != 0.0f) ? RATIO : 0.0f;
        const float* src = &g_kf[((size_t)h * NTOK + n) * MF + m0];
        #pragma unroll
        for (int j = 0; j < 4; j++) {
            int col = sc + 32 * j;
            float4 v = *(const float4*)&src[col];
            float4 w;
            w.x = (ex2f(fmaf(v.x, L2E, -cc)) + 1e-4f) * msk;
            w.y = (ex2f(fmaf(v.y, L2E, -cc)) + 1e-4f) * msk;
            w.z = (ex2f(fmaf(v.z, L2E, -cc)) + 1e-4f) * msk;
            w.w = (ex2f(fmaf(v.w, L2E, -cc)) + 1e-4f) * msk;
            *(float4*)&As[sr * CSA + col] = w;
            ksacc[j * 4 + 0] += w.x; ksacc[j * 4 + 1] += w.y;
            ksacc[j * 4 + 2] += w.z; ksacc[j * 4 + 3] += w.w;
        }
        #pragma unroll
        for (int j = 0; j < 2; j++) {
            int fi = t * 2 + j;
            int row = fi >> 4, col = (fi & 15) * 4;
            *(float4*)&Bs[row * CSB + col] =
                *(const float4*)&g_v[(size_t)(nbase + c + row) * DIM + h * DH + col];
        }
        __syncthreads();
        #pragma unroll
        for (int kk = 0; kk < 4; kk++) {
            int k = kk * 8;
            uint32_t af[2][4], bf[4][2];
            #pragma unroll
            for (int mt = 0; mt < 2; mt++) {
                int m = warp_m + mt * 16 + g;
                af[mt][0] = to_tf32u(As[(k + q) * CSA + m]);
                af[mt][1] = to_tf32u(As[(k + q) * CSA + m + 8]);
                af[mt][2] = to_tf32u(As[(k + 4 + q) * CSA + m]);
                af[mt][3] = to_tf32u(As[(k + 4 + q) * CSA + m + 8]);
            }
            #pragma unroll
            for (int nt = 0; nt < 4; nt++) {
                int n2 = warp_n + nt * 8 + g;
                bf[nt][0] = to_tf32u(Bs[(k + q) * CSB + n2]);
                bf[nt][1] = to_tf32u(Bs[(k + 4 + q) * CSB + n2]);
            }
            #pragma unroll
            for (int mt = 0; mt < 2; mt++)
                #pragma unroll
                for (int nt = 0; nt < 4; nt++)
                    mma8(acc[mt][nt], af[mt], bf[nt]);
        }
        __syncthreads();
    }

    #pragma unroll
    for (int j = 0; j < 4; j++) {
        int col = sc + 32 * j;
        *(float4*)&As[sr * CSA + col] = make_float4(ksacc[j*4], ksacc[j*4+1], ksacc[j*4+2], ksacc[j*4+3]);
    }
    __syncthreads();
    if (t < 128) {
        float s = 0.f;
        #pragma unroll
        for (int r = 0; r < 32; r++) s += As[r * CSA + t];
        g_ksump[((size_t)zs * HEADS + h) * MF + m0 + t] = s;
    }
    float* ctxp = &g_ctxp[((size_t)zs * HEADS + h) * MF * DH];
    #pragma unroll
    for (int mt = 0; mt < 2; mt++)
        #pragma unroll
        for (int nt = 0; nt < 4; nt++)
            #pragma unroll
            for (int e = 0; e < 4; e++) {
                int m = m0 + warp_m + mt * 16 + g + (e >> 1) * 8;
                int d = warp_n + nt * 8 + q * 2 + (e & 1);
                ctxp[(size_t)m * DH + d] = acc[mt][nt][e];
            }
}

// ---------------- reduce partials ----------------
__global__ __launch_bounds__(256) void reduce_kernel() {
    int i = blockIdx.x * 256 + threadIdx.x;
    int nt = gridDim.x * 256;
    for (int j = i; j < HEADS * MF * DH; j += nt) {
        float s = 0.f;
        #pragma unroll
        for (int z = 0; z < 8; z++) s += g_ctxp[(size_t)z * HEADS * MF * DH + j];
        g_ctx[j] = s;
    }
    for (int j = i; j < HEADS * MF; j += nt) {
        float s = 0.f;
        #pragma unroll
        for (int z = 0; z < 8; z++) s += g_ksump[(size_t)z * HEADS * MF + j];
        g_ksum[j] = s;
    }
}

// ---------------- attn GEMM fp16: o = (qf @ ctx)/den, half output ---------
#define ATS 40   /* halves stride = 20 words */
__global__ __launch_bounds__(256) void attngemm_kernel() {
    __shared__ __half As[128 * ATS];
    __shared__ __half Bs[64 * ATS];
    __shared__ float ksums[MF];
    __shared__ float dens[128];
    int h = blockIdx.x, n0 = blockIdx.y * 128;
    int t = threadIdx.x, lane = t & 31, wid = t >> 5;
    int warp_m = (wid & 3) * 32, warp_n = (wid >> 2) * 32;
    int q = lane & 3, g = lane >> 2;

    ksums[t] = g_ksum[h * MF + t];
    __syncthreads();

    int sr = t >> 1;
    int n = n0 + sr;
    float mq = fmaxf(g_maxq2[h * NTOK + n], g_maxq2[(size_t)HEADS * NTOK + h * NTOK + n]);
    float cc = (g_diagq[h * NTOK + n] + mq) * L2E;
    float denp = 0.f;

    float acc[2][4][4];
    #pragma unroll
    for (int mt = 0; mt < 2; mt++)
        #pragma unroll
        for (int nt = 0; nt < 4; nt++)
            #pragma unroll
            for (int e = 0; e < 4; e++) acc[mt][nt][e] = 0.f;

    for (int c = 0; c < 256; c += 32) {
        const float* src = &g_qf[((size_t)h * NTOK + n) * MF + c];
        #pragma unroll
        for (int j = 0; j < 4; j++) {
            int col = ((t & 1) * 4 + j) * 4;
            float4 v = *(const float4*)&src[col];
            float4 w;
            w.x = RATIO * (ex2f(fmaf(v.x, L2E, -cc)) + 1e-4f);
            w.y = RATIO * (ex2f(fmaf(v.y, L2E, -cc)) + 1e-4f);
            w.z = RATIO * (ex2f(fmaf(v.z, L2E, -cc)) + 1e-4f);
            w.w = RATIO * (ex2f(fmaf(v.w, L2E, -cc)) + 1e-4f);
            *(__half2*)&As[sr * ATS + col] = __floats2half2_rn(w.x, w.y);
            *(__half2*)&As[sr * ATS + col + 2] = __floats2half2_rn(w.z, w.w);
            denp += w.x * ksums[c + col] + w.y * ksums[c + col + 1]
                  + w.z * ksums[c + col + 2] + w.w * ksums[c + col + 3];
        }
        // Bs: ctx [m=c+row][d] -> transposed half [d][k=row]
        #pragma unroll
        for (int j = 0; j < 2; j++) {
            int fi = t * 2 + j;
            int row = fi >> 4, col4 = (fi & 15) * 4;
            float4 v = *(const float4*)&g_ctx[(size_t)h * MF * DH + (size_t)(c + row) * DH + col4];
            Bs[(col4 + 0) * ATS + row] = __float2half(v.x);
            Bs[(col4 + 1) * ATS + row] = __float2half(v.y);
            Bs[(col4 + 2) * ATS + row] = __float2half(v.z);
            Bs[(col4 + 3) * ATS + row] = __float2half(v.w);
        }
        __syncthreads();
        const uint32_t* aw = (const uint32_t*)As;
        const uint32_t* bw = (const uint32_t*)Bs;
        #pragma unroll
        for (int ks = 0; ks < 2; ks++) {
            uint32_t af[2][4], bf[4][2];
            #pragma unroll
            for (int mt = 0; mt < 2; mt++) {
                int m = warp_m + mt * 16 + g;
                af[mt][0] = aw[m * 20 + ks * 8 + q];
                af[mt][1] = aw[(m + 8) * 20 + ks * 8 + q];
                af[mt][2] = aw[m * 20 + ks * 8 + q + 4];
                af[mt][3] = aw[(m + 8) * 20 + ks * 8 + q + 4];
            }
            #pragma unroll
            for (int nt = 0; nt < 4; nt++) {
                int d = warp_n + nt * 8 + g;
                bf[nt][0] = bw[d * 20 + ks * 8 + q];
                bf[nt][1] = bw[d * 20 + ks * 8 + q + 4];
            }
            #pragma unroll
            for (int mt = 0; mt < 2; mt++)
                #pragma unroll
                for (int nt = 0; nt < 4; nt++)
                    mma16(acc[mt][nt], af[mt], bf[nt]);
        }
        __syncthreads();
    }

    denp += __shfl_xor_sync(0xffffffffu, denp, 1);
    if ((t & 1) == 0) dens[sr] = denp;
    __syncthreads();

    #pragma unroll
    for (int mt = 0; mt < 2; mt++)
        #pragma unroll
        for (int nt = 0; nt < 4; nt++)
            #pragma unroll
            for (int e = 0; e < 4; e++) {
                int row = warp_m + mt * 16 + g + (e >> 1) * 8;
                int d = warp_n + nt * 8 + q * 2 + (e & 1);
                g_attnh[(size_t)(n0 + row) * DIM + h * DH + d] =
                    __float2half(acc[mt][nt][e] / dens[row]);
            }
}

// ---------------- output head ----------------
__global__ __launch_bounds__(128) void wout_kernel(const float* __restrict__ Wout,
                                                   const float* __restrict__ bout,
                                                   float* __restrict__ out) {
    int n = blockIdx.x, t = threadIdx.x;
    __shared__ float xs[DIM];
    for (int i = t; i < DIM; i += 128) xs[i] = g_h[n * DIM + i];
    __syncthreads();
    if (t < VOCAB) {
        float acc = bout[t];
        for (int k = 0; k < DIM; k++) acc += xs[k] * Wout[k * VOCAB + t];
        out[n * VOCAB + t] = acc;
    }
}

// ---------------- host ----------------
extern "C" void kernel_launch(void* const* d_in, const int* in_sizes, int n_in,
                              void* d_out, int out_size) {
    const float* methy = (const float*)d_in[0];
    const int* chromo = (const int*)d_in[1];
    const int* pos    = (const int*)d_in[2];
    const float* mt = (const float*)d_in[3];
    const float* ct = (const float*)d_in[4];
    const float* pt = (const float*)d_in[5];
    const float* ln1g = (const float*)d_in[6];
    const float* ln1b = (const float*)d_in[7];
    const float* ln2g = (const float*)d_in[8];
    const float* ln2b = (const float*)d_in[9];
    const float* Wq = (const float*)d_in[10];
    const float* Wk = (const float*)d_in[11];
    const float* Wv = (const float*)d_in[12];
    const float* Wo = (const float*)d_in[13];
    const float* bo = (const float*)d_in[14];
    const float* W1 = (const float*)d_in[15];
    const float* b1 = (const float*)d_in[16];
    const float* W2 = (const float*)d_in[17];
    const float* b2 = (const float*)d_in[18];
    const float* proj = (const float*)d_in[19];
    const float* nfg = (const float*)d_in[20];
    const float* nfb = (const float*)d_in[21];
    const float* Wout = (const float*)d_in[22];
    const float* bout = (const float*)d_in[23];
    float* out = (float*)d_out;

    float *px, *ph, *pq, *pk, *pv;
    __half *phh, *pattnh, *pffh, *pwh;
    cudaGetSymbolAddress((void**)&px, g_x);
    cudaGetSymbolAddress((void**)&ph, g_h);
    cudaGetSymbolAddress((void**)&phh, g_hh);
    cudaGetSymbolAddress((void**)&pq, g_q);
    cudaGetSymbolAddress((void**)&pk, g_k);
    cudaGetSymbolAddress((void**)&pv, g_v);
    cudaGetSymbolAddress((void**)&pattnh, g_attnh);
    cudaGetSymbolAddress((void**)&pffh, g_ffh);
    cudaGetSymbolAddress((void**)&pwh, g_wh);

    const int GEMMH_SMEM = HSTAGES * 2 * HAELE * 2;                  // 110,592
    cudaFuncSetAttribute(tgemm_h, cudaFuncAttributeMaxDynamicSharedMemorySize, GEMMH_SMEM);

    wconv_sq<<<dim3(24, 24, DEPTH * 4), 256>>>(Wq, Wk, Wv, Wo);
    wconv_ff<<<dim3(2304, DEPTH, 2), 256>>>(W1, W2);
    embed_kernel<<<NTOK, 256>>>(methy, chromo, pos, mt, ct, pt);

    dim3 gqkv(DIM / 128, NTOK / 128, 3);
    dim3 gsk3(DIM / 128, NTOK / 128, 3);
    dim3 gff(FF / 128, NTOK / 128, 1);
    dim3 gfeat(2, 32, HEADS * 2);
    dim3 gctx(HEADS, 2, 8);
    dim3 gattn(HEADS, NTOK / 128);

    for (int l = 0; l < DEPTH; l++) {
        const float* pj = proj + (size_t)l * MF * DH;
        const __half* wl = pwh + (size_t)l * LOFF;
        // --- attention ---
        ln_kernel<<<NTOK, 192>>>(px, ln1g + l * DIM, ln1b + l * DIM, ph, phh);
        tgemm_h<<<gqkv, 256, GEMMH_SMEM>>>(phh,
            wl + WOQ, wl + WOK, wl + WOV,
            nullptr, pq, pk, pv, DIM, DIM, 0, 1, 0);
        featgemm_kernel<<<gfeat, 256>>>(pj);
        ctxgemm_kernel<<<gctx, 256>>>(methy);
        reduce_kernel<<<192, 256>>>();
        attngemm_kernel<<<gattn, 256>>>();
        tgemm_h<<<gsk3, 256, GEMMH_SMEM>>>(pattnh,
            wl + WOO, nullptr, nullptr,
            bo + l * DIM, px, nullptr, nullptr, DIM, DIM, 0, 3, 0);
        // --- FFN ---
        ln_kernel<<<NTOK, 192>>>(px, ln2g + l * DIM, ln2b + l * DIM, ph, phh);
        tgemm_h<<<gff, 256, GEMMH_SMEM>>>(phh,
            wl + WO1, nullptr, nullptr,
            b1 + l * FF, (float*)pffh, nullptr, nullptr, FF, DIM, 1, 1, 1);
        tgemm_h<<<gsk3, 256, GEMMH_SMEM>>>(pffh,
            wl + WO2, nullptr, nullptr,
            b2 + l * DIM, px, nullptr, nullptr, DIM, FF, 0, 3, 0);
    }

    ln_kernel<<<NTOK, 192>>>(px, nfg, nfb, ph, phh);
    wout_kernel<<<NTOK, 128>>>(Wout, bout, out);
}

// round 15
// speedup vs baseline: 7.0514x; 1.0003x over previous
#include <cuda_runtime.h>
#include <cuda_fp16.h>
#include <math.h>
#include <stdint.h>

#define NTOK 4096
#define DIM 768
#define DEPTH 6
#define HEADS 12
#define DH 64
#define FF 3072
#define MF 256
#define VOCAB 102
#define DNORM 0.35355339059327373f   /* 64^-0.25 */
#define RATIO 0.0625f                /* 256^-0.5 */
#define L2E 1.4426950408889634f
#define NZS 16                        /* ctx n-splits */

// per-layer half-weight offsets (in halves)
#define LOFF 7077888
#define WOQ 0
#define WOK 589824
#define WOV 1179648
#define WOO 1769472
#define WO1 2359296
#define WO2 4718592

// ---------------- scratch (device globals, no allocation) ----------------
__device__ float g_x[NTOK * DIM];
__device__ float g_h[NTOK * DIM];
__device__ __align__(16) __half g_hh[NTOK * DIM];
__device__ float g_q[NTOK * DIM];
__device__ float g_k[NTOK * DIM];
__device__ float g_v[NTOK * DIM];
__device__ __align__(16) __half g_attnh[NTOK * DIM];
__device__ __align__(16) __half g_ffh[NTOK * FF];
__device__ __align__(16) __half g_wh[(size_t)DEPTH * LOFF];
__device__ float g_qf[HEADS * NTOK * MF];     // raw xd
__device__ float g_kf[HEADS * NTOK * MF];     // raw xd
__device__ float g_diagq[HEADS * NTOK];
__device__ float g_diagk[HEADS * NTOK];
__device__ float g_maxq2[2 * HEADS * NTOK];
__device__ float g_maxk2[HEADS * 64];
__device__ float g_ksum[HEADS * MF];
__device__ float g_ctx[HEADS * MF * DH];
__device__ float g_ctxp[NZS * HEADS * MF * DH];
__device__ float g_ksump[NZS * HEADS * MF];

// ---------------- helpers ----------------
__device__ __forceinline__ float tanh_fast(float x) {
    float r;
    asm("tanh.approx.f32 %0, %1;" : "=f"(r) : "f"(x));
    return r;
}

__device__ __forceinline__ float ex2f(float y) {
    float r;
    asm("ex2.approx.f32 %0, %1;" : "=f"(r) : "f"(y));
    return r;
}

__device__ __forceinline__ float gelu_tanh(float u) {
    return 0.5f * u * (1.0f + tanh_fast(0.7978845608028654f * (u + 0.044715f * u * u * u)));
}

__device__ __forceinline__ uint32_t to_tf32u(float x) {
    float r;
    asm("cvt.rna.tf32.f32 %0, %1;" : "=f"(r) : "f"(x));
    return __float_as_uint(r);
}

__device__ __forceinline__ void mma8(float* c, const uint32_t* a, const uint32_t* b) {
    asm volatile(
        "mma.sync.aligned.m16n8k8.row.col.f32.tf32.tf32.f32 "
        "{%0,%1,%2,%3}, {%4,%5,%6,%7}, {%8,%9}, {%0,%1,%2,%3};"
        : "+f"(c[0]), "+f"(c[1]), "+f"(c[2]), "+f"(c[3])
        : "r"(a[0]), "r"(a[1]), "r"(a[2]), "r"(a[3]), "r"(b[0]), "r"(b[1]));
}

__device__ __forceinline__ void mma16(float* c, const uint32_t* a, const uint32_t* b) {
    asm volatile(
        "mma.sync.aligned.m16n8k16.row.col.f32.f16.f16.f32 "
        "{%0,%1,%2,%3}, {%4,%5,%6,%7}, {%8,%9}, {%0,%1,%2,%3};"
        : "+f"(c[0]), "+f"(c[1]), "+f"(c[2]), "+f"(c[3])
        : "r"(a[0]), "r"(a[1]), "r"(a[2]), "r"(a[3]), "r"(b[0]), "r"(b[1]));
}

__device__ __forceinline__ void ldsm4(uint32_t* r, uint32_t addr) {
    asm volatile("ldmatrix.sync.aligned.m8n8.x4.shared.b16 {%0,%1,%2,%3}, [%4];"
        : "=r"(r[0]), "=r"(r[1]), "=r"(r[2]), "=r"(r[3]) : "r"(addr));
}

__device__ __forceinline__ void cp_async16(uint32_t dst, const void* src) {
    asm volatile("cp.async.cg.shared.global [%0], [%1], 16;" :: "r"(dst), "l"(src));
}
__device__ __forceinline__ void cp_commit() { asm volatile("cp.async.commit_group;"); }
__device__ __forceinline__ void cp_wait1() { asm volatile("cp.async.wait_group 1;"); }
__device__ __forceinline__ void cp_wait0() { asm volatile("cp.async.wait_group 0;"); }

// ---------------- weight convert + transpose helpers ----------------------
__device__ __forceinline__ void wtile_transpose(const float* src, __half* dst,
                                                int K, int N, int k0, int n0) {
    __shared__ float tile[32][33];
    int tx = threadIdx.x & 31, ty = threadIdx.x >> 5;   // 32x8
    #pragma unroll
    for (int i = 0; i < 4; i++)
        tile[ty + i * 8][tx] = src[(size_t)(k0 + ty + i * 8) * N + n0 + tx];
    __syncthreads();
    #pragma unroll
    for (int i = 0; i < 4; i++)
        dst[(size_t)(n0 + ty + i * 8) * K + k0 + tx] = __float2half(tile[tx][ty + i * 8]);
}

__global__ __launch_bounds__(256) void wconv_sq(const float* __restrict__ Wq,
                                                const float* __restrict__ Wk,
                                                const float* __restrict__ Wv,
                                                const float* __restrict__ Wo) {
    int zz = blockIdx.z, l = zz >> 2, mat = zz & 3;
    const float* srcs[4] = {Wq, Wk, Wv, Wo};
    const size_t offs[4] = {WOQ, WOK, WOV, WOO};
    wtile_transpose(srcs[mat] + (size_t)l * DIM * DIM,
                    g_wh + (size_t)l * LOFF + offs[mat],
                    DIM, DIM, blockIdx.y * 32, blockIdx.x * 32);
}

__global__ __launch_bounds__(256) void wconv_ff(const float* __restrict__ W1,
                                                const float* __restrict__ W2) {
    int l = blockIdx.y, mat = blockIdx.z, f = blockIdx.x;
    int K, N, n0, k0;
    size_t off;
    const float* src;
    if (mat == 0) { K = DIM; N = FF;  n0 = (f % 96) * 32; k0 = (f / 96) * 32; off = WO1; src = W1; }
    else          { K = FF;  N = DIM; n0 = (f % 24) * 32; k0 = (f / 24) * 32; off = WO2; src = W2; }
    wtile_transpose(src + (size_t)l * K * N,
                    g_wh + (size_t)l * LOFF + off, K, N, k0, n0);
}

// ---------------- embedding + bucketize ----------------
__global__ void embed_kernel(const float* __restrict__ methy,
                             const int* __restrict__ chromo,
                             const int* __restrict__ pos,
                             const float* __restrict__ mt,
                             const float* __restrict__ ct,
                             const float* __restrict__ pt) {
    int n = blockIdx.x;
    float x = methy[n];
    int idx = (x > -2.0f) + (x > -1.0f);
    #pragma unroll 4
    for (int i = 0; i < 100; i++) idx += ((float)i * 0.01f < x) ? 1 : 0;
    int c = chromo[n], p = pos[n];
    const float* mrow = mt + (size_t)idx * DIM;
    const float* prow = pt + (size_t)p * DIM;
    const float* crow = ct + (size_t)c * DIM;
    for (int d = threadIdx.x; d < DIM; d += blockDim.x)
        g_x[n * DIM + d] = mrow[d] + prow[d] + crow[d];
}

// ---------------- layernorm: 192 thr, float4, shfl; fp32 out optional -----
__global__ __launch_bounds__(192) void ln_kernel(const float* __restrict__ in,
                                                 const float* __restrict__ g,
                                                 const float* __restrict__ b,
                                                 float* __restrict__ out,
                                                 __half* __restrict__ outh) {
    int n = blockIdx.x, t = threadIdx.x;
    int lane = t & 31, wid = t >> 5;
    __shared__ float ws[6], ws2[6];
    float4 v = *(const float4*)&in[(size_t)n * DIM + t * 4];
    float s = v.x + v.y + v.z + v.w;
    for (int off = 16; off; off >>= 1) s += __shfl_xor_sync(0xffffffffu, s, off);
    if (lane == 0) ws[wid] = s;
    __syncthreads();
    float mu = (ws[0] + ws[1] + ws[2] + ws[3] + ws[4] + ws[5]) * (1.0f / DIM);
    float dx = v.x - mu, dy = v.y - mu, dz = v.z - mu, dw = v.w - mu;
    float s2 = dx * dx + dy * dy + dz * dz + dw * dw;
    for (int off = 16; off; off >>= 1) s2 += __shfl_xor_sync(0xffffffffu, s2, off);
    if (lane == 0) ws2[wid] = s2;
    __syncthreads();
    float rstd = rsqrtf((ws2[0] + ws2[1] + ws2[2] + ws2[3] + ws2[4] + ws2[5]) * (1.0f / DIM) + 1e-5f);
    float4 gg = *(const float4*)&g[t * 4];
    float4 bb = *(const float4*)&b[t * 4];
    float4 o;
    o.x = dx * rstd * gg.x + bb.x;
    o.y = dy * rstd * gg.y + bb.y;
    o.z = dz * rstd * gg.z + bb.z;
    o.w = dw * rstd * gg.w + bb.w;
    if (out) *(float4*)&out[(size_t)n * DIM + t * 4] = o;
    *(__half2*)&outh[(size_t)n * DIM + t * 4] = __floats2half2_rn(o.x, o.y);
    *(__half2*)&outh[(size_t)n * DIM + t * 4 + 2] = __floats2half2_rn(o.z, o.w);
}

// ---------------- FP16 GEMM 128x128x64h, cp.async 3-stage, ldmatrix -------
#define BKH 64
#define SAH 72
#define HAELE (128 * SAH)
#define HSTAGES 3

__global__ __launch_bounds__(256, 2) void tgemm_h(const __half* __restrict__ A,
                                                  const __half* __restrict__ B0,
                                                  const __half* __restrict__ B1,
                                                  const __half* __restrict__ B2,
                                                  const float* __restrict__ bias,
                                                  float* __restrict__ C0,
                                                  float* __restrict__ C1,
                                                  float* __restrict__ C2,
                                                  int Nn, int Kk, int act, int splitk,
                                                  int outhalf) {
    extern __shared__ __half hsm[];
    int z = blockIdx.z;
    const __half* B = B0;
    float* C = C0;
    int koff = 0, Keff = Kk;
    if (splitk > 1) {
        Keff = Kk / splitk;
        koff = z * Keff;
    } else {
        B = (z == 0) ? B0 : ((z == 1) ? B1 : B2);
        C = (z == 0) ? C0 : ((z == 1) ? C1 : C2);
    }

    int t = threadIdx.x;
    int rb = blockIdx.y * 128, cb = blockIdx.x * 128;
    int lane = t & 31, wid = t >> 5;
    int warp_m = (wid & 1) * 64, warp_n = (wid >> 1) * 32;
    int q = lane & 3, g = lane >> 2;

    int tr = t >> 3;
    int tc = (t & 7) * 8;

    const __half* Abase = A + (size_t)(rb + tr) * Kk + koff + tc;
    const __half* Bbase = B + (size_t)(cb + tr) * Kk + koff + tc;

    uint32_t smA = (uint32_t)__cvta_generic_to_shared(hsm);
    uint32_t smB = smA + HSTAGES * HAELE * 2;
    uint32_t adst = smA + (uint32_t)((tr * SAH + tc) * 2);
    uint32_t bdst = smB + (uint32_t)((tr * SAH + tc) * 2);

    uint32_t aoff[4], boff[2];
    {
        int r = (lane & 7) + ((lane >> 3) & 1) * 8;
        int kh = (lane >> 4) * 8;
        #pragma unroll
        for (int mt = 0; mt < 4; mt++)
            aoff[mt] = (uint32_t)(((warp_m + mt * 16 + r) * SAH + kh) * 2);
        int rn = lane & 7;
        int khb = ((lane >> 3) & 1) * 8;
        int pb = lane >> 4;
        #pragma unroll
        for (int p = 0; p < 2; p++)
            boff[p] = (uint32_t)(((warp_n + (p * 2 + pb) * 8 + rn) * SAH + khb) * 2);
    }

    int niter = Keff / BKH;

    #pragma unroll
    for (int s = 0; s < 2; s++) {
        if (s < niter) {
            size_t k0 = (size_t)s * BKH;
            #pragma unroll
            for (int i = 0; i < 4; i++)
                cp_async16(adst + (uint32_t)(s * HAELE * 2 + i * 32 * SAH * 2),
                           Abase + (size_t)(32 * i) * Kk + k0);
            #pragma unroll
            for (int i = 0; i < 4; i++)
                cp_async16(bdst + (uint32_t)(s * HAELE * 2 + i * 32 * SAH * 2),
                           Bbase + (size_t)(32 * i) * Kk + k0);
        }
        cp_commit();
    }

    float acc[4][4][4];
    #pragma unroll
    for (int mt = 0; mt < 4; mt++)
        #pragma unroll
        for (int nt = 0; nt < 4; nt++)
            #pragma unroll
            for (int e = 0; e < 4; e++) acc[mt][nt][e] = 0.f;

    for (int it = 0; it < niter; it++) {
        if (it + 1 < niter) cp_wait1(); else cp_wait0();
        __syncthreads();
        if (it + 2 < niter) {
            int s = (it + 2) % HSTAGES;
            size_t k0 = (size_t)(it + 2) * BKH;
            #pragma unroll
            for (int i = 0; i < 4; i++)
                cp_async16(adst + (uint32_t)(s * HAELE * 2 + i * 32 * SAH * 2),
                           Abase + (size_t)(32 * i) * Kk + k0);
            #pragma unroll
            for (int i = 0; i < 4; i++)
                cp_async16(bdst + (uint32_t)(s * HAELE * 2 + i * 32 * SAH * 2),
                           Bbase + (size_t)(32 * i) * Kk + k0);
        }
        cp_commit();

        uint32_t sa = smA + (uint32_t)((it % HSTAGES) * HAELE * 2);
        uint32_t sb = smB + (uint32_t)((it % HSTAGES) * HAELE * 2);
        #pragma unroll
        for (int ks = 0; ks < 4; ks++) {
            uint32_t kbyte = (uint32_t)(ks * 32);
            uint32_t af[4][4], bfr[2][4];
            #pragma unroll
            for (int mt = 0; mt < 4; mt++) ldsm4(af[mt], sa + aoff[mt] + kbyte);
            #pragma unroll
            for (int p = 0; p < 2; p++) ldsm4(bfr[p], sb + boff[p] + kbyte);
            #pragma unroll
            for (int mt = 0; mt < 4; mt++)
                #pragma unroll
                for (int nt = 0; nt < 4; nt++)
                    mma16(acc[mt][nt], af[mt], &bfr[nt >> 1][(nt & 1) * 2]);
        }
    }
    __syncthreads();

    // epilogue
    if (splitk > 1) {
        #pragma unroll
        for (int mt = 0; mt < 4; mt++)
            #pragma unroll
            for (int nt = 0; nt < 4; nt++)
                #pragma unroll
                for (int e = 0; e < 4; e++) {
                    int row = rb + warp_m + mt * 16 + g + (e >> 1) * 8;
                    int col = cb + warp_n + nt * 8 + q * 2 + (e & 1);
                    float val = acc[mt][nt][e];
                    if (bias && z == 0) val += bias[col];
                    atomicAdd(&C[(size_t)row * Nn + col], val);
                }
    } else {
        #pragma unroll
        for (int mt = 0; mt < 4; mt++)
            #pragma unroll
            for (int nt = 0; nt < 4; nt++)
                #pragma unroll
                for (int eh = 0; eh < 2; eh++) {
                    int row = rb + warp_m + mt * 16 + g + eh * 8;
                    int col = cb + warp_n + nt * 8 + q * 2;
                    float v0 = acc[mt][nt][eh * 2];
                    float v1 = acc[mt][nt][eh * 2 + 1];
                    if (bias) { v0 += bias[col]; v1 += bias[col + 1]; }
                    if (act) { v0 = gelu_tanh(v0); v1 = gelu_tanh(v1); }
                    if (outhalf)
                        *(__half2*)&((__half*)C)[(size_t)row * Nn + col] = __floats2half2_rn(v0, v1);
                    else
                        *(float2*)&C[(size_t)row * Nn + col] = make_float2(v0, v1);
                }
    }
}

// ---------------- feature GEMM fp16 ----------------
#define FSH 72
__global__ __launch_bounds__(256, 2) void featgemm_kernel(const float* __restrict__ proj) {
    __shared__ __half As[128 * FSH];
    __shared__ __half Bs[128 * FSH];
    __shared__ float diagacc[128];
    __shared__ float wred[8];
    __shared__ float redq[4][128];
    int hk = blockIdx.z, h = hk >> 1, isK = hk & 1;
    const float* X = isK ? g_k : g_q;
    float* dst = isK ? g_kf : g_qf;
    int n0 = blockIdx.y * 128, m0 = blockIdx.x * 128;
    int t = threadIdx.x, lane = t & 31, wid = t >> 5;
    int warp_m = (wid & 1) * 64, warp_n = (wid >> 1) * 32;
    int q = lane & 3, g = lane >> 2;
    bool dodiag = (blockIdx.x == 0);

    if (t < 128) diagacc[t] = 0.f;
    __syncthreads();

    #pragma unroll
    for (int j = 0; j < 8; j++) {
        int i = t + j * 256;
        int row = i >> 4, c = (i & 15) * 4;
        float4 v = *(const float4*)&X[(size_t)(n0 + row) * DIM + h * DH + c];
        *(__half2*)&As[row * FSH + c] = __floats2half2_rn(v.x, v.y);
        *(__half2*)&As[row * FSH + c + 2] = __floats2half2_rn(v.z, v.w);
        if (dodiag)
            atomicAdd(&diagacc[row], v.x * v.x + v.y * v.y + v.z * v.z + v.w * v.w);
    }
    #pragma unroll
    for (int j = 0; j < 8; j++) {
        int i = t + j * 256;
        int m = i >> 4, d = (i & 15) * 4;
        float4 v = *(const float4*)&proj[(size_t)(m0 + m) * DH + d];
        *(__half2*)&Bs[m * FSH + d] = __floats2half2_rn(v.x * DNORM, v.y * DNORM);
        *(__half2*)&Bs[m * FSH + d + 2] = __floats2half2_rn(v.z * DNORM, v.w * DNORM);
    }
    __syncthreads();

    float acc[4][4][4];
    #pragma unroll
    for (int mt = 0; mt < 4; mt++)
        #pragma unroll
        for (int nt = 0; nt < 4; nt++)
            #pragma unroll
            for (int e = 0; e < 4; e++) acc[mt][nt][e] = 0.f;

    const uint32_t* asw = (const uint32_t*)As;
    const uint32_t* bsw = (const uint32_t*)Bs;
    #pragma unroll
    for (int ks = 0; ks < 4; ks++) {
        int k0w = ks * 8;
        uint32_t af[4][4], bf[4][2];
        #pragma unroll
        for (int mt = 0; mt < 4; mt++) {
            int m = warp_m + mt * 16 + g;
            af[mt][0] = asw[m * 36 + k0w + q];
            af[mt][1] = asw[(m + 8) * 36 + k0w + q];
            af[mt][2] = asw[m * 36 + k0w + q + 4];
            af[mt][3] = asw[(m + 8) * 36 + k0w + q + 4];
        }
        #pragma unroll
        for (int nt = 0; nt < 4; nt++) {
            int n = warp_n + nt * 8 + g;
            bf[nt][0] = bsw[n * 36 + k0w + q];
            bf[nt][1] = bsw[n * 36 + k0w + q + 4];
        }
        #pragma unroll
        for (int mt = 0; mt < 4; mt++)
            #pragma unroll
            for (int nt = 0; nt < 4; nt++)
                mma16(acc[mt][nt], af[mt], bf[nt]);
    }

    if (dodiag && t < 128) {
        float* dg = isK ? g_diagk : g_diagq;
        dg[h * NTOK + n0 + t] = 0.5f * (DNORM * DNORM) * diagacc[t];
    }

    #pragma unroll
    for (int mt = 0; mt < 4; mt++)
        #pragma unroll
        for (int nt = 0; nt < 4; nt++)
            #pragma unroll
            for (int e = 0; e < 4; e++) {
                int row = warp_m + mt * 16 + g + (e >> 1) * 8;
                int col = warp_n + nt * 8 + q * 2 + (e & 1);
                dst[((size_t)h * NTOK + n0 + row) * MF + m0 + col] = acc[mt][nt][e];
            }

    if (!isK) {
        #pragma unroll
        for (int mt = 0; mt < 4; mt++)
            #pragma unroll
            for (int eh = 0; eh < 2; eh++) {
                float v = -1e30f;
                #pragma unroll
                for (int nt = 0; nt < 4; nt++) {
                    v = fmaxf(v, acc[mt][nt][eh * 2]);
                    v = fmaxf(v, acc[mt][nt][eh * 2 + 1]);
                }
                v = fmaxf(v, __shfl_xor_sync(0xffffffffu, v, 1));
                v = fmaxf(v, __shfl_xor_sync(0xffffffffu, v, 2));
                if (q == 0)
                    redq[wid >> 1][warp_m + mt * 16 + g + eh * 8] = v;
            }
        __syncthreads();
        if (t < 128) {
            float v = fmaxf(fmaxf(redq[0][t], redq[1][t]), fmaxf(redq[2][t], redq[3][t]));
            g_maxq2[(size_t)blockIdx.x * HEADS * NTOK + h * NTOK + n0 + t] = v;
        }
    } else {
        float v = -1e30f;
        #pragma unroll
        for (int mt = 0; mt < 4; mt++)
            #pragma unroll
            for (int nt = 0; nt < 4; nt++)
                #pragma unroll
                for (int e = 0; e < 4; e++) v = fmaxf(v, acc[mt][nt][e]);
        for (int off = 16; off; off >>= 1) v = fmaxf(v, __shfl_xor_sync(0xffffffffu, v, off));
        if (lane == 0) wred[wid] = v;
        __syncthreads();
        if (t == 0) {
            float mx = wred[0];
            #pragma unroll
            for (int w = 1; w < 8; w++) mx = fmaxf(mx, wred[w]);
            g_maxk2[h * 64 + blockIdx.y * 2 + blockIdx.x] = mx;
        }
    }
}

// ---------------- ctx GEMM (tf32, NZS partials, fast exp) -----------------
#define CSA 136
#define CSB 72
__global__ __launch_bounds__(256) void ctxgemm_kernel(const float* __restrict__ methy) {
    __shared__ float As[32 * CSA];
    __shared__ float Bs[32 * CSB];
    __shared__ float mkred[64];
    int h = blockIdx.x, m0 = blockIdx.y * 128, zs = blockIdx.z;
    int nbase = zs * (NTOK / NZS);
    int t = threadIdx.x, lane = t & 31, wid = t >> 5;
    int warp_m = (wid & 3) * 32, warp_n = (wid >> 2) * 32;
    int q = lane & 3, g = lane >> 2;

    if (t < 64) mkred[t] = g_maxk2[h * 64 + t];
    __syncthreads();
    float mk = mkred[0];
    #pragma unroll
    for (int i = 1; i < 64; i++) mk = fmaxf(mk, mkred[i]);

    int sr = t >> 3;
    int sc = (t & 7) * 4;

    float acc[2][4][4];
    #pragma unroll
    for (int mt = 0; mt < 2; mt++)
        #pragma unroll
        for (int nt = 0; nt < 4; nt++)
            #pragma unroll
            for (int e = 0; e < 4; e++) acc[mt][nt][e] = 0.f;
    float ksacc[16];
    #pragma unroll
    for (int i = 0; i < 16; i++) ksacc[i] = 0.f;

    for (int c = 0; c < NTOK / NZS; c += 32) {
        int n = nbase + c + sr;
        float cc = (g_diagk[h * NTOK + n] + mk) * L2E;
        float msk = (methy[n] != 0.0f) ? RATIO : 0.0f;
        const float* src = &g_kf[((size_t)h * NTOK + n) * MF + m0];
        #pragma unroll
        for (int j = 0; j < 4; j++) {
            int col = sc + 32 * j;
            float4 v = *(const float4*)&src[col];
            float4 w;
            w.x = (ex2f(fmaf(v.x, L2E, -cc)) + 1e-4f) * msk;
            w.y = (ex2f(fmaf(v.y, L2E, -cc)) + 1e-4f) * msk;
            w.z = (ex2f(fmaf(v.z, L2E, -cc)) + 1e-4f) * msk;
            w.w = (ex2f(fmaf(v.w, L2E, -cc)) + 1e-4f) * msk;
            *(float4*)&As[sr * CSA + col] = w;
            ksacc[j * 4 + 0] += w.x; ksacc[j * 4 + 1] += w.y;
            ksacc[j * 4 + 2] += w.z; ksacc[j * 4 + 3] += w.w;
        }
        #pragma unroll
        for (int j = 0; j < 2; j++) {
            int fi = t * 2 + j;
            int row = fi >> 4, col = (fi & 15) * 4;
            *(float4*)&Bs[row * CSB + col] =
                *(const float4*)&g_v[(size_t)(nbase + c + row) * DIM + h * DH + col];
        }
        __syncthreads();
        #pragma unroll
        for (int kk = 0; kk < 4; kk++) {
            int k = kk * 8;
            uint32_t af[2][4], bf[4][2];
            #pragma unroll
            for (int mt = 0; mt < 2; mt++) {
                int m = warp_m + mt * 16 + g;
                af[mt][0] = to_tf32u(As[(k + q) * CSA + m]);
                af[mt][1] = to_tf32u(As[(k + q) * CSA + m + 8]);
                af[mt][2] = to_tf32u(As[(k + 4 + q) * CSA + m]);
                af[mt][3] = to_tf32u(As[(k + 4 + q) * CSA + m + 8]);
            }
            #pragma unroll
            for (int nt = 0; nt < 4; nt++) {
                int n2 = warp_n + nt * 8 + g;
                bf[nt][0] = to_tf32u(Bs[(k + q) * CSB + n2]);
                bf[nt][1] = to_tf32u(Bs[(k + 4 + q) * CSB + n2]);
            }
            #pragma unroll
            for (int mt = 0; mt < 2; mt++)
                #pragma unroll
                for (int nt = 0; nt < 4; nt++)
                    mma8(acc[mt][nt], af[mt], bf[nt]);
        }
        __syncthreads();
    }

    #pragma unroll
    for (int j = 0; j < 4; j++) {
        int col = sc + 32 * j;
        *(float4*)&As[sr * CSA + col] = make_float4(ksacc[j*4], ksacc[j*4+1], ksacc[j*4+2], ksacc[j*4+3]);
    }
    __syncthreads();
    if (t < 128) {
        float s = 0.f;
        #pragma unroll
        for (int r = 0; r < 32; r++) s += As[r * CSA + t];
        g_ksump[((size_t)zs * HEADS + h) * MF + m0 + t] = s;
    }
    float* ctxp = &g_ctxp[((size_t)zs * HEADS + h) * MF * DH];
    #pragma unroll
    for (int mt = 0; mt < 2; mt++)
        #pragma unroll
        for (int nt = 0; nt < 4; nt++)
            #pragma unroll
            for (int e = 0; e < 4; e++) {
                int m = m0 + warp_m + mt * 16 + g + (e >> 1) * 8;
                int d = warp_n + nt * 8 + q * 2 + (e & 1);
                ctxp[(size_t)m * DH + d] = acc[mt][nt][e];
            }
}

// ---------------- reduce partials ----------------
__global__ __launch_bounds__(256) void reduce_kernel() {
    int i = blockIdx.x * 256 + threadIdx.x;
    int nt = gridDim.x * 256;
    for (int j = i; j < HEADS * MF * DH; j += nt) {
        float s = 0.f;
        #pragma unroll
        for (int z = 0; z < NZS; z++) s += g_ctxp[(size_t)z * HEADS * MF * DH + j];
        g_ctx[j] = s;
    }
    for (int j = i; j < HEADS * MF; j += nt) {
        float s = 0.f;
        #pragma unroll
        for (int z = 0; z < NZS; z++) s += g_ksump[(size_t)z * HEADS * MF + j];
        g_ksum[j] = s;
    }
}

// ---------------- attn GEMM fp16: o = (qf @ ctx)/den, half output ---------
#define ATS 40   /* halves stride = 20 words */
__global__ __launch_bounds__(256) void attngemm_kernel() {
    __shared__ __half As[128 * ATS];
    __shared__ __half Bs[64 * ATS];
    __shared__ float ksums[MF];
    __shared__ float dens[128];
    int h = blockIdx.x, n0 = blockIdx.y * 128;
    int t = threadIdx.x, lane = t & 31, wid = t >> 5;
    int warp_m = (wid & 3) * 32, warp_n = (wid >> 2) * 32;
    int q = lane & 3, g = lane >> 2;

    ksums[t] = g_ksum[h * MF + t];
    __syncthreads();

    int sr = t >> 1;
    int n = n0 + sr;
    float mq = fmaxf(g_maxq2[h * NTOK + n], g_maxq2[(size_t)HEADS * NTOK + h * NTOK + n]);
    float cc = (g_diagq[h * NTOK + n] + mq) * L2E;
    float denp = 0.f;

    float acc[2][4][4];
    #pragma unroll
    for (int mt = 0; mt < 2; mt++)
        #pragma unroll
        for (int nt = 0; nt < 4; nt++)
            #pragma unroll
            for (int e = 0; e < 4; e++) acc[mt][nt][e] = 0.f;

    for (int c = 0; c < 256; c += 32) {
        const float* src = &g_qf[((size_t)h * NTOK + n) * MF + c];
        #pragma unroll
        for (int j = 0; j < 4; j++) {
            int col = ((t & 1) * 4 + j) * 4;
            float4 v = *(const float4*)&src[col];
            float4 w;
            w.x = RATIO * (ex2f(fmaf(v.x, L2E, -cc)) + 1e-4f);
            w.y = RATIO * (ex2f(fmaf(v.y, L2E, -cc)) + 1e-4f);
            w.z = RATIO * (ex2f(fmaf(v.z, L2E, -cc)) + 1e-4f);
            w.w = RATIO * (ex2f(fmaf(v.w, L2E, -cc)) + 1e-4f);
            *(__half2*)&As[sr * ATS + col] = __floats2half2_rn(w.x, w.y);
            *(__half2*)&As[sr * ATS + col + 2] = __floats2half2_rn(w.z, w.w);
            denp += w.x * ksums[c + col] + w.y * ksums[c + col + 1]
                  + w.z * ksums[c + col + 2] + w.w * ksums[c + col + 3];
        }
        #pragma unroll
        for (int j = 0; j < 2; j++) {
            int fi = t * 2 + j;
            int row = fi >> 4, col4 = (fi & 15) * 4;
            float4 v = *(const float4*)&g_ctx[(size_t)h * MF * DH + (size_t)(c + row) * DH + col4];
            Bs[(col4 + 0) * ATS + row] = __float2half(v.x);
            Bs[(col4 + 1) * ATS + row] = __float2half(v.y);
            Bs[(col4 + 2) * ATS + row] = __float2half(v.z);
            Bs[(col4 + 3) * ATS + row] = __float2half(v.w);
        }
        __syncthreads();
        const uint32_t* aw = (const uint32_t*)As;
        const uint32_t* bw = (const uint32_t*)Bs;
        #pragma unroll
        for (int ks = 0; ks < 2; ks++) {
            uint32_t af[2][4], bf[4][2];
            #pragma unroll
            for (int mt = 0; mt < 2; mt++) {
                int m = warp_m + mt * 16 + g;
                af[mt][0] = aw[m * 20 + ks * 8 + q];
                af[mt][1] = aw[(m + 8) * 20 + ks * 8 + q];
                af[mt][2] = aw[m * 20 + ks * 8 + q + 4];
                af[mt][3] = aw[(m + 8) * 20 + ks * 8 + q + 4];
            }
            #pragma unroll
            for (int nt = 0; nt < 4; nt++) {
                int d = warp_n + nt * 8 + g;
                bf[nt][0] = bw[d * 20 + ks * 8 + q];
                bf[nt][1] = bw[d * 20 + ks * 8 + q + 4];
            }
            #pragma unroll
            for (int mt = 0; mt < 2; mt++)
                #pragma unroll
                for (int nt = 0; nt < 4; nt++)
                    mma16(acc[mt][nt], af[mt], bf[nt]);
        }
        __syncthreads();
    }

    denp += __shfl_xor_sync(0xffffffffu, denp, 1);
    if ((t & 1) == 0) dens[sr] = denp;
    __syncthreads();

    #pragma unroll
    for (int mt = 0; mt < 2; mt++)
        #pragma unroll
        for (int nt = 0; nt < 4; nt++)
            #pragma unroll
            for (int e = 0; e < 4; e++) {
                int row = warp_m + mt * 16 + g + (e >> 1) * 8;
                int d = warp_n + nt * 8 + q * 2 + (e & 1);
                g_attnh[(size_t)(n0 + row) * DIM + h * DH + d] =
                    __float2half(acc[mt][nt][e] / dens[row]);
            }
}

// ---------------- output head ----------------
__global__ __launch_bounds__(128) void wout_kernel(const float* __restrict__ Wout,
                                                   const float* __restrict__ bout,
                                                   float* __restrict__ out) {
    int n = blockIdx.x, t = threadIdx.x;
    __shared__ float xs[DIM];
    for (int i = t; i < DIM; i += 128) xs[i] = g_h[n * DIM + i];
    __syncthreads();
    if (t < VOCAB) {
        float acc = bout[t];
        for (int k = 0; k < DIM; k++) acc += xs[k] * Wout[k * VOCAB + t];
        out[n * VOCAB + t] = acc;
    }
}

// ---------------- host ----------------
extern "C" void kernel_launch(void* const* d_in, const int* in_sizes, int n_in,
                              void* d_out, int out_size) {
    const float* methy = (const float*)d_in[0];
    const int* chromo = (const int*)d_in[1];
    const int* pos    = (const int*)d_in[2];
    const float* mt = (const float*)d_in[3];
    const float* ct = (const float*)d_in[4];
    const float* pt = (const float*)d_in[5];
    const float* ln1g = (const float*)d_in[6];
    const float* ln1b = (const float*)d_in[7];
    const float* ln2g = (const float*)d_in[8];
    const float* ln2b = (const float*)d_in[9];
    const float* Wq = (const float*)d_in[10];
    const float* Wk = (const float*)d_in[11];
    const float* Wv = (const float*)d_in[12];
    const float* Wo = (const float*)d_in[13];
    const float* bo = (const float*)d_in[14];
    const float* W1 = (const float*)d_in[15];
    const float* b1 = (const float*)d_in[16];
    const float* W2 = (const float*)d_in[17];
    const float* b2 = (const float*)d_in[18];
    const float* proj = (const float*)d_in[19];
    const float* nfg = (const float*)d_in[20];
    const float* nfb = (const float*)d_in[21];
    const float* Wout = (const float*)d_in[22];
    const float* bout = (const float*)d_in[23];
    float* out = (float*)d_out;

    float *px, *ph, *pq, *pk, *pv;
    __half *phh, *pattnh, *pffh, *pwh;
    cudaGetSymbolAddress((void**)&px, g_x);
    cudaGetSymbolAddress((void**)&ph, g_h);
    cudaGetSymbolAddress((void**)&phh, g_hh);
    cudaGetSymbolAddress((void**)&pq, g_q);
    cudaGetSymbolAddress((void**)&pk, g_k);
    cudaGetSymbolAddress((void**)&pv, g_v);
    cudaGetSymbolAddress((void**)&pattnh, g_attnh);
    cudaGetSymbolAddress((void**)&pffh, g_ffh);
    cudaGetSymbolAddress((void**)&pwh, g_wh);

    const int GEMMH_SMEM = HSTAGES * 2 * HAELE * 2;                  // 110,592
    cudaFuncSetAttribute(tgemm_h, cudaFuncAttributeMaxDynamicSharedMemorySize, GEMMH_SMEM);

    wconv_sq<<<dim3(24, 24, DEPTH * 4), 256>>>(Wq, Wk, Wv, Wo);
    wconv_ff<<<dim3(2304, DEPTH, 2), 256>>>(W1, W2);
    embed_kernel<<<NTOK, 256>>>(methy, chromo, pos, mt, ct, pt);

    dim3 gqkv(DIM / 128, NTOK / 128, 3);
    dim3 gsk3(DIM / 128, NTOK / 128, 3);
    dim3 gff(FF / 128, NTOK / 128, 1);
    dim3 gfeat(2, 32, HEADS * 2);
    dim3 gctx(HEADS, 2, NZS);
    dim3 gattn(HEADS, NTOK / 128);

    for (int l = 0; l < DEPTH; l++) {
        const float* pj = proj + (size_t)l * MF * DH;
        const __half* wl = pwh + (size_t)l * LOFF;
        // --- attention ---
        ln_kernel<<<NTOK, 192>>>(px, ln1g + l * DIM, ln1b + l * DIM, nullptr, phh);
        tgemm_h<<<gqkv, 256, GEMMH_SMEM>>>(phh,
            wl + WOQ, wl + WOK, wl + WOV,
            nullptr, pq, pk, pv, DIM, DIM, 0, 1, 0);
        featgemm_kernel<<<gfeat, 256>>>(pj);
        ctxgemm_kernel<<<gctx, 256>>>(methy);
        reduce_kernel<<<192, 256>>>();
        attngemm_kernel<<<gattn, 256>>>();
        tgemm_h<<<gsk3, 256, GEMMH_SMEM>>>(pattnh,
            wl + WOO, nullptr, nullptr,
            bo + l * DIM, px, nullptr, nullptr, DIM, DIM, 0, 3, 0);
        // --- FFN ---
        ln_kernel<<<NTOK, 192>>>(px, ln2g + l * DIM, ln2b + l * DIM, nullptr, phh);
        tgemm_h<<<gff, 256, GEMMH_SMEM>>>(phh,
            wl + WO1, nullptr, nullptr,
            b1 + l * FF, (float*)pffh, nullptr, nullptr, FF, DIM, 1, 1, 1);
        tgemm_h<<<gsk3, 256, GEMMH_SMEM>>>(pffh,
            wl + WO2, nullptr, nullptr,
            b2 + l * DIM, px, nullptr, nullptr, DIM, FF, 0, 3, 0);
    }

    ln_kernel<<<NTOK, 192>>>(px, nfg, nfb, ph, phh);
    wout_kernel<<<NTOK, 128>>>(Wout, bout, out);
}

// round 16
// speedup vs baseline: 7.5581x; 1.0719x over previous
#include <cuda_runtime.h>
#include <cuda_fp16.h>
#include <math.h>
#include <stdint.h>

#define NTOK 4096
#define DIM 768
#define DEPTH 6
#define HEADS 12
#define DH 64
#define FF 3072
#define MF 256
#define VOCAB 102
#define DNORM 0.35355339059327373f   /* 64^-0.25 */
#define RATIO 0.0625f                /* 256^-0.5 */
#define L2E 1.4426950408889634f
#define NZS 16                        /* ctx n-splits */

// per-layer half-weight offsets (in halves)
#define LOFF 7077888
#define WOQ 0
#define WOK 589824
#define WOV 1179648
#define WOO 1769472
#define WO1 2359296
#define WO2 4718592

// ---------------- scratch (device globals, no allocation) ----------------
__device__ float g_x[NTOK * DIM];
__device__ float g_h[NTOK * DIM];
__device__ __align__(16) __half g_hh[NTOK * DIM];
__device__ float g_q[NTOK * DIM];
__device__ float g_k[NTOK * DIM];
__device__ float g_v[NTOK * DIM];
__device__ __align__(16) __half g_attnh[NTOK * DIM];
__device__ __align__(16) __half g_ffh[NTOK * FF];
__device__ __align__(16) __half g_wh[(size_t)DEPTH * LOFF];
__device__ __align__(16) __half g_qf[HEADS * NTOK * MF];   // raw xd (half)
__device__ __align__(16) __half g_kf[HEADS * NTOK * MF];   // raw xd (half)
__device__ float g_diagq[HEADS * NTOK];
__device__ float g_diagk[HEADS * NTOK];
__device__ float g_maxq2[2 * HEADS * NTOK];
__device__ float g_maxk2[HEADS * 64];
__device__ float g_ksum[HEADS * MF];
__device__ float g_ctx[HEADS * MF * DH];
__device__ float g_ctxp[NZS * HEADS * MF * DH];
__device__ float g_ksump[NZS * HEADS * MF];

// ---------------- helpers ----------------
__device__ __forceinline__ float tanh_fast(float x) {
    float r;
    asm("tanh.approx.f32 %0, %1;" : "=f"(r) : "f"(x));
    return r;
}

__device__ __forceinline__ float ex2f(float y) {
    float r;
    asm("ex2.approx.f32 %0, %1;" : "=f"(r) : "f"(y));
    return r;
}

__device__ __forceinline__ float gelu_tanh(float u) {
    return 0.5f * u * (1.0f + tanh_fast(0.7978845608028654f * (u + 0.044715f * u * u * u)));
}

__device__ __forceinline__ uint32_t to_tf32u(float x) {
    float r;
    asm("cvt.rna.tf32.f32 %0, %1;" : "=f"(r) : "f"(x));
    return __float_as_uint(r);
}

__device__ __forceinline__ void mma8(float* c, const uint32_t* a, const uint32_t* b) {
    asm volatile(
        "mma.sync.aligned.m16n8k8.row.col.f32.tf32.tf32.f32 "
        "{%0,%1,%2,%3}, {%4,%5,%6,%7}, {%8,%9}, {%0,%1,%2,%3};"
        : "+f"(c[0]), "+f"(c[1]), "+f"(c[2]), "+f"(c[3])
        : "r"(a[0]), "r"(a[1]), "r"(a[2]), "r"(a[3]), "r"(b[0]), "r"(b[1]));
}

__device__ __forceinline__ void mma16(float* c, const uint32_t* a, const uint32_t* b) {
    asm volatile(
        "mma.sync.aligned.m16n8k16.row.col.f32.f16.f16.f32 "
        "{%0,%1,%2,%3}, {%4,%5,%6,%7}, {%8,%9}, {%0,%1,%2,%3};"
        : "+f"(c[0]), "+f"(c[1]), "+f"(c[2]), "+f"(c[3])
        : "r"(a[0]), "r"(a[1]), "r"(a[2]), "r"(a[3]), "r"(b[0]), "r"(b[1]));
}

__device__ __forceinline__ void ldsm4(uint32_t* r, uint32_t addr) {
    asm volatile("ldmatrix.sync.aligned.m8n8.x4.shared.b16 {%0,%1,%2,%3}, [%4];"
        : "=r"(r[0]), "=r"(r[1]), "=r"(r[2]), "=r"(r[3]) : "r"(addr));
}

__device__ __forceinline__ void cp_async16(uint32_t dst, const void* src) {
    asm volatile("cp.async.cg.shared.global [%0], [%1], 16;" :: "r"(dst), "l"(src));
}
__device__ __forceinline__ void cp_commit() { asm volatile("cp.async.commit_group;"); }
__device__ __forceinline__ void cp_wait1() { asm volatile("cp.async.wait_group 1;"); }
__device__ __forceinline__ void cp_wait0() { asm volatile("cp.async.wait_group 0;"); }

// ---------------- weight convert + transpose helpers ----------------------
__device__ __forceinline__ void wtile_transpose(const float* src, __half* dst,
                                                int K, int N, int k0, int n0) {
    __shared__ float tile[32][33];
    int tx = threadIdx.x & 31, ty = threadIdx.x >> 5;   // 32x8
    #pragma unroll
    for (int i = 0; i < 4; i++)
        tile[ty + i * 8][tx] = src[(size_t)(k0 + ty + i * 8) * N + n0 + tx];
    __syncthreads();
    #pragma unroll
    for (int i = 0; i < 4; i++)
        dst[(size_t)(n0 + ty + i * 8) * K + k0 + tx] = __float2half(tile[tx][ty + i * 8]);
}

__global__ __launch_bounds__(256) void wconv_sq(const float* __restrict__ Wq,
                                                const float* __restrict__ Wk,
                                                const float* __restrict__ Wv,
                                                const float* __restrict__ Wo) {
    int zz = blockIdx.z, l = zz >> 2, mat = zz & 3;
    const float* srcs[4] = {Wq, Wk, Wv, Wo};
    const size_t offs[4] = {WOQ, WOK, WOV, WOO};
    wtile_transpose(srcs[mat] + (size_t)l * DIM * DIM,
                    g_wh + (size_t)l * LOFF + offs[mat],
                    DIM, DIM, blockIdx.y * 32, blockIdx.x * 32);
}

__global__ __launch_bounds__(256) void wconv_ff(const float* __restrict__ W1,
                                                const float* __restrict__ W2) {
    int l = blockIdx.y, mat = blockIdx.z, f = blockIdx.x;
    int K, N, n0, k0;
    size_t off;
    const float* src;
    if (mat == 0) { K = DIM; N = FF;  n0 = (f % 96) * 32; k0 = (f / 96) * 32; off = WO1; src = W1; }
    else          { K = FF;  N = DIM; n0 = (f % 24) * 32; k0 = (f / 24) * 32; off = WO2; src = W2; }
    wtile_transpose(src + (size_t)l * K * N,
                    g_wh + (size_t)l * LOFF + off, K, N, k0, n0);
}

// ---------------- embedding + bucketize ----------------
__global__ void embed_kernel(const float* __restrict__ methy,
                             const int* __restrict__ chromo,
                             const int* __restrict__ pos,
                             const float* __restrict__ mt,
                             const float* __restrict__ ct,
                             const float* __restrict__ pt) {
    int n = blockIdx.x;
    float x = methy[n];
    int idx = (x > -2.0f) + (x > -1.0f);
    #pragma unroll 4
    for (int i = 0; i < 100; i++) idx += ((float)i * 0.01f < x) ? 1 : 0;
    int c = chromo[n], p = pos[n];
    const float* mrow = mt + (size_t)idx * DIM;
    const float* prow = pt + (size_t)p * DIM;
    const float* crow = ct + (size_t)c * DIM;
    for (int d = threadIdx.x; d < DIM; d += blockDim.x)
        g_x[n * DIM + d] = mrow[d] + prow[d] + crow[d];
}

// ---------------- layernorm: 2 rows/block, 384 thr, float4, shfl ----------
__global__ __launch_bounds__(384) void ln_kernel(const float* __restrict__ in,
                                                 const float* __restrict__ g,
                                                 const float* __restrict__ b,
                                                 float* __restrict__ out,
                                                 __half* __restrict__ outh) {
    int t = threadIdx.x;
    int half_id = t >= 192;
    int n = blockIdx.x * 2 + half_id;
    int tl = t - half_id * 192;        // 0..191 within row
    int lane = t & 31, wid = t >> 5;   // warps 0-5 row0, 6-11 row1
    __shared__ float ws[12], ws2[12];
    float4 v = *(const float4*)&in[(size_t)n * DIM + tl * 4];
    float s = v.x + v.y + v.z + v.w;
    for (int off = 16; off; off >>= 1) s += __shfl_xor_sync(0xffffffffu, s, off);
    if (lane == 0) ws[wid] = s;
    __syncthreads();
    int wb = half_id * 6;
    float mu = (ws[wb] + ws[wb+1] + ws[wb+2] + ws[wb+3] + ws[wb+4] + ws[wb+5]) * (1.0f / DIM);
    float dx = v.x - mu, dy = v.y - mu, dz = v.z - mu, dw = v.w - mu;
    float s2 = dx * dx + dy * dy + dz * dz + dw * dw;
    for (int off = 16; off; off >>= 1) s2 += __shfl_xor_sync(0xffffffffu, s2, off);
    if (lane == 0) ws2[wid] = s2;
    __syncthreads();
    float rstd = rsqrtf((ws2[wb] + ws2[wb+1] + ws2[wb+2] + ws2[wb+3] + ws2[wb+4] + ws2[wb+5]) * (1.0f / DIM) + 1e-5f);
    float4 gg = *(const float4*)&g[tl * 4];
    float4 bb = *(const float4*)&b[tl * 4];
    float4 o;
    o.x = dx * rstd * gg.x + bb.x;
    o.y = dy * rstd * gg.y + bb.y;
    o.z = dz * rstd * gg.z + bb.z;
    o.w = dw * rstd * gg.w + bb.w;
    if (out) *(float4*)&out[(size_t)n * DIM + tl * 4] = o;
    *(__half2*)&outh[(size_t)n * DIM + tl * 4] = __floats2half2_rn(o.x, o.y);
    *(__half2*)&outh[(size_t)n * DIM + tl * 4 + 2] = __floats2half2_rn(o.z, o.w);
}

// ---------------- FP16 GEMM 128x128x64h, cp.async 3-stage, ldmatrix -------
#define BKH 64
#define SAH 72
#define HAELE (128 * SAH)
#define HSTAGES 3

__global__ __launch_bounds__(256, 2) void tgemm_h(const __half* __restrict__ A,
                                                  const __half* __restrict__ B0,
                                                  const __half* __restrict__ B1,
                                                  const __half* __restrict__ B2,
                                                  const float* __restrict__ bias,
                                                  float* __restrict__ C0,
                                                  float* __restrict__ C1,
                                                  float* __restrict__ C2,
                                                  int Nn, int Kk, int act, int splitk,
                                                  int outhalf) {
    extern __shared__ __half hsm[];
    int z = blockIdx.z;
    const __half* B = B0;
    float* C = C0;
    int koff = 0, Keff = Kk;
    if (splitk > 1) {
        Keff = Kk / splitk;
        koff = z * Keff;
    } else {
        B = (z == 0) ? B0 : ((z == 1) ? B1 : B2);
        C = (z == 0) ? C0 : ((z == 1) ? C1 : C2);
    }

    int t = threadIdx.x;
    int rb = blockIdx.y * 128, cb = blockIdx.x * 128;
    int lane = t & 31, wid = t >> 5;
    int warp_m = (wid & 1) * 64, warp_n = (wid >> 1) * 32;
    int q = lane & 3, g = lane >> 2;

    int tr = t >> 3;
    int tc = (t & 7) * 8;

    const __half* Abase = A + (size_t)(rb + tr) * Kk + koff + tc;
    const __half* Bbase = B + (size_t)(cb + tr) * Kk + koff + tc;

    uint32_t smA = (uint32_t)__cvta_generic_to_shared(hsm);
    uint32_t smB = smA + HSTAGES * HAELE * 2;
    uint32_t adst = smA + (uint32_t)((tr * SAH + tc) * 2);
    uint32_t bdst = smB + (uint32_t)((tr * SAH + tc) * 2);

    uint32_t aoff[4], boff[2];
    {
        int r = (lane & 7) + ((lane >> 3) & 1) * 8;
        int kh = (lane >> 4) * 8;
        #pragma unroll
        for (int mt = 0; mt < 4; mt++)
            aoff[mt] = (uint32_t)(((warp_m + mt * 16 + r) * SAH + kh) * 2);
        int rn = lane & 7;
        int khb = ((lane >> 3) & 1) * 8;
        int pb = lane >> 4;
        #pragma unroll
        for (int p = 0; p < 2; p++)
            boff[p] = (uint32_t)(((warp_n + (p * 2 + pb) * 8 + rn) * SAH + khb) * 2);
    }

    int niter = Keff / BKH;

    #pragma unroll
    for (int s = 0; s < 2; s++) {
        if (s < niter) {
            size_t k0 = (size_t)s * BKH;
            #pragma unroll
            for (int i = 0; i < 4; i++)
                cp_async16(adst + (uint32_t)(s * HAELE * 2 + i * 32 * SAH * 2),
                           Abase + (size_t)(32 * i) * Kk + k0);
            #pragma unroll
            for (int i = 0; i < 4; i++)
                cp_async16(bdst + (uint32_t)(s * HAELE * 2 + i * 32 * SAH * 2),
                           Bbase + (size_t)(32 * i) * Kk + k0);
        }
        cp_commit();
    }

    float acc[4][4][4];
    #pragma unroll
    for (int mt = 0; mt < 4; mt++)
        #pragma unroll
        for (int nt = 0; nt < 4; nt++)
            #pragma unroll
            for (int e = 0; e < 4; e++) acc[mt][nt][e] = 0.f;

    for (int it = 0; it < niter; it++) {
        if (it + 1 < niter) cp_wait1(); else cp_wait0();
        __syncthreads();
        if (it + 2 < niter) {
            int s = (it + 2) % HSTAGES;
            size_t k0 = (size_t)(it + 2) * BKH;
            #pragma unroll
            for (int i = 0; i < 4; i++)
                cp_async16(adst + (uint32_t)(s * HAELE * 2 + i * 32 * SAH * 2),
                           Abase + (size_t)(32 * i) * Kk + k0);
            #pragma unroll
            for (int i = 0; i < 4; i++)
                cp_async16(bdst + (uint32_t)(s * HAELE * 2 + i * 32 * SAH * 2),
                           Bbase + (size_t)(32 * i) * Kk + k0);
        }
        cp_commit();

        uint32_t sa = smA + (uint32_t)((it % HSTAGES) * HAELE * 2);
        uint32_t sb = smB + (uint32_t)((it % HSTAGES) * HAELE * 2);
        #pragma unroll
        for (int ks = 0; ks < 4; ks++) {
            uint32_t kbyte = (uint32_t)(ks * 32);
            uint32_t af[4][4], bfr[2][4];
            #pragma unroll
            for (int mt = 0; mt < 4; mt++) ldsm4(af[mt], sa + aoff[mt] + kbyte);
            #pragma unroll
            for (int p = 0; p < 2; p++) ldsm4(bfr[p], sb + boff[p] + kbyte);
            #pragma unroll
            for (int mt = 0; mt < 4; mt++)
                #pragma unroll
                for (int nt = 0; nt < 4; nt++)
                    mma16(acc[mt][nt], af[mt], &bfr[nt >> 1][(nt & 1) * 2]);
        }
    }
    __syncthreads();

    // epilogue
    if (splitk > 1) {
        #pragma unroll
        for (int mt = 0; mt < 4; mt++)
            #pragma unroll
            for (int nt = 0; nt < 4; nt++)
                #pragma unroll
                for (int e = 0; e < 4; e++) {
                    int row = rb + warp_m + mt * 16 + g + (e >> 1) * 8;
                    int col = cb + warp_n + nt * 8 + q * 2 + (e & 1);
                    float val = acc[mt][nt][e];
                    if (bias && z == 0) val += bias[col];
                    atomicAdd(&C[(size_t)row * Nn + col], val);
                }
    } else {
        #pragma unroll
        for (int mt = 0; mt < 4; mt++)
            #pragma unroll
            for (int nt = 0; nt < 4; nt++)
                #pragma unroll
                for (int eh = 0; eh < 2; eh++) {
                    int row = rb + warp_m + mt * 16 + g + eh * 8;
                    int col = cb + warp_n + nt * 8 + q * 2;
                    float v0 = acc[mt][nt][eh * 2];
                    float v1 = acc[mt][nt][eh * 2 + 1];
                    if (bias) { v0 += bias[col]; v1 += bias[col + 1]; }
                    if (act) { v0 = gelu_tanh(v0); v1 = gelu_tanh(v1); }
                    if (outhalf)
                        *(__half2*)&((__half*)C)[(size_t)row * Nn + col] = __floats2half2_rn(v0, v1);
                    else
                        *(float2*)&C[(size_t)row * Nn + col] = make_float2(v0, v1);
                }
    }
}

// ---------------- feature GEMM fp16 (half xd output) ----------------------
#define FSH 72
__global__ __launch_bounds__(256, 2) void featgemm_kernel(const float* __restrict__ proj) {
    __shared__ __half As[128 * FSH];
    __shared__ __half Bs[128 * FSH];
    __shared__ float diagacc[128];
    __shared__ float wred[8];
    __shared__ float redq[4][128];
    int hk = blockIdx.z, h = hk >> 1, isK = hk & 1;
    const float* X = isK ? g_k : g_q;
    __half* dst = isK ? g_kf : g_qf;
    int n0 = blockIdx.y * 128, m0 = blockIdx.x * 128;
    int t = threadIdx.x, lane = t & 31, wid = t >> 5;
    int warp_m = (wid & 1) * 64, warp_n = (wid >> 1) * 32;
    int q = lane & 3, g = lane >> 2;
    bool dodiag = (blockIdx.x == 0);

    if (t < 128) diagacc[t] = 0.f;
    __syncthreads();

    #pragma unroll
    for (int j = 0; j < 8; j++) {
        int i = t + j * 256;
        int row = i >> 4, c = (i & 15) * 4;
        float4 v = *(const float4*)&X[(size_t)(n0 + row) * DIM + h * DH + c];
        *(__half2*)&As[row * FSH + c] = __floats2half2_rn(v.x, v.y);
        *(__half2*)&As[row * FSH + c + 2] = __floats2half2_rn(v.z, v.w);
        if (dodiag)
            atomicAdd(&diagacc[row], v.x * v.x + v.y * v.y + v.z * v.z + v.w * v.w);
    }
    #pragma unroll
    for (int j = 0; j < 8; j++) {
        int i = t + j * 256;
        int m = i >> 4, d = (i & 15) * 4;
        float4 v = *(const float4*)&proj[(size_t)(m0 + m) * DH + d];
        *(__half2*)&Bs[m * FSH + d] = __floats2half2_rn(v.x * DNORM, v.y * DNORM);
        *(__half2*)&Bs[m * FSH + d + 2] = __floats2half2_rn(v.z * DNORM, v.w * DNORM);
    }
    __syncthreads();

    float acc[4][4][4];
    #pragma unroll
    for (int mt = 0; mt < 4; mt++)
        #pragma unroll
        for (int nt = 0; nt < 4; nt++)
            #pragma unroll
            for (int e = 0; e < 4; e++) acc[mt][nt][e] = 0.f;

    const uint32_t* asw = (const uint32_t*)As;
    const uint32_t* bsw = (const uint32_t*)Bs;
    #pragma unroll
    for (int ks = 0; ks < 4; ks++) {
        int k0w = ks * 8;
        uint32_t af[4][4], bf[4][2];
        #pragma unroll
        for (int mt = 0; mt < 4; mt++) {
            int m = warp_m + mt * 16 + g;
            af[mt][0] = asw[m * 36 + k0w + q];
            af[mt][1] = asw[(m + 8) * 36 + k0w + q];
            af[mt][2] = asw[m * 36 + k0w + q + 4];
            af[mt][3] = asw[(m + 8) * 36 + k0w + q + 4];
        }
        #pragma unroll
        for (int nt = 0; nt < 4; nt++) {
            int n = warp_n + nt * 8 + g;
            bf[nt][0] = bsw[n * 36 + k0w + q];
            bf[nt][1] = bsw[n * 36 + k0w + q + 4];
        }
        #pragma unroll
        for (int mt = 0; mt < 4; mt++)
            #pragma unroll
            for (int nt = 0; nt < 4; nt++)
                mma16(acc[mt][nt], af[mt], bf[nt]);
    }

    if (dodiag && t < 128) {
        float* dg = isK ? g_diagk : g_diagq;
        dg[h * NTOK + n0 + t] = 0.5f * (DNORM * DNORM) * diagacc[t];
    }

    // store raw xd as half (paired stores)
    #pragma unroll
    for (int mt = 0; mt < 4; mt++)
        #pragma unroll
        for (int nt = 0; nt < 4; nt++)
            #pragma unroll
            for (int eh = 0; eh < 2; eh++) {
                int row = warp_m + mt * 16 + g + eh * 8;
                int col = warp_n + nt * 8 + q * 2;
                *(__half2*)&dst[((size_t)h * NTOK + n0 + row) * MF + m0 + col] =
                    __floats2half2_rn(acc[mt][nt][eh * 2], acc[mt][nt][eh * 2 + 1]);
            }

    if (!isK) {
        #pragma unroll
        for (int mt = 0; mt < 4; mt++)
            #pragma unroll
            for (int eh = 0; eh < 2; eh++) {
                float v = -1e30f;
                #pragma unroll
                for (int nt = 0; nt < 4; nt++) {
                    v = fmaxf(v, acc[mt][nt][eh * 2]);
                    v = fmaxf(v, acc[mt][nt][eh * 2 + 1]);
                }
                v = fmaxf(v, __shfl_xor_sync(0xffffffffu, v, 1));
                v = fmaxf(v, __shfl_xor_sync(0xffffffffu, v, 2));
                if (q == 0)
                    redq[wid >> 1][warp_m + mt * 16 + g + eh * 8] = v;
            }
        __syncthreads();
        if (t < 128) {
            float v = fmaxf(fmaxf(redq[0][t], redq[1][t]), fmaxf(redq[2][t], redq[3][t]));
            g_maxq2[(size_t)blockIdx.x * HEADS * NTOK + h * NTOK + n0 + t] = v;
        }
    } else {
        float v = -1e30f;
        #pragma unroll
        for (int mt = 0; mt < 4; mt++)
            #pragma unroll
            for (int nt = 0; nt < 4; nt++)
                #pragma unroll
                for (int e = 0; e < 4; e++) v = fmaxf(v, acc[mt][nt][e]);
        for (int off = 16; off; off >>= 1) v = fmaxf(v, __shfl_xor_sync(0xffffffffu, v, off));
        if (lane == 0) wred[wid] = v;
        __syncthreads();
        if (t == 0) {
            float mx = wred[0];
            #pragma unroll
            for (int w = 1; w < 8; w++) mx = fmaxf(mx, wred[w]);
            g_maxk2[h * 64 + blockIdx.y * 2 + blockIdx.x] = mx;
        }
    }
}

// ---------------- ctx GEMM (tf32, NZS partials, fast exp, half kf) --------
#define CSA 136
#define CSB 72
__global__ __launch_bounds__(256) void ctxgemm_kernel(const float* __restrict__ methy) {
    __shared__ float As[32 * CSA];
    __shared__ float Bs[32 * CSB];
    __shared__ float mkred[64];
    int h = blockIdx.x, m0 = blockIdx.y * 128, zs = blockIdx.z;
    int nbase = zs * (NTOK / NZS);
    int t = threadIdx.x, lane = t & 31, wid = t >> 5;
    int warp_m = (wid & 3) * 32, warp_n = (wid >> 2) * 32;
    int q = lane & 3, g = lane >> 2;

    if (t < 64) mkred[t] = g_maxk2[h * 64 + t];
    __syncthreads();
    float mk = mkred[0];
    #pragma unroll
    for (int i = 1; i < 64; i++) mk = fmaxf(mk, mkred[i]);

    int sr = t >> 3;
    int sc = (t & 7) * 4;

    float acc[2][4][4];
    #pragma unroll
    for (int mt = 0; mt < 2; mt++)
        #pragma unroll
        for (int nt = 0; nt < 4; nt++)
            #pragma unroll
            for (int e = 0; e < 4; e++) acc[mt][nt][e] = 0.f;
    float ksacc[16];
    #pragma unroll
    for (int i = 0; i < 16; i++) ksacc[i] = 0.f;

    for (int c = 0; c < NTOK / NZS; c += 32) {
        int n = nbase + c + sr;
        float cc = (g_diagk[h * NTOK + n] + mk) * L2E;
        float msk = (methy[n] != 0.0f) ? RATIO : 0.0f;
        const __half* src = &g_kf[((size_t)h * NTOK + n) * MF + m0];
        #pragma unroll
        for (int j = 0; j < 4; j++) {
            int col = sc + 32 * j;
            float2 f0 = __half22float2(*(const __half2*)&src[col]);
            float2 f1 = __half22float2(*(const __half2*)&src[col + 2]);
            float4 w;
            w.x = (ex2f(fmaf(f0.x, L2E, -cc)) + 1e-4f) * msk;
            w.y = (ex2f(fmaf(f0.y, L2E, -cc)) + 1e-4f) * msk;
            w.z = (ex2f(fmaf(f1.x, L2E, -cc)) + 1e-4f) * msk;
            w.w = (ex2f(fmaf(f1.y, L2E, -cc)) + 1e-4f) * msk;
            *(float4*)&As[sr * CSA + col] = w;
            ksacc[j * 4 + 0] += w.x; ksacc[j * 4 + 1] += w.y;
            ksacc[j * 4 + 2] += w.z; ksacc[j * 4 + 3] += w.w;
        }
        #pragma unroll
        for (int j = 0; j < 2; j++) {
            int fi = t * 2 + j;
            int row = fi >> 4, col = (fi & 15) * 4;
            *(float4*)&Bs[row * CSB + col] =
                *(const float4*)&g_v[(size_t)(nbase + c + row) * DIM + h * DH + col];
        }
        __syncthreads();
        #pragma unroll
        for (int kk = 0; kk < 4; kk++) {
            int k = kk * 8;
            uint32_t af[2][4], bf[4][2];
            #pragma unroll
            for (int mt = 0; mt < 2; mt++) {
                int m = warp_m + mt * 16 + g;
                af[mt][0] = to_tf32u(As[(k + q) * CSA + m]);
                af[mt][1] = to_tf32u(As[(k + q) * CSA + m + 8]);
                af[mt][2] = to_tf32u(As[(k + 4 + q) * CSA + m]);
                af[mt][3] = to_tf32u(As[(k + 4 + q) * CSA + m + 8]);
            }
            #pragma unroll
            for (int nt = 0; nt < 4; nt++) {
                int n2 = warp_n + nt * 8 + g;
                bf[nt][0] = to_tf32u(Bs[(k + q) * CSB + n2]);
                bf[nt][1] = to_tf32u(Bs[(k + 4 + q) * CSB + n2]);
            }
            #pragma unroll
            for (int mt = 0; mt < 2; mt++)
                #pragma unroll
                for (int nt = 0; nt < 4; nt++)
                    mma8(acc[mt][nt], af[mt], bf[nt]);
        }
        __syncthreads();
    }

    #pragma unroll
    for (int j = 0; j < 4; j++) {
        int col = sc + 32 * j;
        *(float4*)&As[sr * CSA + col] = make_float4(ksacc[j*4], ksacc[j*4+1], ksacc[j*4+2], ksacc[j*4+3]);
    }
    __syncthreads();
    if (t < 128) {
        float s = 0.f;
        #pragma unroll
        for (int r = 0; r < 32; r++) s += As[r * CSA + t];
        g_ksump[((size_t)zs * HEADS + h) * MF + m0 + t] = s;
    }
    float* ctxp = &g_ctxp[((size_t)zs * HEADS + h) * MF * DH];
    #pragma unroll
    for (int mt = 0; mt < 2; mt++)
        #pragma unroll
        for (int nt = 0; nt < 4; nt++)
            #pragma unroll
            for (int e = 0; e < 4; e++) {
                int m = m0 + warp_m + mt * 16 + g + (e >> 1) * 8;
                int d = warp_n + nt * 8 + q * 2 + (e & 1);
                ctxp[(size_t)m * DH + d] = acc[mt][nt][e];
            }
}

// ---------------- reduce partials ----------------
__global__ __launch_bounds__(256) void reduce_kernel() {
    int i = blockIdx.x * 256 + threadIdx.x;
    int nt = gridDim.x * 256;
    for (int j = i; j < HEADS * MF * DH; j += nt) {
        float s = 0.f;
        #pragma unroll
        for (int z = 0; z < NZS; z++) s += g_ctxp[(size_t)z * HEADS * MF * DH + j];
        g_ctx[j] = s;
    }
    for (int j = i; j < HEADS * MF; j += nt) {
        float s = 0.f;
        #pragma unroll
        for (int z = 0; z < NZS; z++) s += g_ksump[(size_t)z * HEADS * MF + j];
        g_ksum[j] = s;
    }
}

// ---------------- attn GEMM fp16 (half qf in), half output ----------------
#define ATS 40   /* halves stride = 20 words */
__global__ __launch_bounds__(256) void attngemm_kernel() {
    __shared__ __half As[128 * ATS];
    __shared__ __half Bs[64 * ATS];
    __shared__ float ksums[MF];
    __shared__ float dens[128];
    int h = blockIdx.x, n0 = blockIdx.y * 128;
    int t = threadIdx.x, lane = t & 31, wid = t >> 5;
    int warp_m = (wid & 3) * 32, warp_n = (wid >> 2) * 32;
    int q = lane & 3, g = lane >> 2;

    ksums[t] = g_ksum[h * MF + t];
    __syncthreads();

    int sr = t >> 1;
    int n = n0 + sr;
    float mq = fmaxf(g_maxq2[h * NTOK + n], g_maxq2[(size_t)HEADS * NTOK + h * NTOK + n]);
    float cc = (g_diagq[h * NTOK + n] + mq) * L2E;
    float denp = 0.f;

    float acc[2][4][4];
    #pragma unroll
    for (int mt = 0; mt < 2; mt++)
        #pragma unroll
        for (int nt = 0; nt < 4; nt++)
            #pragma unroll
            for (int e = 0; e < 4; e++) acc[mt][nt][e] = 0.f;

    for (int c = 0; c < 256; c += 32) {
        const __half* src = &g_qf[((size_t)h * NTOK + n) * MF + c];
        #pragma unroll
        for (int j = 0; j < 4; j++) {
            int col = ((t & 1) * 4 + j) * 4;
            float2 f0 = __half22float2(*(const __half2*)&src[col]);
            float2 f1 = __half22float2(*(const __half2*)&src[col + 2]);
            float4 w;
            w.x = RATIO * (ex2f(fmaf(f0.x, L2E, -cc)) + 1e-4f);
            w.y = RATIO * (ex2f(fmaf(f0.y, L2E, -cc)) + 1e-4f);
            w.z = RATIO * (ex2f(fmaf(f1.x, L2E, -cc)) + 1e-4f);
            w.w = RATIO * (ex2f(fmaf(f1.y, L2E, -cc)) + 1e-4f);
            *(__half2*)&As[sr * ATS + col] = __floats2half2_rn(w.x, w.y);
            *(__half2*)&As[sr * ATS + col + 2] = __floats2half2_rn(w.z, w.w);
            denp += w.x * ksums[c + col] + w.y * ksums[c + col + 1]
                  + w.z * ksums[c + col + 2] + w.w * ksums[c + col + 3];
        }
        #pragma unroll
        for (int j = 0; j < 2; j++) {
            int fi = t * 2 + j;
            int row = fi >> 4, col4 = (fi & 15) * 4;
            float4 v = *(const float4*)&g_ctx[(size_t)h * MF * DH + (size_t)(c + row) * DH + col4];
            Bs[(col4 + 0) * ATS + row] = __float2half(v.x);
            Bs[(col4 + 1) * ATS + row] = __float2half(v.y);
            Bs[(col4 + 2) * ATS + row] = __float2half(v.z);
            Bs[(col4 + 3) * ATS + row] = __float2half(v.w);
        }
        __syncthreads();
        const uint32_t* aw = (const uint32_t*)As;
        const uint32_t* bw = (const uint32_t*)Bs;
        #pragma unroll
        for (int ks = 0; ks < 2; ks++) {
            uint32_t af[2][4], bf[4][2];
            #pragma unroll
            for (int mt = 0; mt < 2; mt++) {
                int m = warp_m + mt * 16 + g;
                af[mt][0] = aw[m * 20 + ks * 8 + q];
                af[mt][1] = aw[(m + 8) * 20 + ks * 8 + q];
                af[mt][2] = aw[m * 20 + ks * 8 + q + 4];
                af[mt][3] = aw[(m + 8) * 20 + ks * 8 + q + 4];
            }
            #pragma unroll
            for (int nt = 0; nt < 4; nt++) {
                int d = warp_n + nt * 8 + g;
                bf[nt][0] = bw[d * 20 + ks * 8 + q];
                bf[nt][1] = bw[d * 20 + ks * 8 + q + 4];
            }
            #pragma unroll
            for (int mt = 0; mt < 2; mt++)
                #pragma unroll
                for (int nt = 0; nt < 4; nt++)
                    mma16(acc[mt][nt], af[mt], bf[nt]);
        }
        __syncthreads();
    }

    denp += __shfl_xor_sync(0xffffffffu, denp, 1);
    if ((t & 1) == 0) dens[sr] = denp;
    __syncthreads();

    #pragma unroll
    for (int mt = 0; mt < 2; mt++)
        #pragma unroll
        for (int nt = 0; nt < 4; nt++)
            #pragma unroll
            for (int e = 0; e < 4; e++) {
                int row = warp_m + mt * 16 + g + (e >> 1) * 8;
                int d = warp_n + nt * 8 + q * 2 + (e & 1);
                g_attnh[(size_t)(n0 + row) * DIM + h * DH + d] =
                    __float2half(acc[mt][nt][e] / dens[row]);
            }
}

// ---------------- output head ----------------
__global__ __launch_bounds__(128) void wout_kernel(const float* __restrict__ Wout,
                                                   const float* __restrict__ bout,
                                                   float* __restrict__ out) {
    int n = blockIdx.x, t = threadIdx.x;
    __shared__ float xs[DIM];
    for (int i = t; i < DIM; i += 128) xs[i] = g_h[n * DIM + i];
    __syncthreads();
    if (t < VOCAB) {
        float acc = bout[t];
        for (int k = 0; k < DIM; k++) acc += xs[k] * Wout[k * VOCAB + t];
        out[n * VOCAB + t] = acc;
    }
}

// ---------------- host ----------------
extern "C" void kernel_launch(void* const* d_in, const int* in_sizes, int n_in,
                              void* d_out, int out_size) {
    const float* methy = (const float*)d_in[0];
    const int* chromo = (const int*)d_in[1];
    const int* pos    = (const int*)d_in[2];
    const float* mt = (const float*)d_in[3];
    const float* ct = (const float*)d_in[4];
    const float* pt = (const float*)d_in[5];
    const float* ln1g = (const float*)d_in[6];
    const float* ln1b = (const float*)d_in[7];
    const float* ln2g = (const float*)d_in[8];
    const float* ln2b = (const float*)d_in[9];
    const float* Wq = (const float*)d_in[10];
    const float* Wk = (const float*)d_in[11];
    const float* Wv = (const float*)d_in[12];
    const float* Wo = (const float*)d_in[13];
    const float* bo = (const float*)d_in[14];
    const float* W1 = (const float*)d_in[15];
    const float* b1 = (const float*)d_in[16];
    const float* W2 = (const float*)d_in[17];
    const float* b2 = (const float*)d_in[18];
    const float* proj = (const float*)d_in[19];
    const float* nfg = (const float*)d_in[20];
    const float* nfb = (const float*)d_in[21];
    const float* Wout = (const float*)d_in[22];
    const float* bout = (const float*)d_in[23];
    float* out = (float*)d_out;

    float *px, *ph, *pq, *pk, *pv;
    __half *phh, *pattnh, *pffh, *pwh;
    cudaGetSymbolAddress((void**)&px, g_x);
    cudaGetSymbolAddress((void**)&ph, g_h);
    cudaGetSymbolAddress((void**)&phh, g_hh);
    cudaGetSymbolAddress((void**)&pq, g_q);
    cudaGetSymbolAddress((void**)&pk, g_k);
    cudaGetSymbolAddress((void**)&pv, g_v);
    cudaGetSymbolAddress((void**)&pattnh, g_attnh);
    cudaGetSymbolAddress((void**)&pffh, g_ffh);
    cudaGetSymbolAddress((void**)&pwh, g_wh);

    const int GEMMH_SMEM = HSTAGES * 2 * HAELE * 2;                  // 110,592
    cudaFuncSetAttribute(tgemm_h, cudaFuncAttributeMaxDynamicSharedMemorySize, GEMMH_SMEM);

    wconv_sq<<<dim3(24, 24, DEPTH * 4), 256>>>(Wq, Wk, Wv, Wo);
    wconv_ff<<<dim3(2304, DEPTH, 2), 256>>>(W1, W2);
    embed_kernel<<<NTOK, 256>>>(methy, chromo, pos, mt, ct, pt);

    dim3 gqkv(DIM / 128, NTOK / 128, 3);
    dim3 gsk3(DIM / 128, NTOK / 128, 3);
    dim3 gff(FF / 128, NTOK / 128, 1);
    dim3 gfeat(2, 32, HEADS * 2);
    dim3 gctx(HEADS, 2, NZS);
    dim3 gattn(HEADS, NTOK / 128);

    for (int l = 0; l < DEPTH; l++) {
        const float* pj = proj + (size_t)l * MF * DH;
        const __half* wl = pwh + (size_t)l * LOFF;
        // --- attention ---
        ln_kernel<<<NTOK / 2, 384>>>(px, ln1g + l * DIM, ln1b + l * DIM, nullptr, phh);
        tgemm_h<<<gqkv, 256, GEMMH_SMEM>>>(phh,
            wl + WOQ, wl + WOK, wl + WOV,
            nullptr, pq, pk, pv, DIM, DIM, 0, 1, 0);
        featgemm_kernel<<<gfeat, 256>>>(pj);
        ctxgemm_kernel<<<gctx, 256>>>(methy);
        reduce_kernel<<<192, 256>>>();
        attngemm_kernel<<<gattn, 256>>>();
        tgemm_h<<<gsk3, 256, GEMMH_SMEM>>>(pattnh,
            wl + WOO, nullptr, nullptr,
            bo + l * DIM, px, nullptr, nullptr, DIM, DIM, 0, 3, 0);
        // --- FFN ---
        ln_kernel<<<NTOK / 2, 384>>>(px, ln2g + l * DIM, ln2b + l * DIM, nullptr, phh);
        tgemm_h<<<gff, 256, GEMMH_SMEM>>>(phh,
            wl + WO1, nullptr, nullptr,
            b1 + l * FF, (float*)pffh, nullptr, nullptr, FF, DIM, 1, 1, 1);
        tgemm_h<<<gsk3, 256, GEMMH_SMEM>>>(pffh,
            wl + WO2, nullptr, nullptr,
            b2 + l * DIM, px, nullptr, nullptr, DIM, FF, 0, 3, 0);
    }

    ln_kernel<<<NTOK / 2, 384>>>(px, nfg, nfb, ph, phh);
    wout_kernel<<<NTOK, 128>>>(Wout, bout, out);
}